// round 1
// baseline (speedup 1.0000x reference)
#include <cuda_runtime.h>
#include <math.h>

#define BB   16
#define NN   64
#define PREV 6
#define PRED 30
#define HH   256
#define EE   (NN*(NN-1))      // 4032
#define ROWS_E (BB*EE)        // 64512
#define ROWS_N (BB*NN)        // 1024

// ---------------- static scratch (no runtime allocation) ----------------
__device__ float d_x[ROWS_N*HH];
__device__ float d_xTop[ROWS_N*HH];
__device__ float d_xBot[ROWS_N*HH];
__device__ float d_h1[ROWS_E*HH];
__device__ float d_h2[ROWS_E*HH];
__device__ float d_inc[ROWS_N*HH];
__device__ float d_incsq[ROWS_N*HH];
__device__ float d_outg[ROWS_N*HH];
__device__ float d_nodes[ROWS_N*2*HH];
__device__ float d_nh1[ROWS_N*HH];
__device__ float d_mraw[ROWS_N*HH];
__device__ float d_cat[ROWS_N*2*HH];
__device__ float d_fused[ROWS_N*HH];
__device__ float d_ae[HH], d_ce[HH], d_an[HH], d_cn[HH];
__device__ int   d_recv[EE], d_send[EE];
__device__ int   d_listrec[NN*EE], d_listsend[NN*EE];
__device__ int   d_cntrec[NN], d_cntsend[NN];
__device__ float d_degrec[NN], d_degsend[NN];

__device__ __forceinline__ float elu_f(float x) { return x > 0.f ? x : (expf(x) - 1.f); }

// ---------------- derive edge indices from one-hot matrices ----------------
__global__ void derive_kernel(const float* __restrict__ rel_rec,
                              const float* __restrict__ rel_send,
                              int* __restrict__ recv_idx, int* __restrict__ send_idx) {
    int e = blockIdx.x * blockDim.x + threadIdx.x;
    if (e >= EE) return;
    int r = 0, s = 0; float br = -1.f, bs = -1.f;
    for (int n = 0; n < NN; n++) {
        float vr = rel_rec[e*NN + n];
        float vs = rel_send[e*NN + n];
        if (vr > br) { br = vr; r = n; }
        if (vs > bs) { bs = vs; s = n; }
    }
    recv_idx[e] = r; send_idx[e] = s;
}

// deterministic per-node edge lists (increasing e order)
__global__ void build_lists_kernel(const int* __restrict__ recv_idx,
                                   const int* __restrict__ send_idx,
                                   int* list_rec, int* list_send,
                                   int* cnt_rec, int* cnt_send,
                                   float* deg_rec, float* deg_send) {
    int t = threadIdx.x;  // 128 threads
    if (t < NN) {
        int n = t, c = 0;
        for (int e = 0; e < EE; e++) if (recv_idx[e] == n) list_rec[n*EE + (c++)] = e;
        cnt_rec[n] = c;
        deg_rec[n] = (c == 0) ? 1.f : (float)c;
    } else if (t < 2*NN) {
        int n = t - NN, c = 0;
        for (int e = 0; e < EE; e++) if (send_idx[e] == n) list_send[n*EE + (c++)] = e;
        cnt_send[n] = c;
        deg_send[n] = (c == 0) ? 1.f : (float)c;
    }
}

// ---------------- trajectory embedding: x = rel_pos @ W_traj + b ----------------
__global__ void traj_kernel(const float* __restrict__ centers,
                            const float* __restrict__ W, const float* __restrict__ bias,
                            float* __restrict__ x) {
    int row = blockIdx.x;            // b*N+n
    int h = threadIdx.x;             // 256
    __shared__ float rp[PREV*2];
    if (h < PREV*2) {
        int p = h >> 1, c = h & 1;
        float v = 0.f;
        if (p > 0) v = centers[row*PREV*2 + p*2 + c] - centers[row*PREV*2 + (p-1)*2 + c];
        rp[h] = v;
    }
    __syncthreads();
    float acc = bias[h];
    #pragma unroll
    for (int k = 0; k < PREV*2; k++) acc += rp[k] * W[k*HH + h];
    x[row*HH + h] = acc;
}

// ---------------- generic tiled fp32 GEMM: C = act(A@B + bias) ----------------
// A[M,K] row-major, B[K,N] row-major, C[M,N] row-major.
template<bool ELU>
__global__ void gemm_kernel(const float* __restrict__ A, const float* __restrict__ Bm,
                            const float* __restrict__ bias, float* __restrict__ C,
                            int M, int N, int K) {
    __shared__ float As[64][16];
    __shared__ float Bs[16][64];
    int tid = threadIdx.x;               // 256 threads
    int tx = tid & 15, ty = tid >> 4;
    int row0 = blockIdx.y * 64;
    int col0 = blockIdx.x * 64;
    float acc[4][4] = {};

    int ar = tid >> 2;                   // 0..63
    int akb = (tid & 3) * 4;             // 0,4,8,12

    for (int k0 = 0; k0 < K; k0 += 16) {
        // load A tile (float4 per thread)
        if (row0 + ar < M) {
            const float4 a4 = *reinterpret_cast<const float4*>(&A[(row0 + ar)*K + k0 + akb]);
            As[ar][akb+0] = a4.x; As[ar][akb+1] = a4.y;
            As[ar][akb+2] = a4.z; As[ar][akb+3] = a4.w;
        } else {
            As[ar][akb+0] = 0.f; As[ar][akb+1] = 0.f;
            As[ar][akb+2] = 0.f; As[ar][akb+3] = 0.f;
        }
        // load B tile
        #pragma unroll
        for (int i = 0; i < 4; i++) {
            int li = tid + i*256;
            int kk = li >> 6, cc = li & 63;
            float v = 0.f;
            if (k0 + kk < K && col0 + cc < N) v = Bm[(k0+kk)*N + col0 + cc];
            Bs[kk][cc] = v;
        }
        __syncthreads();
        #pragma unroll
        for (int kk = 0; kk < 16; kk++) {
            float a0 = As[ty   ][kk], a1 = As[ty+16][kk];
            float a2 = As[ty+32][kk], a3 = As[ty+48][kk];
            float b0 = Bs[kk][tx   ], b1 = Bs[kk][tx+16];
            float b2 = Bs[kk][tx+32], b3 = Bs[kk][tx+48];
            acc[0][0] += a0*b0; acc[0][1] += a0*b1; acc[0][2] += a0*b2; acc[0][3] += a0*b3;
            acc[1][0] += a1*b0; acc[1][1] += a1*b1; acc[1][2] += a1*b2; acc[1][3] += a1*b3;
            acc[2][0] += a2*b0; acc[2][1] += a2*b1; acc[2][2] += a2*b2; acc[2][3] += a2*b3;
            acc[3][0] += a3*b0; acc[3][1] += a3*b1; acc[3][2] += a3*b2; acc[3][3] += a3*b3;
        }
        __syncthreads();
    }
    #pragma unroll
    for (int i = 0; i < 4; i++) {
        int r = row0 + ty + 16*i;
        if (r >= M) continue;
        #pragma unroll
        for (int j = 0; j < 4; j++) {
            int cc = col0 + tx + 16*j;
            if (cc >= N) continue;
            float v = acc[i][j];
            if (bias) v += bias[cc];
            if (ELU) v = elu_f(v);
            C[r*N + cc] = v;
        }
    }
}

// ---------------- edge layer-1: gather + add + ELU ----------------
__global__ void edge_h1_kernel(const float* __restrict__ xTop, const float* __restrict__ xBot,
                               const float* __restrict__ b1,
                               const int* __restrict__ recv_idx, const int* __restrict__ send_idx,
                               float* __restrict__ h1) {
    int row = blockIdx.x;                // 0..ROWS_E-1
    int h = threadIdx.x;
    int b = row / EE, e = row - b*EE;
    float v = xTop[(b*NN + recv_idx[e])*HH + h]
            + xBot[(b*NN + send_idx[e])*HH + h] + b1[h];
    h1[row*HH + h] = elu_f(v);
}

// ---------------- per-node gather-sum of h2 + per-node sum-of-squares ----------------
__global__ void incoming_kernel(const float* __restrict__ h2,
                                const int* __restrict__ list_rec, const int* __restrict__ cnt_rec,
                                float* __restrict__ inc_raw, float* __restrict__ sq_part) {
    int b = blockIdx.x >> 6, n = blockIdx.x & 63;
    int h = threadIdx.x;
    int cnt = cnt_rec[n];
    float acc = 0.f, accsq = 0.f;
    for (int k = 0; k < cnt; k++) {
        int e = list_rec[n*EE + k];
        float v = h2[(b*EE + e)*HH + h];
        acc += v; accsq += v*v;
    }
    inc_raw[blockIdx.x*HH + h] = acc;
    sq_part[blockIdx.x*HH + h] = accsq;
}

__global__ void outgoing_kernel(const float* __restrict__ h2,
                                const int* __restrict__ list_send, const int* __restrict__ cnt_send,
                                float* __restrict__ out_raw) {
    int b = blockIdx.x >> 6, n = blockIdx.x & 63;
    int h = threadIdx.x;
    int cnt = cnt_send[n];
    float acc = 0.f;
    for (int k = 0; k < cnt; k++) {
        int e = list_send[n*EE + k];
        acc += h2[(b*EE + e)*HH + h];
    }
    out_raw[blockIdx.x*HH + h] = acc;
}

// ---------------- BN stats -> affine (a,c): deterministic tree reduce ----------------
// SRC_SQ=false: sums sum_part and sq_part columns; SRC_SQ=true: sq computed from sum_part values.
template<bool SRC_SQ>
__global__ void stats_kernel(const float* __restrict__ sum_part, const float* __restrict__ sq_part,
                             const float* __restrict__ gamma, const float* __restrict__ beta,
                             float* __restrict__ a, float* __restrict__ c,
                             int nrows, float count) {
    int h = blockIdx.x;
    float s = 0.f, sq = 0.f;
    for (int r = threadIdx.x; r < nrows; r += 256) {
        float v = sum_part[r*HH + h];
        s += v;
        if (SRC_SQ) sq += v*v; else sq += sq_part[r*HH + h];
    }
    __shared__ float ss[256], ssq[256];
    ss[threadIdx.x] = s; ssq[threadIdx.x] = sq;
    __syncthreads();
    for (int st = 128; st > 0; st >>= 1) {
        if (threadIdx.x < st) { ss[threadIdx.x] += ss[threadIdx.x+st]; ssq[threadIdx.x] += ssq[threadIdx.x+st]; }
        __syncthreads();
    }
    if (threadIdx.x == 0) {
        float mu = ss[0] / count;
        float var = ssq[0] / count - mu*mu;
        float av = gamma[h] * rsqrtf(var + 1e-5f);
        a[h] = av;
        c[h] = beta[h] - mu * av;
    }
}

// ---------------- build node-MLP input: [a*(inc/deg)+c , a*(out/deg)+c] ----------------
__global__ void build_nodes_kernel(const float* __restrict__ inc_raw, const float* __restrict__ out_raw,
                                   const float* __restrict__ a, const float* __restrict__ c,
                                   const float* __restrict__ deg_rec, const float* __restrict__ deg_send,
                                   float* __restrict__ nodes) {
    int row = blockIdx.x;
    int h = threadIdx.x;
    int n = row & 63;
    float av = a[h], cv = c[h];
    nodes[row*2*HH + h]      = av * (inc_raw[row*HH + h] / deg_rec[n])  + cv;
    nodes[row*2*HH + HH + h] = av * (out_raw[row*HH + h] / deg_send[n]) + cv;
}

// ---------------- build fuse input: [x , a*m_raw + c] ----------------
__global__ void build_cat_kernel(const float* __restrict__ x, const float* __restrict__ mraw,
                                 const float* __restrict__ a, const float* __restrict__ c,
                                 float* __restrict__ cat) {
    int row = blockIdx.x;
    int h = threadIdx.x;
    cat[row*2*HH + h]      = x[row*HH + h];
    cat[row*2*HH + HH + h] = a[h] * mraw[row*HH + h] + c[h];
}

// ---------------- cumsum + add current location ----------------
__global__ void pos_kernel(const float* __restrict__ rel, const float* __restrict__ centers,
                           float* __restrict__ pos_out) {
    int t = blockIdx.x * blockDim.x + threadIdx.x;
    if (t >= ROWS_N*2) return;
    int row = t >> 1, cdim = t & 1;
    float cur = centers[row*PREV*2 + (PREV-1)*2 + cdim];
    float acc = 0.f;
    for (int p = 0; p < PRED; p++) {
        acc += rel[row*PRED*2 + p*2 + cdim];
        pos_out[row*PRED*2 + p*2 + cdim] = acc + cur;
    }
}

// ---------------- launcher ----------------
extern "C" void kernel_launch(void* const* d_in, const int* in_sizes, int n_in,
                              void* d_out, int out_size) {
    const float* centers  = (const float*)d_in[0];
    const float* rel_rec  = (const float*)d_in[1];
    const float* rel_send = (const float*)d_in[2];
    const float* W_traj   = (const float*)d_in[3];
    const float* b_traj   = (const float*)d_in[4];
    const float* n2e_W1   = (const float*)d_in[5];
    const float* n2e_b1   = (const float*)d_in[6];
    const float* n2e_W2   = (const float*)d_in[7];
    const float* n2e_b2   = (const float*)d_in[8];
    const float* n2e_g    = (const float*)d_in[9];
    const float* n2e_be   = (const float*)d_in[10];
    const float* e2n_W1   = (const float*)d_in[11];
    const float* e2n_b1   = (const float*)d_in[12];
    const float* e2n_W2   = (const float*)d_in[13];
    const float* e2n_b2   = (const float*)d_in[14];
    const float* e2n_g    = (const float*)d_in[15];
    const float* e2n_be   = (const float*)d_in[16];
    const float* W_fuse   = (const float*)d_in[17];
    const float* b_fuse   = (const float*)d_in[18];
    const float* W_pred   = (const float*)d_in[19];
    const float* b_pred   = (const float*)d_in[20];
    float* out = (float*)d_out;

    float *p_x, *p_xTop, *p_xBot, *p_h1, *p_h2, *p_inc, *p_incsq, *p_outg;
    float *p_nodes, *p_nh1, *p_mraw, *p_cat, *p_fused;
    float *p_ae, *p_ce, *p_an, *p_cn, *p_degrec, *p_degsend;
    int *p_recv, *p_send, *p_lr, *p_ls, *p_cr, *p_cs;
    cudaGetSymbolAddress((void**)&p_x, d_x);
    cudaGetSymbolAddress((void**)&p_xTop, d_xTop);
    cudaGetSymbolAddress((void**)&p_xBot, d_xBot);
    cudaGetSymbolAddress((void**)&p_h1, d_h1);
    cudaGetSymbolAddress((void**)&p_h2, d_h2);
    cudaGetSymbolAddress((void**)&p_inc, d_inc);
    cudaGetSymbolAddress((void**)&p_incsq, d_incsq);
    cudaGetSymbolAddress((void**)&p_outg, d_outg);
    cudaGetSymbolAddress((void**)&p_nodes, d_nodes);
    cudaGetSymbolAddress((void**)&p_nh1, d_nh1);
    cudaGetSymbolAddress((void**)&p_mraw, d_mraw);
    cudaGetSymbolAddress((void**)&p_cat, d_cat);
    cudaGetSymbolAddress((void**)&p_fused, d_fused);
    cudaGetSymbolAddress((void**)&p_ae, d_ae);
    cudaGetSymbolAddress((void**)&p_ce, d_ce);
    cudaGetSymbolAddress((void**)&p_an, d_an);
    cudaGetSymbolAddress((void**)&p_cn, d_cn);
    cudaGetSymbolAddress((void**)&p_degrec, d_degrec);
    cudaGetSymbolAddress((void**)&p_degsend, d_degsend);
    cudaGetSymbolAddress((void**)&p_recv, d_recv);
    cudaGetSymbolAddress((void**)&p_send, d_send);
    cudaGetSymbolAddress((void**)&p_lr, d_listrec);
    cudaGetSymbolAddress((void**)&p_ls, d_listsend);
    cudaGetSymbolAddress((void**)&p_cr, d_cntrec);
    cudaGetSymbolAddress((void**)&p_cs, d_cntsend);

    // 1. edge indices + lists
    derive_kernel<<<(EE+255)/256, 256>>>(rel_rec, rel_send, p_recv, p_send);
    build_lists_kernel<<<1, 128>>>(p_recv, p_send, p_lr, p_ls, p_cr, p_cs, p_degrec, p_degsend);

    // 2. trajectory embedding
    traj_kernel<<<ROWS_N, HH>>>(centers, W_traj, b_traj, p_x);

    // 3. pre-edge products: xTop = x@W1[:256], xBot = x@W1[256:]
    gemm_kernel<false><<<dim3(HH/64, ROWS_N/64), 256>>>(p_x, n2e_W1,            nullptr, p_xTop, ROWS_N, HH, HH);
    gemm_kernel<false><<<dim3(HH/64, ROWS_N/64), 256>>>(p_x, n2e_W1 + HH*HH,    nullptr, p_xBot, ROWS_N, HH, HH);

    // 4. edge MLP
    edge_h1_kernel<<<ROWS_E, HH>>>(p_xTop, p_xBot, n2e_b1, p_recv, p_send, p_h1);
    gemm_kernel<true><<<dim3(HH/64, ROWS_E/64), 256>>>(p_h1, n2e_W2, n2e_b2, p_h2, ROWS_E, HH, HH);

    // 5. scatter sums + edge BN stats
    incoming_kernel<<<ROWS_N, HH>>>(p_h2, p_lr, p_cr, p_inc, p_incsq);
    outgoing_kernel<<<ROWS_N, HH>>>(p_h2, p_ls, p_cs, p_outg);
    stats_kernel<false><<<HH, 256>>>(p_inc, p_incsq, n2e_g, n2e_be, p_ae, p_ce, ROWS_N, (float)ROWS_E);

    // 6. node MLP
    build_nodes_kernel<<<ROWS_N, HH>>>(p_inc, p_outg, p_ae, p_ce, p_degrec, p_degsend, p_nodes);
    gemm_kernel<true><<<dim3(HH/64, ROWS_N/64), 256>>>(p_nodes, e2n_W1, e2n_b1, p_nh1, ROWS_N, HH, 2*HH);
    gemm_kernel<true><<<dim3(HH/64, ROWS_N/64), 256>>>(p_nh1, e2n_W2, e2n_b2, p_mraw, ROWS_N, HH, HH);
    stats_kernel<true><<<HH, 256>>>(p_mraw, nullptr, e2n_g, e2n_be, p_an, p_cn, ROWS_N, (float)ROWS_N);

    // 7. fuse + predict
    build_cat_kernel<<<ROWS_N, HH>>>(p_x, p_mraw, p_an, p_cn, p_cat);
    gemm_kernel<false><<<dim3(HH/64, ROWS_N/64), 256>>>(p_cat, W_fuse, b_fuse, p_fused, ROWS_N, HH, 2*HH);
    gemm_kernel<false><<<dim3(1, ROWS_N/64), 256>>>(p_fused, W_pred, b_pred, out, ROWS_N, PRED*2, HH);

    // 8. cumulative positions
    pos_kernel<<<(ROWS_N*2+255)/256, 256>>>(out, centers, out + ROWS_N*PRED*2);
}

// round 2
// speedup vs baseline: 1.3028x; 1.3028x over previous
#include <cuda_runtime.h>
#include <math.h>

#define BB   16
#define NN   64
#define PREV 6
#define PRED 30
#define HH   256
#define EE   (NN*(NN-1))      // 4032
#define ROWS_E (BB*EE)        // 64512
#define ROWS_N (BB*NN)        // 1024

// ---------------- static scratch (no runtime allocation) ----------------
__device__ float d_x[ROWS_N*HH];
__device__ float d_xTop[ROWS_N*HH];
__device__ float d_xBot[ROWS_N*HH];
__device__ float d_h2[ROWS_E*HH];
__device__ float d_inc[ROWS_N*HH];
__device__ float d_incsq[ROWS_N*HH];
__device__ float d_outg[ROWS_N*HH];
__device__ float d_nodes[ROWS_N*2*HH];
__device__ float d_nh1[ROWS_N*HH];
__device__ float d_mraw[ROWS_N*HH];
__device__ float d_cat[ROWS_N*2*HH];
__device__ float d_fused[ROWS_N*HH];
__device__ float d_ae[HH], d_ce[HH], d_an[HH], d_cn[HH];
__device__ int   d_recv[EE], d_send[EE];
__device__ int   d_listrec[NN*EE], d_listsend[NN*EE];
__device__ int   d_cntrec[NN], d_cntsend[NN];
__device__ float d_degrec[NN], d_degsend[NN];

__device__ __forceinline__ float elu_f(float x) { return x > 0.f ? x : (expf(x) - 1.f); }

__device__ __forceinline__ unsigned f2tf32(float x) {
    unsigned r;
    asm("cvt.rna.tf32.f32 %0, %1;" : "=r"(r) : "f"(x));
    return r;
}

// ---------------- derive edge indices from one-hot matrices ----------------
__global__ void derive_kernel(const float* __restrict__ rel_rec,
                              const float* __restrict__ rel_send,
                              int* __restrict__ recv_idx, int* __restrict__ send_idx) {
    int e = blockIdx.x * blockDim.x + threadIdx.x;
    if (e >= EE) return;
    int r = 0, s = 0; float br = -1.f, bs = -1.f;
    for (int n = 0; n < NN; n++) {
        float vr = rel_rec[e*NN + n];
        float vs = rel_send[e*NN + n];
        if (vr > br) { br = vr; r = n; }
        if (vs > bs) { bs = vs; s = n; }
    }
    recv_idx[e] = r; send_idx[e] = s;
}

__global__ void build_lists_kernel(const int* __restrict__ recv_idx,
                                   const int* __restrict__ send_idx,
                                   int* list_rec, int* list_send,
                                   int* cnt_rec, int* cnt_send,
                                   float* deg_rec, float* deg_send) {
    int t = threadIdx.x;  // 128 threads
    if (t < NN) {
        int n = t, c = 0;
        for (int e = 0; e < EE; e++) if (recv_idx[e] == n) list_rec[n*EE + (c++)] = e;
        cnt_rec[n] = c;
        deg_rec[n] = (c == 0) ? 1.f : (float)c;
    } else if (t < 2*NN) {
        int n = t - NN, c = 0;
        for (int e = 0; e < EE; e++) if (send_idx[e] == n) list_send[n*EE + (c++)] = e;
        cnt_send[n] = c;
        deg_send[n] = (c == 0) ? 1.f : (float)c;
    }
}

// ---------------- trajectory embedding ----------------
__global__ void traj_kernel(const float* __restrict__ centers,
                            const float* __restrict__ W, const float* __restrict__ bias,
                            float* __restrict__ x) {
    int row = blockIdx.x;
    int h = threadIdx.x;
    __shared__ float rp[PREV*2];
    if (h < PREV*2) {
        int p = h >> 1, c = h & 1;
        float v = 0.f;
        if (p > 0) v = centers[row*PREV*2 + p*2 + c] - centers[row*PREV*2 + (p-1)*2 + c];
        rp[h] = v;
    }
    __syncthreads();
    float acc = bias[h];
    #pragma unroll
    for (int k = 0; k < PREV*2; k++) acc += rp[k] * W[k*HH + h];
    x[row*HH + h] = acc;
}

// ---------------- generic tiled fp32 GEMM (small matrices) ----------------
template<bool ELU>
__global__ void gemm_kernel(const float* __restrict__ A, const float* __restrict__ Bm,
                            const float* __restrict__ bias, float* __restrict__ C,
                            int M, int N, int K) {
    __shared__ float As[64][16];
    __shared__ float Bs[16][64];
    int tid = threadIdx.x;
    int tx = tid & 15, ty = tid >> 4;
    int row0 = blockIdx.y * 64;
    int col0 = blockIdx.x * 64;
    float acc[4][4] = {};
    int ar = tid >> 2;
    int akb = (tid & 3) * 4;

    for (int k0 = 0; k0 < K; k0 += 16) {
        if (row0 + ar < M) {
            const float4 a4 = *reinterpret_cast<const float4*>(&A[(row0 + ar)*K + k0 + akb]);
            As[ar][akb+0] = a4.x; As[ar][akb+1] = a4.y;
            As[ar][akb+2] = a4.z; As[ar][akb+3] = a4.w;
        } else {
            As[ar][akb+0] = 0.f; As[ar][akb+1] = 0.f;
            As[ar][akb+2] = 0.f; As[ar][akb+3] = 0.f;
        }
        #pragma unroll
        for (int i = 0; i < 4; i++) {
            int li = tid + i*256;
            int kk = li >> 6, cc = li & 63;
            float v = 0.f;
            if (k0 + kk < K && col0 + cc < N) v = Bm[(k0+kk)*N + col0 + cc];
            Bs[kk][cc] = v;
        }
        __syncthreads();
        #pragma unroll
        for (int kk = 0; kk < 16; kk++) {
            float a0 = As[ty   ][kk], a1 = As[ty+16][kk];
            float a2 = As[ty+32][kk], a3 = As[ty+48][kk];
            float b0 = Bs[kk][tx   ], b1 = Bs[kk][tx+16];
            float b2 = Bs[kk][tx+32], b3 = Bs[kk][tx+48];
            acc[0][0] += a0*b0; acc[0][1] += a0*b1; acc[0][2] += a0*b2; acc[0][3] += a0*b3;
            acc[1][0] += a1*b0; acc[1][1] += a1*b1; acc[1][2] += a1*b2; acc[1][3] += a1*b3;
            acc[2][0] += a2*b0; acc[2][1] += a2*b1; acc[2][2] += a2*b2; acc[2][3] += a2*b3;
            acc[3][0] += a3*b0; acc[3][1] += a3*b1; acc[3][2] += a3*b2; acc[3][3] += a3*b3;
        }
        __syncthreads();
    }
    #pragma unroll
    for (int i = 0; i < 4; i++) {
        int r = row0 + ty + 16*i;
        if (r >= M) continue;
        #pragma unroll
        for (int j = 0; j < 4; j++) {
            int cc = col0 + tx + 16*j;
            if (cc >= N) continue;
            float v = acc[i][j];
            if (bias) v += bias[cc];
            if (ELU) v = elu_f(v);
            C[r*N + cc] = v;
        }
    }
}

// =======================================================================
// Fused edge GEMM (THE big one): h2 = elu( elu(xTop[recv]+xBot[send]+b1) @ W2 + b2 )
// tf32 tensor cores, mma.sync m16n8k8. Block tile 128x64, K-step 32.
// 256 threads = 8 warps arranged 4 (M) x 2 (N): warp tile 32x32.
// =======================================================================
__global__ __launch_bounds__(256)
void edge_gemm2_kernel(const float* __restrict__ xTop, const float* __restrict__ xBot,
                       const float* __restrict__ b1,
                       const float* __restrict__ W2, const float* __restrict__ b2,
                       const int* __restrict__ recv_idx, const int* __restrict__ send_idx,
                       float* __restrict__ h2) {
    // A stored k-major: AsT[k][row], padded row-dim 136 for conflict-free frag loads
    __shared__ unsigned AsT[32][136];
    __shared__ unsigned Bs[32][72];
    __shared__ int topBase[128], botBase[128];

    const int tid  = threadIdx.x;
    const int lane = tid & 31;
    const int warp = tid >> 5;
    const int warpM = warp & 3;          // 0..3 -> M rows warpM*32
    const int warpN = warp >> 2;         // 0..1 -> N cols warpN*32
    const int row0 = blockIdx.y * 128;
    const int col0 = blockIdx.x * 64;

    // gather bases
    if (tid < 128) {
        int grow = row0 + tid;
        int b = grow / EE;
        int e = grow - b * EE;
        topBase[tid] = (b*NN + recv_idx[e]) * HH;
        botBase[tid] = (b*NN + send_idx[e]) * HH;
    }
    __syncthreads();

    float acc[2][4][4] = {};   // [mtile][ntile][4 regs]

    const int g = lane >> 2;       // 0..7
    const int t4 = lane & 3;       // 0..3
    const int mrow0 = warpM * 32;
    const int ncol0 = warpN * 32;

    for (int k0 = 0; k0 < HH; k0 += 32) {
        // ---- A tile: 128 rows x 32 cols, built from gather+add+bias+elu, tf32 ----
        #pragma unroll
        for (int it = 0; it < 4; it++) {
            int task = it*256 + tid;         // 0..1023
            int row  = task & 127;
            int cg   = task >> 7;            // 0..7 (4-col group)
            int cb   = k0 + cg*4;
            float4 a = *reinterpret_cast<const float4*>(&xTop[topBase[row] + cb]);
            float4 bv = *reinterpret_cast<const float4*>(&xBot[botBase[row] + cb]);
            float4 bb = *reinterpret_cast<const float4*>(&b1[cb]);
            AsT[cg*4+0][row] = f2tf32(elu_f(a.x + bv.x + bb.x));
            AsT[cg*4+1][row] = f2tf32(elu_f(a.y + bv.y + bb.y));
            AsT[cg*4+2][row] = f2tf32(elu_f(a.z + bv.z + bb.z));
            AsT[cg*4+3][row] = f2tf32(elu_f(a.w + bv.w + bb.w));
        }
        // ---- B tile: 32 k x 64 n ----
        #pragma unroll
        for (int it = 0; it < 8; it++) {
            int task = it*256 + tid;         // 0..2047
            int kk = task >> 6, cc = task & 63;
            Bs[kk][cc] = f2tf32(W2[(k0+kk)*HH + col0 + cc]);
        }
        __syncthreads();

        // ---- MMA: 4 k-substeps of 8 ----
        #pragma unroll
        for (int ks = 0; ks < 32; ks += 8) {
            unsigned afr[2][4];
            #pragma unroll
            for (int i = 0; i < 2; i++) {
                int r = mrow0 + i*16;
                afr[i][0] = AsT[ks + t4    ][r + g    ];
                afr[i][1] = AsT[ks + t4    ][r + g + 8];
                afr[i][2] = AsT[ks + t4 + 4][r + g    ];
                afr[i][3] = AsT[ks + t4 + 4][r + g + 8];
            }
            unsigned bfr[4][2];
            #pragma unroll
            for (int j = 0; j < 4; j++) {
                int c = ncol0 + j*8 + g;
                bfr[j][0] = Bs[ks + t4    ][c];
                bfr[j][1] = Bs[ks + t4 + 4][c];
            }
            #pragma unroll
            for (int i = 0; i < 2; i++) {
                #pragma unroll
                for (int j = 0; j < 4; j++) {
                    asm volatile(
                        "mma.sync.aligned.m16n8k8.row.col.f32.tf32.tf32.f32 "
                        "{%0,%1,%2,%3}, {%4,%5,%6,%7}, {%8,%9}, {%0,%1,%2,%3};"
                        : "+f"(acc[i][j][0]), "+f"(acc[i][j][1]),
                          "+f"(acc[i][j][2]), "+f"(acc[i][j][3])
                        : "r"(afr[i][0]), "r"(afr[i][1]), "r"(afr[i][2]), "r"(afr[i][3]),
                          "r"(bfr[j][0]), "r"(bfr[j][1]));
                }
            }
        }
        __syncthreads();
    }

    // ---- epilogue: bias + elu + store ----
    #pragma unroll
    for (int i = 0; i < 2; i++) {
        int r_lo = row0 + mrow0 + i*16 + g;
        #pragma unroll
        for (int j = 0; j < 4; j++) {
            int c = col0 + ncol0 + j*8 + t4*2;
            float bb0 = b2[c], bb1 = b2[c+1];
            h2[(long)r_lo*HH + c    ] = elu_f(acc[i][j][0] + bb0);
            h2[(long)r_lo*HH + c + 1] = elu_f(acc[i][j][1] + bb1);
            h2[(long)(r_lo+8)*HH + c    ] = elu_f(acc[i][j][2] + bb0);
            h2[(long)(r_lo+8)*HH + c + 1] = elu_f(acc[i][j][3] + bb1);
        }
    }
}

// ---------------- per-node gather-sums ----------------
__global__ void incoming_kernel(const float* __restrict__ h2,
                                const int* __restrict__ list_rec, const int* __restrict__ cnt_rec,
                                float* __restrict__ inc_raw, float* __restrict__ sq_part) {
    int b = blockIdx.x >> 6, n = blockIdx.x & 63;
    int h = threadIdx.x;
    int cnt = cnt_rec[n];
    float acc = 0.f, accsq = 0.f;
    for (int k = 0; k < cnt; k++) {
        int e = list_rec[n*EE + k];
        float v = h2[(b*EE + e)*HH + h];
        acc += v; accsq += v*v;
    }
    inc_raw[blockIdx.x*HH + h] = acc;
    sq_part[blockIdx.x*HH + h] = accsq;
}

__global__ void outgoing_kernel(const float* __restrict__ h2,
                                const int* __restrict__ list_send, const int* __restrict__ cnt_send,
                                float* __restrict__ out_raw) {
    int b = blockIdx.x >> 6, n = blockIdx.x & 63;
    int h = threadIdx.x;
    int cnt = cnt_send[n];
    float acc = 0.f;
    for (int k = 0; k < cnt; k++) {
        int e = list_send[n*EE + k];
        acc += h2[(b*EE + e)*HH + h];
    }
    out_raw[blockIdx.x*HH + h] = acc;
}

// ---------------- BN stats -> affine (a,c) ----------------
template<bool SRC_SQ>
__global__ void stats_kernel(const float* __restrict__ sum_part, const float* __restrict__ sq_part,
                             const float* __restrict__ gamma, const float* __restrict__ beta,
                             float* __restrict__ a, float* __restrict__ c,
                             int nrows, float count) {
    int h = blockIdx.x;
    float s = 0.f, sq = 0.f;
    for (int r = threadIdx.x; r < nrows; r += 256) {
        float v = sum_part[r*HH + h];
        s += v;
        if (SRC_SQ) sq += v*v; else sq += sq_part[r*HH + h];
    }
    __shared__ float ss[256], ssq[256];
    ss[threadIdx.x] = s; ssq[threadIdx.x] = sq;
    __syncthreads();
    for (int st = 128; st > 0; st >>= 1) {
        if (threadIdx.x < st) { ss[threadIdx.x] += ss[threadIdx.x+st]; ssq[threadIdx.x] += ssq[threadIdx.x+st]; }
        __syncthreads();
    }
    if (threadIdx.x == 0) {
        float mu = ss[0] / count;
        float var = ssq[0] / count - mu*mu;
        float av = gamma[h] * rsqrtf(var + 1e-5f);
        a[h] = av;
        c[h] = beta[h] - mu * av;
    }
}

__global__ void build_nodes_kernel(const float* __restrict__ inc_raw, const float* __restrict__ out_raw,
                                   const float* __restrict__ a, const float* __restrict__ c,
                                   const float* __restrict__ deg_rec, const float* __restrict__ deg_send,
                                   float* __restrict__ nodes) {
    int row = blockIdx.x;
    int h = threadIdx.x;
    int n = row & 63;
    float av = a[h], cv = c[h];
    nodes[row*2*HH + h]      = av * (inc_raw[row*HH + h] / deg_rec[n])  + cv;
    nodes[row*2*HH + HH + h] = av * (out_raw[row*HH + h] / deg_send[n]) + cv;
}

__global__ void build_cat_kernel(const float* __restrict__ x, const float* __restrict__ mraw,
                                 const float* __restrict__ a, const float* __restrict__ c,
                                 float* __restrict__ cat) {
    int row = blockIdx.x;
    int h = threadIdx.x;
    cat[row*2*HH + h]      = x[row*HH + h];
    cat[row*2*HH + HH + h] = a[h] * mraw[row*HH + h] + c[h];
}

__global__ void pos_kernel(const float* __restrict__ rel, const float* __restrict__ centers,
                           float* __restrict__ pos_out) {
    int t = blockIdx.x * blockDim.x + threadIdx.x;
    if (t >= ROWS_N*2) return;
    int row = t >> 1, cdim = t & 1;
    float cur = centers[row*PREV*2 + (PREV-1)*2 + cdim];
    float acc = 0.f;
    for (int p = 0; p < PRED; p++) {
        acc += rel[row*PRED*2 + p*2 + cdim];
        pos_out[row*PRED*2 + p*2 + cdim] = acc + cur;
    }
}

// ---------------- launcher ----------------
extern "C" void kernel_launch(void* const* d_in, const int* in_sizes, int n_in,
                              void* d_out, int out_size) {
    const float* centers  = (const float*)d_in[0];
    const float* rel_rec  = (const float*)d_in[1];
    const float* rel_send = (const float*)d_in[2];
    const float* W_traj   = (const float*)d_in[3];
    const float* b_traj   = (const float*)d_in[4];
    const float* n2e_W1   = (const float*)d_in[5];
    const float* n2e_b1   = (const float*)d_in[6];
    const float* n2e_W2   = (const float*)d_in[7];
    const float* n2e_b2   = (const float*)d_in[8];
    const float* n2e_g    = (const float*)d_in[9];
    const float* n2e_be   = (const float*)d_in[10];
    const float* e2n_W1   = (const float*)d_in[11];
    const float* e2n_b1   = (const float*)d_in[12];
    const float* e2n_W2   = (const float*)d_in[13];
    const float* e2n_b2   = (const float*)d_in[14];
    const float* e2n_g    = (const float*)d_in[15];
    const float* e2n_be   = (const float*)d_in[16];
    const float* W_fuse   = (const float*)d_in[17];
    const float* b_fuse   = (const float*)d_in[18];
    const float* W_pred   = (const float*)d_in[19];
    const float* b_pred   = (const float*)d_in[20];
    float* out = (float*)d_out;

    float *p_x, *p_xTop, *p_xBot, *p_h2, *p_inc, *p_incsq, *p_outg;
    float *p_nodes, *p_nh1, *p_mraw, *p_cat, *p_fused;
    float *p_ae, *p_ce, *p_an, *p_cn, *p_degrec, *p_degsend;
    int *p_recv, *p_send, *p_lr, *p_ls, *p_cr, *p_cs;
    cudaGetSymbolAddress((void**)&p_x, d_x);
    cudaGetSymbolAddress((void**)&p_xTop, d_xTop);
    cudaGetSymbolAddress((void**)&p_xBot, d_xBot);
    cudaGetSymbolAddress((void**)&p_h2, d_h2);
    cudaGetSymbolAddress((void**)&p_inc, d_inc);
    cudaGetSymbolAddress((void**)&p_incsq, d_incsq);
    cudaGetSymbolAddress((void**)&p_outg, d_outg);
    cudaGetSymbolAddress((void**)&p_nodes, d_nodes);
    cudaGetSymbolAddress((void**)&p_nh1, d_nh1);
    cudaGetSymbolAddress((void**)&p_mraw, d_mraw);
    cudaGetSymbolAddress((void**)&p_cat, d_cat);
    cudaGetSymbolAddress((void**)&p_fused, d_fused);
    cudaGetSymbolAddress((void**)&p_ae, d_ae);
    cudaGetSymbolAddress((void**)&p_ce, d_ce);
    cudaGetSymbolAddress((void**)&p_an, d_an);
    cudaGetSymbolAddress((void**)&p_cn, d_cn);
    cudaGetSymbolAddress((void**)&p_degrec, d_degrec);
    cudaGetSymbolAddress((void**)&p_degsend, d_degsend);
    cudaGetSymbolAddress((void**)&p_recv, d_recv);
    cudaGetSymbolAddress((void**)&p_send, d_send);
    cudaGetSymbolAddress((void**)&p_lr, d_listrec);
    cudaGetSymbolAddress((void**)&p_ls, d_listsend);
    cudaGetSymbolAddress((void**)&p_cr, d_cntrec);
    cudaGetSymbolAddress((void**)&p_cs, d_cntsend);

    // 1. edge indices + lists
    derive_kernel<<<(EE+255)/256, 256>>>(rel_rec, rel_send, p_recv, p_send);
    build_lists_kernel<<<1, 128>>>(p_recv, p_send, p_lr, p_ls, p_cr, p_cs, p_degrec, p_degsend);

    // 2. trajectory embedding
    traj_kernel<<<ROWS_N, HH>>>(centers, W_traj, b_traj, p_x);

    // 3. pre-edge products: xTop = x@W1[:256], xBot = x@W1[256:]
    gemm_kernel<false><<<dim3(HH/64, ROWS_N/64), 256>>>(p_x, n2e_W1,         nullptr, p_xTop, ROWS_N, HH, HH);
    gemm_kernel<false><<<dim3(HH/64, ROWS_N/64), 256>>>(p_x, n2e_W1 + HH*HH, nullptr, p_xBot, ROWS_N, HH, HH);

    // 4. fused edge MLP (gather + elu + tf32 tensor GEMM + bias + elu)
    edge_gemm2_kernel<<<dim3(HH/64, ROWS_E/128), 256>>>(p_xTop, p_xBot, n2e_b1,
                                                        n2e_W2, n2e_b2,
                                                        p_recv, p_send, p_h2);

    // 5. scatter sums + edge BN stats
    incoming_kernel<<<ROWS_N, HH>>>(p_h2, p_lr, p_cr, p_inc, p_incsq);
    outgoing_kernel<<<ROWS_N, HH>>>(p_h2, p_ls, p_cs, p_outg);
    stats_kernel<false><<<HH, 256>>>(p_inc, p_incsq, n2e_g, n2e_be, p_ae, p_ce, ROWS_N, (float)ROWS_E);

    // 6. node MLP
    build_nodes_kernel<<<ROWS_N, HH>>>(p_inc, p_outg, p_ae, p_ce, p_degrec, p_degsend, p_nodes);
    gemm_kernel<true><<<dim3(HH/64, ROWS_N/64), 256>>>(p_nodes, e2n_W1, e2n_b1, p_nh1, ROWS_N, HH, 2*HH);
    gemm_kernel<true><<<dim3(HH/64, ROWS_N/64), 256>>>(p_nh1, e2n_W2, e2n_b2, p_mraw, ROWS_N, HH, HH);
    stats_kernel<true><<<HH, 256>>>(p_mraw, nullptr, e2n_g, e2n_be, p_an, p_cn, ROWS_N, (float)ROWS_N);

    // 7. fuse + predict
    build_cat_kernel<<<ROWS_N, HH>>>(p_x, p_mraw, p_an, p_cn, p_cat);
    gemm_kernel<false><<<dim3(HH/64, ROWS_N/64), 256>>>(p_cat, W_fuse, b_fuse, p_fused, ROWS_N, HH, 2*HH);
    gemm_kernel<false><<<dim3(1, ROWS_N/64), 256>>>(p_fused, W_pred, b_pred, out, ROWS_N, PRED*2, HH);

    // 8. cumulative positions
    pos_kernel<<<(ROWS_N*2+255)/256, 256>>>(out, centers, out + ROWS_N*PRED*2);
}

// round 3
// speedup vs baseline: 2.3385x; 1.7950x over previous
#include <cuda_runtime.h>
#include <cuda_bf16.h>
#include <math.h>

#define BB   16
#define NN   64
#define PREV 6
#define PRED 30
#define HH   256
#define EE   (NN*(NN-1))      // 4032
#define ROWS_E (BB*EE)        // 64512
#define ROWS_N (BB*NN)        // 1024

// ---------------- static scratch ----------------
__device__ float d_x[ROWS_N*HH];
__device__ float d_xTop[ROWS_N*HH];
__device__ float d_xBot[ROWS_N*HH];
__device__ float d_h2[ROWS_E*HH];
__device__ float d_inc[ROWS_N*HH];
__device__ float d_incsq[ROWS_N*HH];
__device__ float d_outg[ROWS_N*HH];
__device__ float d_nodes[ROWS_N*2*HH];
__device__ float d_nh1[ROWS_N*HH];
__device__ float d_mraw[ROWS_N*HH];
__device__ float d_cat[ROWS_N*2*HH];
__device__ float d_fused[ROWS_N*HH];
__device__ float d_ae[HH], d_ce[HH], d_an[HH], d_cn[HH];
__device__ int   d_recv[EE], d_send[EE];
__device__ int   d_listrec[NN*EE], d_listsend[NN*EE];
__device__ int   d_cntrec[NN], d_cntsend[NN];
__device__ float d_degrec[NN], d_degsend[NN];

__device__ __forceinline__ float elu_f(float x)  { return x > 0.f ? x : (expf(x) - 1.f); }
__device__ __forceinline__ float elu_ff(float x) { return x > 0.f ? x : (__expf(x) - 1.f); }

__device__ __forceinline__ unsigned f2tf32(float x) {
    unsigned r;
    asm("cvt.rna.tf32.f32 %0, %1;" : "=r"(r) : "f"(x));
    return r;
}
__device__ __forceinline__ unsigned packbf2(float lo, float hi) {
    __nv_bfloat162 v = __floats2bfloat162_rn(lo, hi);
    return *reinterpret_cast<unsigned*>(&v);
}

// ---------------- derive edge indices ----------------
__global__ void derive_kernel(const float* __restrict__ rel_rec,
                              const float* __restrict__ rel_send,
                              int* __restrict__ recv_idx, int* __restrict__ send_idx) {
    int e = blockIdx.x * blockDim.x + threadIdx.x;
    if (e >= EE) return;
    int r = 0, s = 0; float br = -1.f, bs = -1.f;
    for (int n = 0; n < NN; n++) {
        float vr = rel_rec[e*NN + n];
        float vs = rel_send[e*NN + n];
        if (vr > br) { br = vr; r = n; }
        if (vs > bs) { bs = vs; s = n; }
    }
    recv_idx[e] = r; send_idx[e] = s;
}

// ---------------- parallel deterministic list build ----------------
// 128 blocks (0..63: recv lists, 64..127: send lists), 64 threads each.
__global__ void build_lists_kernel(const int* __restrict__ recv_idx,
                                   const int* __restrict__ send_idx,
                                   int* __restrict__ list_rec, int* __restrict__ list_send,
                                   int* __restrict__ cnt_rec, int* __restrict__ cnt_send,
                                   float* __restrict__ deg_rec, float* __restrict__ deg_send) {
    const bool isSend = blockIdx.x >= NN;
    const int n = blockIdx.x & (NN-1);
    const int* __restrict__ idx = isSend ? send_idx : recv_idx;
    int* __restrict__ list = (isSend ? list_send : list_rec) + n*EE;
    const int t = threadIdx.x;            // 64 threads
    const int CH = EE / 64;               // 63
    const int base = t * CH;
    int c = 0;
    for (int i = 0; i < CH; i++) c += (idx[base+i] == n) ? 1 : 0;
    __shared__ int pre[64];
    pre[t] = c;
    __syncthreads();
    // inclusive Hillis-Steele scan
    for (int off = 1; off < 64; off <<= 1) {
        int v = (t >= off) ? pre[t-off] : 0;
        __syncthreads();
        pre[t] += v;
        __syncthreads();
    }
    int offset = pre[t] - c;              // exclusive prefix
    for (int i = 0; i < CH; i++) {
        int e = base + i;
        if (idx[e] == n) list[offset++] = e;
    }
    if (t == 63) {
        int tot = pre[63];
        if (isSend) { cnt_send[n] = tot; deg_send[n] = tot ? (float)tot : 1.f; }
        else        { cnt_rec[n]  = tot; deg_rec[n]  = tot ? (float)tot : 1.f; }
    }
}

// ---------------- trajectory embedding ----------------
__global__ void traj_kernel(const float* __restrict__ centers,
                            const float* __restrict__ W, const float* __restrict__ bias,
                            float* __restrict__ x) {
    int row = blockIdx.x;
    int h = threadIdx.x;
    __shared__ float rp[PREV*2];
    if (h < PREV*2) {
        int p = h >> 1, c = h & 1;
        float v = 0.f;
        if (p > 0) v = centers[row*PREV*2 + p*2 + c] - centers[row*PREV*2 + (p-1)*2 + c];
        rp[h] = v;
    }
    __syncthreads();
    float acc = bias[h];
    #pragma unroll
    for (int k = 0; k < PREV*2; k++) acc += rp[k] * W[k*HH + h];
    x[row*HH + h] = acc;
}

// =======================================================================
// Generic tf32 tensor-core GEMM: C = act(A@B + bias).
// Block tile 64x64, K-step 32, 256 threads = 8 warps as 2(M) x 4(N).
// Optional second (B,C) pair selected by blockIdx.z (for xTop/xBot fusion).
// K must be a multiple of 32, M a multiple of 64. N guarded if GUARD_N.
// =======================================================================
template<bool ELU, bool GUARD_N>
__global__ __launch_bounds__(256)
void mma_gemm_tf32(const float* __restrict__ A,
                   const float* __restrict__ B0, const float* __restrict__ B1,
                   const float* __restrict__ bias,
                   float* __restrict__ C0, float* __restrict__ C1,
                   int M, int N, int K) {
    const float* __restrict__ Bm = (blockIdx.z == 0) ? B0 : B1;
    float* __restrict__ C = (blockIdx.z == 0) ? C0 : C1;

    __shared__ unsigned As[64][36];   // [row][k] tf32
    __shared__ unsigned Bs[64][36];   // [n][k]   tf32
    const int tid  = threadIdx.x;
    const int lane = tid & 31;
    const int warp = tid >> 5;
    const int warpM = warp & 1;        // rows warpM*32
    const int warpN = warp >> 1;       // cols warpN*16
    const int g  = lane >> 2;
    const int t4 = lane & 3;
    const int row0 = blockIdx.y * 64;
    const int col0 = blockIdx.x * 64;

    float acc[2][2][4] = {};

    for (int k0 = 0; k0 < K; k0 += 32) {
        // A tile: 64 rows x 32 k. tasks: (row, kquad) lanes cover consecutive kquads
        #pragma unroll
        for (int it = 0; it < 2; it++) {
            int task = it*256 + tid;       // 0..511
            int kq  = task & 7;
            int row = task >> 3;           // 0..63
            float4 a = *reinterpret_cast<const float4*>(&A[(long)(row0+row)*K + k0 + kq*4]);
            As[row][kq*4+0] = f2tf32(a.x);
            As[row][kq*4+1] = f2tf32(a.y);
            As[row][kq*4+2] = f2tf32(a.z);
            As[row][kq*4+3] = f2tf32(a.w);
        }
        // B tile: 32 k x 64 n, stored transposed [n][k]
        #pragma unroll
        for (int it = 0; it < 8; it++) {
            int task = it*256 + tid;       // 0..2047
            int cc = task & 63;
            int kk = task >> 6;            // 0..31
            float v = 0.f;
            if (!GUARD_N || col0 + cc < N) v = Bm[(long)(k0+kk)*N + col0 + cc];
            Bs[cc][kk] = f2tf32(v);
        }
        __syncthreads();

        #pragma unroll
        for (int ks = 0; ks < 32; ks += 8) {
            unsigned afr[2][4];
            #pragma unroll
            for (int i = 0; i < 2; i++) {
                int r = warpM*32 + i*16;
                afr[i][0] = As[r + g    ][ks + t4    ];
                afr[i][1] = As[r + g + 8][ks + t4    ];
                afr[i][2] = As[r + g    ][ks + t4 + 4];
                afr[i][3] = As[r + g + 8][ks + t4 + 4];
            }
            unsigned bfr[2][2];
            #pragma unroll
            for (int j = 0; j < 2; j++) {
                int nn = warpN*16 + j*8 + g;
                bfr[j][0] = Bs[nn][ks + t4    ];
                bfr[j][1] = Bs[nn][ks + t4 + 4];
            }
            #pragma unroll
            for (int i = 0; i < 2; i++)
                #pragma unroll
                for (int j = 0; j < 2; j++)
                    asm volatile(
                        "mma.sync.aligned.m16n8k8.row.col.f32.tf32.tf32.f32 "
                        "{%0,%1,%2,%3}, {%4,%5,%6,%7}, {%8,%9}, {%0,%1,%2,%3};"
                        : "+f"(acc[i][j][0]), "+f"(acc[i][j][1]),
                          "+f"(acc[i][j][2]), "+f"(acc[i][j][3])
                        : "r"(afr[i][0]), "r"(afr[i][1]), "r"(afr[i][2]), "r"(afr[i][3]),
                          "r"(bfr[j][0]), "r"(bfr[j][1]));
        }
        __syncthreads();
    }

    #pragma unroll
    for (int i = 0; i < 2; i++) {
        int r = row0 + warpM*32 + i*16 + g;
        #pragma unroll
        for (int j = 0; j < 2; j++) {
            int c = col0 + warpN*16 + j*8 + t4*2;
            #pragma unroll
            for (int h = 0; h < 2; h++) {
                int cc = c + h;
                if (GUARD_N && cc >= N) continue;
                float bb = bias ? bias[cc] : 0.f;
                float v0 = acc[i][j][h]   + bb;
                float v1 = acc[i][j][2+h] + bb;
                if (ELU) { v0 = elu_f(v0); v1 = elu_f(v1); }
                C[(long)r*N + cc]     = v0;
                C[(long)(r+8)*N + cc] = v1;
            }
        }
    }
}

// =======================================================================
// Fused edge GEMM (bf16 tensor cores):
//   h2 = elu( elu(xTop[recv]+xBot[send]+b1) @ W2 + b2 )
// Block tile 128x128, K-step 32, mma.m16n8k16.bf16.
// 256 threads = 8 warps as 4(M) x 2(N); warp tile 32x64.
// =======================================================================
__global__ __launch_bounds__(256, 2)
void edge_gemm2_bf16(const float* __restrict__ xTop, const float* __restrict__ xBot,
                     const float* __restrict__ b1,
                     const float* __restrict__ W2, const float* __restrict__ b2,
                     const int* __restrict__ recv_idx, const int* __restrict__ send_idx,
                     float* __restrict__ h2) {
    __shared__ __nv_bfloat16 As[128][40];    // [row][k]
    __shared__ __nv_bfloat16 Bsn[128][40];   // [n][k]
    __shared__ int topBase[128], botBase[128];

    const int tid  = threadIdx.x;
    const int lane = tid & 31;
    const int warp = tid >> 5;
    const int warpM = warp & 3;          // rows warpM*32
    const int warpN = warp >> 2;         // cols warpN*64
    const int g  = lane >> 2;
    const int t4 = lane & 3;
    const int row0 = blockIdx.y * 128;
    const int col0 = blockIdx.x * 128;

    if (tid < 128) {
        int grow = row0 + tid;
        int b = grow / EE;
        int e = grow - b * EE;
        topBase[tid] = (b*NN + recv_idx[e]) * HH;
        botBase[tid] = (b*NN + send_idx[e]) * HH;
    }
    __syncthreads();

    float acc[2][8][4] = {};
    const int mrow0 = warpM * 32;
    const int ncol0 = warpN * 64;

    for (int k0 = 0; k0 < HH; k0 += 32) {
        // ---- A tile: 128 rows x 32 k, gather + add + bias + elu -> bf16 ----
        #pragma unroll
        for (int it = 0; it < 4; it++) {
            int task = it*256 + tid;         // 0..1023
            int row  = task & 127;
            int cg   = task >> 7;            // 0..7
            int cb   = k0 + cg*4;
            float4 a  = *reinterpret_cast<const float4*>(&xTop[topBase[row] + cb]);
            float4 bv = *reinterpret_cast<const float4*>(&xBot[botBase[row] + cb]);
            float4 bb = *reinterpret_cast<const float4*>(&b1[cb]);
            unsigned p0 = packbf2(elu_ff(a.x + bv.x + bb.x), elu_ff(a.y + bv.y + bb.y));
            unsigned p1 = packbf2(elu_ff(a.z + bv.z + bb.z), elu_ff(a.w + bv.w + bb.w));
            uint2* dst = reinterpret_cast<uint2*>(&As[row][cg*4]);
            *dst = make_uint2(p0, p1);
        }
        // ---- B tile: 32 k x 128 n, transposed [n][k] as packed k-pairs ----
        #pragma unroll
        for (int it = 0; it < 8; it++) {
            int task = it*256 + tid;         // 0..2047
            int cc = task & 127;
            int kp = task >> 7;              // 0..15
            float w0 = W2[(long)(k0 + 2*kp    )*HH + col0 + cc];
            float w1 = W2[(long)(k0 + 2*kp + 1)*HH + col0 + cc];
            *reinterpret_cast<unsigned*>(&Bsn[cc][2*kp]) = packbf2(w0, w1);
        }
        __syncthreads();

        // ---- MMA: 2 k-substeps of 16 ----
        #pragma unroll
        for (int ks = 0; ks < 32; ks += 16) {
            unsigned afr[2][4];
            #pragma unroll
            for (int i = 0; i < 2; i++) {
                int r = mrow0 + i*16;
                afr[i][0] = *reinterpret_cast<unsigned*>(&As[r + g    ][ks + 2*t4    ]);
                afr[i][1] = *reinterpret_cast<unsigned*>(&As[r + g + 8][ks + 2*t4    ]);
                afr[i][2] = *reinterpret_cast<unsigned*>(&As[r + g    ][ks + 2*t4 + 8]);
                afr[i][3] = *reinterpret_cast<unsigned*>(&As[r + g + 8][ks + 2*t4 + 8]);
            }
            #pragma unroll
            for (int j = 0; j < 8; j++) {
                int nn = ncol0 + j*8 + g;
                unsigned b0 = *reinterpret_cast<unsigned*>(&Bsn[nn][ks + 2*t4    ]);
                unsigned b1r = *reinterpret_cast<unsigned*>(&Bsn[nn][ks + 2*t4 + 8]);
                #pragma unroll
                for (int i = 0; i < 2; i++)
                    asm volatile(
                        "mma.sync.aligned.m16n8k16.row.col.f32.bf16.bf16.f32 "
                        "{%0,%1,%2,%3}, {%4,%5,%6,%7}, {%8,%9}, {%0,%1,%2,%3};"
                        : "+f"(acc[i][j][0]), "+f"(acc[i][j][1]),
                          "+f"(acc[i][j][2]), "+f"(acc[i][j][3])
                        : "r"(afr[i][0]), "r"(afr[i][1]), "r"(afr[i][2]), "r"(afr[i][3]),
                          "r"(b0), "r"(b1r));
            }
        }
        __syncthreads();
    }

    // ---- epilogue: bias + elu + store ----
    #pragma unroll
    for (int i = 0; i < 2; i++) {
        int r_lo = row0 + mrow0 + i*16 + g;
        #pragma unroll
        for (int j = 0; j < 8; j++) {
            int c = col0 + ncol0 + j*8 + t4*2;
            float bb0 = b2[c], bb1 = b2[c+1];
            h2[(long)r_lo*HH + c    ]     = elu_ff(acc[i][j][0] + bb0);
            h2[(long)r_lo*HH + c + 1]     = elu_ff(acc[i][j][1] + bb1);
            h2[(long)(r_lo+8)*HH + c    ] = elu_ff(acc[i][j][2] + bb0);
            h2[(long)(r_lo+8)*HH + c + 1] = elu_ff(acc[i][j][3] + bb1);
        }
    }
}

// ---------------- combined per-node gather sums (incoming + outgoing) ----------------
__global__ void scatter_kernel(const float* __restrict__ h2,
                               const int* __restrict__ list_rec, const int* __restrict__ cnt_rec,
                               const int* __restrict__ list_send, const int* __restrict__ cnt_send,
                               float* __restrict__ inc_raw, float* __restrict__ sq_part,
                               float* __restrict__ out_raw) {
    int id = blockIdx.x;               // 0..2047
    bool isOut = id >= ROWS_N;
    int bn = id & (ROWS_N-1);
    int b = bn >> 6, n = bn & 63;
    int h = threadIdx.x;
    if (!isOut) {
        int cnt = cnt_rec[n];
        float acc = 0.f, accsq = 0.f;
        for (int k = 0; k < cnt; k++) {
            int e = list_rec[n*EE + k];
            float v = h2[(long)(b*EE + e)*HH + h];
            acc += v; accsq += v*v;
        }
        inc_raw[bn*HH + h] = acc;
        sq_part[bn*HH + h] = accsq;
    } else {
        int cnt = cnt_send[n];
        float acc = 0.f;
        for (int k = 0; k < cnt; k++) {
            int e = list_send[n*EE + k];
            acc += h2[(long)(b*EE + e)*HH + h];
        }
        out_raw[bn*HH + h] = acc;
    }
}

// ---------------- BN stats -> affine (a,c) ----------------
template<bool SRC_SQ>
__global__ void stats_kernel(const float* __restrict__ sum_part, const float* __restrict__ sq_part,
                             const float* __restrict__ gamma, const float* __restrict__ beta,
                             float* __restrict__ a, float* __restrict__ c,
                             int nrows, float count) {
    int h = blockIdx.x;
    float s = 0.f, sq = 0.f;
    for (int r = threadIdx.x; r < nrows; r += 256) {
        float v = sum_part[r*HH + h];
        s += v;
        if (SRC_SQ) sq += v*v; else sq += sq_part[r*HH + h];
    }
    __shared__ float ss[256], ssq[256];
    ss[threadIdx.x] = s; ssq[threadIdx.x] = sq;
    __syncthreads();
    for (int st = 128; st > 0; st >>= 1) {
        if (threadIdx.x < st) { ss[threadIdx.x] += ss[threadIdx.x+st]; ssq[threadIdx.x] += ssq[threadIdx.x+st]; }
        __syncthreads();
    }
    if (threadIdx.x == 0) {
        float mu = ss[0] / count;
        float var = ssq[0] / count - mu*mu;
        float av = gamma[h] * rsqrtf(var + 1e-5f);
        a[h] = av;
        c[h] = beta[h] - mu * av;
    }
}

__global__ void build_nodes_kernel(const float* __restrict__ inc_raw, const float* __restrict__ out_raw,
                                   const float* __restrict__ a, const float* __restrict__ c,
                                   const float* __restrict__ deg_rec, const float* __restrict__ deg_send,
                                   float* __restrict__ nodes) {
    int row = blockIdx.x;
    int h = threadIdx.x;
    int n = row & 63;
    float av = a[h], cv = c[h];
    nodes[row*2*HH + h]      = av * (inc_raw[row*HH + h] / deg_rec[n])  + cv;
    nodes[row*2*HH + HH + h] = av * (out_raw[row*HH + h] / deg_send[n]) + cv;
}

__global__ void build_cat_kernel(const float* __restrict__ x, const float* __restrict__ mraw,
                                 const float* __restrict__ a, const float* __restrict__ c,
                                 float* __restrict__ cat) {
    int row = blockIdx.x;
    int h = threadIdx.x;
    cat[row*2*HH + h]      = x[row*HH + h];
    cat[row*2*HH + HH + h] = a[h] * mraw[row*HH + h] + c[h];
}

__global__ void pos_kernel(const float* __restrict__ rel, const float* __restrict__ centers,
                           float* __restrict__ pos_out) {
    int t = blockIdx.x * blockDim.x + threadIdx.x;
    if (t >= ROWS_N*2) return;
    int row = t >> 1, cdim = t & 1;
    float cur = centers[row*PREV*2 + (PREV-1)*2 + cdim];
    float acc = 0.f;
    for (int p = 0; p < PRED; p++) {
        acc += rel[row*PRED*2 + p*2 + cdim];
        pos_out[row*PRED*2 + p*2 + cdim] = acc + cur;
    }
}

// ---------------- launcher ----------------
extern "C" void kernel_launch(void* const* d_in, const int* in_sizes, int n_in,
                              void* d_out, int out_size) {
    const float* centers  = (const float*)d_in[0];
    const float* rel_rec  = (const float*)d_in[1];
    const float* rel_send = (const float*)d_in[2];
    const float* W_traj   = (const float*)d_in[3];
    const float* b_traj   = (const float*)d_in[4];
    const float* n2e_W1   = (const float*)d_in[5];
    const float* n2e_b1   = (const float*)d_in[6];
    const float* n2e_W2   = (const float*)d_in[7];
    const float* n2e_b2   = (const float*)d_in[8];
    const float* n2e_g    = (const float*)d_in[9];
    const float* n2e_be   = (const float*)d_in[10];
    const float* e2n_W1   = (const float*)d_in[11];
    const float* e2n_b1   = (const float*)d_in[12];
    const float* e2n_W2   = (const float*)d_in[13];
    const float* e2n_b2   = (const float*)d_in[14];
    const float* e2n_g    = (const float*)d_in[15];
    const float* e2n_be   = (const float*)d_in[16];
    const float* W_fuse   = (const float*)d_in[17];
    const float* b_fuse   = (const float*)d_in[18];
    const float* W_pred   = (const float*)d_in[19];
    const float* b_pred   = (const float*)d_in[20];
    float* out = (float*)d_out;

    float *p_x, *p_xTop, *p_xBot, *p_h2, *p_inc, *p_incsq, *p_outg;
    float *p_nodes, *p_nh1, *p_mraw, *p_cat, *p_fused;
    float *p_ae, *p_ce, *p_an, *p_cn, *p_degrec, *p_degsend;
    int *p_recv, *p_send, *p_lr, *p_ls, *p_cr, *p_cs;
    cudaGetSymbolAddress((void**)&p_x, d_x);
    cudaGetSymbolAddress((void**)&p_xTop, d_xTop);
    cudaGetSymbolAddress((void**)&p_xBot, d_xBot);
    cudaGetSymbolAddress((void**)&p_h2, d_h2);
    cudaGetSymbolAddress((void**)&p_inc, d_inc);
    cudaGetSymbolAddress((void**)&p_incsq, d_incsq);
    cudaGetSymbolAddress((void**)&p_outg, d_outg);
    cudaGetSymbolAddress((void**)&p_nodes, d_nodes);
    cudaGetSymbolAddress((void**)&p_nh1, d_nh1);
    cudaGetSymbolAddress((void**)&p_mraw, d_mraw);
    cudaGetSymbolAddress((void**)&p_cat, d_cat);
    cudaGetSymbolAddress((void**)&p_fused, d_fused);
    cudaGetSymbolAddress((void**)&p_ae, d_ae);
    cudaGetSymbolAddress((void**)&p_ce, d_ce);
    cudaGetSymbolAddress((void**)&p_an, d_an);
    cudaGetSymbolAddress((void**)&p_cn, d_cn);
    cudaGetSymbolAddress((void**)&p_degrec, d_degrec);
    cudaGetSymbolAddress((void**)&p_degsend, d_degsend);
    cudaGetSymbolAddress((void**)&p_recv, d_recv);
    cudaGetSymbolAddress((void**)&p_send, d_send);
    cudaGetSymbolAddress((void**)&p_lr, d_listrec);
    cudaGetSymbolAddress((void**)&p_ls, d_listsend);
    cudaGetSymbolAddress((void**)&p_cr, d_cntrec);
    cudaGetSymbolAddress((void**)&p_cs, d_cntsend);

    // 1. edge indices + per-node lists (parallel, deterministic)
    derive_kernel<<<(EE+255)/256, 256>>>(rel_rec, rel_send, p_recv, p_send);
    build_lists_kernel<<<128, 64>>>(p_recv, p_send, p_lr, p_ls, p_cr, p_cs, p_degrec, p_degsend);

    // 2. trajectory embedding
    traj_kernel<<<ROWS_N, HH>>>(centers, W_traj, b_traj, p_x);

    // 3. xTop = x@W1[:256], xBot = x@W1[256:]  (fused, tensor cores, z=2)
    mma_gemm_tf32<false,false><<<dim3(HH/64, ROWS_N/64, 2), 256>>>(
        p_x, n2e_W1, n2e_W1 + HH*HH, nullptr, p_xTop, p_xBot, ROWS_N, HH, HH);

    // 4. fused edge MLP (gather + elu + bf16 tensor GEMM + bias + elu)
    edge_gemm2_bf16<<<dim3(HH/128, ROWS_E/128), 256>>>(p_xTop, p_xBot, n2e_b1,
                                                       n2e_W2, n2e_b2,
                                                       p_recv, p_send, p_h2);

    // 5. scatter sums (incoming+outgoing in one launch) + edge BN stats
    scatter_kernel<<<2*ROWS_N, HH>>>(p_h2, p_lr, p_cr, p_ls, p_cs, p_inc, p_incsq, p_outg);
    stats_kernel<false><<<HH, 256>>>(p_inc, p_incsq, n2e_g, n2e_be, p_ae, p_ce, ROWS_N, (float)ROWS_E);

    // 6. node MLP
    build_nodes_kernel<<<ROWS_N, HH>>>(p_inc, p_outg, p_ae, p_ce, p_degrec, p_degsend, p_nodes);
    mma_gemm_tf32<true,false><<<dim3(HH/64, ROWS_N/64), 256>>>(
        p_nodes, e2n_W1, nullptr, e2n_b1, p_nh1, nullptr, ROWS_N, HH, 2*HH);
    mma_gemm_tf32<true,false><<<dim3(HH/64, ROWS_N/64), 256>>>(
        p_nh1, e2n_W2, nullptr, e2n_b2, p_mraw, nullptr, ROWS_N, HH, HH);
    stats_kernel<true><<<HH, 256>>>(p_mraw, nullptr, e2n_g, e2n_be, p_an, p_cn, ROWS_N, (float)ROWS_N);

    // 7. fuse + predict
    build_cat_kernel<<<ROWS_N, HH>>>(p_x, p_mraw, p_an, p_cn, p_cat);
    mma_gemm_tf32<false,false><<<dim3(HH/64, ROWS_N/64), 256>>>(
        p_cat, W_fuse, nullptr, b_fuse, p_fused, nullptr, ROWS_N, HH, 2*HH);
    mma_gemm_tf32<false,true><<<dim3(1, ROWS_N/64), 256>>>(
        p_fused, W_pred, nullptr, b_pred, out, nullptr, ROWS_N, PRED*2, HH);

    // 8. cumulative positions
    pos_kernel<<<(ROWS_N*2+255)/256, 256>>>(out, centers, out + ROWS_N*PRED*2);
}

// round 4
// speedup vs baseline: 2.4102x; 1.0307x over previous
#include <cuda_runtime.h>
#include <cuda_bf16.h>
#include <math.h>

#define BB   16
#define NN   64
#define PREV 6
#define PRED 30
#define HH   256
#define EE   (NN*(NN-1))      // 4032
#define ROWS_E (BB*EE)        // 64512
#define ROWS_N (BB*NN)        // 1024

// ---------------- static scratch ----------------
__device__ float d_x[ROWS_N*HH];
__device__ float d_xTop[ROWS_N*HH];
__device__ float d_xBot[ROWS_N*HH];
__device__ float d_h2[ROWS_E*HH];
__device__ float d_inc[ROWS_N*HH];
__device__ float d_incsq[ROWS_N*HH];
__device__ float d_outg[ROWS_N*HH];
__device__ float d_nh1[ROWS_N*HH];
__device__ float d_mraw[ROWS_N*HH];
__device__ float d_fused[ROWS_N*HH];
__device__ float d_ae[HH], d_ce[HH], d_an[HH], d_cn[HH];
__device__ int   d_recv[EE], d_send[EE];
__device__ int   d_listrec[NN*EE], d_listsend[NN*EE];
__device__ int   d_cntrec[NN], d_cntsend[NN];
__device__ float d_invdegrec[NN], d_invdegsend[NN];

__device__ __forceinline__ float elu_f(float x)  { return x > 0.f ? x : (expf(x) - 1.f); }
__device__ __forceinline__ float elu_ff(float x) { return x > 0.f ? x : (__expf(x) - 1.f); }

__device__ __forceinline__ unsigned f2tf32(float x) {
    unsigned r;
    asm("cvt.rna.tf32.f32 %0, %1;" : "=r"(r) : "f"(x));
    return r;
}
__device__ __forceinline__ unsigned packbf2(float lo, float hi) {
    __nv_bfloat162 v = __floats2bfloat162_rn(lo, hi);
    return *reinterpret_cast<unsigned*>(&v);
}

// ---------------- derive edge indices ----------------
__global__ void derive_kernel(const float* __restrict__ rel_rec,
                              const float* __restrict__ rel_send,
                              int* __restrict__ recv_idx, int* __restrict__ send_idx) {
    int e = blockIdx.x * blockDim.x + threadIdx.x;
    if (e >= EE) return;
    int r = 0, s = 0; float br = -1.f, bs = -1.f;
    for (int n = 0; n < NN; n++) {
        float vr = rel_rec[e*NN + n];
        float vs = rel_send[e*NN + n];
        if (vr > br) { br = vr; r = n; }
        if (vs > bs) { bs = vs; s = n; }
    }
    recv_idx[e] = r; send_idx[e] = s;
}

// ---------------- parallel deterministic list build (stores INVERSE deg) ----------------
__global__ void build_lists_kernel(const int* __restrict__ recv_idx,
                                   const int* __restrict__ send_idx,
                                   int* __restrict__ list_rec, int* __restrict__ list_send,
                                   int* __restrict__ cnt_rec, int* __restrict__ cnt_send,
                                   float* __restrict__ invdeg_rec, float* __restrict__ invdeg_send) {
    const bool isSend = blockIdx.x >= NN;
    const int n = blockIdx.x & (NN-1);
    const int* __restrict__ idx = isSend ? send_idx : recv_idx;
    int* __restrict__ list = (isSend ? list_send : list_rec) + n*EE;
    const int t = threadIdx.x;            // 64 threads
    const int CH = EE / 64;               // 63
    const int base = t * CH;
    int c = 0;
    for (int i = 0; i < CH; i++) c += (idx[base+i] == n) ? 1 : 0;
    __shared__ int pre[64];
    pre[t] = c;
    __syncthreads();
    for (int off = 1; off < 64; off <<= 1) {
        int v = (t >= off) ? pre[t-off] : 0;
        __syncthreads();
        pre[t] += v;
        __syncthreads();
    }
    int offset = pre[t] - c;
    for (int i = 0; i < CH; i++) {
        int e = base + i;
        if (idx[e] == n) list[offset++] = e;
    }
    if (t == 63) {
        int tot = pre[63];
        float iv = tot ? 1.f/(float)tot : 1.f;
        if (isSend) { cnt_send[n] = tot; invdeg_send[n] = iv; }
        else        { cnt_rec[n]  = tot; invdeg_rec[n]  = iv; }
    }
}

// ---------------- trajectory embedding ----------------
__global__ void traj_kernel(const float* __restrict__ centers,
                            const float* __restrict__ W, const float* __restrict__ bias,
                            float* __restrict__ x) {
    int row = blockIdx.x;
    int h = threadIdx.x;
    __shared__ float rp[PREV*2];
    if (h < PREV*2) {
        int p = h >> 1, c = h & 1;
        float v = 0.f;
        if (p > 0) v = centers[row*PREV*2 + p*2 + c] - centers[row*PREV*2 + (p-1)*2 + c];
        rp[h] = v;
    }
    __syncthreads();
    float acc = bias[h];
    #pragma unroll
    for (int k = 0; k < PREV*2; k++) acc += rp[k] * W[k*HH + h];
    x[row*HH + h] = acc;
}

// =======================================================================
// Generic pipelined tf32 GEMM: C = act(A'@B + bias), A' built on the fly.
// AMODE 0: A' = A0 (row stride K)
// AMODE 1: A' = [a*(inc*invDegR)+c , a*(outg*invDegS)+c]  (K=512, halves stride HH)
// AMODE 2: A' = [x , a*mraw+c]                            (K=512, halves stride HH)
// Block tile 64x64, K-step 32, register prefetch of next tile.
// blockIdx.z selects (B0,C0)/(B1,C1) for dual-output launches.
// =======================================================================
template<int AMODE, bool ELU, bool GUARD_N>
__global__ __launch_bounds__(256)
void mma_gemm_v2(const float* __restrict__ A0, const float* __restrict__ A1,
                 const float* __restrict__ aVec, const float* __restrict__ cVec,
                 const float* __restrict__ invDegR, const float* __restrict__ invDegS,
                 const float* __restrict__ B0, const float* __restrict__ B1,
                 const float* __restrict__ bias,
                 float* __restrict__ C0, float* __restrict__ C1,
                 int M, int N, int K) {
    const float* __restrict__ Bm = (blockIdx.z == 0) ? B0 : B1;
    float* __restrict__ C = (blockIdx.z == 0) ? C0 : C1;

    __shared__ unsigned Asm[64][36];   // [row][k] tf32
    __shared__ unsigned Bsm[32][72];   // [k][n]   tf32
    const int tid  = threadIdx.x;
    const int lane = tid & 31;
    const int warp = tid >> 5;
    const int warpM = warp & 1;
    const int warpN = warp >> 1;
    const int g  = lane >> 2;
    const int t4 = lane & 3;
    const int row0 = blockIdx.y * 64;
    const int col0 = blockIdx.x * 64;

    // A tasks (2): (row, kquad)
    int arow[2], akq[2];
    // B tasks (2): (k, nquad)
    int bkk[2], bq[2];
    #pragma unroll
    for (int it = 0; it < 2; it++) {
        int ta = it*256 + tid;
        akq[it] = ta & 7;  arow[it] = ta >> 3;
        bkk[it] = ta >> 4; bq[it]  = ta & 15;
    }

    float4 pa[2], pb[2];
    #pragma unroll
    for (int it = 0; it < 2; it++) {
        // A load tile 0
        {
            int gk = akq[it]*4;
            if (AMODE == 0) {
                pa[it] = *reinterpret_cast<const float4*>(&A0[(long)(row0+arow[it])*K + gk]);
            } else {
                const float* src = (gk >= HH) ? A1 : A0;
                pa[it] = *reinterpret_cast<const float4*>(&src[(long)(row0+arow[it])*HH + (gk & (HH-1))]);
            }
        }
        // B load tile 0
        {
            int c0 = col0 + bq[it]*4;
            if (!GUARD_N) {
                pb[it] = *reinterpret_cast<const float4*>(&Bm[(long)bkk[it]*N + c0]);
            } else {
                float4 v;
                v.x = (c0+0 < N) ? Bm[(long)bkk[it]*N + c0+0] : 0.f;
                v.y = (c0+1 < N) ? Bm[(long)bkk[it]*N + c0+1] : 0.f;
                v.z = (c0+2 < N) ? Bm[(long)bkk[it]*N + c0+2] : 0.f;
                v.w = (c0+3 < N) ? Bm[(long)bkk[it]*N + c0+3] : 0.f;
                pb[it] = v;
            }
        }
    }

    float acc[2][2][4] = {};

    for (int k0 = 0; k0 < K; k0 += 32) {
        // ---- store current tile (with transform) ----
        #pragma unroll
        for (int it = 0; it < 2; it++) {
            int gk = k0 + akq[it]*4;
            float4 v = pa[it];
            if (AMODE == 1) {
                int col = gk & (HH-1);
                float invd = ((gk >= HH) ? invDegS : invDegR)[(row0+arow[it]) & (NN-1)];
                float4 a4 = *reinterpret_cast<const float4*>(&aVec[col]);
                float4 c4 = *reinterpret_cast<const float4*>(&cVec[col]);
                v.x = a4.x*(v.x*invd)+c4.x; v.y = a4.y*(v.y*invd)+c4.y;
                v.z = a4.z*(v.z*invd)+c4.z; v.w = a4.w*(v.w*invd)+c4.w;
            } else if (AMODE == 2) {
                if (gk >= HH) {
                    int col = gk & (HH-1);
                    float4 a4 = *reinterpret_cast<const float4*>(&aVec[col]);
                    float4 c4 = *reinterpret_cast<const float4*>(&cVec[col]);
                    v.x = a4.x*v.x+c4.x; v.y = a4.y*v.y+c4.y;
                    v.z = a4.z*v.z+c4.z; v.w = a4.w*v.w+c4.w;
                }
            }
            Asm[arow[it]][akq[it]*4+0] = f2tf32(v.x);
            Asm[arow[it]][akq[it]*4+1] = f2tf32(v.y);
            Asm[arow[it]][akq[it]*4+2] = f2tf32(v.z);
            Asm[arow[it]][akq[it]*4+3] = f2tf32(v.w);

            float4 w = pb[it];
            Bsm[bkk[it]][bq[it]*4+0] = f2tf32(w.x);
            Bsm[bkk[it]][bq[it]*4+1] = f2tf32(w.y);
            Bsm[bkk[it]][bq[it]*4+2] = f2tf32(w.z);
            Bsm[bkk[it]][bq[it]*4+3] = f2tf32(w.w);
        }
        // ---- prefetch next tile into regs ----
        if (k0 + 32 < K) {
            int kn = k0 + 32;
            #pragma unroll
            for (int it = 0; it < 2; it++) {
                int gk = kn + akq[it]*4;
                if (AMODE == 0) {
                    pa[it] = *reinterpret_cast<const float4*>(&A0[(long)(row0+arow[it])*K + gk]);
                } else {
                    const float* src = (gk >= HH) ? A1 : A0;
                    pa[it] = *reinterpret_cast<const float4*>(&src[(long)(row0+arow[it])*HH + (gk & (HH-1))]);
                }
                int c0 = col0 + bq[it]*4;
                if (!GUARD_N) {
                    pb[it] = *reinterpret_cast<const float4*>(&Bm[(long)(kn+bkk[it])*N + c0]);
                } else {
                    float4 v;
                    v.x = (c0+0 < N) ? Bm[(long)(kn+bkk[it])*N + c0+0] : 0.f;
                    v.y = (c0+1 < N) ? Bm[(long)(kn+bkk[it])*N + c0+1] : 0.f;
                    v.z = (c0+2 < N) ? Bm[(long)(kn+bkk[it])*N + c0+2] : 0.f;
                    v.w = (c0+3 < N) ? Bm[(long)(kn+bkk[it])*N + c0+3] : 0.f;
                    pb[it] = v;
                }
            }
        }
        __syncthreads();

        #pragma unroll
        for (int ks = 0; ks < 32; ks += 8) {
            unsigned afr[2][4];
            #pragma unroll
            for (int i = 0; i < 2; i++) {
                int r = warpM*32 + i*16;
                afr[i][0] = Asm[r + g    ][ks + t4    ];
                afr[i][1] = Asm[r + g + 8][ks + t4    ];
                afr[i][2] = Asm[r + g    ][ks + t4 + 4];
                afr[i][3] = Asm[r + g + 8][ks + t4 + 4];
            }
            unsigned bfr[2][2];
            #pragma unroll
            for (int j = 0; j < 2; j++) {
                int nn = warpN*16 + j*8 + g;
                bfr[j][0] = Bsm[ks + t4    ][nn];
                bfr[j][1] = Bsm[ks + t4 + 4][nn];
            }
            #pragma unroll
            for (int i = 0; i < 2; i++)
                #pragma unroll
                for (int j = 0; j < 2; j++)
                    asm volatile(
                        "mma.sync.aligned.m16n8k8.row.col.f32.tf32.tf32.f32 "
                        "{%0,%1,%2,%3}, {%4,%5,%6,%7}, {%8,%9}, {%0,%1,%2,%3};"
                        : "+f"(acc[i][j][0]), "+f"(acc[i][j][1]),
                          "+f"(acc[i][j][2]), "+f"(acc[i][j][3])
                        : "r"(afr[i][0]), "r"(afr[i][1]), "r"(afr[i][2]), "r"(afr[i][3]),
                          "r"(bfr[j][0]), "r"(bfr[j][1]));
        }
        __syncthreads();
    }

    #pragma unroll
    for (int i = 0; i < 2; i++) {
        int r = row0 + warpM*32 + i*16 + g;
        #pragma unroll
        for (int j = 0; j < 2; j++) {
            int c = col0 + warpN*16 + j*8 + t4*2;
            #pragma unroll
            for (int h = 0; h < 2; h++) {
                int cc = c + h;
                if (GUARD_N && cc >= N) continue;
                float bb = bias ? bias[cc] : 0.f;
                float v0 = acc[i][j][h]   + bb;
                float v1 = acc[i][j][2+h] + bb;
                if (ELU) { v0 = elu_f(v0); v1 = elu_f(v1); }
                C[(long)r*N + cc]     = v0;
                C[(long)(r+8)*N + cc] = v1;
            }
        }
    }
}

// =======================================================================
// Pred GEMM + cumsum epilogue: rel = fused@W_pred + b; pos = cumsum(rel)+cur
// M=1024, N=60 (guarded, tile 64), K=256. One block = 64 rows.
// =======================================================================
__global__ __launch_bounds__(256)
void pred_pos_kernel(const float* __restrict__ A0, const float* __restrict__ Bm,
                     const float* __restrict__ bias, const float* __restrict__ centers,
                     float* __restrict__ out) {
    const int N = PRED*2;   // 60
    const int K = HH;
    __shared__ unsigned Asm[64][36];
    __shared__ unsigned Bsm[32][72];
    __shared__ float Cs[64][64];
    const int tid  = threadIdx.x;
    const int lane = tid & 31;
    const int warp = tid >> 5;
    const int warpM = warp & 1;
    const int warpN = warp >> 1;
    const int g  = lane >> 2;
    const int t4 = lane & 3;
    const int row0 = blockIdx.y * 64;

    int arow[2], akq[2], bkk[2], bq[2];
    #pragma unroll
    for (int it = 0; it < 2; it++) {
        int ta = it*256 + tid;
        akq[it] = ta & 7;  arow[it] = ta >> 3;
        bkk[it] = ta >> 4; bq[it]  = ta & 15;
    }
    float4 pa[2], pb[2];
    #pragma unroll
    for (int it = 0; it < 2; it++) {
        pa[it] = *reinterpret_cast<const float4*>(&A0[(long)(row0+arow[it])*K + akq[it]*4]);
        int c0 = bq[it]*4;
        float4 v;
        v.x = (c0+0 < N) ? Bm[(long)bkk[it]*N + c0+0] : 0.f;
        v.y = (c0+1 < N) ? Bm[(long)bkk[it]*N + c0+1] : 0.f;
        v.z = (c0+2 < N) ? Bm[(long)bkk[it]*N + c0+2] : 0.f;
        v.w = (c0+3 < N) ? Bm[(long)bkk[it]*N + c0+3] : 0.f;
        pb[it] = v;
    }

    float acc[2][2][4] = {};
    for (int k0 = 0; k0 < K; k0 += 32) {
        #pragma unroll
        for (int it = 0; it < 2; it++) {
            float4 v = pa[it];
            Asm[arow[it]][akq[it]*4+0] = f2tf32(v.x);
            Asm[arow[it]][akq[it]*4+1] = f2tf32(v.y);
            Asm[arow[it]][akq[it]*4+2] = f2tf32(v.z);
            Asm[arow[it]][akq[it]*4+3] = f2tf32(v.w);
            float4 w = pb[it];
            Bsm[bkk[it]][bq[it]*4+0] = f2tf32(w.x);
            Bsm[bkk[it]][bq[it]*4+1] = f2tf32(w.y);
            Bsm[bkk[it]][bq[it]*4+2] = f2tf32(w.z);
            Bsm[bkk[it]][bq[it]*4+3] = f2tf32(w.w);
        }
        if (k0 + 32 < K) {
            int kn = k0 + 32;
            #pragma unroll
            for (int it = 0; it < 2; it++) {
                pa[it] = *reinterpret_cast<const float4*>(&A0[(long)(row0+arow[it])*K + kn + akq[it]*4]);
                int c0 = bq[it]*4;
                float4 v;
                v.x = (c0+0 < N) ? Bm[(long)(kn+bkk[it])*N + c0+0] : 0.f;
                v.y = (c0+1 < N) ? Bm[(long)(kn+bkk[it])*N + c0+1] : 0.f;
                v.z = (c0+2 < N) ? Bm[(long)(kn+bkk[it])*N + c0+2] : 0.f;
                v.w = (c0+3 < N) ? Bm[(long)(kn+bkk[it])*N + c0+3] : 0.f;
                pb[it] = v;
            }
        }
        __syncthreads();
        #pragma unroll
        for (int ks = 0; ks < 32; ks += 8) {
            unsigned afr[2][4];
            #pragma unroll
            for (int i = 0; i < 2; i++) {
                int r = warpM*32 + i*16;
                afr[i][0] = Asm[r + g    ][ks + t4    ];
                afr[i][1] = Asm[r + g + 8][ks + t4    ];
                afr[i][2] = Asm[r + g    ][ks + t4 + 4];
                afr[i][3] = Asm[r + g + 8][ks + t4 + 4];
            }
            unsigned bfr[2][2];
            #pragma unroll
            for (int j = 0; j < 2; j++) {
                int nn = warpN*16 + j*8 + g;
                bfr[j][0] = Bsm[ks + t4    ][nn];
                bfr[j][1] = Bsm[ks + t4 + 4][nn];
            }
            #pragma unroll
            for (int i = 0; i < 2; i++)
                #pragma unroll
                for (int j = 0; j < 2; j++)
                    asm volatile(
                        "mma.sync.aligned.m16n8k8.row.col.f32.tf32.tf32.f32 "
                        "{%0,%1,%2,%3}, {%4,%5,%6,%7}, {%8,%9}, {%0,%1,%2,%3};"
                        : "+f"(acc[i][j][0]), "+f"(acc[i][j][1]),
                          "+f"(acc[i][j][2]), "+f"(acc[i][j][3])
                        : "r"(afr[i][0]), "r"(afr[i][1]), "r"(afr[i][2]), "r"(afr[i][3]),
                          "r"(bfr[j][0]), "r"(bfr[j][1]));
        }
        __syncthreads();
    }

    // stage into smem
    #pragma unroll
    for (int i = 0; i < 2; i++) {
        int r = warpM*32 + i*16 + g;
        #pragma unroll
        for (int j = 0; j < 2; j++) {
            int c = warpN*16 + j*8 + t4*2;
            #pragma unroll
            for (int h = 0; h < 2; h++) {
                int cc = c + h;
                float bb = (cc < N) ? bias[cc] : 0.f;
                Cs[r][cc]   = acc[i][j][h]   + bb;
                Cs[r+8][cc] = acc[i][j][2+h] + bb;
            }
        }
    }
    __syncthreads();

    // cumsum + write rel and pos
    if (tid < 128) {
        int lrow = tid >> 1, dimc = tid & 1;
        int grow = row0 + lrow;
        float cur = centers[grow*PREV*2 + (PREV-1)*2 + dimc];
        float accum = 0.f;
        #pragma unroll
        for (int p = 0; p < PRED; p++) {
            float v = Cs[lrow][2*p + dimc];
            out[(long)grow*N + 2*p + dimc] = v;
            accum += v;
            out[(long)(ROWS_N)*N + (long)grow*N + 2*p + dimc] = accum + cur;
        }
    }
}

// =======================================================================
// Fused edge GEMM (bf16): h2 = elu( elu(xTop[recv]+xBot[send]+b1) @ W2 + b2 )
// 128x128 tile, K-step 32, register prefetch of next gather tile.
// =======================================================================
__global__ __launch_bounds__(256, 2)
void edge_gemm2_bf16(const float* __restrict__ xTop, const float* __restrict__ xBot,
                     const float* __restrict__ b1,
                     const float* __restrict__ W2, const float* __restrict__ b2,
                     const int* __restrict__ recv_idx, const int* __restrict__ send_idx,
                     float* __restrict__ h2) {
    __shared__ __nv_bfloat16 As[128][40];    // [row][k]
    __shared__ __nv_bfloat16 Bsn[128][40];   // [n][k]
    __shared__ int topBase[128], botBase[128];

    const int tid  = threadIdx.x;
    const int lane = tid & 31;
    const int warp = tid >> 5;
    const int warpM = warp & 3;
    const int warpN = warp >> 2;
    const int g  = lane >> 2;
    const int t4 = lane & 3;
    const int row0 = blockIdx.y * 128;
    const int col0 = blockIdx.x * 128;

    if (tid < 128) {
        int grow = row0 + tid;
        int b = grow / EE;
        int e = grow - b * EE;
        topBase[tid] = (b*NN + recv_idx[e]) * HH;
        botBase[tid] = (b*NN + send_idx[e]) * HH;
    }
    __syncthreads();

    int arow[4], acg[4];
    float4 pa[4], pbv[4];
    #pragma unroll
    for (int it = 0; it < 4; it++) {
        int task = it*256 + tid;
        arow[it] = task & 127;
        acg[it]  = task >> 7;
        pa[it]  = *reinterpret_cast<const float4*>(&xTop[topBase[arow[it]] + acg[it]*4]);
        pbv[it] = *reinterpret_cast<const float4*>(&xBot[botBase[arow[it]] + acg[it]*4]);
    }

    float acc[2][8][4] = {};
    const int mrow0 = warpM * 32;
    const int ncol0 = warpN * 64;

    for (int k0 = 0; k0 < HH; k0 += 32) {
        // ---- store A from prefetch regs (add + bias + elu -> bf16) ----
        #pragma unroll
        for (int it = 0; it < 4; it++) {
            int cb = k0 + acg[it]*4;
            float4 bb = *reinterpret_cast<const float4*>(&b1[cb]);
            float4 a = pa[it], bv = pbv[it];
            unsigned p0 = packbf2(elu_ff(a.x + bv.x + bb.x), elu_ff(a.y + bv.y + bb.y));
            unsigned p1 = packbf2(elu_ff(a.z + bv.z + bb.z), elu_ff(a.w + bv.w + bb.w));
            *reinterpret_cast<uint2*>(&As[arow[it]][acg[it]*4]) = make_uint2(p0, p1);
        }
        // ---- B tile direct (L2-hot weights) ----
        #pragma unroll
        for (int it = 0; it < 8; it++) {
            int task = it*256 + tid;
            int cc = task & 127;
            int kp = task >> 7;
            float w0 = W2[(long)(k0 + 2*kp    )*HH + col0 + cc];
            float w1 = W2[(long)(k0 + 2*kp + 1)*HH + col0 + cc];
            *reinterpret_cast<unsigned*>(&Bsn[cc][2*kp]) = packbf2(w0, w1);
        }
        // ---- prefetch next gather tile ----
        if (k0 + 32 < HH) {
            #pragma unroll
            for (int it = 0; it < 4; it++) {
                int cb = k0 + 32 + acg[it]*4;
                pa[it]  = *reinterpret_cast<const float4*>(&xTop[topBase[arow[it]] + cb]);
                pbv[it] = *reinterpret_cast<const float4*>(&xBot[botBase[arow[it]] + cb]);
            }
        }
        __syncthreads();

        #pragma unroll
        for (int ks = 0; ks < 32; ks += 16) {
            unsigned afr[2][4];
            #pragma unroll
            for (int i = 0; i < 2; i++) {
                int r = mrow0 + i*16;
                afr[i][0] = *reinterpret_cast<unsigned*>(&As[r + g    ][ks + 2*t4    ]);
                afr[i][1] = *reinterpret_cast<unsigned*>(&As[r + g + 8][ks + 2*t4    ]);
                afr[i][2] = *reinterpret_cast<unsigned*>(&As[r + g    ][ks + 2*t4 + 8]);
                afr[i][3] = *reinterpret_cast<unsigned*>(&As[r + g + 8][ks + 2*t4 + 8]);
            }
            #pragma unroll
            for (int j = 0; j < 8; j++) {
                int nn = ncol0 + j*8 + g;
                unsigned b0 = *reinterpret_cast<unsigned*>(&Bsn[nn][ks + 2*t4    ]);
                unsigned b1r = *reinterpret_cast<unsigned*>(&Bsn[nn][ks + 2*t4 + 8]);
                #pragma unroll
                for (int i = 0; i < 2; i++)
                    asm volatile(
                        "mma.sync.aligned.m16n8k16.row.col.f32.bf16.bf16.f32 "
                        "{%0,%1,%2,%3}, {%4,%5,%6,%7}, {%8,%9}, {%0,%1,%2,%3};"
                        : "+f"(acc[i][j][0]), "+f"(acc[i][j][1]),
                          "+f"(acc[i][j][2]), "+f"(acc[i][j][3])
                        : "r"(afr[i][0]), "r"(afr[i][1]), "r"(afr[i][2]), "r"(afr[i][3]),
                          "r"(b0), "r"(b1r));
            }
        }
        __syncthreads();
    }

    #pragma unroll
    for (int i = 0; i < 2; i++) {
        int r_lo = row0 + mrow0 + i*16 + g;
        #pragma unroll
        for (int j = 0; j < 8; j++) {
            int c = col0 + ncol0 + j*8 + t4*2;
            float bb0 = b2[c], bb1 = b2[c+1];
            h2[(long)r_lo*HH + c    ]     = elu_ff(acc[i][j][0] + bb0);
            h2[(long)r_lo*HH + c + 1]     = elu_ff(acc[i][j][1] + bb1);
            h2[(long)(r_lo+8)*HH + c    ] = elu_ff(acc[i][j][2] + bb0);
            h2[(long)(r_lo+8)*HH + c + 1] = elu_ff(acc[i][j][3] + bb1);
        }
    }
}

// ---------------- combined per-node gather sums ----------------
__global__ void scatter_kernel(const float* __restrict__ h2,
                               const int* __restrict__ list_rec, const int* __restrict__ cnt_rec,
                               const int* __restrict__ list_send, const int* __restrict__ cnt_send,
                               float* __restrict__ inc_raw, float* __restrict__ sq_part,
                               float* __restrict__ out_raw) {
    int id = blockIdx.x;               // 0..2047
    bool isOut = id >= ROWS_N;
    int bn = id & (ROWS_N-1);
    int b = bn >> 6, n = bn & 63;
    int h = threadIdx.x;
    if (!isOut) {
        int cnt = cnt_rec[n];
        float acc = 0.f, accsq = 0.f;
        for (int k = 0; k < cnt; k++) {
            int e = list_rec[n*EE + k];
            float v = h2[(long)(b*EE + e)*HH + h];
            acc += v; accsq += v*v;
        }
        inc_raw[bn*HH + h] = acc;
        sq_part[bn*HH + h] = accsq;
    } else {
        int cnt = cnt_send[n];
        float acc = 0.f;
        for (int k = 0; k < cnt; k++) {
            int e = list_send[n*EE + k];
            acc += h2[(long)(b*EE + e)*HH + h];
        }
        out_raw[bn*HH + h] = acc;
    }
}

// ---------------- BN stats -> affine (a,c) ----------------
template<bool SRC_SQ>
__global__ void stats_kernel(const float* __restrict__ sum_part, const float* __restrict__ sq_part,
                             const float* __restrict__ gamma, const float* __restrict__ beta,
                             float* __restrict__ a, float* __restrict__ c,
                             int nrows, float count) {
    int h = blockIdx.x;
    float s = 0.f, sq = 0.f;
    for (int r = threadIdx.x; r < nrows; r += 256) {
        float v = sum_part[r*HH + h];
        s += v;
        if (SRC_SQ) sq += v*v; else sq += sq_part[r*HH + h];
    }
    __shared__ float ss[256], ssq[256];
    ss[threadIdx.x] = s; ssq[threadIdx.x] = sq;
    __syncthreads();
    for (int st = 128; st > 0; st >>= 1) {
        if (threadIdx.x < st) { ss[threadIdx.x] += ss[threadIdx.x+st]; ssq[threadIdx.x] += ssq[threadIdx.x+st]; }
        __syncthreads();
    }
    if (threadIdx.x == 0) {
        float mu = ss[0] / count;
        float var = ssq[0] / count - mu*mu;
        float av = gamma[h] * rsqrtf(var + 1e-5f);
        a[h] = av;
        c[h] = beta[h] - mu * av;
    }
}

// ---------------- launcher ----------------
extern "C" void kernel_launch(void* const* d_in, const int* in_sizes, int n_in,
                              void* d_out, int out_size) {
    const float* centers  = (const float*)d_in[0];
    const float* rel_rec  = (const float*)d_in[1];
    const float* rel_send = (const float*)d_in[2];
    const float* W_traj   = (const float*)d_in[3];
    const float* b_traj   = (const float*)d_in[4];
    const float* n2e_W1   = (const float*)d_in[5];
    const float* n2e_b1   = (const float*)d_in[6];
    const float* n2e_W2   = (const float*)d_in[7];
    const float* n2e_b2   = (const float*)d_in[8];
    const float* n2e_g    = (const float*)d_in[9];
    const float* n2e_be   = (const float*)d_in[10];
    const float* e2n_W1   = (const float*)d_in[11];
    const float* e2n_b1   = (const float*)d_in[12];
    const float* e2n_W2   = (const float*)d_in[13];
    const float* e2n_b2   = (const float*)d_in[14];
    const float* e2n_g    = (const float*)d_in[15];
    const float* e2n_be   = (const float*)d_in[16];
    const float* W_fuse   = (const float*)d_in[17];
    const float* b_fuse   = (const float*)d_in[18];
    const float* W_pred   = (const float*)d_in[19];
    const float* b_pred   = (const float*)d_in[20];
    float* out = (float*)d_out;

    float *p_x, *p_xTop, *p_xBot, *p_h2, *p_inc, *p_incsq, *p_outg;
    float *p_nh1, *p_mraw, *p_fused;
    float *p_ae, *p_ce, *p_an, *p_cn, *p_idr, *p_ids;
    int *p_recv, *p_send, *p_lr, *p_ls, *p_cr, *p_cs;
    cudaGetSymbolAddress((void**)&p_x, d_x);
    cudaGetSymbolAddress((void**)&p_xTop, d_xTop);
    cudaGetSymbolAddress((void**)&p_xBot, d_xBot);
    cudaGetSymbolAddress((void**)&p_h2, d_h2);
    cudaGetSymbolAddress((void**)&p_inc, d_inc);
    cudaGetSymbolAddress((void**)&p_incsq, d_incsq);
    cudaGetSymbolAddress((void**)&p_outg, d_outg);
    cudaGetSymbolAddress((void**)&p_nh1, d_nh1);
    cudaGetSymbolAddress((void**)&p_mraw, d_mraw);
    cudaGetSymbolAddress((void**)&p_fused, d_fused);
    cudaGetSymbolAddress((void**)&p_ae, d_ae);
    cudaGetSymbolAddress((void**)&p_ce, d_ce);
    cudaGetSymbolAddress((void**)&p_an, d_an);
    cudaGetSymbolAddress((void**)&p_cn, d_cn);
    cudaGetSymbolAddress((void**)&p_idr, d_invdegrec);
    cudaGetSymbolAddress((void**)&p_ids, d_invdegsend);
    cudaGetSymbolAddress((void**)&p_recv, d_recv);
    cudaGetSymbolAddress((void**)&p_send, d_send);
    cudaGetSymbolAddress((void**)&p_lr, d_listrec);
    cudaGetSymbolAddress((void**)&p_ls, d_listsend);
    cudaGetSymbolAddress((void**)&p_cr, d_cntrec);
    cudaGetSymbolAddress((void**)&p_cs, d_cntsend);

    // 1. edge indices + lists
    derive_kernel<<<(EE+255)/256, 256>>>(rel_rec, rel_send, p_recv, p_send);
    build_lists_kernel<<<128, 64>>>(p_recv, p_send, p_lr, p_ls, p_cr, p_cs, p_idr, p_ids);

    // 2. trajectory embedding
    traj_kernel<<<ROWS_N, HH>>>(centers, W_traj, b_traj, p_x);

    // 3. xTop/xBot (dual-output, pipelined tf32)
    mma_gemm_v2<0,false,false><<<dim3(HH/64, ROWS_N/64, 2), 256>>>(
        p_x, nullptr, nullptr, nullptr, nullptr, nullptr,
        n2e_W1, n2e_W1 + HH*HH, nullptr, p_xTop, p_xBot, ROWS_N, HH, HH);

    // 4. fused edge MLP
    edge_gemm2_bf16<<<dim3(HH/128, ROWS_E/128), 256>>>(p_xTop, p_xBot, n2e_b1,
                                                       n2e_W2, n2e_b2,
                                                       p_recv, p_send, p_h2);

    // 5. scatter sums + edge BN stats
    scatter_kernel<<<2*ROWS_N, HH>>>(p_h2, p_lr, p_cr, p_ls, p_cs, p_inc, p_incsq, p_outg);
    stats_kernel<false><<<HH, 256>>>(p_inc, p_incsq, n2e_g, n2e_be, p_ae, p_ce, ROWS_N, (float)ROWS_E);

    // 6. node MLP (layer 1 with fused normalize/affine A-build)
    mma_gemm_v2<1,true,false><<<dim3(HH/64, ROWS_N/64, 1), 256>>>(
        p_inc, p_outg, p_ae, p_ce, p_idr, p_ids,
        e2n_W1, e2n_W1, e2n_b1, p_nh1, p_nh1, ROWS_N, HH, 2*HH);
    mma_gemm_v2<0,true,false><<<dim3(HH/64, ROWS_N/64, 1), 256>>>(
        p_nh1, nullptr, nullptr, nullptr, nullptr, nullptr,
        e2n_W2, e2n_W2, e2n_b2, p_mraw, p_mraw, ROWS_N, HH, HH);
    stats_kernel<true><<<HH, 256>>>(p_mraw, nullptr, e2n_g, e2n_be, p_an, p_cn, ROWS_N, (float)ROWS_N);

    // 7. fuse (cat built in A-loader) + predict (+ fused cumsum epilogue)
    mma_gemm_v2<2,false,false><<<dim3(HH/64, ROWS_N/64, 1), 256>>>(
        p_x, p_mraw, p_an, p_cn, nullptr, nullptr,
        W_fuse, W_fuse, b_fuse, p_fused, p_fused, ROWS_N, HH, 2*HH);
    pred_pos_kernel<<<dim3(1, ROWS_N/64), 256>>>(p_fused, W_pred, b_pred, centers, out);
}

// round 6
// speedup vs baseline: 2.4210x; 1.0045x over previous
#include <cuda_runtime.h>
#include <cuda_bf16.h>
#include <math.h>
#include <stdint.h>

#define BB   16
#define NN   64
#define PREV 6
#define PRED 30
#define HH   256
#define EE   (NN*(NN-1))      // 4032
#define ROWS_E (BB*EE)        // 64512
#define ROWS_N (BB*NN)        // 1024

// ---------------- static scratch ----------------
__device__ float d_x[ROWS_N*HH];
__device__ float d_xTop[ROWS_N*HH];
__device__ float d_xBot[ROWS_N*HH];
__device__ float d_h2[ROWS_E*HH];
__device__ float d_inc[ROWS_N*HH];
__device__ float d_incsq[ROWS_N*HH];
__device__ float d_outg[ROWS_N*HH];
__device__ float d_nh1[ROWS_N*HH];
__device__ float d_mraw[ROWS_N*HH];
__device__ float d_fused[ROWS_N*HH];
__device__ float d_ae[HH], d_ce[HH], d_an[HH], d_cn[HH];
__device__ int   d_recv[EE], d_send[EE];
__device__ int   d_listrec[NN*EE], d_listsend[NN*EE];
__device__ int   d_cntrec[NN], d_cntsend[NN];
__device__ float d_invdegrec[NN], d_invdegsend[NN];
__device__ __nv_bfloat16 d_w2t[HH*HH];   // W2^T in bf16: [n][k]

__device__ __forceinline__ float elu_f(float x)  { return x > 0.f ? x : (expf(x) - 1.f); }
__device__ __forceinline__ float elu_ff(float x) { return x > 0.f ? x : (__expf(x) - 1.f); }

__device__ __forceinline__ unsigned f2tf32(float x) {
    unsigned r;
    asm("cvt.rna.tf32.f32 %0, %1;" : "=r"(r) : "f"(x));
    return r;
}
__device__ __forceinline__ unsigned packbf2(float lo, float hi) {
    __nv_bfloat162 v = __floats2bfloat162_rn(lo, hi);
    return *reinterpret_cast<unsigned*>(&v);
}

// ---------------- derive edge indices ----------------
__global__ void derive_kernel(const float* __restrict__ rel_rec,
                              const float* __restrict__ rel_send,
                              int* __restrict__ recv_idx, int* __restrict__ send_idx) {
    int e = blockIdx.x * blockDim.x + threadIdx.x;
    if (e >= EE) return;
    int r = 0, s = 0; float br = -1.f, bs = -1.f;
    for (int n = 0; n < NN; n++) {
        float vr = rel_rec[e*NN + n];
        float vs = rel_send[e*NN + n];
        if (vr > br) { br = vr; r = n; }
        if (vs > bs) { bs = vs; s = n; }
    }
    recv_idx[e] = r; send_idx[e] = s;
}

// ---------------- parallel deterministic list build ----------------
__global__ void build_lists_kernel(const int* __restrict__ recv_idx,
                                   const int* __restrict__ send_idx,
                                   int* __restrict__ list_rec, int* __restrict__ list_send,
                                   int* __restrict__ cnt_rec, int* __restrict__ cnt_send,
                                   float* __restrict__ invdeg_rec, float* __restrict__ invdeg_send) {
    const bool isSend = blockIdx.x >= NN;
    const int n = blockIdx.x & (NN-1);
    const int* __restrict__ idx = isSend ? send_idx : recv_idx;
    int* __restrict__ list = (isSend ? list_send : list_rec) + n*EE;
    const int t = threadIdx.x;            // 64 threads
    const int CH = EE / 64;               // 63
    const int base = t * CH;
    int c = 0;
    for (int i = 0; i < CH; i++) c += (idx[base+i] == n) ? 1 : 0;
    __shared__ int pre[64];
    pre[t] = c;
    __syncthreads();
    for (int off = 1; off < 64; off <<= 1) {
        int v = (t >= off) ? pre[t-off] : 0;
        __syncthreads();
        pre[t] += v;
        __syncthreads();
    }
    int offset = pre[t] - c;
    for (int i = 0; i < CH; i++) {
        int e = base + i;
        if (idx[e] == n) list[offset++] = e;
    }
    if (t == 63) {
        int tot = pre[63];
        float iv = tot ? 1.f/(float)tot : 1.f;
        if (isSend) { cnt_send[n] = tot; invdeg_send[n] = iv; }
        else        { cnt_rec[n]  = tot; invdeg_rec[n]  = iv; }
    }
}

// ---------------- W2 transpose + bf16 convert ----------------
__global__ void w2t_kernel(const float* __restrict__ W2, __nv_bfloat16* __restrict__ out) {
    int n = blockIdx.x;            // 256
    int k = threadIdx.x;           // 256
    out[n*HH + k] = __float2bfloat16(W2[k*HH + n]);
}

// ---------------- trajectory embedding ----------------
__global__ void traj_kernel(const float* __restrict__ centers,
                            const float* __restrict__ W, const float* __restrict__ bias,
                            float* __restrict__ x) {
    int row = blockIdx.x;
    int h = threadIdx.x;
    __shared__ float rp[PREV*2];
    if (h < PREV*2) {
        int p = h >> 1, c = h & 1;
        float v = 0.f;
        if (p > 0) v = centers[row*PREV*2 + p*2 + c] - centers[row*PREV*2 + (p-1)*2 + c];
        rp[h] = v;
    }
    __syncthreads();
    float acc = bias[h];
    #pragma unroll
    for (int k = 0; k < PREV*2; k++) acc += rp[k] * W[k*HH + h];
    x[row*HH + h] = acc;
}

// =======================================================================
// Generic double-buffered tf32 GEMM: C = act(A'@B + bias), A' built on the fly.
// AMODE 0: A' = A0 (row stride K)
// AMODE 1: A' = [a*(inc*invDegR)+c , a*(outg*invDegS)+c]  (K=512)
// AMODE 2: A' = [x , a*mraw+c]                            (K=512)
// Block tile 64x64, K-step 32, one __syncthreads per step.
// =======================================================================
template<int AMODE, bool ELU, bool GUARD_N>
__global__ __launch_bounds__(256)
void mma_gemm_v2(const float* __restrict__ A0, const float* __restrict__ A1,
                 const float* __restrict__ aVec, const float* __restrict__ cVec,
                 const float* __restrict__ invDegR, const float* __restrict__ invDegS,
                 const float* __restrict__ B0, const float* __restrict__ B1,
                 const float* __restrict__ bias,
                 float* __restrict__ C0, float* __restrict__ C1,
                 int M, int N, int K) {
    const float* __restrict__ Bm = (blockIdx.z == 0) ? B0 : B1;
    float* __restrict__ C = (blockIdx.z == 0) ? C0 : C1;

    __shared__ unsigned Asm[2][64][36];
    __shared__ unsigned Bsm[2][32][72];
    const int tid  = threadIdx.x;
    const int lane = tid & 31;
    const int warp = tid >> 5;
    const int warpM = warp & 1;
    const int warpN = warp >> 1;
    const int g  = lane >> 2;
    const int t4 = lane & 3;
    const int row0 = blockIdx.y * 64;
    const int col0 = blockIdx.x * 64;

    int arow[2], akq[2], bkk[2], bq[2];
    #pragma unroll
    for (int it = 0; it < 2; it++) {
        int ta = it*256 + tid;
        akq[it] = ta & 7;  arow[it] = ta >> 3;
        bkk[it] = ta >> 4; bq[it]  = ta & 15;
    }

    float4 pa[2], pb[2];

    auto prefetch = [&](int k0) {
        #pragma unroll
        for (int it = 0; it < 2; it++) {
            int gk = k0 + akq[it]*4;
            if (AMODE == 0) {
                pa[it] = *reinterpret_cast<const float4*>(&A0[(long)(row0+arow[it])*K + gk]);
            } else {
                const float* src = (gk >= HH) ? A1 : A0;
                pa[it] = *reinterpret_cast<const float4*>(&src[(long)(row0+arow[it])*HH + (gk & (HH-1))]);
            }
            int c0 = col0 + bq[it]*4;
            if (!GUARD_N) {
                pb[it] = *reinterpret_cast<const float4*>(&Bm[(long)(k0+bkk[it])*N + c0]);
            } else {
                float4 v;
                v.x = (c0+0 < N) ? Bm[(long)(k0+bkk[it])*N + c0+0] : 0.f;
                v.y = (c0+1 < N) ? Bm[(long)(k0+bkk[it])*N + c0+1] : 0.f;
                v.z = (c0+2 < N) ? Bm[(long)(k0+bkk[it])*N + c0+2] : 0.f;
                v.w = (c0+3 < N) ? Bm[(long)(k0+bkk[it])*N + c0+3] : 0.f;
                pb[it] = v;
            }
        }
    };

    auto store = [&](int s, int k0) {
        #pragma unroll
        for (int it = 0; it < 2; it++) {
            int gk = k0 + akq[it]*4;
            float4 v = pa[it];
            if (AMODE == 1) {
                int col = gk & (HH-1);
                float invd = ((gk >= HH) ? invDegS : invDegR)[(row0+arow[it]) & (NN-1)];
                float4 a4 = *reinterpret_cast<const float4*>(&aVec[col]);
                float4 c4 = *reinterpret_cast<const float4*>(&cVec[col]);
                v.x = a4.x*(v.x*invd)+c4.x; v.y = a4.y*(v.y*invd)+c4.y;
                v.z = a4.z*(v.z*invd)+c4.z; v.w = a4.w*(v.w*invd)+c4.w;
            } else if (AMODE == 2) {
                if (gk >= HH) {
                    int col = gk & (HH-1);
                    float4 a4 = *reinterpret_cast<const float4*>(&aVec[col]);
                    float4 c4 = *reinterpret_cast<const float4*>(&cVec[col]);
                    v.x = a4.x*v.x+c4.x; v.y = a4.y*v.y+c4.y;
                    v.z = a4.z*v.z+c4.z; v.w = a4.w*v.w+c4.w;
                }
            }
            Asm[s][arow[it]][akq[it]*4+0] = f2tf32(v.x);
            Asm[s][arow[it]][akq[it]*4+1] = f2tf32(v.y);
            Asm[s][arow[it]][akq[it]*4+2] = f2tf32(v.z);
            Asm[s][arow[it]][akq[it]*4+3] = f2tf32(v.w);

            float4 w = pb[it];
            Bsm[s][bkk[it]][bq[it]*4+0] = f2tf32(w.x);
            Bsm[s][bkk[it]][bq[it]*4+1] = f2tf32(w.y);
            Bsm[s][bkk[it]][bq[it]*4+2] = f2tf32(w.z);
            Bsm[s][bkk[it]][bq[it]*4+3] = f2tf32(w.w);
        }
    };

    float acc[2][2][4] = {};
    const int nIter = K >> 5;

    prefetch(0);
    store(0, 0);
    __syncthreads();

    for (int i = 0; i < nIter; i++) {
        int cur = i & 1;
        if (i + 1 < nIter) prefetch((i+1) * 32);

        #pragma unroll
        for (int ks = 0; ks < 32; ks += 8) {
            unsigned afr[2][4];
            #pragma unroll
            for (int ii = 0; ii < 2; ii++) {
                int r = warpM*32 + ii*16;
                afr[ii][0] = Asm[cur][r + g    ][ks + t4    ];
                afr[ii][1] = Asm[cur][r + g + 8][ks + t4    ];
                afr[ii][2] = Asm[cur][r + g    ][ks + t4 + 4];
                afr[ii][3] = Asm[cur][r + g + 8][ks + t4 + 4];
            }
            unsigned bfr[2][2];
            #pragma unroll
            for (int j = 0; j < 2; j++) {
                int nn = warpN*16 + j*8 + g;
                bfr[j][0] = Bsm[cur][ks + t4    ][nn];
                bfr[j][1] = Bsm[cur][ks + t4 + 4][nn];
            }
            #pragma unroll
            for (int ii = 0; ii < 2; ii++)
                #pragma unroll
                for (int j = 0; j < 2; j++)
                    asm volatile(
                        "mma.sync.aligned.m16n8k8.row.col.f32.tf32.tf32.f32 "
                        "{%0,%1,%2,%3}, {%4,%5,%6,%7}, {%8,%9}, {%0,%1,%2,%3};"
                        : "+f"(acc[ii][j][0]), "+f"(acc[ii][j][1]),
                          "+f"(acc[ii][j][2]), "+f"(acc[ii][j][3])
                        : "r"(afr[ii][0]), "r"(afr[ii][1]), "r"(afr[ii][2]), "r"(afr[ii][3]),
                          "r"(bfr[j][0]), "r"(bfr[j][1]));
        }
        if (i + 1 < nIter) store(cur ^ 1, (i+1) * 32);
        __syncthreads();
    }

    #pragma unroll
    for (int i = 0; i < 2; i++) {
        int r = row0 + warpM*32 + i*16 + g;
        #pragma unroll
        for (int j = 0; j < 2; j++) {
            int c = col0 + warpN*16 + j*8 + t4*2;
            #pragma unroll
            for (int h = 0; h < 2; h++) {
                int cc = c + h;
                if (GUARD_N && cc >= N) continue;
                float bb = bias ? bias[cc] : 0.f;
                float v0 = acc[i][j][h]   + bb;
                float v1 = acc[i][j][2+h] + bb;
                if (ELU) { v0 = elu_f(v0); v1 = elu_f(v1); }
                C[(long)r*N + cc]     = v0;
                C[(long)(r+8)*N + cc] = v1;
            }
        }
    }
}

// =======================================================================
// Pred GEMM + cumsum epilogue (unchanged from R4 passing version)
// =======================================================================
__global__ __launch_bounds__(256)
void pred_pos_kernel(const float* __restrict__ A0, const float* __restrict__ Bm,
                     const float* __restrict__ bias, const float* __restrict__ centers,
                     float* __restrict__ out) {
    const int N = PRED*2;
    const int K = HH;
    __shared__ unsigned Asm[64][36];
    __shared__ unsigned Bsm[32][72];
    __shared__ float Cs[64][64];
    const int tid  = threadIdx.x;
    const int lane = tid & 31;
    const int warp = tid >> 5;
    const int warpM = warp & 1;
    const int warpN = warp >> 1;
    const int g  = lane >> 2;
    const int t4 = lane & 3;
    const int row0 = blockIdx.y * 64;

    int arow[2], akq[2], bkk[2], bq[2];
    #pragma unroll
    for (int it = 0; it < 2; it++) {
        int ta = it*256 + tid;
        akq[it] = ta & 7;  arow[it] = ta >> 3;
        bkk[it] = ta >> 4; bq[it]  = ta & 15;
    }
    float4 pa[2], pb[2];
    #pragma unroll
    for (int it = 0; it < 2; it++) {
        pa[it] = *reinterpret_cast<const float4*>(&A0[(long)(row0+arow[it])*K + akq[it]*4]);
        int c0 = bq[it]*4;
        float4 v;
        v.x = (c0+0 < N) ? Bm[(long)bkk[it]*N + c0+0] : 0.f;
        v.y = (c0+1 < N) ? Bm[(long)bkk[it]*N + c0+1] : 0.f;
        v.z = (c0+2 < N) ? Bm[(long)bkk[it]*N + c0+2] : 0.f;
        v.w = (c0+3 < N) ? Bm[(long)bkk[it]*N + c0+3] : 0.f;
        pb[it] = v;
    }

    float acc[2][2][4] = {};
    for (int k0 = 0; k0 < K; k0 += 32) {
        #pragma unroll
        for (int it = 0; it < 2; it++) {
            float4 v = pa[it];
            Asm[arow[it]][akq[it]*4+0] = f2tf32(v.x);
            Asm[arow[it]][akq[it]*4+1] = f2tf32(v.y);
            Asm[arow[it]][akq[it]*4+2] = f2tf32(v.z);
            Asm[arow[it]][akq[it]*4+3] = f2tf32(v.w);
            float4 w = pb[it];
            Bsm[bkk[it]][bq[it]*4+0] = f2tf32(w.x);
            Bsm[bkk[it]][bq[it]*4+1] = f2tf32(w.y);
            Bsm[bkk[it]][bq[it]*4+2] = f2tf32(w.z);
            Bsm[bkk[it]][bq[it]*4+3] = f2tf32(w.w);
        }
        if (k0 + 32 < K) {
            int kn = k0 + 32;
            #pragma unroll
            for (int it = 0; it < 2; it++) {
                pa[it] = *reinterpret_cast<const float4*>(&A0[(long)(row0+arow[it])*K + kn + akq[it]*4]);
                int c0 = bq[it]*4;
                float4 v;
                v.x = (c0+0 < N) ? Bm[(long)(kn+bkk[it])*N + c0+0] : 0.f;
                v.y = (c0+1 < N) ? Bm[(long)(kn+bkk[it])*N + c0+1] : 0.f;
                v.z = (c0+2 < N) ? Bm[(long)(kn+bkk[it])*N + c0+2] : 0.f;
                v.w = (c0+3 < N) ? Bm[(long)(kn+bkk[it])*N + c0+3] : 0.f;
                pb[it] = v;
            }
        }
        __syncthreads();
        #pragma unroll
        for (int ks = 0; ks < 32; ks += 8) {
            unsigned afr[2][4];
            #pragma unroll
            for (int i = 0; i < 2; i++) {
                int r = warpM*32 + i*16;
                afr[i][0] = Asm[r + g    ][ks + t4    ];
                afr[i][1] = Asm[r + g + 8][ks + t4    ];
                afr[i][2] = Asm[r + g    ][ks + t4 + 4];
                afr[i][3] = Asm[r + g + 8][ks + t4 + 4];
            }
            unsigned bfr[2][2];
            #pragma unroll
            for (int j = 0; j < 2; j++) {
                int nn = warpN*16 + j*8 + g;
                bfr[j][0] = Bsm[ks + t4    ][nn];
                bfr[j][1] = Bsm[ks + t4 + 4][nn];
            }
            #pragma unroll
            for (int i = 0; i < 2; i++)
                #pragma unroll
                for (int j = 0; j < 2; j++)
                    asm volatile(
                        "mma.sync.aligned.m16n8k8.row.col.f32.tf32.tf32.f32 "
                        "{%0,%1,%2,%3}, {%4,%5,%6,%7}, {%8,%9}, {%0,%1,%2,%3};"
                        : "+f"(acc[i][j][0]), "+f"(acc[i][j][1]),
                          "+f"(acc[i][j][2]), "+f"(acc[i][j][3])
                        : "r"(afr[i][0]), "r"(afr[i][1]), "r"(afr[i][2]), "r"(afr[i][3]),
                          "r"(bfr[j][0]), "r"(bfr[j][1]));
        }
        __syncthreads();
    }

    #pragma unroll
    for (int i = 0; i < 2; i++) {
        int r = warpM*32 + i*16 + g;
        #pragma unroll
        for (int j = 0; j < 2; j++) {
            int c = warpN*16 + j*8 + t4*2;
            #pragma unroll
            for (int h = 0; h < 2; h++) {
                int cc = c + h;
                float bb = (cc < N) ? bias[cc] : 0.f;
                Cs[r][cc]   = acc[i][j][h]   + bb;
                Cs[r+8][cc] = acc[i][j][2+h] + bb;
            }
        }
    }
    __syncthreads();

    if (tid < 128) {
        int lrow = tid >> 1, dimc = tid & 1;
        int grow = row0 + lrow;
        float cur = centers[grow*PREV*2 + (PREV-1)*2 + dimc];
        float accum = 0.f;
        #pragma unroll
        for (int p = 0; p < PRED; p++) {
            float v = Cs[lrow][2*p + dimc];
            out[(long)grow*N + 2*p + dimc] = v;
            accum += v;
            out[(long)(ROWS_N)*N + (long)grow*N + 2*p + dimc] = accum + cur;
        }
    }
}

// =======================================================================
// Fused edge GEMM (bf16, double-buffered):
//   h2 = elu( elu(xTop[recv]+xBot[send]+b1) @ W2 + b2 )
// 128x128 tile, K-step 32, 2-stage smem, one sync per step.
// B read from pre-transposed bf16 W2^T.
// =======================================================================
__global__ __launch_bounds__(256, 2)
void edge_gemm2_bf16(const float* __restrict__ xTop, const float* __restrict__ xBot,
                     const float* __restrict__ b1,
                     const __nv_bfloat16* __restrict__ w2t, const float* __restrict__ b2,
                     const int* __restrict__ recv_idx, const int* __restrict__ send_idx,
                     float* __restrict__ h2) {
    __shared__ __nv_bfloat16 As[2][128][40];    // [stage][row][k]
    __shared__ __nv_bfloat16 Bsn[2][128][40];   // [stage][n][k]
    __shared__ int topBase[128], botBase[128];

    const int tid  = threadIdx.x;
    const int lane = tid & 31;
    const int warp = tid >> 5;
    const int warpM = warp & 3;
    const int warpN = warp >> 2;
    const int g  = lane >> 2;
    const int t4 = lane & 3;
    const int row0 = blockIdx.y * 128;
    const int col0 = blockIdx.x * 128;

    if (tid < 128) {
        int grow = row0 + tid;
        int b = grow / EE;
        int e = grow - b * EE;
        topBase[tid] = (b*NN + recv_idx[e]) * HH;
        botBase[tid] = (b*NN + send_idx[e]) * HH;
    }
    __syncthreads();

    // A tasks: 1024 (row, 4-col group); B tasks: 512 (n, 8-col group)
    int arow[4], acg[4];
    int bn[2], bkh[2];
    #pragma unroll
    for (int it = 0; it < 4; it++) {
        int task = it*256 + tid;
        arow[it] = task & 127;
        acg[it]  = task >> 7;
    }
    #pragma unroll
    for (int it = 0; it < 2; it++) {
        int task = it*256 + tid;
        bn[it]  = task & 127;
        bkh[it] = task >> 7;          // 0..3
    }

    float4 pa[4], pbv[4];
    uint4 pw[2];

    auto prefetch = [&](int k0) {
        #pragma unroll
        for (int it = 0; it < 4; it++) {
            int cb = k0 + acg[it]*4;
            pa[it]  = *reinterpret_cast<const float4*>(&xTop[topBase[arow[it]] + cb]);
            pbv[it] = *reinterpret_cast<const float4*>(&xBot[botBase[arow[it]] + cb]);
        }
        #pragma unroll
        for (int it = 0; it < 2; it++) {
            pw[it] = *reinterpret_cast<const uint4*>(&w2t[(long)(col0 + bn[it])*HH + k0 + bkh[it]*8]);
        }
    };

    auto store = [&](int s, int k0) {
        #pragma unroll
        for (int it = 0; it < 4; it++) {
            int cb = k0 + acg[it]*4;
            float4 bb = *reinterpret_cast<const float4*>(&b1[cb]);
            float4 a = pa[it], bv = pbv[it];
            unsigned p0 = packbf2(elu_ff(a.x + bv.x + bb.x), elu_ff(a.y + bv.y + bb.y));
            unsigned p1 = packbf2(elu_ff(a.z + bv.z + bb.z), elu_ff(a.w + bv.w + bb.w));
            *reinterpret_cast<uint2*>(&As[s][arow[it]][acg[it]*4]) = make_uint2(p0, p1);
        }
        #pragma unroll
        for (int it = 0; it < 2; it++) {
            *reinterpret_cast<uint4*>(&Bsn[s][bn[it]][bkh[it]*8]) = pw[it];
        }
    };

    float acc[2][8][4] = {};
    const int mrow0 = warpM * 32;
    const int ncol0 = warpN * 64;

    prefetch(0);
    store(0, 0);
    __syncthreads();

    #pragma unroll 1
    for (int i = 0; i < 8; i++) {
        int cur = i & 1;
        if (i < 7) prefetch((i+1) * 32);

        #pragma unroll
        for (int ks = 0; ks < 32; ks += 16) {
            unsigned afr[2][4];
            #pragma unroll
            for (int ii = 0; ii < 2; ii++) {
                int r = mrow0 + ii*16;
                afr[ii][0] = *reinterpret_cast<unsigned*>(&As[cur][r + g    ][ks + 2*t4    ]);
                afr[ii][1] = *reinterpret_cast<unsigned*>(&As[cur][r + g + 8][ks + 2*t4    ]);
                afr[ii][2] = *reinterpret_cast<unsigned*>(&As[cur][r + g    ][ks + 2*t4 + 8]);
                afr[ii][3] = *reinterpret_cast<unsigned*>(&As[cur][r + g + 8][ks + 2*t4 + 8]);
            }
            #pragma unroll
            for (int j = 0; j < 8; j++) {
                int nn = ncol0 + j*8 + g;
                unsigned b0 = *reinterpret_cast<unsigned*>(&Bsn[cur][nn][ks + 2*t4    ]);
                unsigned b1r = *reinterpret_cast<unsigned*>(&Bsn[cur][nn][ks + 2*t4 + 8]);
                #pragma unroll
                for (int ii = 0; ii < 2; ii++)
                    asm volatile(
                        "mma.sync.aligned.m16n8k16.row.col.f32.bf16.bf16.f32 "
                        "{%0,%1,%2,%3}, {%4,%5,%6,%7}, {%8,%9}, {%0,%1,%2,%3};"
                        : "+f"(acc[ii][j][0]), "+f"(acc[ii][j][1]),
                          "+f"(acc[ii][j][2]), "+f"(acc[ii][j][3])
                        : "r"(afr[ii][0]), "r"(afr[ii][1]), "r"(afr[ii][2]), "r"(afr[ii][3]),
                          "r"(b0), "r"(b1r));
            }
        }
        if (i < 7) store(cur ^ 1, (i+1) * 32);
        __syncthreads();
    }

    #pragma unroll
    for (int i = 0; i < 2; i++) {
        int r_lo = row0 + mrow0 + i*16 + g;
        #pragma unroll
        for (int j = 0; j < 8; j++) {
            int c = col0 + ncol0 + j*8 + t4*2;
            float bb0 = b2[c], bb1 = b2[c+1];
            h2[(long)r_lo*HH + c    ]     = elu_ff(acc[i][j][0] + bb0);
            h2[(long)r_lo*HH + c + 1]     = elu_ff(acc[i][j][1] + bb1);
            h2[(long)(r_lo+8)*HH + c    ] = elu_ff(acc[i][j][2] + bb0);
            h2[(long)(r_lo+8)*HH + c + 1] = elu_ff(acc[i][j][3] + bb1);
        }
    }
}

// ---------------- combined per-node gather sums ----------------
__global__ void scatter_kernel(const float* __restrict__ h2,
                               const int* __restrict__ list_rec, const int* __restrict__ cnt_rec,
                               const int* __restrict__ list_send, const int* __restrict__ cnt_send,
                               float* __restrict__ inc_raw, float* __restrict__ sq_part,
                               float* __restrict__ out_raw) {
    int id = blockIdx.x;
    bool isOut = id >= ROWS_N;
    int bn = id & (ROWS_N-1);
    int b = bn >> 6, n = bn & 63;
    int h = threadIdx.x;
    if (!isOut) {
        int cnt = cnt_rec[n];
        float acc = 0.f, accsq = 0.f;
        for (int k = 0; k < cnt; k++) {
            int e = list_rec[n*EE + k];
            float v = h2[(long)(b*EE + e)*HH + h];
            acc += v; accsq += v*v;
        }
        inc_raw[bn*HH + h] = acc;
        sq_part[bn*HH + h] = accsq;
    } else {
        int cnt = cnt_send[n];
        float acc = 0.f;
        for (int k = 0; k < cnt; k++) {
            int e = list_send[n*EE + k];
            acc += h2[(long)(b*EE + e)*HH + h];
        }
        out_raw[bn*HH + h] = acc;
    }
}

// ---------------- BN stats -> affine (a,c) ----------------
template<bool SRC_SQ>
__global__ void stats_kernel(const float* __restrict__ sum_part, const float* __restrict__ sq_part,
                             const float* __restrict__ gamma, const float* __restrict__ beta,
                             float* __restrict__ a, float* __restrict__ c,
                             int nrows, float count) {
    int h = blockIdx.x;
    float s = 0.f, sq = 0.f;
    for (int r = threadIdx.x; r < nrows; r += 256) {
        float v = sum_part[r*HH + h];
        s += v;
        if (SRC_SQ) sq += v*v; else sq += sq_part[r*HH + h];
    }
    __shared__ float ss[256], ssq[256];
    ss[threadIdx.x] = s; ssq[threadIdx.x] = sq;
    __syncthreads();
    for (int st = 128; st > 0; st >>= 1) {
        if (threadIdx.x < st) { ss[threadIdx.x] += ss[threadIdx.x+st]; ssq[threadIdx.x] += ssq[threadIdx.x+st]; }
        __syncthreads();
    }
    if (threadIdx.x == 0) {
        float mu = ss[0] / count;
        float var = ssq[0] / count - mu*mu;
        float av = gamma[h] * rsqrtf(var + 1e-5f);
        a[h] = av;
        c[h] = beta[h] - mu * av;
    }
}

// ---------------- launcher ----------------
extern "C" void kernel_launch(void* const* d_in, const int* in_sizes, int n_in,
                              void* d_out, int out_size) {
    const float* centers  = (const float*)d_in[0];
    const float* rel_rec  = (const float*)d_in[1];
    const float* rel_send = (const float*)d_in[2];
    const float* W_traj   = (const float*)d_in[3];
    const float* b_traj   = (const float*)d_in[4];
    const float* n2e_W1   = (const float*)d_in[5];
    const float* n2e_b1   = (const float*)d_in[6];
    const float* n2e_W2   = (const float*)d_in[7];
    const float* n2e_b2   = (const float*)d_in[8];
    const float* n2e_g    = (const float*)d_in[9];
    const float* n2e_be   = (const float*)d_in[10];
    const float* e2n_W1   = (const float*)d_in[11];
    const float* e2n_b1   = (const float*)d_in[12];
    const float* e2n_W2   = (const float*)d_in[13];
    const float* e2n_b2   = (const float*)d_in[14];
    const float* e2n_g    = (const float*)d_in[15];
    const float* e2n_be   = (const float*)d_in[16];
    const float* W_fuse   = (const float*)d_in[17];
    const float* b_fuse   = (const float*)d_in[18];
    const float* W_pred   = (const float*)d_in[19];
    const float* b_pred   = (const float*)d_in[20];
    float* out = (float*)d_out;

    float *p_x, *p_xTop, *p_xBot, *p_h2, *p_inc, *p_incsq, *p_outg;
    float *p_nh1, *p_mraw, *p_fused;
    float *p_ae, *p_ce, *p_an, *p_cn, *p_idr, *p_ids;
    int *p_recv, *p_send, *p_lr, *p_ls, *p_cr, *p_cs;
    __nv_bfloat16 *p_w2t;
    cudaGetSymbolAddress((void**)&p_x, d_x);
    cudaGetSymbolAddress((void**)&p_xTop, d_xTop);
    cudaGetSymbolAddress((void**)&p_xBot, d_xBot);
    cudaGetSymbolAddress((void**)&p_h2, d_h2);
    cudaGetSymbolAddress((void**)&p_inc, d_inc);
    cudaGetSymbolAddress((void**)&p_incsq, d_incsq);
    cudaGetSymbolAddress((void**)&p_outg, d_outg);
    cudaGetSymbolAddress((void**)&p_nh1, d_nh1);
    cudaGetSymbolAddress((void**)&p_mraw, d_mraw);
    cudaGetSymbolAddress((void**)&p_fused, d_fused);
    cudaGetSymbolAddress((void**)&p_ae, d_ae);
    cudaGetSymbolAddress((void**)&p_ce, d_ce);
    cudaGetSymbolAddress((void**)&p_an, d_an);
    cudaGetSymbolAddress((void**)&p_cn, d_cn);
    cudaGetSymbolAddress((void**)&p_idr, d_invdegrec);
    cudaGetSymbolAddress((void**)&p_ids, d_invdegsend);
    cudaGetSymbolAddress((void**)&p_recv, d_recv);
    cudaGetSymbolAddress((void**)&p_send, d_send);
    cudaGetSymbolAddress((void**)&p_lr, d_listrec);
    cudaGetSymbolAddress((void**)&p_ls, d_listsend);
    cudaGetSymbolAddress((void**)&p_cr, d_cntrec);
    cudaGetSymbolAddress((void**)&p_cs, d_cntsend);
    cudaGetSymbolAddress((void**)&p_w2t, d_w2t);

    // 1. edge indices + lists + W2^T bf16
    derive_kernel<<<(EE+255)/256, 256>>>(rel_rec, rel_send, p_recv, p_send);
    build_lists_kernel<<<128, 64>>>(p_recv, p_send, p_lr, p_ls, p_cr, p_cs, p_idr, p_ids);
    w2t_kernel<<<HH, HH>>>(n2e_W2, p_w2t);

    // 2. trajectory embedding
    traj_kernel<<<ROWS_N, HH>>>(centers, W_traj, b_traj, p_x);

    // 3. xTop/xBot (dual-output, double-buffered tf32)
    mma_gemm_v2<0,false,false><<<dim3(HH/64, ROWS_N/64, 2), 256>>>(
        p_x, nullptr, nullptr, nullptr, nullptr, nullptr,
        n2e_W1, n2e_W1 + HH*HH, nullptr, p_xTop, p_xBot, ROWS_N, HH, HH);

    // 4. fused edge MLP (double-buffered bf16)
    edge_gemm2_bf16<<<dim3(HH/128, ROWS_E/128), 256>>>(p_xTop, p_xBot, n2e_b1,
                                                       p_w2t, n2e_b2,
                                                       p_recv, p_send, p_h2);

    // 5. scatter sums + edge BN stats
    scatter_kernel<<<2*ROWS_N, HH>>>(p_h2, p_lr, p_cr, p_ls, p_cs, p_inc, p_incsq, p_outg);
    stats_kernel<false><<<HH, 256>>>(p_inc, p_incsq, n2e_g, n2e_be, p_ae, p_ce, ROWS_N, (float)ROWS_E);

    // 6. node MLP
    mma_gemm_v2<1,true,false><<<dim3(HH/64, ROWS_N/64, 1), 256>>>(
        p_inc, p_outg, p_ae, p_ce, p_idr, p_ids,
        e2n_W1, e2n_W1, e2n_b1, p_nh1, p_nh1, ROWS_N, HH, 2*HH);
    mma_gemm_v2<0,true,false><<<dim3(HH/64, ROWS_N/64, 1), 256>>>(
        p_nh1, nullptr, nullptr, nullptr, nullptr, nullptr,
        e2n_W2, e2n_W2, e2n_b2, p_mraw, p_mraw, ROWS_N, HH, HH);
    stats_kernel<true><<<HH, 256>>>(p_mraw, nullptr, e2n_g, e2n_be, p_an, p_cn, ROWS_N, (float)ROWS_N);

    // 7. fuse + predict (+ fused cumsum epilogue)
    mma_gemm_v2<2,false,false><<<dim3(HH/64, ROWS_N/64, 1), 256>>>(
        p_x, p_mraw, p_an, p_cn, nullptr, nullptr,
        W_fuse, W_fuse, b_fuse, p_fused, p_fused, ROWS_N, HH, 2*HH);
    pred_pos_kernel<<<dim3(1, ROWS_N/64), 256>>>(p_fused, W_pred, b_pred, centers, out);
}

// round 7
// speedup vs baseline: 2.4749x; 1.0223x over previous
#include <cuda_runtime.h>
#include <cuda_bf16.h>
#include <math.h>
#include <stdint.h>

#define BB   16
#define NN   64
#define PREV 6
#define PRED 30
#define HH   256
#define EE   (NN*(NN-1))      // 4032
#define ROWS_E (BB*EE)        // 64512
#define ROWS_N (BB*NN)        // 1024

// ---------------- static scratch ----------------
__device__ float d_x[ROWS_N*HH];
__device__ float d_xTop[ROWS_N*HH];
__device__ float d_xBot[ROWS_N*HH];
__device__ float d_h2[ROWS_E*HH];
__device__ float d_inc[ROWS_N*HH];
__device__ float d_incsq[ROWS_N*HH];
__device__ float d_outg[ROWS_N*HH];
__device__ float d_nh1[ROWS_N*HH];
__device__ float d_mraw[ROWS_N*HH];
__device__ float d_fused[ROWS_N*HH];
__device__ float d_ae[HH], d_ce[HH], d_an[HH], d_cn[HH];
__device__ int   d_recv[EE], d_send[EE];
__device__ int   d_listrec[NN*EE], d_listsend[NN*EE];
__device__ int   d_cntrec[NN], d_cntsend[NN];
__device__ float d_invdegrec[NN], d_invdegsend[NN];
__device__ __nv_bfloat16 d_w2t[HH*HH];   // W2^T in bf16: [n][k]

__device__ __forceinline__ float elu_f(float x)  { return x > 0.f ? x : (expf(x) - 1.f); }
__device__ __forceinline__ float elu_ff(float x) { return x > 0.f ? x : (__expf(x) - 1.f); }

__device__ __forceinline__ unsigned f2tf32(float x) {
    unsigned r;
    asm("cvt.rna.tf32.f32 %0, %1;" : "=r"(r) : "f"(x));
    return r;
}
__device__ __forceinline__ unsigned packbf2(float lo, float hi) {
    __nv_bfloat162 v = __floats2bfloat162_rn(lo, hi);
    return *reinterpret_cast<unsigned*>(&v);
}
__device__ __forceinline__ uint32_t smem_u32(const void* p) {
    uint32_t a;
    asm("{ .reg .u64 t; cvta.to.shared.u64 t, %1; cvt.u32.u64 %0, t; }" : "=r"(a) : "l"(p));
    return a;
}

#define LDSM4(r0,r1,r2,r3,addr) \
    asm volatile("ldmatrix.sync.aligned.m8n8.x4.shared.b16 {%0,%1,%2,%3}, [%4];" \
        : "=r"(r0), "=r"(r1), "=r"(r2), "=r"(r3) : "r"(addr))

// ---------------- derive edge indices ----------------
__global__ void derive_kernel(const float* __restrict__ rel_rec,
                              const float* __restrict__ rel_send,
                              int* __restrict__ recv_idx, int* __restrict__ send_idx) {
    int e = blockIdx.x * blockDim.x + threadIdx.x;
    if (e >= EE) return;
    int r = 0, s = 0; float br = -1.f, bs = -1.f;
    for (int n = 0; n < NN; n++) {
        float vr = rel_rec[e*NN + n];
        float vs = rel_send[e*NN + n];
        if (vr > br) { br = vr; r = n; }
        if (vs > bs) { bs = vs; s = n; }
    }
    recv_idx[e] = r; send_idx[e] = s;
}

// ---------------- parallel deterministic list build ----------------
__global__ void build_lists_kernel(const int* __restrict__ recv_idx,
                                   const int* __restrict__ send_idx,
                                   int* __restrict__ list_rec, int* __restrict__ list_send,
                                   int* __restrict__ cnt_rec, int* __restrict__ cnt_send,
                                   float* __restrict__ invdeg_rec, float* __restrict__ invdeg_send) {
    const bool isSend = blockIdx.x >= NN;
    const int n = blockIdx.x & (NN-1);
    const int* __restrict__ idx = isSend ? send_idx : recv_idx;
    int* __restrict__ list = (isSend ? list_send : list_rec) + n*EE;
    const int t = threadIdx.x;            // 64 threads
    const int CH = EE / 64;               // 63
    const int base = t * CH;
    int c = 0;
    for (int i = 0; i < CH; i++) c += (idx[base+i] == n) ? 1 : 0;
    __shared__ int pre[64];
    pre[t] = c;
    __syncthreads();
    for (int off = 1; off < 64; off <<= 1) {
        int v = (t >= off) ? pre[t-off] : 0;
        __syncthreads();
        pre[t] += v;
        __syncthreads();
    }
    int offset = pre[t] - c;
    for (int i = 0; i < CH; i++) {
        int e = base + i;
        if (idx[e] == n) list[offset++] = e;
    }
    if (t == 63) {
        int tot = pre[63];
        float iv = tot ? 1.f/(float)tot : 1.f;
        if (isSend) { cnt_send[n] = tot; invdeg_send[n] = iv; }
        else        { cnt_rec[n]  = tot; invdeg_rec[n]  = iv; }
    }
}

// ---------------- trajectory embedding + fused W2 transpose ----------------
// blocks 0..1023: traj rows; blocks 1024..1279: W2^T bf16 rows
__global__ void traj_w2t_kernel(const float* __restrict__ centers,
                                const float* __restrict__ W, const float* __restrict__ bias,
                                const float* __restrict__ W2, __nv_bfloat16* __restrict__ w2t,
                                float* __restrict__ x) {
    if (blockIdx.x >= ROWS_N) {
        int n = blockIdx.x - ROWS_N;   // 0..255
        int k = threadIdx.x;           // 0..255
        w2t[n*HH + k] = __float2bfloat16(W2[k*HH + n]);
        return;
    }
    int row = blockIdx.x;
    int h = threadIdx.x;
    __shared__ float rp[PREV*2];
    if (h < PREV*2) {
        int p = h >> 1, c = h & 1;
        float v = 0.f;
        if (p > 0) v = centers[row*PREV*2 + p*2 + c] - centers[row*PREV*2 + (p-1)*2 + c];
        rp[h] = v;
    }
    __syncthreads();
    float acc = bias[h];
    #pragma unroll
    for (int k = 0; k < PREV*2; k++) acc += rp[k] * W[k*HH + h];
    x[row*HH + h] = acc;
}

// =======================================================================
// Generic double-buffered tf32 GEMM (unchanged from R6 passing version)
// =======================================================================
template<int AMODE, bool ELU, bool GUARD_N>
__global__ __launch_bounds__(256)
void mma_gemm_v2(const float* __restrict__ A0, const float* __restrict__ A1,
                 const float* __restrict__ aVec, const float* __restrict__ cVec,
                 const float* __restrict__ invDegR, const float* __restrict__ invDegS,
                 const float* __restrict__ B0, const float* __restrict__ B1,
                 const float* __restrict__ bias,
                 float* __restrict__ C0, float* __restrict__ C1,
                 int M, int N, int K) {
    const float* __restrict__ Bm = (blockIdx.z == 0) ? B0 : B1;
    float* __restrict__ C = (blockIdx.z == 0) ? C0 : C1;

    __shared__ unsigned Asm[2][64][36];
    __shared__ unsigned Bsm[2][32][72];
    const int tid  = threadIdx.x;
    const int lane = tid & 31;
    const int warp = tid >> 5;
    const int warpM = warp & 1;
    const int warpN = warp >> 1;
    const int g  = lane >> 2;
    const int t4 = lane & 3;
    const int row0 = blockIdx.y * 64;
    const int col0 = blockIdx.x * 64;

    int arow[2], akq[2], bkk[2], bq[2];
    #pragma unroll
    for (int it = 0; it < 2; it++) {
        int ta = it*256 + tid;
        akq[it] = ta & 7;  arow[it] = ta >> 3;
        bkk[it] = ta >> 4; bq[it]  = ta & 15;
    }

    float4 pa[2], pb[2];

    auto prefetch = [&](int k0) {
        #pragma unroll
        for (int it = 0; it < 2; it++) {
            int gk = k0 + akq[it]*4;
            if (AMODE == 0) {
                pa[it] = *reinterpret_cast<const float4*>(&A0[(long)(row0+arow[it])*K + gk]);
            } else {
                const float* src = (gk >= HH) ? A1 : A0;
                pa[it] = *reinterpret_cast<const float4*>(&src[(long)(row0+arow[it])*HH + (gk & (HH-1))]);
            }
            int c0 = col0 + bq[it]*4;
            if (!GUARD_N) {
                pb[it] = *reinterpret_cast<const float4*>(&Bm[(long)(k0+bkk[it])*N + c0]);
            } else {
                float4 v;
                v.x = (c0+0 < N) ? Bm[(long)(k0+bkk[it])*N + c0+0] : 0.f;
                v.y = (c0+1 < N) ? Bm[(long)(k0+bkk[it])*N + c0+1] : 0.f;
                v.z = (c0+2 < N) ? Bm[(long)(k0+bkk[it])*N + c0+2] : 0.f;
                v.w = (c0+3 < N) ? Bm[(long)(k0+bkk[it])*N + c0+3] : 0.f;
                pb[it] = v;
            }
        }
    };

    auto store = [&](int s, int k0) {
        #pragma unroll
        for (int it = 0; it < 2; it++) {
            int gk = k0 + akq[it]*4;
            float4 v = pa[it];
            if (AMODE == 1) {
                int col = gk & (HH-1);
                float invd = ((gk >= HH) ? invDegS : invDegR)[(row0+arow[it]) & (NN-1)];
                float4 a4 = *reinterpret_cast<const float4*>(&aVec[col]);
                float4 c4 = *reinterpret_cast<const float4*>(&cVec[col]);
                v.x = a4.x*(v.x*invd)+c4.x; v.y = a4.y*(v.y*invd)+c4.y;
                v.z = a4.z*(v.z*invd)+c4.z; v.w = a4.w*(v.w*invd)+c4.w;
            } else if (AMODE == 2) {
                if (gk >= HH) {
                    int col = gk & (HH-1);
                    float4 a4 = *reinterpret_cast<const float4*>(&aVec[col]);
                    float4 c4 = *reinterpret_cast<const float4*>(&cVec[col]);
                    v.x = a4.x*v.x+c4.x; v.y = a4.y*v.y+c4.y;
                    v.z = a4.z*v.z+c4.z; v.w = a4.w*v.w+c4.w;
                }
            }
            Asm[s][arow[it]][akq[it]*4+0] = f2tf32(v.x);
            Asm[s][arow[it]][akq[it]*4+1] = f2tf32(v.y);
            Asm[s][arow[it]][akq[it]*4+2] = f2tf32(v.z);
            Asm[s][arow[it]][akq[it]*4+3] = f2tf32(v.w);

            float4 w = pb[it];
            Bsm[s][bkk[it]][bq[it]*4+0] = f2tf32(w.x);
            Bsm[s][bkk[it]][bq[it]*4+1] = f2tf32(w.y);
            Bsm[s][bkk[it]][bq[it]*4+2] = f2tf32(w.z);
            Bsm[s][bkk[it]][bq[it]*4+3] = f2tf32(w.w);
        }
    };

    float acc[2][2][4] = {};
    const int nIter = K >> 5;

    prefetch(0);
    store(0, 0);
    __syncthreads();

    for (int i = 0; i < nIter; i++) {
        int cur = i & 1;
        if (i + 1 < nIter) prefetch((i+1) * 32);

        #pragma unroll
        for (int ks = 0; ks < 32; ks += 8) {
            unsigned afr[2][4];
            #pragma unroll
            for (int ii = 0; ii < 2; ii++) {
                int r = warpM*32 + ii*16;
                afr[ii][0] = Asm[cur][r + g    ][ks + t4    ];
                afr[ii][1] = Asm[cur][r + g + 8][ks + t4    ];
                afr[ii][2] = Asm[cur][r + g    ][ks + t4 + 4];
                afr[ii][3] = Asm[cur][r + g + 8][ks + t4 + 4];
            }
            unsigned bfr[2][2];
            #pragma unroll
            for (int j = 0; j < 2; j++) {
                int nn = warpN*16 + j*8 + g;
                bfr[j][0] = Bsm[cur][ks + t4    ][nn];
                bfr[j][1] = Bsm[cur][ks + t4 + 4][nn];
            }
            #pragma unroll
            for (int ii = 0; ii < 2; ii++)
                #pragma unroll
                for (int j = 0; j < 2; j++)
                    asm volatile(
                        "mma.sync.aligned.m16n8k8.row.col.f32.tf32.tf32.f32 "
                        "{%0,%1,%2,%3}, {%4,%5,%6,%7}, {%8,%9}, {%0,%1,%2,%3};"
                        : "+f"(acc[ii][j][0]), "+f"(acc[ii][j][1]),
                          "+f"(acc[ii][j][2]), "+f"(acc[ii][j][3])
                        : "r"(afr[ii][0]), "r"(afr[ii][1]), "r"(afr[ii][2]), "r"(afr[ii][3]),
                          "r"(bfr[j][0]), "r"(bfr[j][1]));
        }
        if (i + 1 < nIter) store(cur ^ 1, (i+1) * 32);
        __syncthreads();
    }

    #pragma unroll
    for (int i = 0; i < 2; i++) {
        int r = row0 + warpM*32 + i*16 + g;
        #pragma unroll
        for (int j = 0; j < 2; j++) {
            int c = col0 + warpN*16 + j*8 + t4*2;
            #pragma unroll
            for (int h = 0; h < 2; h++) {
                int cc = c + h;
                if (GUARD_N && cc >= N) continue;
                float bb = bias ? bias[cc] : 0.f;
                float v0 = acc[i][j][h]   + bb;
                float v1 = acc[i][j][2+h] + bb;
                if (ELU) { v0 = elu_f(v0); v1 = elu_f(v1); }
                C[(long)r*N + cc]     = v0;
                C[(long)(r+8)*N + cc] = v1;
            }
        }
    }
}

// =======================================================================
// Pred GEMM + cumsum epilogue (unchanged)
// =======================================================================
__global__ __launch_bounds__(256)
void pred_pos_kernel(const float* __restrict__ A0, const float* __restrict__ Bm,
                     const float* __restrict__ bias, const float* __restrict__ centers,
                     float* __restrict__ out) {
    const int N = PRED*2;
    const int K = HH;
    __shared__ unsigned Asm[64][36];
    __shared__ unsigned Bsm[32][72];
    __shared__ float Cs[64][64];
    const int tid  = threadIdx.x;
    const int lane = tid & 31;
    const int warp = tid >> 5;
    const int warpM = warp & 1;
    const int warpN = warp >> 1;
    const int g  = lane >> 2;
    const int t4 = lane & 3;
    const int row0 = blockIdx.y * 64;

    int arow[2], akq[2], bkk[2], bq[2];
    #pragma unroll
    for (int it = 0; it < 2; it++) {
        int ta = it*256 + tid;
        akq[it] = ta & 7;  arow[it] = ta >> 3;
        bkk[it] = ta >> 4; bq[it]  = ta & 15;
    }
    float4 pa[2], pb[2];
    #pragma unroll
    for (int it = 0; it < 2; it++) {
        pa[it] = *reinterpret_cast<const float4*>(&A0[(long)(row0+arow[it])*K + akq[it]*4]);
        int c0 = bq[it]*4;
        float4 v;
        v.x = (c0+0 < N) ? Bm[(long)bkk[it]*N + c0+0] : 0.f;
        v.y = (c0+1 < N) ? Bm[(long)bkk[it]*N + c0+1] : 0.f;
        v.z = (c0+2 < N) ? Bm[(long)bkk[it]*N + c0+2] : 0.f;
        v.w = (c0+3 < N) ? Bm[(long)bkk[it]*N + c0+3] : 0.f;
        pb[it] = v;
    }

    float acc[2][2][4] = {};
    for (int k0 = 0; k0 < K; k0 += 32) {
        #pragma unroll
        for (int it = 0; it < 2; it++) {
            float4 v = pa[it];
            Asm[arow[it]][akq[it]*4+0] = f2tf32(v.x);
            Asm[arow[it]][akq[it]*4+1] = f2tf32(v.y);
            Asm[arow[it]][akq[it]*4+2] = f2tf32(v.z);
            Asm[arow[it]][akq[it]*4+3] = f2tf32(v.w);
            float4 w = pb[it];
            Bsm[bkk[it]][bq[it]*4+0] = f2tf32(w.x);
            Bsm[bkk[it]][bq[it]*4+1] = f2tf32(w.y);
            Bsm[bkk[it]][bq[it]*4+2] = f2tf32(w.z);
            Bsm[bkk[it]][bq[it]*4+3] = f2tf32(w.w);
        }
        if (k0 + 32 < K) {
            int kn = k0 + 32;
            #pragma unroll
            for (int it = 0; it < 2; it++) {
                pa[it] = *reinterpret_cast<const float4*>(&A0[(long)(row0+arow[it])*K + kn + akq[it]*4]);
                int c0 = bq[it]*4;
                float4 v;
                v.x = (c0+0 < N) ? Bm[(long)(kn+bkk[it])*N + c0+0] : 0.f;
                v.y = (c0+1 < N) ? Bm[(long)(kn+bkk[it])*N + c0+1] : 0.f;
                v.z = (c0+2 < N) ? Bm[(long)(kn+bkk[it])*N + c0+2] : 0.f;
                v.w = (c0+3 < N) ? Bm[(long)(kn+bkk[it])*N + c0+3] : 0.f;
                pb[it] = v;
            }
        }
        __syncthreads();
        #pragma unroll
        for (int ks = 0; ks < 32; ks += 8) {
            unsigned afr[2][4];
            #pragma unroll
            for (int i = 0; i < 2; i++) {
                int r = warpM*32 + i*16;
                afr[i][0] = Asm[r + g    ][ks + t4    ];
                afr[i][1] = Asm[r + g + 8][ks + t4    ];
                afr[i][2] = Asm[r + g    ][ks + t4 + 4];
                afr[i][3] = Asm[r + g + 8][ks + t4 + 4];
            }
            unsigned bfr[2][2];
            #pragma unroll
            for (int j = 0; j < 2; j++) {
                int nn = warpN*16 + j*8 + g;
                bfr[j][0] = Bsm[ks + t4    ][nn];
                bfr[j][1] = Bsm[ks + t4 + 4][nn];
            }
            #pragma unroll
            for (int i = 0; i < 2; i++)
                #pragma unroll
                for (int j = 0; j < 2; j++)
                    asm volatile(
                        "mma.sync.aligned.m16n8k8.row.col.f32.tf32.tf32.f32 "
                        "{%0,%1,%2,%3}, {%4,%5,%6,%7}, {%8,%9}, {%0,%1,%2,%3};"
                        : "+f"(acc[i][j][0]), "+f"(acc[i][j][1]),
                          "+f"(acc[i][j][2]), "+f"(acc[i][j][3])
                        : "r"(afr[i][0]), "r"(afr[i][1]), "r"(afr[i][2]), "r"(afr[i][3]),
                          "r"(bfr[j][0]), "r"(bfr[j][1]));
        }
        __syncthreads();
    }

    #pragma unroll
    for (int i = 0; i < 2; i++) {
        int r = warpM*32 + i*16 + g;
        #pragma unroll
        for (int j = 0; j < 2; j++) {
            int c = warpN*16 + j*8 + t4*2;
            #pragma unroll
            for (int h = 0; h < 2; h++) {
                int cc = c + h;
                float bb = (cc < N) ? bias[cc] : 0.f;
                Cs[r][cc]   = acc[i][j][h]   + bb;
                Cs[r+8][cc] = acc[i][j][2+h] + bb;
            }
        }
    }
    __syncthreads();

    if (tid < 128) {
        int lrow = tid >> 1, dimc = tid & 1;
        int grow = row0 + lrow;
        float cur = centers[grow*PREV*2 + (PREV-1)*2 + dimc];
        float accum = 0.f;
        #pragma unroll
        for (int p = 0; p < PRED; p++) {
            float v = Cs[lrow][2*p + dimc];
            out[(long)grow*N + 2*p + dimc] = v;
            accum += v;
            out[(long)(ROWS_N)*N + (long)grow*N + 2*p + dimc] = accum + cur;
        }
    }
}

// =======================================================================
// Fused edge GEMM (bf16, double-buffered, ldmatrix fragment loads):
//   h2 = elu( elu(xTop[recv]+xBot[send]+b1) @ W2 + b2 )
// 128x128 tile, K-step 32, 2-stage smem, LDSM.x4 frag loads.
// =======================================================================
__global__ __launch_bounds__(256, 2)
void edge_gemm2_bf16(const float* __restrict__ xTop, const float* __restrict__ xBot,
                     const float* __restrict__ b1,
                     const __nv_bfloat16* __restrict__ w2t, const float* __restrict__ b2,
                     const int* __restrict__ recv_idx, const int* __restrict__ send_idx,
                     float* __restrict__ h2) {
    __shared__ __align__(16) __nv_bfloat16 As[2][128][40];    // [stage][row][k]
    __shared__ __align__(16) __nv_bfloat16 Bsn[2][128][40];   // [stage][n][k]
    __shared__ int topBase[128], botBase[128];

    const int tid  = threadIdx.x;
    const int lane = tid & 31;
    const int warp = tid >> 5;
    const int warpM = warp & 3;
    const int warpN = warp >> 2;
    const int row0 = blockIdx.y * 128;
    const int col0 = blockIdx.x * 128;

    if (tid < 128) {
        int grow = row0 + tid;
        int b = grow / EE;
        int e = grow - b * EE;
        topBase[tid] = (b*NN + recv_idx[e]) * HH;
        botBase[tid] = (b*NN + send_idx[e]) * HH;
    }
    __syncthreads();

    // staging tasks
    int arow[4], acg[4];
    int bn[2], bkh[2];
    #pragma unroll
    for (int it = 0; it < 4; it++) {
        int task = it*256 + tid;
        arow[it] = task & 127;
        acg[it]  = task >> 7;
    }
    #pragma unroll
    for (int it = 0; it < 2; it++) {
        int task = it*256 + tid;
        bn[it]  = task & 127;
        bkh[it] = task >> 7;          // 0..3
    }

    float4 pa[4], pbv[4];
    uint4 pw[2];

    auto prefetch = [&](int k0) {
        #pragma unroll
        for (int it = 0; it < 4; it++) {
            int cb = k0 + acg[it]*4;
            pa[it]  = *reinterpret_cast<const float4*>(&xTop[topBase[arow[it]] + cb]);
            pbv[it] = *reinterpret_cast<const float4*>(&xBot[botBase[arow[it]] + cb]);
        }
        #pragma unroll
        for (int it = 0; it < 2; it++) {
            pw[it] = *reinterpret_cast<const uint4*>(&w2t[(long)(col0 + bn[it])*HH + k0 + bkh[it]*8]);
        }
    };

    auto store = [&](int s, int k0) {
        #pragma unroll
        for (int it = 0; it < 4; it++) {
            int cb = k0 + acg[it]*4;
            float4 bb = *reinterpret_cast<const float4*>(&b1[cb]);
            float4 a = pa[it], bv = pbv[it];
            unsigned p0 = packbf2(elu_ff(a.x + bv.x + bb.x), elu_ff(a.y + bv.y + bb.y));
            unsigned p1 = packbf2(elu_ff(a.z + bv.z + bb.z), elu_ff(a.w + bv.w + bb.w));
            *reinterpret_cast<uint2*>(&As[s][arow[it]][acg[it]*4]) = make_uint2(p0, p1);
        }
        #pragma unroll
        for (int it = 0; it < 2; it++) {
            *reinterpret_cast<uint4*>(&Bsn[s][bn[it]][bkh[it]*8]) = pw[it];
        }
    };

    // ldmatrix lane decomposition
    const int lt  = lane >> 3;        // tile index 0..3
    const int lrw = lane & 7;         // row within tile
    const int mrow0 = warpM * 32;
    const int ncol0 = warpN * 64;
    // A: tiles [rows r..+7 @k, rows r+8..+15 @k, rows r..+7 @k+8, rows r+8..+15 @k+8]
    const uint32_t aBase0 = smem_u32(&As[0][0][0]);
    const uint32_t bBase0 = smem_u32(&Bsn[0][0][0]);
    const uint32_t STG_STRIDE = 128u * 40u * 2u;   // 10240 bytes per stage
    const uint32_t aLanePart = (uint32_t)(mrow0 + (lt & 1)*8 + lrw) * 80u + (uint32_t)(lt >> 1) * 16u;
    const uint32_t bLanePart = (uint32_t)(ncol0 + lt*8 + lrw) * 80u;

    float acc[2][8][4] = {};

    prefetch(0);
    store(0, 0);
    __syncthreads();

    #pragma unroll 1
    for (int i = 0; i < 8; i++) {
        int cur = i & 1;
        if (i < 7) prefetch((i+1) * 32);

        const uint32_t aCur = aBase0 + (uint32_t)cur * STG_STRIDE + aLanePart;
        const uint32_t bCur = bBase0 + (uint32_t)cur * STG_STRIDE + bLanePart;

        #pragma unroll
        for (int ks = 0; ks < 32; ks += 16) {
            unsigned afr[2][4];
            #pragma unroll
            for (int ii = 0; ii < 2; ii++) {
                LDSM4(afr[ii][0], afr[ii][1], afr[ii][2], afr[ii][3],
                      aCur + (uint32_t)ii*1280u + (uint32_t)ks*2u);
            }
            unsigned bfr[8][2];
            #pragma unroll
            for (int jb = 0; jb < 2; jb++) {
                #pragma unroll
                for (int kh = 0; kh < 2; kh++) {
                    unsigned t0, t1, t2, t3;
                    LDSM4(t0, t1, t2, t3,
                          bCur + (uint32_t)jb*2560u + (uint32_t)ks*2u + (uint32_t)kh*16u);
                    bfr[jb*4+0][kh] = t0;
                    bfr[jb*4+1][kh] = t1;
                    bfr[jb*4+2][kh] = t2;
                    bfr[jb*4+3][kh] = t3;
                }
            }
            #pragma unroll
            for (int j = 0; j < 8; j++) {
                #pragma unroll
                for (int ii = 0; ii < 2; ii++)
                    asm volatile(
                        "mma.sync.aligned.m16n8k16.row.col.f32.bf16.bf16.f32 "
                        "{%0,%1,%2,%3}, {%4,%5,%6,%7}, {%8,%9}, {%0,%1,%2,%3};"
                        : "+f"(acc[ii][j][0]), "+f"(acc[ii][j][1]),
                          "+f"(acc[ii][j][2]), "+f"(acc[ii][j][3])
                        : "r"(afr[ii][0]), "r"(afr[ii][1]), "r"(afr[ii][2]), "r"(afr[ii][3]),
                          "r"(bfr[j][0]), "r"(bfr[j][1]));
            }
        }
        if (i < 7) store(cur ^ 1, (i+1) * 32);
        __syncthreads();
    }

    const int g  = lane >> 2;
    const int t4 = lane & 3;
    #pragma unroll
    for (int i = 0; i < 2; i++) {
        int r_lo = row0 + mrow0 + i*16 + g;
        #pragma unroll
        for (int j = 0; j < 8; j++) {
            int c = col0 + ncol0 + j*8 + t4*2;
            float bb0 = b2[c], bb1 = b2[c+1];
            h2[(long)r_lo*HH + c    ]     = elu_ff(acc[i][j][0] + bb0);
            h2[(long)r_lo*HH + c + 1]     = elu_ff(acc[i][j][1] + bb1);
            h2[(long)(r_lo+8)*HH + c    ] = elu_ff(acc[i][j][2] + bb0);
            h2[(long)(r_lo+8)*HH + c + 1] = elu_ff(acc[i][j][3] + bb1);
        }
    }
}

// ---------------- combined per-node gather sums ----------------
__global__ void scatter_kernel(const float* __restrict__ h2,
                               const int* __restrict__ list_rec, const int* __restrict__ cnt_rec,
                               const int* __restrict__ list_send, const int* __restrict__ cnt_send,
                               float* __restrict__ inc_raw, float* __restrict__ sq_part,
                               float* __restrict__ out_raw) {
    int id = blockIdx.x;
    bool isOut = id >= ROWS_N;
    int bn = id & (ROWS_N-1);
    int b = bn >> 6, n = bn & 63;
    int h = threadIdx.x;
    if (!isOut) {
        int cnt = cnt_rec[n];
        float acc = 0.f, accsq = 0.f;
        for (int k = 0; k < cnt; k++) {
            int e = list_rec[n*EE + k];
            float v = h2[(long)(b*EE + e)*HH + h];
            acc += v; accsq += v*v;
        }
        inc_raw[bn*HH + h] = acc;
        sq_part[bn*HH + h] = accsq;
    } else {
        int cnt = cnt_send[n];
        float acc = 0.f;
        for (int k = 0; k < cnt; k++) {
            int e = list_send[n*EE + k];
            acc += h2[(long)(b*EE + e)*HH + h];
        }
        out_raw[bn*HH + h] = acc;
    }
}

// ---------------- BN stats -> affine (a,c) ----------------
template<bool SRC_SQ>
__global__ void stats_kernel(const float* __restrict__ sum_part, const float* __restrict__ sq_part,
                             const float* __restrict__ gamma, const float* __restrict__ beta,
                             float* __restrict__ a, float* __restrict__ c,
                             int nrows, float count) {
    int h = blockIdx.x;
    float s = 0.f, sq = 0.f;
    for (int r = threadIdx.x; r < nrows; r += 256) {
        float v = sum_part[r*HH + h];
        s += v;
        if (SRC_SQ) sq += v*v; else sq += sq_part[r*HH + h];
    }
    __shared__ float ss[256], ssq[256];
    ss[threadIdx.x] = s; ssq[threadIdx.x] = sq;
    __syncthreads();
    for (int st = 128; st > 0; st >>= 1) {
        if (threadIdx.x < st) { ss[threadIdx.x] += ss[threadIdx.x+st]; ssq[threadIdx.x] += ssq[threadIdx.x+st]; }
        __syncthreads();
    }
    if (threadIdx.x == 0) {
        float mu = ss[0] / count;
        float var = ssq[0] / count - mu*mu;
        float av = gamma[h] * rsqrtf(var + 1e-5f);
        a[h] = av;
        c[h] = beta[h] - mu * av;
    }
}

// ---------------- launcher ----------------
extern "C" void kernel_launch(void* const* d_in, const int* in_sizes, int n_in,
                              void* d_out, int out_size) {
    const float* centers  = (const float*)d_in[0];
    const float* rel_rec  = (const float*)d_in[1];
    const float* rel_send = (const float*)d_in[2];
    const float* W_traj   = (const float*)d_in[3];
    const float* b_traj   = (const float*)d_in[4];
    const float* n2e_W1   = (const float*)d_in[5];
    const float* n2e_b1   = (const float*)d_in[6];
    const float* n2e_W2   = (const float*)d_in[7];
    const float* n2e_b2   = (const float*)d_in[8];
    const float* n2e_g    = (const float*)d_in[9];
    const float* n2e_be   = (const float*)d_in[10];
    const float* e2n_W1   = (const float*)d_in[11];
    const float* e2n_b1   = (const float*)d_in[12];
    const float* e2n_W2   = (const float*)d_in[13];
    const float* e2n_b2   = (const float*)d_in[14];
    const float* e2n_g    = (const float*)d_in[15];
    const float* e2n_be   = (const float*)d_in[16];
    const float* W_fuse   = (const float*)d_in[17];
    const float* b_fuse   = (const float*)d_in[18];
    const float* W_pred   = (const float*)d_in[19];
    const float* b_pred   = (const float*)d_in[20];
    float* out = (float*)d_out;

    float *p_x, *p_xTop, *p_xBot, *p_h2, *p_inc, *p_incsq, *p_outg;
    float *p_nh1, *p_mraw, *p_fused;
    float *p_ae, *p_ce, *p_an, *p_cn, *p_idr, *p_ids;
    int *p_recv, *p_send, *p_lr, *p_ls, *p_cr, *p_cs;
    __nv_bfloat16 *p_w2t;
    cudaGetSymbolAddress((void**)&p_x, d_x);
    cudaGetSymbolAddress((void**)&p_xTop, d_xTop);
    cudaGetSymbolAddress((void**)&p_xBot, d_xBot);
    cudaGetSymbolAddress((void**)&p_h2, d_h2);
    cudaGetSymbolAddress((void**)&p_inc, d_inc);
    cudaGetSymbolAddress((void**)&p_incsq, d_incsq);
    cudaGetSymbolAddress((void**)&p_outg, d_outg);
    cudaGetSymbolAddress((void**)&p_nh1, d_nh1);
    cudaGetSymbolAddress((void**)&p_mraw, d_mraw);
    cudaGetSymbolAddress((void**)&p_fused, d_fused);
    cudaGetSymbolAddress((void**)&p_ae, d_ae);
    cudaGetSymbolAddress((void**)&p_ce, d_ce);
    cudaGetSymbolAddress((void**)&p_an, d_an);
    cudaGetSymbolAddress((void**)&p_cn, d_cn);
    cudaGetSymbolAddress((void**)&p_idr, d_invdegrec);
    cudaGetSymbolAddress((void**)&p_ids, d_invdegsend);
    cudaGetSymbolAddress((void**)&p_recv, d_recv);
    cudaGetSymbolAddress((void**)&p_send, d_send);
    cudaGetSymbolAddress((void**)&p_lr, d_listrec);
    cudaGetSymbolAddress((void**)&p_ls, d_listsend);
    cudaGetSymbolAddress((void**)&p_cr, d_cntrec);
    cudaGetSymbolAddress((void**)&p_cs, d_cntsend);
    cudaGetSymbolAddress((void**)&p_w2t, d_w2t);

    // 1. edge indices (needed by edge GEMM)
    derive_kernel<<<(EE+255)/256, 256>>>(rel_rec, rel_send, p_recv, p_send);

    // 2. trajectory embedding + fused W2^T bf16
    traj_w2t_kernel<<<ROWS_N + HH, HH>>>(centers, W_traj, b_traj, n2e_W2, p_w2t, p_x);

    // 3. xTop/xBot (dual-output, double-buffered tf32)
    mma_gemm_v2<0,false,false><<<dim3(HH/64, ROWS_N/64, 2), 256>>>(
        p_x, nullptr, nullptr, nullptr, nullptr, nullptr,
        n2e_W1, n2e_W1 + HH*HH, nullptr, p_xTop, p_xBot, ROWS_N, HH, HH);

    // 4. fused edge MLP (double-buffered bf16, ldmatrix)  <-- profiled launch
    edge_gemm2_bf16<<<dim3(HH/128, ROWS_E/128), 256>>>(p_xTop, p_xBot, n2e_b1,
                                                       p_w2t, n2e_b2,
                                                       p_recv, p_send, p_h2);

    // 5. per-node edge lists (only needed by scatter)
    build_lists_kernel<<<128, 64>>>(p_recv, p_send, p_lr, p_ls, p_cr, p_cs, p_idr, p_ids);

    // 6. scatter sums + edge BN stats
    scatter_kernel<<<2*ROWS_N, HH>>>(p_h2, p_lr, p_cr, p_ls, p_cs, p_inc, p_incsq, p_outg);
    stats_kernel<false><<<HH, 256>>>(p_inc, p_incsq, n2e_g, n2e_be, p_ae, p_ce, ROWS_N, (float)ROWS_E);

    // 7. node MLP
    mma_gemm_v2<1,true,false><<<dim3(HH/64, ROWS_N/64, 1), 256>>>(
        p_inc, p_outg, p_ae, p_ce, p_idr, p_ids,
        e2n_W1, e2n_W1, e2n_b1, p_nh1, p_nh1, ROWS_N, HH, 2*HH);
    mma_gemm_v2<0,true,false><<<dim3(HH/64, ROWS_N/64, 1), 256>>>(
        p_nh1, nullptr, nullptr, nullptr, nullptr, nullptr,
        e2n_W2, e2n_W2, e2n_b2, p_mraw, p_mraw, ROWS_N, HH, HH);
    stats_kernel<true><<<HH, 256>>>(p_mraw, nullptr, e2n_g, e2n_be, p_an, p_cn, ROWS_N, (float)ROWS_N);

    // 8. fuse + predict (+ fused cumsum epilogue)
    mma_gemm_v2<2,false,false><<<dim3(HH/64, ROWS_N/64, 1), 256>>>(
        p_x, p_mraw, p_an, p_cn, nullptr, nullptr,
        W_fuse, W_fuse, b_fuse, p_fused, p_fused, ROWS_N, HH, 2*HH);
    pred_pos_kernel<<<dim3(1, ROWS_N/64), 256>>>(p_fused, W_pred, b_pred, centers, out);
}

// round 8
// speedup vs baseline: 2.9757x; 1.2024x over previous
#include <cuda_runtime.h>
#include <cuda_bf16.h>
#include <math.h>
#include <stdint.h>

#define BB   16
#define NN   64
#define PREV 6
#define PRED 30
#define HH   256
#define EE   (NN*(NN-1))      // 4032
#define ROWS_E (BB*EE)        // 64512
#define ROWS_N (BB*NN)        // 1024

// ---------------- static scratch ----------------
__device__ float d_x[ROWS_N*HH];
__device__ float d_xTop[ROWS_N*HH];
__device__ float d_xBot[ROWS_N*HH];
__device__ float d_h2[ROWS_E*HH];
__device__ float d_inc[ROWS_N*HH];
__device__ float d_incsq[ROWS_N*HH];
__device__ float d_outg[ROWS_N*HH];
__device__ float d_nh1[ROWS_N*HH];
__device__ float d_mraw[ROWS_N*HH];
__device__ float d_fused[ROWS_N*HH];
__device__ float d_ae[HH], d_ce[HH], d_an[HH], d_cn[HH];
__device__ int   d_recv[EE], d_send[EE];
__device__ int   d_listrec[NN*EE], d_listsend[NN*EE];
__device__ int   d_cntrec[NN], d_cntsend[NN];
__device__ float d_invdegrec[NN], d_invdegsend[NN];
__device__ __nv_bfloat16 d_w2t[HH*HH];   // W2^T in bf16: [n][k]

__device__ __forceinline__ float elu_f(float x)  { return x > 0.f ? x : (expf(x) - 1.f); }
__device__ __forceinline__ float elu_ff(float x) { return x > 0.f ? x : (__expf(x) - 1.f); }

__device__ __forceinline__ unsigned f2tf32(float x) {
    unsigned r;
    asm("cvt.rna.tf32.f32 %0, %1;" : "=r"(r) : "f"(x));
    return r;
}
__device__ __forceinline__ unsigned packbf2(float lo, float hi) {
    __nv_bfloat162 v = __floats2bfloat162_rn(lo, hi);
    return *reinterpret_cast<unsigned*>(&v);
}
__device__ __forceinline__ uint32_t smem_u32(const void* p) {
    uint32_t a;
    asm("{ .reg .u64 t; cvta.to.shared.u64 t, %1; cvt.u32.u64 %0, t; }" : "=r"(a) : "l"(p));
    return a;
}

#define LDSM4(r0,r1,r2,r3,addr) \
    asm volatile("ldmatrix.sync.aligned.m8n8.x4.shared.b16 {%0,%1,%2,%3}, [%4];" \
        : "=r"(r0), "=r"(r1), "=r"(r2), "=r"(r3) : "r"(addr))

// ---------------- derive edge indices ----------------
__global__ void derive_kernel(const float* __restrict__ rel_rec,
                              const float* __restrict__ rel_send,
                              int* __restrict__ recv_idx, int* __restrict__ send_idx) {
    int e = blockIdx.x * blockDim.x + threadIdx.x;
    if (e >= EE) return;
    int r = 0, s = 0; float br = -1.f, bs = -1.f;
    for (int n = 0; n < NN; n++) {
        float vr = rel_rec[e*NN + n];
        float vs = rel_send[e*NN + n];
        if (vr > br) { br = vr; r = n; }
        if (vs > bs) { bs = vs; s = n; }
    }
    recv_idx[e] = r; send_idx[e] = s;
}

// ---------------- parallel deterministic list build ----------------
__global__ void build_lists_kernel(const int* __restrict__ recv_idx,
                                   const int* __restrict__ send_idx,
                                   int* __restrict__ list_rec, int* __restrict__ list_send,
                                   int* __restrict__ cnt_rec, int* __restrict__ cnt_send,
                                   float* __restrict__ invdeg_rec, float* __restrict__ invdeg_send) {
    const bool isSend = blockIdx.x >= NN;
    const int n = blockIdx.x & (NN-1);
    const int* __restrict__ idx = isSend ? send_idx : recv_idx;
    int* __restrict__ list = (isSend ? list_send : list_rec) + n*EE;
    const int t = threadIdx.x;            // 64 threads
    const int CH = EE / 64;               // 63
    const int base = t * CH;
    int c = 0;
    for (int i = 0; i < CH; i++) c += (idx[base+i] == n) ? 1 : 0;
    __shared__ int pre[64];
    pre[t] = c;
    __syncthreads();
    for (int off = 1; off < 64; off <<= 1) {
        int v = (t >= off) ? pre[t-off] : 0;
        __syncthreads();
        pre[t] += v;
        __syncthreads();
    }
    int offset = pre[t] - c;
    for (int i = 0; i < CH; i++) {
        int e = base + i;
        if (idx[e] == n) list[offset++] = e;
    }
    if (t == 63) {
        int tot = pre[63];
        float iv = tot ? 1.f/(float)tot : 1.f;
        if (isSend) { cnt_send[n] = tot; invdeg_send[n] = iv; }
        else        { cnt_rec[n]  = tot; invdeg_rec[n]  = iv; }
    }
}

// ---------------- trajectory embedding + fused W2 transpose ----------------
__global__ void traj_w2t_kernel(const float* __restrict__ centers,
                                const float* __restrict__ W, const float* __restrict__ bias,
                                const float* __restrict__ W2, __nv_bfloat16* __restrict__ w2t,
                                float* __restrict__ x) {
    if (blockIdx.x >= ROWS_N) {
        int n = blockIdx.x - ROWS_N;   // 0..255
        int k = threadIdx.x;           // 0..255
        w2t[n*HH + k] = __float2bfloat16(W2[k*HH + n]);
        return;
    }
    int row = blockIdx.x;
    int h = threadIdx.x;
    __shared__ float rp[PREV*2];
    if (h < PREV*2) {
        int p = h >> 1, c = h & 1;
        float v = 0.f;
        if (p > 0) v = centers[row*PREV*2 + p*2 + c] - centers[row*PREV*2 + (p-1)*2 + c];
        rp[h] = v;
    }
    __syncthreads();
    float acc = bias[h];
    #pragma unroll
    for (int k = 0; k < PREV*2; k++) acc += rp[k] * W[k*HH + h];
    x[row*HH + h] = acc;
}

// =======================================================================
// Generic double-buffered tf32 GEMM (unchanged)
// =======================================================================
template<int AMODE, bool ELU, bool GUARD_N>
__global__ __launch_bounds__(256)
void mma_gemm_v2(const float* __restrict__ A0, const float* __restrict__ A1,
                 const float* __restrict__ aVec, const float* __restrict__ cVec,
                 const float* __restrict__ invDegR, const float* __restrict__ invDegS,
                 const float* __restrict__ B0, const float* __restrict__ B1,
                 const float* __restrict__ bias,
                 float* __restrict__ C0, float* __restrict__ C1,
                 int M, int N, int K) {
    const float* __restrict__ Bm = (blockIdx.z == 0) ? B0 : B1;
    float* __restrict__ C = (blockIdx.z == 0) ? C0 : C1;

    __shared__ unsigned Asm[2][64][36];
    __shared__ unsigned Bsm[2][32][72];
    const int tid  = threadIdx.x;
    const int lane = tid & 31;
    const int warp = tid >> 5;
    const int warpM = warp & 1;
    const int warpN = warp >> 1;
    const int g  = lane >> 2;
    const int t4 = lane & 3;
    const int row0 = blockIdx.y * 64;
    const int col0 = blockIdx.x * 64;

    int arow[2], akq[2], bkk[2], bq[2];
    #pragma unroll
    for (int it = 0; it < 2; it++) {
        int ta = it*256 + tid;
        akq[it] = ta & 7;  arow[it] = ta >> 3;
        bkk[it] = ta >> 4; bq[it]  = ta & 15;
    }

    float4 pa[2], pb[2];

    auto prefetch = [&](int k0) {
        #pragma unroll
        for (int it = 0; it < 2; it++) {
            int gk = k0 + akq[it]*4;
            if (AMODE == 0) {
                pa[it] = *reinterpret_cast<const float4*>(&A0[(long)(row0+arow[it])*K + gk]);
            } else {
                const float* src = (gk >= HH) ? A1 : A0;
                pa[it] = *reinterpret_cast<const float4*>(&src[(long)(row0+arow[it])*HH + (gk & (HH-1))]);
            }
            int c0 = col0 + bq[it]*4;
            if (!GUARD_N) {
                pb[it] = *reinterpret_cast<const float4*>(&Bm[(long)(k0+bkk[it])*N + c0]);
            } else {
                float4 v;
                v.x = (c0+0 < N) ? Bm[(long)(k0+bkk[it])*N + c0+0] : 0.f;
                v.y = (c0+1 < N) ? Bm[(long)(k0+bkk[it])*N + c0+1] : 0.f;
                v.z = (c0+2 < N) ? Bm[(long)(k0+bkk[it])*N + c0+2] : 0.f;
                v.w = (c0+3 < N) ? Bm[(long)(k0+bkk[it])*N + c0+3] : 0.f;
                pb[it] = v;
            }
        }
    };

    auto store = [&](int s, int k0) {
        #pragma unroll
        for (int it = 0; it < 2; it++) {
            int gk = k0 + akq[it]*4;
            float4 v = pa[it];
            if (AMODE == 1) {
                int col = gk & (HH-1);
                float invd = ((gk >= HH) ? invDegS : invDegR)[(row0+arow[it]) & (NN-1)];
                float4 a4 = *reinterpret_cast<const float4*>(&aVec[col]);
                float4 c4 = *reinterpret_cast<const float4*>(&cVec[col]);
                v.x = a4.x*(v.x*invd)+c4.x; v.y = a4.y*(v.y*invd)+c4.y;
                v.z = a4.z*(v.z*invd)+c4.z; v.w = a4.w*(v.w*invd)+c4.w;
            } else if (AMODE == 2) {
                if (gk >= HH) {
                    int col = gk & (HH-1);
                    float4 a4 = *reinterpret_cast<const float4*>(&aVec[col]);
                    float4 c4 = *reinterpret_cast<const float4*>(&cVec[col]);
                    v.x = a4.x*v.x+c4.x; v.y = a4.y*v.y+c4.y;
                    v.z = a4.z*v.z+c4.z; v.w = a4.w*v.w+c4.w;
                }
            }
            Asm[s][arow[it]][akq[it]*4+0] = f2tf32(v.x);
            Asm[s][arow[it]][akq[it]*4+1] = f2tf32(v.y);
            Asm[s][arow[it]][akq[it]*4+2] = f2tf32(v.z);
            Asm[s][arow[it]][akq[it]*4+3] = f2tf32(v.w);

            float4 w = pb[it];
            Bsm[s][bkk[it]][bq[it]*4+0] = f2tf32(w.x);
            Bsm[s][bkk[it]][bq[it]*4+1] = f2tf32(w.y);
            Bsm[s][bkk[it]][bq[it]*4+2] = f2tf32(w.z);
            Bsm[s][bkk[it]][bq[it]*4+3] = f2tf32(w.w);
        }
    };

    float acc[2][2][4] = {};
    const int nIter = K >> 5;

    prefetch(0);
    store(0, 0);
    __syncthreads();

    for (int i = 0; i < nIter; i++) {
        int cur = i & 1;
        if (i + 1 < nIter) prefetch((i+1) * 32);

        #pragma unroll
        for (int ks = 0; ks < 32; ks += 8) {
            unsigned afr[2][4];
            #pragma unroll
            for (int ii = 0; ii < 2; ii++) {
                int r = warpM*32 + ii*16;
                afr[ii][0] = Asm[cur][r + g    ][ks + t4    ];
                afr[ii][1] = Asm[cur][r + g + 8][ks + t4    ];
                afr[ii][2] = Asm[cur][r + g    ][ks + t4 + 4];
                afr[ii][3] = Asm[cur][r + g + 8][ks + t4 + 4];
            }
            unsigned bfr[2][2];
            #pragma unroll
            for (int j = 0; j < 2; j++) {
                int nn = warpN*16 + j*8 + g;
                bfr[j][0] = Bsm[cur][ks + t4    ][nn];
                bfr[j][1] = Bsm[cur][ks + t4 + 4][nn];
            }
            #pragma unroll
            for (int ii = 0; ii < 2; ii++)
                #pragma unroll
                for (int j = 0; j < 2; j++)
                    asm volatile(
                        "mma.sync.aligned.m16n8k8.row.col.f32.tf32.tf32.f32 "
                        "{%0,%1,%2,%3}, {%4,%5,%6,%7}, {%8,%9}, {%0,%1,%2,%3};"
                        : "+f"(acc[ii][j][0]), "+f"(acc[ii][j][1]),
                          "+f"(acc[ii][j][2]), "+f"(acc[ii][j][3])
                        : "r"(afr[ii][0]), "r"(afr[ii][1]), "r"(afr[ii][2]), "r"(afr[ii][3]),
                          "r"(bfr[j][0]), "r"(bfr[j][1]));
        }
        if (i + 1 < nIter) store(cur ^ 1, (i+1) * 32);
        __syncthreads();
    }

    #pragma unroll
    for (int i = 0; i < 2; i++) {
        int r = row0 + warpM*32 + i*16 + g;
        #pragma unroll
        for (int j = 0; j < 2; j++) {
            int c = col0 + warpN*16 + j*8 + t4*2;
            #pragma unroll
            for (int h = 0; h < 2; h++) {
                int cc = c + h;
                if (GUARD_N && cc >= N) continue;
                float bb = bias ? bias[cc] : 0.f;
                float v0 = acc[i][j][h]   + bb;
                float v1 = acc[i][j][2+h] + bb;
                if (ELU) { v0 = elu_f(v0); v1 = elu_f(v1); }
                C[(long)r*N + cc]     = v0;
                C[(long)(r+8)*N + cc] = v1;
            }
        }
    }
}

// =======================================================================
// Pred GEMM + cumsum epilogue (unchanged)
// =======================================================================
__global__ __launch_bounds__(256)
void pred_pos_kernel(const float* __restrict__ A0, const float* __restrict__ Bm,
                     const float* __restrict__ bias, const float* __restrict__ centers,
                     float* __restrict__ out) {
    const int N = PRED*2;
    const int K = HH;
    __shared__ unsigned Asm[64][36];
    __shared__ unsigned Bsm[32][72];
    __shared__ float Cs[64][64];
    const int tid  = threadIdx.x;
    const int lane = tid & 31;
    const int warp = tid >> 5;
    const int warpM = warp & 1;
    const int warpN = warp >> 1;
    const int g  = lane >> 2;
    const int t4 = lane & 3;
    const int row0 = blockIdx.y * 64;

    int arow[2], akq[2], bkk[2], bq[2];
    #pragma unroll
    for (int it = 0; it < 2; it++) {
        int ta = it*256 + tid;
        akq[it] = ta & 7;  arow[it] = ta >> 3;
        bkk[it] = ta >> 4; bq[it]  = ta & 15;
    }
    float4 pa[2], pb[2];
    #pragma unroll
    for (int it = 0; it < 2; it++) {
        pa[it] = *reinterpret_cast<const float4*>(&A0[(long)(row0+arow[it])*K + akq[it]*4]);
        int c0 = bq[it]*4;
        float4 v;
        v.x = (c0+0 < N) ? Bm[(long)bkk[it]*N + c0+0] : 0.f;
        v.y = (c0+1 < N) ? Bm[(long)bkk[it]*N + c0+1] : 0.f;
        v.z = (c0+2 < N) ? Bm[(long)bkk[it]*N + c0+2] : 0.f;
        v.w = (c0+3 < N) ? Bm[(long)bkk[it]*N + c0+3] : 0.f;
        pb[it] = v;
    }

    float acc[2][2][4] = {};
    for (int k0 = 0; k0 < K; k0 += 32) {
        #pragma unroll
        for (int it = 0; it < 2; it++) {
            float4 v = pa[it];
            Asm[arow[it]][akq[it]*4+0] = f2tf32(v.x);
            Asm[arow[it]][akq[it]*4+1] = f2tf32(v.y);
            Asm[arow[it]][akq[it]*4+2] = f2tf32(v.z);
            Asm[arow[it]][akq[it]*4+3] = f2tf32(v.w);
            float4 w = pb[it];
            Bsm[bkk[it]][bq[it]*4+0] = f2tf32(w.x);
            Bsm[bkk[it]][bq[it]*4+1] = f2tf32(w.y);
            Bsm[bkk[it]][bq[it]*4+2] = f2tf32(w.z);
            Bsm[bkk[it]][bq[it]*4+3] = f2tf32(w.w);
        }
        if (k0 + 32 < K) {
            int kn = k0 + 32;
            #pragma unroll
            for (int it = 0; it < 2; it++) {
                pa[it] = *reinterpret_cast<const float4*>(&A0[(long)(row0+arow[it])*K + kn + akq[it]*4]);
                int c0 = bq[it]*4;
                float4 v;
                v.x = (c0+0 < N) ? Bm[(long)(kn+bkk[it])*N + c0+0] : 0.f;
                v.y = (c0+1 < N) ? Bm[(long)(kn+bkk[it])*N + c0+1] : 0.f;
                v.z = (c0+2 < N) ? Bm[(long)(kn+bkk[it])*N + c0+2] : 0.f;
                v.w = (c0+3 < N) ? Bm[(long)(kn+bkk[it])*N + c0+3] : 0.f;
                pb[it] = v;
            }
        }
        __syncthreads();
        #pragma unroll
        for (int ks = 0; ks < 32; ks += 8) {
            unsigned afr[2][4];
            #pragma unroll
            for (int i = 0; i < 2; i++) {
                int r = warpM*32 + i*16;
                afr[i][0] = Asm[r + g    ][ks + t4    ];
                afr[i][1] = Asm[r + g + 8][ks + t4    ];
                afr[i][2] = Asm[r + g    ][ks + t4 + 4];
                afr[i][3] = Asm[r + g + 8][ks + t4 + 4];
            }
            unsigned bfr[2][2];
            #pragma unroll
            for (int j = 0; j < 2; j++) {
                int nn = warpN*16 + j*8 + g;
                bfr[j][0] = Bsm[ks + t4    ][nn];
                bfr[j][1] = Bsm[ks + t4 + 4][nn];
            }
            #pragma unroll
            for (int i = 0; i < 2; i++)
                #pragma unroll
                for (int j = 0; j < 2; j++)
                    asm volatile(
                        "mma.sync.aligned.m16n8k8.row.col.f32.tf32.tf32.f32 "
                        "{%0,%1,%2,%3}, {%4,%5,%6,%7}, {%8,%9}, {%0,%1,%2,%3};"
                        : "+f"(acc[i][j][0]), "+f"(acc[i][j][1]),
                          "+f"(acc[i][j][2]), "+f"(acc[i][j][3])
                        : "r"(afr[i][0]), "r"(afr[i][1]), "r"(afr[i][2]), "r"(afr[i][3]),
                          "r"(bfr[j][0]), "r"(bfr[j][1]));
        }
        __syncthreads();
    }

    #pragma unroll
    for (int i = 0; i < 2; i++) {
        int r = warpM*32 + i*16 + g;
        #pragma unroll
        for (int j = 0; j < 2; j++) {
            int c = warpN*16 + j*8 + t4*2;
            #pragma unroll
            for (int h = 0; h < 2; h++) {
                int cc = c + h;
                float bb = (cc < N) ? bias[cc] : 0.f;
                Cs[r][cc]   = acc[i][j][h]   + bb;
                Cs[r+8][cc] = acc[i][j][2+h] + bb;
            }
        }
    }
    __syncthreads();

    if (tid < 128) {
        int lrow = tid >> 1, dimc = tid & 1;
        int grow = row0 + lrow;
        float cur = centers[grow*PREV*2 + (PREV-1)*2 + dimc];
        float accum = 0.f;
        #pragma unroll
        for (int p = 0; p < PRED; p++) {
            float v = Cs[lrow][2*p + dimc];
            out[(long)grow*N + 2*p + dimc] = v;
            accum += v;
            out[(long)(ROWS_N)*N + (long)grow*N + 2*p + dimc] = accum + cur;
        }
    }
}

// =======================================================================
// Fused edge GEMM (bf16, double-buffered, ldmatrix, COALESCED gathers):
//   h2 = elu( elu(xTop[recv]+xBot[send]+b1) @ W2 + b2 )
// A-load: lanes sweep k within one row -> 4 lines/warp-load (was 32).
// B-load: lanes sweep k within one n  -> 8 lines/warp-load (was 32).
// =======================================================================
__global__ __launch_bounds__(256, 2)
void edge_gemm2_bf16(const float* __restrict__ xTop, const float* __restrict__ xBot,
                     const float* __restrict__ b1,
                     const __nv_bfloat16* __restrict__ w2t, const float* __restrict__ b2,
                     const int* __restrict__ recv_idx, const int* __restrict__ send_idx,
                     float* __restrict__ h2) {
    __shared__ __align__(16) __nv_bfloat16 As[2][128][40];    // [stage][row][k]
    __shared__ __align__(16) __nv_bfloat16 Bsn[2][128][40];   // [stage][n][k]
    __shared__ int topBase[128], botBase[128];

    const int tid  = threadIdx.x;
    const int lane = tid & 31;
    const int warp = tid >> 5;
    const int warpM = warp & 3;
    const int warpN = warp >> 2;
    const int row0 = blockIdx.y * 128;
    const int col0 = blockIdx.x * 128;

    if (tid < 128) {
        int grow = row0 + tid;
        int b = grow / EE;
        int e = grow - b * EE;
        topBase[tid] = (b*NN + recv_idx[e]) * HH;
        botBase[tid] = (b*NN + send_idx[e]) * HH;
    }
    __syncthreads();

    // staging tasks — k-major lane mapping for coalescing
    int arow[4], acg[4];
    int bn[2], bkh[2];
    #pragma unroll
    for (int it = 0; it < 4; it++) {
        int task = it*256 + tid;
        acg[it]  = task & 7;          // lanes sweep k-quads within a row
        arow[it] = task >> 3;
    }
    #pragma unroll
    for (int it = 0; it < 2; it++) {
        int task = it*256 + tid;
        bkh[it] = task & 3;           // lanes sweep k-halves within an n-row
        bn[it]  = task >> 2;
    }

    float4 pa[4], pbv[4];
    uint4 pw[2];

    auto prefetch = [&](int k0) {
        #pragma unroll
        for (int it = 0; it < 4; it++) {
            int cb = k0 + acg[it]*4;
            pa[it]  = *reinterpret_cast<const float4*>(&xTop[topBase[arow[it]] + cb]);
            pbv[it] = *reinterpret_cast<const float4*>(&xBot[botBase[arow[it]] + cb]);
        }
        #pragma unroll
        for (int it = 0; it < 2; it++) {
            pw[it] = *reinterpret_cast<const uint4*>(&w2t[(long)(col0 + bn[it])*HH + k0 + bkh[it]*8]);
        }
    };

    auto store = [&](int s, int k0) {
        #pragma unroll
        for (int it = 0; it < 4; it++) {
            int cb = k0 + acg[it]*4;
            float4 bb = *reinterpret_cast<const float4*>(&b1[cb]);
            float4 a = pa[it], bv = pbv[it];
            unsigned p0 = packbf2(elu_ff(a.x + bv.x + bb.x), elu_ff(a.y + bv.y + bb.y));
            unsigned p1 = packbf2(elu_ff(a.z + bv.z + bb.z), elu_ff(a.w + bv.w + bb.w));
            *reinterpret_cast<uint2*>(&As[s][arow[it]][acg[it]*4]) = make_uint2(p0, p1);
        }
        #pragma unroll
        for (int it = 0; it < 2; it++) {
            *reinterpret_cast<uint4*>(&Bsn[s][bn[it]][bkh[it]*8]) = pw[it];
        }
    };

    // ldmatrix lane decomposition (unchanged)
    const int lt  = lane >> 3;
    const int lrw = lane & 7;
    const int mrow0 = warpM * 32;
    const int ncol0 = warpN * 64;
    const uint32_t aBase0 = smem_u32(&As[0][0][0]);
    const uint32_t bBase0 = smem_u32(&Bsn[0][0][0]);
    const uint32_t STG_STRIDE = 128u * 40u * 2u;   // 10240 bytes per stage
    const uint32_t aLanePart = (uint32_t)(mrow0 + (lt & 1)*8 + lrw) * 80u + (uint32_t)(lt >> 1) * 16u;
    const uint32_t bLanePart = (uint32_t)(ncol0 + lt*8 + lrw) * 80u;

    float acc[2][8][4] = {};

    prefetch(0);
    store(0, 0);
    __syncthreads();

    #pragma unroll 1
    for (int i = 0; i < 8; i++) {
        int cur = i & 1;
        if (i < 7) prefetch((i+1) * 32);

        const uint32_t aCur = aBase0 + (uint32_t)cur * STG_STRIDE + aLanePart;
        const uint32_t bCur = bBase0 + (uint32_t)cur * STG_STRIDE + bLanePart;

        #pragma unroll
        for (int ks = 0; ks < 32; ks += 16) {
            unsigned afr[2][4];
            #pragma unroll
            for (int ii = 0; ii < 2; ii++) {
                LDSM4(afr[ii][0], afr[ii][1], afr[ii][2], afr[ii][3],
                      aCur + (uint32_t)ii*1280u + (uint32_t)ks*2u);
            }
            unsigned bfr[8][2];
            #pragma unroll
            for (int jb = 0; jb < 2; jb++) {
                #pragma unroll
                for (int kh = 0; kh < 2; kh++) {
                    unsigned t0, t1, t2, t3;
                    LDSM4(t0, t1, t2, t3,
                          bCur + (uint32_t)jb*2560u + (uint32_t)ks*2u + (uint32_t)kh*16u);
                    bfr[jb*4+0][kh] = t0;
                    bfr[jb*4+1][kh] = t1;
                    bfr[jb*4+2][kh] = t2;
                    bfr[jb*4+3][kh] = t3;
                }
            }
            #pragma unroll
            for (int j = 0; j < 8; j++) {
                #pragma unroll
                for (int ii = 0; ii < 2; ii++)
                    asm volatile(
                        "mma.sync.aligned.m16n8k16.row.col.f32.bf16.bf16.f32 "
                        "{%0,%1,%2,%3}, {%4,%5,%6,%7}, {%8,%9}, {%0,%1,%2,%3};"
                        : "+f"(acc[ii][j][0]), "+f"(acc[ii][j][1]),
                          "+f"(acc[ii][j][2]), "+f"(acc[ii][j][3])
                        : "r"(afr[ii][0]), "r"(afr[ii][1]), "r"(afr[ii][2]), "r"(afr[ii][3]),
                          "r"(bfr[j][0]), "r"(bfr[j][1]));
            }
        }
        if (i < 7) store(cur ^ 1, (i+1) * 32);
        __syncthreads();
    }

    const int g  = lane >> 2;
    const int t4 = lane & 3;
    #pragma unroll
    for (int i = 0; i < 2; i++) {
        int r_lo = row0 + mrow0 + i*16 + g;
        #pragma unroll
        for (int j = 0; j < 8; j++) {
            int c = col0 + ncol0 + j*8 + t4*2;
            float bb0 = b2[c], bb1 = b2[c+1];
            h2[(long)r_lo*HH + c    ]     = elu_ff(acc[i][j][0] + bb0);
            h2[(long)r_lo*HH + c + 1]     = elu_ff(acc[i][j][1] + bb1);
            h2[(long)(r_lo+8)*HH + c    ] = elu_ff(acc[i][j][2] + bb0);
            h2[(long)(r_lo+8)*HH + c + 1] = elu_ff(acc[i][j][3] + bb1);
        }
    }
}

// ---------------- combined per-node gather sums ----------------
__global__ void scatter_kernel(const float* __restrict__ h2,
                               const int* __restrict__ list_rec, const int* __restrict__ cnt_rec,
                               const int* __restrict__ list_send, const int* __restrict__ cnt_send,
                               float* __restrict__ inc_raw, float* __restrict__ sq_part,
                               float* __restrict__ out_raw) {
    int id = blockIdx.x;
    bool isOut = id >= ROWS_N;
    int bn = id & (ROWS_N-1);
    int b = bn >> 6, n = bn & 63;
    int h = threadIdx.x;
    if (!isOut) {
        int cnt = cnt_rec[n];
        float acc = 0.f, accsq = 0.f;
        for (int k = 0; k < cnt; k++) {
            int e = list_rec[n*EE + k];
            float v = h2[(long)(b*EE + e)*HH + h];
            acc += v; accsq += v*v;
        }
        inc_raw[bn*HH + h] = acc;
        sq_part[bn*HH + h] = accsq;
    } else {
        int cnt = cnt_send[n];
        float acc = 0.f;
        for (int k = 0; k < cnt; k++) {
            int e = list_send[n*EE + k];
            acc += h2[(long)(b*EE + e)*HH + h];
        }
        out_raw[bn*HH + h] = acc;
    }
}

// ---------------- BN stats -> affine (a,c) ----------------
template<bool SRC_SQ>
__global__ void stats_kernel(const float* __restrict__ sum_part, const float* __restrict__ sq_part,
                             const float* __restrict__ gamma, const float* __restrict__ beta,
                             float* __restrict__ a, float* __restrict__ c,
                             int nrows, float count) {
    int h = blockIdx.x;
    float s = 0.f, sq = 0.f;
    for (int r = threadIdx.x; r < nrows; r += 256) {
        float v = sum_part[r*HH + h];
        s += v;
        if (SRC_SQ) sq += v*v; else sq += sq_part[r*HH + h];
    }
    __shared__ float ss[256], ssq[256];
    ss[threadIdx.x] = s; ssq[threadIdx.x] = sq;
    __syncthreads();
    for (int st = 128; st > 0; st >>= 1) {
        if (threadIdx.x < st) { ss[threadIdx.x] += ss[threadIdx.x+st]; ssq[threadIdx.x] += ssq[threadIdx.x+st]; }
        __syncthreads();
    }
    if (threadIdx.x == 0) {
        float mu = ss[0] / count;
        float var = ssq[0] / count - mu*mu;
        float av = gamma[h] * rsqrtf(var + 1e-5f);
        a[h] = av;
        c[h] = beta[h] - mu * av;
    }
}

// ---------------- launcher ----------------
extern "C" void kernel_launch(void* const* d_in, const int* in_sizes, int n_in,
                              void* d_out, int out_size) {
    const float* centers  = (const float*)d_in[0];
    const float* rel_rec  = (const float*)d_in[1];
    const float* rel_send = (const float*)d_in[2];
    const float* W_traj   = (const float*)d_in[3];
    const float* b_traj   = (const float*)d_in[4];
    const float* n2e_W1   = (const float*)d_in[5];
    const float* n2e_b1   = (const float*)d_in[6];
    const float* n2e_W2   = (const float*)d_in[7];
    const float* n2e_b2   = (const float*)d_in[8];
    const float* n2e_g    = (const float*)d_in[9];
    const float* n2e_be   = (const float*)d_in[10];
    const float* e2n_W1   = (const float*)d_in[11];
    const float* e2n_b1   = (const float*)d_in[12];
    const float* e2n_W2   = (const float*)d_in[13];
    const float* e2n_b2   = (const float*)d_in[14];
    const float* e2n_g    = (const float*)d_in[15];
    const float* e2n_be   = (const float*)d_in[16];
    const float* W_fuse   = (const float*)d_in[17];
    const float* b_fuse   = (const float*)d_in[18];
    const float* W_pred   = (const float*)d_in[19];
    const float* b_pred   = (const float*)d_in[20];
    float* out = (float*)d_out;

    float *p_x, *p_xTop, *p_xBot, *p_h2, *p_inc, *p_incsq, *p_outg;
    float *p_nh1, *p_mraw, *p_fused;
    float *p_ae, *p_ce, *p_an, *p_cn, *p_idr, *p_ids;
    int *p_recv, *p_send, *p_lr, *p_ls, *p_cr, *p_cs;
    __nv_bfloat16 *p_w2t;
    cudaGetSymbolAddress((void**)&p_x, d_x);
    cudaGetSymbolAddress((void**)&p_xTop, d_xTop);
    cudaGetSymbolAddress((void**)&p_xBot, d_xBot);
    cudaGetSymbolAddress((void**)&p_h2, d_h2);
    cudaGetSymbolAddress((void**)&p_inc, d_inc);
    cudaGetSymbolAddress((void**)&p_incsq, d_incsq);
    cudaGetSymbolAddress((void**)&p_outg, d_outg);
    cudaGetSymbolAddress((void**)&p_nh1, d_nh1);
    cudaGetSymbolAddress((void**)&p_mraw, d_mraw);
    cudaGetSymbolAddress((void**)&p_fused, d_fused);
    cudaGetSymbolAddress((void**)&p_ae, d_ae);
    cudaGetSymbolAddress((void**)&p_ce, d_ce);
    cudaGetSymbolAddress((void**)&p_an, d_an);
    cudaGetSymbolAddress((void**)&p_cn, d_cn);
    cudaGetSymbolAddress((void**)&p_idr, d_invdegrec);
    cudaGetSymbolAddress((void**)&p_ids, d_invdegsend);
    cudaGetSymbolAddress((void**)&p_recv, d_recv);
    cudaGetSymbolAddress((void**)&p_send, d_send);
    cudaGetSymbolAddress((void**)&p_lr, d_listrec);
    cudaGetSymbolAddress((void**)&p_ls, d_listsend);
    cudaGetSymbolAddress((void**)&p_cr, d_cntrec);
    cudaGetSymbolAddress((void**)&p_cs, d_cntsend);
    cudaGetSymbolAddress((void**)&p_w2t, d_w2t);

    // 1. edge indices
    derive_kernel<<<(EE+255)/256, 256>>>(rel_rec, rel_send, p_recv, p_send);

    // 2. trajectory embedding + fused W2^T bf16
    traj_w2t_kernel<<<ROWS_N + HH, HH>>>(centers, W_traj, b_traj, n2e_W2, p_w2t, p_x);

    // 3. xTop/xBot (dual-output, double-buffered tf32)
    mma_gemm_v2<0,false,false><<<dim3(HH/64, ROWS_N/64, 2), 256>>>(
        p_x, nullptr, nullptr, nullptr, nullptr, nullptr,
        n2e_W1, n2e_W1 + HH*HH, nullptr, p_xTop, p_xBot, ROWS_N, HH, HH);

    // 4. fused edge MLP (coalesced gathers)  <-- profiled launch
    edge_gemm2_bf16<<<dim3(HH/128, ROWS_E/128), 256>>>(p_xTop, p_xBot, n2e_b1,
                                                       p_w2t, n2e_b2,
                                                       p_recv, p_send, p_h2);

    // 5. per-node edge lists
    build_lists_kernel<<<128, 64>>>(p_recv, p_send, p_lr, p_ls, p_cr, p_cs, p_idr, p_ids);

    // 6. scatter sums + edge BN stats
    scatter_kernel<<<2*ROWS_N, HH>>>(p_h2, p_lr, p_cr, p_ls, p_cs, p_inc, p_incsq, p_outg);
    stats_kernel<false><<<HH, 256>>>(p_inc, p_incsq, n2e_g, n2e_be, p_ae, p_ce, ROWS_N, (float)ROWS_E);

    // 7. node MLP
    mma_gemm_v2<1,true,false><<<dim3(HH/64, ROWS_N/64, 1), 256>>>(
        p_inc, p_outg, p_ae, p_ce, p_idr, p_ids,
        e2n_W1, e2n_W1, e2n_b1, p_nh1, p_nh1, ROWS_N, HH, 2*HH);
    mma_gemm_v2<0,true,false><<<dim3(HH/64, ROWS_N/64, 1), 256>>>(
        p_nh1, nullptr, nullptr, nullptr, nullptr, nullptr,
        e2n_W2, e2n_W2, e2n_b2, p_mraw, p_mraw, ROWS_N, HH, HH);
    stats_kernel<true><<<HH, 256>>>(p_mraw, nullptr, e2n_g, e2n_be, p_an, p_cn, ROWS_N, (float)ROWS_N);

    // 8. fuse + predict (+ fused cumsum epilogue)
    mma_gemm_v2<2,false,false><<<dim3(HH/64, ROWS_N/64, 1), 256>>>(
        p_x, p_mraw, p_an, p_cn, nullptr, nullptr,
        W_fuse, W_fuse, b_fuse, p_fused, p_fused, ROWS_N, HH, 2*HH);
    pred_pos_kernel<<<dim3(1, ROWS_N/64), 256>>>(p_fused, W_pred, b_pred, centers, out);
}

// round 9
// speedup vs baseline: 3.2842x; 1.1036x over previous
#include <cuda_runtime.h>
#include <cuda_bf16.h>
#include <math.h>
#include <stdint.h>

#define BB   16
#define NN   64
#define PREV 6
#define PRED 30
#define HH   256
#define EE   (NN*(NN-1))      // 4032
#define ROWS_E (BB*EE)        // 64512
#define ROWS_N (BB*NN)        // 1024

// ---------------- static scratch ----------------
__device__ float d_x[ROWS_N*HH];
__device__ float d_xTop[ROWS_N*HH];
__device__ float d_xBot[ROWS_N*HH];
__device__ float d_h2[ROWS_E*HH];
__device__ float d_inc[ROWS_N*HH];
__device__ float d_incsq[ROWS_N*HH];
__device__ float d_outg[ROWS_N*HH];
__device__ float d_nh1[ROWS_N*HH];
__device__ float d_mraw[ROWS_N*HH];
__device__ float d_fused[ROWS_N*HH];
__device__ float d_ae[HH], d_ce[HH], d_an[HH], d_cn[HH];
__device__ int   d_recv[EE], d_send[EE];
__device__ int   d_listrec[NN*EE], d_listsend[NN*EE];
__device__ int   d_cntrec[NN], d_cntsend[NN];
__device__ float d_invdegrec[NN], d_invdegsend[NN];
__device__ __nv_bfloat16 d_w2t[HH*HH];   // W2^T in bf16: [n][k]

__device__ __forceinline__ float elu_f(float x)  { return x > 0.f ? x : (expf(x) - 1.f); }
__device__ __forceinline__ float elu_ff(float x) { return x > 0.f ? x : (__expf(x) - 1.f); }

__device__ __forceinline__ unsigned f2tf32(float x) {
    unsigned r;
    asm("cvt.rna.tf32.f32 %0, %1;" : "=r"(r) : "f"(x));
    return r;
}
__device__ __forceinline__ unsigned packbf2(float lo, float hi) {
    __nv_bfloat162 v = __floats2bfloat162_rn(lo, hi);
    return *reinterpret_cast<unsigned*>(&v);
}
__device__ __forceinline__ uint32_t smem_u32(const void* p) {
    uint32_t a;
    asm("{ .reg .u64 t; cvta.to.shared.u64 t, %1; cvt.u32.u64 %0, t; }" : "=r"(a) : "l"(p));
    return a;
}

#define LDSM4(r0,r1,r2,r3,addr) \
    asm volatile("ldmatrix.sync.aligned.m8n8.x4.shared.b16 {%0,%1,%2,%3}, [%4];" \
        : "=r"(r0), "=r"(r1), "=r"(r2), "=r"(r3) : "r"(addr))

// ---------------- derive edge indices ----------------
__global__ void derive_kernel(const float* __restrict__ rel_rec,
                              const float* __restrict__ rel_send,
                              int* __restrict__ recv_idx, int* __restrict__ send_idx) {
    int e = blockIdx.x * blockDim.x + threadIdx.x;
    if (e >= EE) return;
    int r = 0, s = 0; float br = -1.f, bs = -1.f;
    for (int n = 0; n < NN; n++) {
        float vr = rel_rec[e*NN + n];
        float vs = rel_send[e*NN + n];
        if (vr > br) { br = vr; r = n; }
        if (vs > bs) { bs = vs; s = n; }
    }
    recv_idx[e] = r; send_idx[e] = s;
}

// ---------------- parallel deterministic list build ----------------
__global__ void build_lists_kernel(const int* __restrict__ recv_idx,
                                   const int* __restrict__ send_idx,
                                   int* __restrict__ list_rec, int* __restrict__ list_send,
                                   int* __restrict__ cnt_rec, int* __restrict__ cnt_send,
                                   float* __restrict__ invdeg_rec, float* __restrict__ invdeg_send) {
    const bool isSend = blockIdx.x >= NN;
    const int n = blockIdx.x & (NN-1);
    const int* __restrict__ idx = isSend ? send_idx : recv_idx;
    int* __restrict__ list = (isSend ? list_send : list_rec) + n*EE;
    const int t = threadIdx.x;            // 64 threads
    const int CH = EE / 64;               // 63
    const int base = t * CH;
    int c = 0;
    for (int i = 0; i < CH; i++) c += (idx[base+i] == n) ? 1 : 0;
    __shared__ int pre[64];
    pre[t] = c;
    __syncthreads();
    for (int off = 1; off < 64; off <<= 1) {
        int v = (t >= off) ? pre[t-off] : 0;
        __syncthreads();
        pre[t] += v;
        __syncthreads();
    }
    int offset = pre[t] - c;
    for (int i = 0; i < CH; i++) {
        int e = base + i;
        if (idx[e] == n) list[offset++] = e;
    }
    if (t == 63) {
        int tot = pre[63];
        float iv = tot ? 1.f/(float)tot : 1.f;
        if (isSend) { cnt_send[n] = tot; invdeg_send[n] = iv; }
        else        { cnt_rec[n]  = tot; invdeg_rec[n]  = iv; }
    }
}

// ---------------- trajectory embedding + fused W2 transpose ----------------
__global__ void traj_w2t_kernel(const float* __restrict__ centers,
                                const float* __restrict__ W, const float* __restrict__ bias,
                                const float* __restrict__ W2, __nv_bfloat16* __restrict__ w2t,
                                float* __restrict__ x) {
    if (blockIdx.x >= ROWS_N) {
        int n = blockIdx.x - ROWS_N;   // 0..255
        int k = threadIdx.x;           // 0..255
        w2t[n*HH + k] = __float2bfloat16(W2[k*HH + n]);
        return;
    }
    int row = blockIdx.x;
    int h = threadIdx.x;
    __shared__ float rp[PREV*2];
    if (h < PREV*2) {
        int p = h >> 1, c = h & 1;
        float v = 0.f;
        if (p > 0) v = centers[row*PREV*2 + p*2 + c] - centers[row*PREV*2 + (p-1)*2 + c];
        rp[h] = v;
    }
    __syncthreads();
    float acc = bias[h];
    #pragma unroll
    for (int k = 0; k < PREV*2; k++) acc += rp[k] * W[k*HH + h];
    x[row*HH + h] = acc;
}

// =======================================================================
// Generic double-buffered tf32 GEMM (unchanged)
// =======================================================================
template<int AMODE, bool ELU, bool GUARD_N>
__global__ __launch_bounds__(256)
void mma_gemm_v2(const float* __restrict__ A0, const float* __restrict__ A1,
                 const float* __restrict__ aVec, const float* __restrict__ cVec,
                 const float* __restrict__ invDegR, const float* __restrict__ invDegS,
                 const float* __restrict__ B0, const float* __restrict__ B1,
                 const float* __restrict__ bias,
                 float* __restrict__ C0, float* __restrict__ C1,
                 int M, int N, int K) {
    const float* __restrict__ Bm = (blockIdx.z == 0) ? B0 : B1;
    float* __restrict__ C = (blockIdx.z == 0) ? C0 : C1;

    __shared__ unsigned Asm[2][64][36];
    __shared__ unsigned Bsm[2][32][72];
    const int tid  = threadIdx.x;
    const int lane = tid & 31;
    const int warp = tid >> 5;
    const int warpM = warp & 1;
    const int warpN = warp >> 1;
    const int g  = lane >> 2;
    const int t4 = lane & 3;
    const int row0 = blockIdx.y * 64;
    const int col0 = blockIdx.x * 64;

    int arow[2], akq[2], bkk[2], bq[2];
    #pragma unroll
    for (int it = 0; it < 2; it++) {
        int ta = it*256 + tid;
        akq[it] = ta & 7;  arow[it] = ta >> 3;
        bkk[it] = ta >> 4; bq[it]  = ta & 15;
    }

    float4 pa[2], pb[2];

    auto prefetch = [&](int k0) {
        #pragma unroll
        for (int it = 0; it < 2; it++) {
            int gk = k0 + akq[it]*4;
            if (AMODE == 0) {
                pa[it] = *reinterpret_cast<const float4*>(&A0[(long)(row0+arow[it])*K + gk]);
            } else {
                const float* src = (gk >= HH) ? A1 : A0;
                pa[it] = *reinterpret_cast<const float4*>(&src[(long)(row0+arow[it])*HH + (gk & (HH-1))]);
            }
            int c0 = col0 + bq[it]*4;
            if (!GUARD_N) {
                pb[it] = *reinterpret_cast<const float4*>(&Bm[(long)(k0+bkk[it])*N + c0]);
            } else {
                float4 v;
                v.x = (c0+0 < N) ? Bm[(long)(k0+bkk[it])*N + c0+0] : 0.f;
                v.y = (c0+1 < N) ? Bm[(long)(k0+bkk[it])*N + c0+1] : 0.f;
                v.z = (c0+2 < N) ? Bm[(long)(k0+bkk[it])*N + c0+2] : 0.f;
                v.w = (c0+3 < N) ? Bm[(long)(k0+bkk[it])*N + c0+3] : 0.f;
                pb[it] = v;
            }
        }
    };

    auto store = [&](int s, int k0) {
        #pragma unroll
        for (int it = 0; it < 2; it++) {
            int gk = k0 + akq[it]*4;
            float4 v = pa[it];
            if (AMODE == 1) {
                int col = gk & (HH-1);
                float invd = ((gk >= HH) ? invDegS : invDegR)[(row0+arow[it]) & (NN-1)];
                float4 a4 = *reinterpret_cast<const float4*>(&aVec[col]);
                float4 c4 = *reinterpret_cast<const float4*>(&cVec[col]);
                v.x = a4.x*(v.x*invd)+c4.x; v.y = a4.y*(v.y*invd)+c4.y;
                v.z = a4.z*(v.z*invd)+c4.z; v.w = a4.w*(v.w*invd)+c4.w;
            } else if (AMODE == 2) {
                if (gk >= HH) {
                    int col = gk & (HH-1);
                    float4 a4 = *reinterpret_cast<const float4*>(&aVec[col]);
                    float4 c4 = *reinterpret_cast<const float4*>(&cVec[col]);
                    v.x = a4.x*v.x+c4.x; v.y = a4.y*v.y+c4.y;
                    v.z = a4.z*v.z+c4.z; v.w = a4.w*v.w+c4.w;
                }
            }
            Asm[s][arow[it]][akq[it]*4+0] = f2tf32(v.x);
            Asm[s][arow[it]][akq[it]*4+1] = f2tf32(v.y);
            Asm[s][arow[it]][akq[it]*4+2] = f2tf32(v.z);
            Asm[s][arow[it]][akq[it]*4+3] = f2tf32(v.w);

            float4 w = pb[it];
            Bsm[s][bkk[it]][bq[it]*4+0] = f2tf32(w.x);
            Bsm[s][bkk[it]][bq[it]*4+1] = f2tf32(w.y);
            Bsm[s][bkk[it]][bq[it]*4+2] = f2tf32(w.z);
            Bsm[s][bkk[it]][bq[it]*4+3] = f2tf32(w.w);
        }
    };

    float acc[2][2][4] = {};
    const int nIter = K >> 5;

    prefetch(0);
    store(0, 0);
    __syncthreads();

    for (int i = 0; i < nIter; i++) {
        int cur = i & 1;
        if (i + 1 < nIter) prefetch((i+1) * 32);

        #pragma unroll
        for (int ks = 0; ks < 32; ks += 8) {
            unsigned afr[2][4];
            #pragma unroll
            for (int ii = 0; ii < 2; ii++) {
                int r = warpM*32 + ii*16;
                afr[ii][0] = Asm[cur][r + g    ][ks + t4    ];
                afr[ii][1] = Asm[cur][r + g + 8][ks + t4    ];
                afr[ii][2] = Asm[cur][r + g    ][ks + t4 + 4];
                afr[ii][3] = Asm[cur][r + g + 8][ks + t4 + 4];
            }
            unsigned bfr[2][2];
            #pragma unroll
            for (int j = 0; j < 2; j++) {
                int nn = warpN*16 + j*8 + g;
                bfr[j][0] = Bsm[cur][ks + t4    ][nn];
                bfr[j][1] = Bsm[cur][ks + t4 + 4][nn];
            }
            #pragma unroll
            for (int ii = 0; ii < 2; ii++)
                #pragma unroll
                for (int j = 0; j < 2; j++)
                    asm volatile(
                        "mma.sync.aligned.m16n8k8.row.col.f32.tf32.tf32.f32 "
                        "{%0,%1,%2,%3}, {%4,%5,%6,%7}, {%8,%9}, {%0,%1,%2,%3};"
                        : "+f"(acc[ii][j][0]), "+f"(acc[ii][j][1]),
                          "+f"(acc[ii][j][2]), "+f"(acc[ii][j][3])
                        : "r"(afr[ii][0]), "r"(afr[ii][1]), "r"(afr[ii][2]), "r"(afr[ii][3]),
                          "r"(bfr[j][0]), "r"(bfr[j][1]));
        }
        if (i + 1 < nIter) store(cur ^ 1, (i+1) * 32);
        __syncthreads();
    }

    #pragma unroll
    for (int i = 0; i < 2; i++) {
        int r = row0 + warpM*32 + i*16 + g;
        #pragma unroll
        for (int j = 0; j < 2; j++) {
            int c = col0 + warpN*16 + j*8 + t4*2;
            #pragma unroll
            for (int h = 0; h < 2; h++) {
                int cc = c + h;
                if (GUARD_N && cc >= N) continue;
                float bb = bias ? bias[cc] : 0.f;
                float v0 = acc[i][j][h]   + bb;
                float v1 = acc[i][j][2+h] + bb;
                if (ELU) { v0 = elu_f(v0); v1 = elu_f(v1); }
                C[(long)r*N + cc]     = v0;
                C[(long)(r+8)*N + cc] = v1;
            }
        }
    }
}

// =======================================================================
// Pred GEMM + cumsum epilogue (unchanged)
// =======================================================================
__global__ __launch_bounds__(256)
void pred_pos_kernel(const float* __restrict__ A0, const float* __restrict__ Bm,
                     const float* __restrict__ bias, const float* __restrict__ centers,
                     float* __restrict__ out) {
    const int N = PRED*2;
    const int K = HH;
    __shared__ unsigned Asm[64][36];
    __shared__ unsigned Bsm[32][72];
    __shared__ float Cs[64][64];
    const int tid  = threadIdx.x;
    const int lane = tid & 31;
    const int warp = tid >> 5;
    const int warpM = warp & 1;
    const int warpN = warp >> 1;
    const int g  = lane >> 2;
    const int t4 = lane & 3;
    const int row0 = blockIdx.y * 64;

    int arow[2], akq[2], bkk[2], bq[2];
    #pragma unroll
    for (int it = 0; it < 2; it++) {
        int ta = it*256 + tid;
        akq[it] = ta & 7;  arow[it] = ta >> 3;
        bkk[it] = ta >> 4; bq[it]  = ta & 15;
    }
    float4 pa[2], pb[2];
    #pragma unroll
    for (int it = 0; it < 2; it++) {
        pa[it] = *reinterpret_cast<const float4*>(&A0[(long)(row0+arow[it])*K + akq[it]*4]);
        int c0 = bq[it]*4;
        float4 v;
        v.x = (c0+0 < N) ? Bm[(long)bkk[it]*N + c0+0] : 0.f;
        v.y = (c0+1 < N) ? Bm[(long)bkk[it]*N + c0+1] : 0.f;
        v.z = (c0+2 < N) ? Bm[(long)bkk[it]*N + c0+2] : 0.f;
        v.w = (c0+3 < N) ? Bm[(long)bkk[it]*N + c0+3] : 0.f;
        pb[it] = v;
    }

    float acc[2][2][4] = {};
    for (int k0 = 0; k0 < K; k0 += 32) {
        #pragma unroll
        for (int it = 0; it < 2; it++) {
            float4 v = pa[it];
            Asm[arow[it]][akq[it]*4+0] = f2tf32(v.x);
            Asm[arow[it]][akq[it]*4+1] = f2tf32(v.y);
            Asm[arow[it]][akq[it]*4+2] = f2tf32(v.z);
            Asm[arow[it]][akq[it]*4+3] = f2tf32(v.w);
            float4 w = pb[it];
            Bsm[bkk[it]][bq[it]*4+0] = f2tf32(w.x);
            Bsm[bkk[it]][bq[it]*4+1] = f2tf32(w.y);
            Bsm[bkk[it]][bq[it]*4+2] = f2tf32(w.z);
            Bsm[bkk[it]][bq[it]*4+3] = f2tf32(w.w);
        }
        if (k0 + 32 < K) {
            int kn = k0 + 32;
            #pragma unroll
            for (int it = 0; it < 2; it++) {
                pa[it] = *reinterpret_cast<const float4*>(&A0[(long)(row0+arow[it])*K + kn + akq[it]*4]);
                int c0 = bq[it]*4;
                float4 v;
                v.x = (c0+0 < N) ? Bm[(long)(kn+bkk[it])*N + c0+0] : 0.f;
                v.y = (c0+1 < N) ? Bm[(long)(kn+bkk[it])*N + c0+1] : 0.f;
                v.z = (c0+2 < N) ? Bm[(long)(kn+bkk[it])*N + c0+2] : 0.f;
                v.w = (c0+3 < N) ? Bm[(long)(kn+bkk[it])*N + c0+3] : 0.f;
                pb[it] = v;
            }
        }
        __syncthreads();
        #pragma unroll
        for (int ks = 0; ks < 32; ks += 8) {
            unsigned afr[2][4];
            #pragma unroll
            for (int i = 0; i < 2; i++) {
                int r = warpM*32 + i*16;
                afr[i][0] = Asm[r + g    ][ks + t4    ];
                afr[i][1] = Asm[r + g + 8][ks + t4    ];
                afr[i][2] = Asm[r + g    ][ks + t4 + 4];
                afr[i][3] = Asm[r + g + 8][ks + t4 + 4];
            }
            unsigned bfr[2][2];
            #pragma unroll
            for (int j = 0; j < 2; j++) {
                int nn = warpN*16 + j*8 + g;
                bfr[j][0] = Bsm[ks + t4    ][nn];
                bfr[j][1] = Bsm[ks + t4 + 4][nn];
            }
            #pragma unroll
            for (int i = 0; i < 2; i++)
                #pragma unroll
                for (int j = 0; j < 2; j++)
                    asm volatile(
                        "mma.sync.aligned.m16n8k8.row.col.f32.tf32.tf32.f32 "
                        "{%0,%1,%2,%3}, {%4,%5,%6,%7}, {%8,%9}, {%0,%1,%2,%3};"
                        : "+f"(acc[i][j][0]), "+f"(acc[i][j][1]),
                          "+f"(acc[i][j][2]), "+f"(acc[i][j][3])
                        : "r"(afr[i][0]), "r"(afr[i][1]), "r"(afr[i][2]), "r"(afr[i][3]),
                          "r"(bfr[j][0]), "r"(bfr[j][1]));
        }
        __syncthreads();
    }

    #pragma unroll
    for (int i = 0; i < 2; i++) {
        int r = warpM*32 + i*16 + g;
        #pragma unroll
        for (int j = 0; j < 2; j++) {
            int c = warpN*16 + j*8 + t4*2;
            #pragma unroll
            for (int h = 0; h < 2; h++) {
                int cc = c + h;
                float bb = (cc < N) ? bias[cc] : 0.f;
                Cs[r][cc]   = acc[i][j][h]   + bb;
                Cs[r+8][cc] = acc[i][j][2+h] + bb;
            }
        }
    }
    __syncthreads();

    if (tid < 128) {
        int lrow = tid >> 1, dimc = tid & 1;
        int grow = row0 + lrow;
        float cur = centers[grow*PREV*2 + (PREV-1)*2 + dimc];
        float accum = 0.f;
        #pragma unroll
        for (int p = 0; p < PRED; p++) {
            float v = Cs[lrow][2*p + dimc];
            out[(long)grow*N + 2*p + dimc] = v;
            accum += v;
            out[(long)(ROWS_N)*N + (long)grow*N + 2*p + dimc] = accum + cur;
        }
    }
}

// =======================================================================
// Fused edge GEMM v3: one CTA = 128 rows x ALL 256 cols.
// Phase 1: build full 128x256 bf16 A tile ONCE into persistent smem.
// Phase 2: two sequential 128-col halves, double-buffered B k-loop.
// Dynamic smem: A[128][264] + B[2][128][40] + bases.
// =======================================================================
#define AK_PAD   264                      // k-extent pad (bf16), stride 528B
#define A_BYTES  (128*AK_PAD*2)           // 67584
#define B_BYTES  (2*128*40*2)             // 20480
#define EDGE_SMEM (A_BYTES + B_BYTES + 1024)

__global__ __launch_bounds__(256, 2)
void edge_gemm2_bf16(const float* __restrict__ xTop, const float* __restrict__ xBot,
                     const float* __restrict__ b1,
                     const __nv_bfloat16* __restrict__ w2t, const float* __restrict__ b2,
                     const int* __restrict__ recv_idx, const int* __restrict__ send_idx,
                     float* __restrict__ h2) {
    extern __shared__ char smraw[];
    __nv_bfloat16* Afull = reinterpret_cast<__nv_bfloat16*>(smraw);          // [128][264]
    __nv_bfloat16* Bsn   = reinterpret_cast<__nv_bfloat16*>(smraw + A_BYTES); // [2][128][40]
    int* topBase = reinterpret_cast<int*>(smraw + A_BYTES + B_BYTES);
    int* botBase = topBase + 128;

    const int tid  = threadIdx.x;
    const int lane = tid & 31;
    const int warp = tid >> 5;
    const int warpM = warp & 3;
    const int warpN = warp >> 2;
    const int row0 = blockIdx.x * 128;

    if (tid < 128) {
        int grow = row0 + tid;
        int b = grow / EE;
        int e = grow - b * EE;
        topBase[tid] = (b*NN + recv_idx[e]) * HH;
        botBase[tid] = (b*NN + send_idx[e]) * HH;
    }
    __syncthreads();

    // ---- Phase 1: build full A tile (128 rows x 256 k), coalesced ----
    // task: row = tid>>6 + 4*it, kq = tid & 63 (lanes sweep k)
    {
        const int kq  = tid & 63;
        const int rb  = tid >> 6;          // 0..3
        const int kb  = kq * 4;
        float4 bb = *reinterpret_cast<const float4*>(&b1[kb]);
        #pragma unroll
        for (int it = 0; it < 32; it++) {
            int row = it*4 + rb;
            float4 a  = *reinterpret_cast<const float4*>(&xTop[topBase[row] + kb]);
            float4 bv = *reinterpret_cast<const float4*>(&xBot[botBase[row] + kb]);
            unsigned p0 = packbf2(elu_ff(a.x + bv.x + bb.x), elu_ff(a.y + bv.y + bb.y));
            unsigned p1 = packbf2(elu_ff(a.z + bv.z + bb.z), elu_ff(a.w + bv.w + bb.w));
            *reinterpret_cast<uint2*>(&Afull[row*AK_PAD + kb]) = make_uint2(p0, p1);
        }
    }

    // B staging tasks (k-major lanes)
    int bn[2], bkh[2];
    #pragma unroll
    for (int it = 0; it < 2; it++) {
        int task = it*256 + tid;
        bkh[it] = task & 3;
        bn[it]  = task >> 2;
    }
    uint4 pw[2];

    // ldmatrix lane decomposition
    const int lt  = lane >> 3;
    const int lrw = lane & 7;
    const int mrow0 = warpM * 32;
    const int ncol0 = warpN * 64;
    const uint32_t aBase = smem_u32(Afull);
    const uint32_t bBase0 = smem_u32(Bsn);
    const uint32_t BSTG = 128u * 40u * 2u;       // 10240 bytes per stage
    const uint32_t aLanePart = (uint32_t)(mrow0 + (lt & 1)*8 + lrw) * (AK_PAD*2u)
                             + (uint32_t)(lt >> 1) * 16u;
    const uint32_t bLanePart = (uint32_t)(ncol0 + lt*8 + lrw) * 80u;

    __syncthreads();   // A tile ready

    const int g  = lane >> 2;
    const int t4 = lane & 3;

    #pragma unroll 1
    for (int half = 0; half < 2; half++) {
        const int col0 = half * 128;

        // prime B stage 0
        #pragma unroll
        for (int it = 0; it < 2; it++)
            pw[it] = *reinterpret_cast<const uint4*>(&w2t[(long)(col0 + bn[it])*HH + bkh[it]*8]);
        #pragma unroll
        for (int it = 0; it < 2; it++)
            *reinterpret_cast<uint4*>(&Bsn[bn[it]*40 + bkh[it]*8]) = pw[it];
        __syncthreads();

        float acc[2][8][4] = {};

        #pragma unroll 1
        for (int i = 0; i < 8; i++) {
            int cur = i & 1;
            if (i < 7) {
                int kn = (i+1) * 32;
                #pragma unroll
                for (int it = 0; it < 2; it++)
                    pw[it] = *reinterpret_cast<const uint4*>(&w2t[(long)(col0 + bn[it])*HH + kn + bkh[it]*8]);
            }

            const uint32_t aCur = aBase + aLanePart + (uint32_t)i * 64u;  // 32 k * 2B
            const uint32_t bCur = bBase0 + (uint32_t)cur * BSTG + bLanePart;

            #pragma unroll
            for (int ks = 0; ks < 32; ks += 16) {
                unsigned afr[2][4];
                #pragma unroll
                for (int ii = 0; ii < 2; ii++) {
                    LDSM4(afr[ii][0], afr[ii][1], afr[ii][2], afr[ii][3],
                          aCur + (uint32_t)ii*(16u*AK_PAD*2u) + (uint32_t)ks*2u);
                }
                unsigned bfr[8][2];
                #pragma unroll
                for (int jb = 0; jb < 2; jb++) {
                    #pragma unroll
                    for (int kh = 0; kh < 2; kh++) {
                        unsigned t0, t1, t2, t3;
                        LDSM4(t0, t1, t2, t3,
                              bCur + (uint32_t)jb*2560u + (uint32_t)ks*2u + (uint32_t)kh*16u);
                        bfr[jb*4+0][kh] = t0;
                        bfr[jb*4+1][kh] = t1;
                        bfr[jb*4+2][kh] = t2;
                        bfr[jb*4+3][kh] = t3;
                    }
                }
                #pragma unroll
                for (int j = 0; j < 8; j++) {
                    #pragma unroll
                    for (int ii = 0; ii < 2; ii++)
                        asm volatile(
                            "mma.sync.aligned.m16n8k16.row.col.f32.bf16.bf16.f32 "
                            "{%0,%1,%2,%3}, {%4,%5,%6,%7}, {%8,%9}, {%0,%1,%2,%3};"
                            : "+f"(acc[ii][j][0]), "+f"(acc[ii][j][1]),
                              "+f"(acc[ii][j][2]), "+f"(acc[ii][j][3])
                            : "r"(afr[ii][0]), "r"(afr[ii][1]), "r"(afr[ii][2]), "r"(afr[ii][3]),
                              "r"(bfr[j][0]), "r"(bfr[j][1]));
                }
            }
            if (i < 7) {
                int nxt = cur ^ 1;
                #pragma unroll
                for (int it = 0; it < 2; it++)
                    *reinterpret_cast<uint4*>(&Bsn[nxt*(128*40) + bn[it]*40 + bkh[it]*8]) = pw[it];
            }
            __syncthreads();
        }

        // epilogue for this half
        #pragma unroll
        for (int i = 0; i < 2; i++) {
            int r_lo = row0 + mrow0 + i*16 + g;
            #pragma unroll
            for (int j = 0; j < 8; j++) {
                int c = col0 + ncol0 + j*8 + t4*2;
                float bb0 = b2[c], bb1 = b2[c+1];
                h2[(long)r_lo*HH + c    ]     = elu_ff(acc[i][j][0] + bb0);
                h2[(long)r_lo*HH + c + 1]     = elu_ff(acc[i][j][1] + bb1);
                h2[(long)(r_lo+8)*HH + c    ] = elu_ff(acc[i][j][2] + bb0);
                h2[(long)(r_lo+8)*HH + c + 1] = elu_ff(acc[i][j][3] + bb1);
            }
        }
        __syncthreads();   // done reading B stages before next half re-primes stage 0
    }
}

// ---------------- combined per-node gather sums ----------------
__global__ void scatter_kernel(const float* __restrict__ h2,
                               const int* __restrict__ list_rec, const int* __restrict__ cnt_rec,
                               const int* __restrict__ list_send, const int* __restrict__ cnt_send,
                               float* __restrict__ inc_raw, float* __restrict__ sq_part,
                               float* __restrict__ out_raw) {
    int id = blockIdx.x;
    bool isOut = id >= ROWS_N;
    int bn = id & (ROWS_N-1);
    int b = bn >> 6, n = bn & 63;
    int h = threadIdx.x;
    if (!isOut) {
        int cnt = cnt_rec[n];
        float acc = 0.f, accsq = 0.f;
        for (int k = 0; k < cnt; k++) {
            int e = list_rec[n*EE + k];
            float v = h2[(long)(b*EE + e)*HH + h];
            acc += v; accsq += v*v;
        }
        inc_raw[bn*HH + h] = acc;
        sq_part[bn*HH + h] = accsq;
    } else {
        int cnt = cnt_send[n];
        float acc = 0.f;
        for (int k = 0; k < cnt; k++) {
            int e = list_send[n*EE + k];
            acc += h2[(long)(b*EE + e)*HH + h];
        }
        out_raw[bn*HH + h] = acc;
    }
}

// ---------------- BN stats -> affine (a,c) ----------------
template<bool SRC_SQ>
__global__ void stats_kernel(const float* __restrict__ sum_part, const float* __restrict__ sq_part,
                             const float* __restrict__ gamma, const float* __restrict__ beta,
                             float* __restrict__ a, float* __restrict__ c,
                             int nrows, float count) {
    int h = blockIdx.x;
    float s = 0.f, sq = 0.f;
    for (int r = threadIdx.x; r < nrows; r += 256) {
        float v = sum_part[r*HH + h];
        s += v;
        if (SRC_SQ) sq += v*v; else sq += sq_part[r*HH + h];
    }
    __shared__ float ss[256], ssq[256];
    ss[threadIdx.x] = s; ssq[threadIdx.x] = sq;
    __syncthreads();
    for (int st = 128; st > 0; st >>= 1) {
        if (threadIdx.x < st) { ss[threadIdx.x] += ss[threadIdx.x+st]; ssq[threadIdx.x] += ssq[threadIdx.x+st]; }
        __syncthreads();
    }
    if (threadIdx.x == 0) {
        float mu = ss[0] / count;
        float var = ssq[0] / count - mu*mu;
        float av = gamma[h] * rsqrtf(var + 1e-5f);
        a[h] = av;
        c[h] = beta[h] - mu * av;
    }
}

// ---------------- launcher ----------------
extern "C" void kernel_launch(void* const* d_in, const int* in_sizes, int n_in,
                              void* d_out, int out_size) {
    const float* centers  = (const float*)d_in[0];
    const float* rel_rec  = (const float*)d_in[1];
    const float* rel_send = (const float*)d_in[2];
    const float* W_traj   = (const float*)d_in[3];
    const float* b_traj   = (const float*)d_in[4];
    const float* n2e_W1   = (const float*)d_in[5];
    const float* n2e_b1   = (const float*)d_in[6];
    const float* n2e_W2   = (const float*)d_in[7];
    const float* n2e_b2   = (const float*)d_in[8];
    const float* n2e_g    = (const float*)d_in[9];
    const float* n2e_be   = (const float*)d_in[10];
    const float* e2n_W1   = (const float*)d_in[11];
    const float* e2n_b1   = (const float*)d_in[12];
    const float* e2n_W2   = (const float*)d_in[13];
    const float* e2n_b2   = (const float*)d_in[14];
    const float* e2n_g    = (const float*)d_in[15];
    const float* e2n_be   = (const float*)d_in[16];
    const float* W_fuse   = (const float*)d_in[17];
    const float* b_fuse   = (const float*)d_in[18];
    const float* W_pred   = (const float*)d_in[19];
    const float* b_pred   = (const float*)d_in[20];
    float* out = (float*)d_out;

    float *p_x, *p_xTop, *p_xBot, *p_h2, *p_inc, *p_incsq, *p_outg;
    float *p_nh1, *p_mraw, *p_fused;
    float *p_ae, *p_ce, *p_an, *p_cn, *p_idr, *p_ids;
    int *p_recv, *p_send, *p_lr, *p_ls, *p_cr, *p_cs;
    __nv_bfloat16 *p_w2t;
    cudaGetSymbolAddress((void**)&p_x, d_x);
    cudaGetSymbolAddress((void**)&p_xTop, d_xTop);
    cudaGetSymbolAddress((void**)&p_xBot, d_xBot);
    cudaGetSymbolAddress((void**)&p_h2, d_h2);
    cudaGetSymbolAddress((void**)&p_inc, d_inc);
    cudaGetSymbolAddress((void**)&p_incsq, d_incsq);
    cudaGetSymbolAddress((void**)&p_outg, d_outg);
    cudaGetSymbolAddress((void**)&p_nh1, d_nh1);
    cudaGetSymbolAddress((void**)&p_mraw, d_mraw);
    cudaGetSymbolAddress((void**)&p_fused, d_fused);
    cudaGetSymbolAddress((void**)&p_ae, d_ae);
    cudaGetSymbolAddress((void**)&p_ce, d_ce);
    cudaGetSymbolAddress((void**)&p_an, d_an);
    cudaGetSymbolAddress((void**)&p_cn, d_cn);
    cudaGetSymbolAddress((void**)&p_idr, d_invdegrec);
    cudaGetSymbolAddress((void**)&p_ids, d_invdegsend);
    cudaGetSymbolAddress((void**)&p_recv, d_recv);
    cudaGetSymbolAddress((void**)&p_send, d_send);
    cudaGetSymbolAddress((void**)&p_lr, d_listrec);
    cudaGetSymbolAddress((void**)&p_ls, d_listsend);
    cudaGetSymbolAddress((void**)&p_cr, d_cntrec);
    cudaGetSymbolAddress((void**)&p_cs, d_cntsend);
    cudaGetSymbolAddress((void**)&p_w2t, d_w2t);

    cudaFuncSetAttribute(edge_gemm2_bf16, cudaFuncAttributeMaxDynamicSharedMemorySize, EDGE_SMEM);

    // 1. edge indices
    derive_kernel<<<(EE+255)/256, 256>>>(rel_rec, rel_send, p_recv, p_send);

    // 2. trajectory embedding + fused W2^T bf16
    traj_w2t_kernel<<<ROWS_N + HH, HH>>>(centers, W_traj, b_traj, n2e_W2, p_w2t, p_x);

    // 3. xTop/xBot (dual-output, double-buffered tf32)
    mma_gemm_v2<0,false,false><<<dim3(HH/64, ROWS_N/64, 2), 256>>>(
        p_x, nullptr, nullptr, nullptr, nullptr, nullptr,
        n2e_W1, n2e_W1 + HH*HH, nullptr, p_xTop, p_xBot, ROWS_N, HH, HH);

    // 4. fused edge MLP v3 (A built once per 128 rows)  <-- profiled launch
    edge_gemm2_bf16<<<ROWS_E/128, 256, EDGE_SMEM>>>(p_xTop, p_xBot, n2e_b1,
                                                    p_w2t, n2e_b2,
                                                    p_recv, p_send, p_h2);

    // 5. per-node edge lists
    build_lists_kernel<<<128, 64>>>(p_recv, p_send, p_lr, p_ls, p_cr, p_cs, p_idr, p_ids);

    // 6. scatter sums + edge BN stats
    scatter_kernel<<<2*ROWS_N, HH>>>(p_h2, p_lr, p_cr, p_ls, p_cs, p_inc, p_incsq, p_outg);
    stats_kernel<false><<<HH, 256>>>(p_inc, p_incsq, n2e_g, n2e_be, p_ae, p_ce, ROWS_N, (float)ROWS_E);

    // 7. node MLP
    mma_gemm_v2<1,true,false><<<dim3(HH/64, ROWS_N/64, 1), 256>>>(
        p_inc, p_outg, p_ae, p_ce, p_idr, p_ids,
        e2n_W1, e2n_W1, e2n_b1, p_nh1, p_nh1, ROWS_N, HH, 2*HH);
    mma_gemm_v2<0,true,false><<<dim3(HH/64, ROWS_N/64, 1), 256>>>(
        p_nh1, nullptr, nullptr, nullptr, nullptr, nullptr,
        e2n_W2, e2n_W2, e2n_b2, p_mraw, p_mraw, ROWS_N, HH, HH);
    stats_kernel<true><<<HH, 256>>>(p_mraw, nullptr, e2n_g, e2n_be, p_an, p_cn, ROWS_N, (float)ROWS_N);

    // 8. fuse + predict (+ fused cumsum epilogue)
    mma_gemm_v2<2,false,false><<<dim3(HH/64, ROWS_N/64, 1), 256>>>(
        p_x, p_mraw, p_an, p_cn, nullptr, nullptr,
        W_fuse, W_fuse, b_fuse, p_fused, p_fused, ROWS_N, HH, 2*HH);
    pred_pos_kernel<<<dim3(1, ROWS_N/64), 256>>>(p_fused, W_pred, b_pred, centers, out);
}

// round 10
// speedup vs baseline: 3.4133x; 1.0393x over previous
#include <cuda_runtime.h>
#include <cuda_bf16.h>
#include <math.h>
#include <stdint.h>

#define BB   16
#define NN   64
#define PREV 6
#define PRED 30
#define HH   256
#define EE   (NN*(NN-1))      // 4032
#define ROWS_E (BB*EE)        // 64512
#define ROWS_N (BB*NN)        // 1024

// ---------------- static scratch ----------------
__device__ float d_x[ROWS_N*HH];
__device__ float d_xTop[ROWS_N*HH];
__device__ float d_xBot[ROWS_N*HH];
__device__ float d_h2[ROWS_E*HH];
__device__ float d_inc[ROWS_N*HH];
__device__ float d_incsq[ROWS_N*HH];
__device__ float d_outg[ROWS_N*HH];
__device__ float d_nh1[ROWS_N*HH];
__device__ float d_mraw[ROWS_N*HH];
__device__ float d_fused[ROWS_N*HH];
__device__ float d_ae[HH], d_ce[HH], d_an[HH], d_cn[HH];
__device__ int   d_recv[EE], d_send[EE];
__device__ int   d_listrec[NN*EE], d_listsend[NN*EE];
__device__ int   d_cntrec[NN], d_cntsend[NN];
__device__ float d_invdegrec[NN], d_invdegsend[NN];
__device__ __nv_bfloat16 d_w2t[HH*HH];   // W2^T in bf16: [n][k]

__device__ __forceinline__ float elu_f(float x)  { return x > 0.f ? x : (expf(x) - 1.f); }
__device__ __forceinline__ float elu_ff(float x) { return x > 0.f ? x : (__expf(x) - 1.f); }

__device__ __forceinline__ unsigned f2tf32(float x) {
    unsigned r;
    asm("cvt.rna.tf32.f32 %0, %1;" : "=r"(r) : "f"(x));
    return r;
}
__device__ __forceinline__ unsigned packbf2(float lo, float hi) {
    __nv_bfloat162 v = __floats2bfloat162_rn(lo, hi);
    return *reinterpret_cast<unsigned*>(&v);
}
__device__ __forceinline__ uint32_t smem_u32(const void* p) {
    uint32_t a;
    asm("{ .reg .u64 t; cvta.to.shared.u64 t, %1; cvt.u32.u64 %0, t; }" : "=r"(a) : "l"(p));
    return a;
}

#define LDSM4(r0,r1,r2,r3,addr) \
    asm volatile("ldmatrix.sync.aligned.m8n8.x4.shared.b16 {%0,%1,%2,%3}, [%4];" \
        : "=r"(r0), "=r"(r1), "=r"(r2), "=r"(r3) : "r"(addr))

// ---------------- fused prep: derive edges + traj embed + W2^T ----------------
// blocks [0,16): derive; [16, 16+1024): traj rows; [1040, 1040+256): w2t rows
__global__ void prep_kernel(const float* __restrict__ rel_rec,
                            const float* __restrict__ rel_send,
                            int* __restrict__ recv_idx, int* __restrict__ send_idx,
                            const float* __restrict__ centers,
                            const float* __restrict__ W, const float* __restrict__ bias,
                            const float* __restrict__ W2, __nv_bfloat16* __restrict__ w2t,
                            float* __restrict__ x) {
    if (blockIdx.x < 16) {
        int e = blockIdx.x * 256 + threadIdx.x;
        if (e >= EE) return;
        int r = 0, s = 0; float br = -1.f, bs = -1.f;
        for (int n = 0; n < NN; n++) {
            float vr = rel_rec[e*NN + n];
            float vs = rel_send[e*NN + n];
            if (vr > br) { br = vr; r = n; }
            if (vs > bs) { bs = vs; s = n; }
        }
        recv_idx[e] = r; send_idx[e] = s;
        return;
    }
    if (blockIdx.x >= 16 + ROWS_N) {
        int n = blockIdx.x - 16 - ROWS_N;
        int k = threadIdx.x;
        w2t[n*HH + k] = __float2bfloat16(W2[k*HH + n]);
        return;
    }
    int row = blockIdx.x - 16;
    int h = threadIdx.x;
    __shared__ float rp[PREV*2];
    if (h < PREV*2) {
        int p = h >> 1, c = h & 1;
        float v = 0.f;
        if (p > 0) v = centers[row*PREV*2 + p*2 + c] - centers[row*PREV*2 + (p-1)*2 + c];
        rp[h] = v;
    }
    __syncthreads();
    float acc = bias[h];
    #pragma unroll
    for (int k = 0; k < PREV*2; k++) acc += rp[k] * W[k*HH + h];
    x[row*HH + h] = acc;
}

// ---------------- parallel deterministic list build ----------------
__global__ void build_lists_kernel(const int* __restrict__ recv_idx,
                                   const int* __restrict__ send_idx,
                                   int* __restrict__ list_rec, int* __restrict__ list_send,
                                   int* __restrict__ cnt_rec, int* __restrict__ cnt_send,
                                   float* __restrict__ invdeg_rec, float* __restrict__ invdeg_send) {
    const bool isSend = blockIdx.x >= NN;
    const int n = blockIdx.x & (NN-1);
    const int* __restrict__ idx = isSend ? send_idx : recv_idx;
    int* __restrict__ list = (isSend ? list_send : list_rec) + n*EE;
    const int t = threadIdx.x;            // 64 threads
    const int CH = EE / 64;               // 63
    const int base = t * CH;
    int c = 0;
    for (int i = 0; i < CH; i++) c += (idx[base+i] == n) ? 1 : 0;
    __shared__ int pre[64];
    pre[t] = c;
    __syncthreads();
    for (int off = 1; off < 64; off <<= 1) {
        int v = (t >= off) ? pre[t-off] : 0;
        __syncthreads();
        pre[t] += v;
        __syncthreads();
    }
    int offset = pre[t] - c;
    for (int i = 0; i < CH; i++) {
        int e = base + i;
        if (idx[e] == n) list[offset++] = e;
    }
    if (t == 63) {
        int tot = pre[63];
        float iv = tot ? 1.f/(float)tot : 1.f;
        if (isSend) { cnt_send[n] = tot; invdeg_send[n] = iv; }
        else        { cnt_rec[n]  = tot; invdeg_rec[n]  = iv; }
    }
}

// =======================================================================
// Generic double-buffered tf32 GEMM (unchanged)
// =======================================================================
template<int AMODE, bool ELU, bool GUARD_N>
__global__ __launch_bounds__(256)
void mma_gemm_v2(const float* __restrict__ A0, const float* __restrict__ A1,
                 const float* __restrict__ aVec, const float* __restrict__ cVec,
                 const float* __restrict__ invDegR, const float* __restrict__ invDegS,
                 const float* __restrict__ B0, const float* __restrict__ B1,
                 const float* __restrict__ bias,
                 float* __restrict__ C0, float* __restrict__ C1,
                 int M, int N, int K) {
    const float* __restrict__ Bm = (blockIdx.z == 0) ? B0 : B1;
    float* __restrict__ C = (blockIdx.z == 0) ? C0 : C1;

    __shared__ unsigned Asm[2][64][36];
    __shared__ unsigned Bsm[2][32][72];
    const int tid  = threadIdx.x;
    const int lane = tid & 31;
    const int warp = tid >> 5;
    const int warpM = warp & 1;
    const int warpN = warp >> 1;
    const int g  = lane >> 2;
    const int t4 = lane & 3;
    const int row0 = blockIdx.y * 64;
    const int col0 = blockIdx.x * 64;

    int arow[2], akq[2], bkk[2], bq[2];
    #pragma unroll
    for (int it = 0; it < 2; it++) {
        int ta = it*256 + tid;
        akq[it] = ta & 7;  arow[it] = ta >> 3;
        bkk[it] = ta >> 4; bq[it]  = ta & 15;
    }

    float4 pa[2], pb[2];

    auto prefetch = [&](int k0) {
        #pragma unroll
        for (int it = 0; it < 2; it++) {
            int gk = k0 + akq[it]*4;
            if (AMODE == 0) {
                pa[it] = *reinterpret_cast<const float4*>(&A0[(long)(row0+arow[it])*K + gk]);
            } else {
                const float* src = (gk >= HH) ? A1 : A0;
                pa[it] = *reinterpret_cast<const float4*>(&src[(long)(row0+arow[it])*HH + (gk & (HH-1))]);
            }
            int c0 = col0 + bq[it]*4;
            if (!GUARD_N) {
                pb[it] = *reinterpret_cast<const float4*>(&Bm[(long)(k0+bkk[it])*N + c0]);
            } else {
                float4 v;
                v.x = (c0+0 < N) ? Bm[(long)(k0+bkk[it])*N + c0+0] : 0.f;
                v.y = (c0+1 < N) ? Bm[(long)(k0+bkk[it])*N + c0+1] : 0.f;
                v.z = (c0+2 < N) ? Bm[(long)(k0+bkk[it])*N + c0+2] : 0.f;
                v.w = (c0+3 < N) ? Bm[(long)(k0+bkk[it])*N + c0+3] : 0.f;
                pb[it] = v;
            }
        }
    };

    auto store = [&](int s, int k0) {
        #pragma unroll
        for (int it = 0; it < 2; it++) {
            int gk = k0 + akq[it]*4;
            float4 v = pa[it];
            if (AMODE == 1) {
                int col = gk & (HH-1);
                float invd = ((gk >= HH) ? invDegS : invDegR)[(row0+arow[it]) & (NN-1)];
                float4 a4 = *reinterpret_cast<const float4*>(&aVec[col]);
                float4 c4 = *reinterpret_cast<const float4*>(&cVec[col]);
                v.x = a4.x*(v.x*invd)+c4.x; v.y = a4.y*(v.y*invd)+c4.y;
                v.z = a4.z*(v.z*invd)+c4.z; v.w = a4.w*(v.w*invd)+c4.w;
            } else if (AMODE == 2) {
                if (gk >= HH) {
                    int col = gk & (HH-1);
                    float4 a4 = *reinterpret_cast<const float4*>(&aVec[col]);
                    float4 c4 = *reinterpret_cast<const float4*>(&cVec[col]);
                    v.x = a4.x*v.x+c4.x; v.y = a4.y*v.y+c4.y;
                    v.z = a4.z*v.z+c4.z; v.w = a4.w*v.w+c4.w;
                }
            }
            Asm[s][arow[it]][akq[it]*4+0] = f2tf32(v.x);
            Asm[s][arow[it]][akq[it]*4+1] = f2tf32(v.y);
            Asm[s][arow[it]][akq[it]*4+2] = f2tf32(v.z);
            Asm[s][arow[it]][akq[it]*4+3] = f2tf32(v.w);

            float4 w = pb[it];
            Bsm[s][bkk[it]][bq[it]*4+0] = f2tf32(w.x);
            Bsm[s][bkk[it]][bq[it]*4+1] = f2tf32(w.y);
            Bsm[s][bkk[it]][bq[it]*4+2] = f2tf32(w.z);
            Bsm[s][bkk[it]][bq[it]*4+3] = f2tf32(w.w);
        }
    };

    float acc[2][2][4] = {};
    const int nIter = K >> 5;

    prefetch(0);
    store(0, 0);
    __syncthreads();

    for (int i = 0; i < nIter; i++) {
        int cur = i & 1;
        if (i + 1 < nIter) prefetch((i+1) * 32);

        #pragma unroll
        for (int ks = 0; ks < 32; ks += 8) {
            unsigned afr[2][4];
            #pragma unroll
            for (int ii = 0; ii < 2; ii++) {
                int r = warpM*32 + ii*16;
                afr[ii][0] = Asm[cur][r + g    ][ks + t4    ];
                afr[ii][1] = Asm[cur][r + g + 8][ks + t4    ];
                afr[ii][2] = Asm[cur][r + g    ][ks + t4 + 4];
                afr[ii][3] = Asm[cur][r + g + 8][ks + t4 + 4];
            }
            unsigned bfr[2][2];
            #pragma unroll
            for (int j = 0; j < 2; j++) {
                int nn = warpN*16 + j*8 + g;
                bfr[j][0] = Bsm[cur][ks + t4    ][nn];
                bfr[j][1] = Bsm[cur][ks + t4 + 4][nn];
            }
            #pragma unroll
            for (int ii = 0; ii < 2; ii++)
                #pragma unroll
                for (int j = 0; j < 2; j++)
                    asm volatile(
                        "mma.sync.aligned.m16n8k8.row.col.f32.tf32.tf32.f32 "
                        "{%0,%1,%2,%3}, {%4,%5,%6,%7}, {%8,%9}, {%0,%1,%2,%3};"
                        : "+f"(acc[ii][j][0]), "+f"(acc[ii][j][1]),
                          "+f"(acc[ii][j][2]), "+f"(acc[ii][j][3])
                        : "r"(afr[ii][0]), "r"(afr[ii][1]), "r"(afr[ii][2]), "r"(afr[ii][3]),
                          "r"(bfr[j][0]), "r"(bfr[j][1]));
        }
        if (i + 1 < nIter) store(cur ^ 1, (i+1) * 32);
        __syncthreads();
    }

    #pragma unroll
    for (int i = 0; i < 2; i++) {
        int r = row0 + warpM*32 + i*16 + g;
        #pragma unroll
        for (int j = 0; j < 2; j++) {
            int c = col0 + warpN*16 + j*8 + t4*2;
            #pragma unroll
            for (int h = 0; h < 2; h++) {
                int cc = c + h;
                if (GUARD_N && cc >= N) continue;
                float bb = bias ? bias[cc] : 0.f;
                float v0 = acc[i][j][h]   + bb;
                float v1 = acc[i][j][2+h] + bb;
                if (ELU) { v0 = elu_f(v0); v1 = elu_f(v1); }
                C[(long)r*N + cc]     = v0;
                C[(long)(r+8)*N + cc] = v1;
            }
        }
    }
}

// =======================================================================
// Pred GEMM + cumsum epilogue (unchanged)
// =======================================================================
__global__ __launch_bounds__(256)
void pred_pos_kernel(const float* __restrict__ A0, const float* __restrict__ Bm,
                     const float* __restrict__ bias, const float* __restrict__ centers,
                     float* __restrict__ out) {
    const int N = PRED*2;
    const int K = HH;
    __shared__ unsigned Asm[64][36];
    __shared__ unsigned Bsm[32][72];
    __shared__ float Cs[64][64];
    const int tid  = threadIdx.x;
    const int lane = tid & 31;
    const int warp = tid >> 5;
    const int warpM = warp & 1;
    const int warpN = warp >> 1;
    const int g  = lane >> 2;
    const int t4 = lane & 3;
    const int row0 = blockIdx.y * 64;

    int arow[2], akq[2], bkk[2], bq[2];
    #pragma unroll
    for (int it = 0; it < 2; it++) {
        int ta = it*256 + tid;
        akq[it] = ta & 7;  arow[it] = ta >> 3;
        bkk[it] = ta >> 4; bq[it]  = ta & 15;
    }
    float4 pa[2], pb[2];
    #pragma unroll
    for (int it = 0; it < 2; it++) {
        pa[it] = *reinterpret_cast<const float4*>(&A0[(long)(row0+arow[it])*K + akq[it]*4]);
        int c0 = bq[it]*4;
        float4 v;
        v.x = (c0+0 < N) ? Bm[(long)bkk[it]*N + c0+0] : 0.f;
        v.y = (c0+1 < N) ? Bm[(long)bkk[it]*N + c0+1] : 0.f;
        v.z = (c0+2 < N) ? Bm[(long)bkk[it]*N + c0+2] : 0.f;
        v.w = (c0+3 < N) ? Bm[(long)bkk[it]*N + c0+3] : 0.f;
        pb[it] = v;
    }

    float acc[2][2][4] = {};
    for (int k0 = 0; k0 < K; k0 += 32) {
        #pragma unroll
        for (int it = 0; it < 2; it++) {
            float4 v = pa[it];
            Asm[arow[it]][akq[it]*4+0] = f2tf32(v.x);
            Asm[arow[it]][akq[it]*4+1] = f2tf32(v.y);
            Asm[arow[it]][akq[it]*4+2] = f2tf32(v.z);
            Asm[arow[it]][akq[it]*4+3] = f2tf32(v.w);
            float4 w = pb[it];
            Bsm[bkk[it]][bq[it]*4+0] = f2tf32(w.x);
            Bsm[bkk[it]][bq[it]*4+1] = f2tf32(w.y);
            Bsm[bkk[it]][bq[it]*4+2] = f2tf32(w.z);
            Bsm[bkk[it]][bq[it]*4+3] = f2tf32(w.w);
        }
        if (k0 + 32 < K) {
            int kn = k0 + 32;
            #pragma unroll
            for (int it = 0; it < 2; it++) {
                pa[it] = *reinterpret_cast<const float4*>(&A0[(long)(row0+arow[it])*K + kn + akq[it]*4]);
                int c0 = bq[it]*4;
                float4 v;
                v.x = (c0+0 < N) ? Bm[(long)(kn+bkk[it])*N + c0+0] : 0.f;
                v.y = (c0+1 < N) ? Bm[(long)(kn+bkk[it])*N + c0+1] : 0.f;
                v.z = (c0+2 < N) ? Bm[(long)(kn+bkk[it])*N + c0+2] : 0.f;
                v.w = (c0+3 < N) ? Bm[(long)(kn+bkk[it])*N + c0+3] : 0.f;
                pb[it] = v;
            }
        }
        __syncthreads();
        #pragma unroll
        for (int ks = 0; ks < 32; ks += 8) {
            unsigned afr[2][4];
            #pragma unroll
            for (int i = 0; i < 2; i++) {
                int r = warpM*32 + i*16;
                afr[i][0] = Asm[r + g    ][ks + t4    ];
                afr[i][1] = Asm[r + g + 8][ks + t4    ];
                afr[i][2] = Asm[r + g    ][ks + t4 + 4];
                afr[i][3] = Asm[r + g + 8][ks + t4 + 4];
            }
            unsigned bfr[2][2];
            #pragma unroll
            for (int j = 0; j < 2; j++) {
                int nn = warpN*16 + j*8 + g;
                bfr[j][0] = Bsm[ks + t4    ][nn];
                bfr[j][1] = Bsm[ks + t4 + 4][nn];
            }
            #pragma unroll
            for (int i = 0; i < 2; i++)
                #pragma unroll
                for (int j = 0; j < 2; j++)
                    asm volatile(
                        "mma.sync.aligned.m16n8k8.row.col.f32.tf32.tf32.f32 "
                        "{%0,%1,%2,%3}, {%4,%5,%6,%7}, {%8,%9}, {%0,%1,%2,%3};"
                        : "+f"(acc[i][j][0]), "+f"(acc[i][j][1]),
                          "+f"(acc[i][j][2]), "+f"(acc[i][j][3])
                        : "r"(afr[i][0]), "r"(afr[i][1]), "r"(afr[i][2]), "r"(afr[i][3]),
                          "r"(bfr[j][0]), "r"(bfr[j][1]));
        }
        __syncthreads();
    }

    #pragma unroll
    for (int i = 0; i < 2; i++) {
        int r = warpM*32 + i*16 + g;
        #pragma unroll
        for (int j = 0; j < 2; j++) {
            int c = warpN*16 + j*8 + t4*2;
            #pragma unroll
            for (int h = 0; h < 2; h++) {
                int cc = c + h;
                float bb = (cc < N) ? bias[cc] : 0.f;
                Cs[r][cc]   = acc[i][j][h]   + bb;
                Cs[r+8][cc] = acc[i][j][2+h] + bb;
            }
        }
    }
    __syncthreads();

    if (tid < 128) {
        int lrow = tid >> 1, dimc = tid & 1;
        int grow = row0 + lrow;
        float cur = centers[grow*PREV*2 + (PREV-1)*2 + dimc];
        float accum = 0.f;
        #pragma unroll
        for (int p = 0; p < PRED; p++) {
            float v = Cs[lrow][2*p + dimc];
            out[(long)grow*N + 2*p + dimc] = v;
            accum += v;
            out[(long)(ROWS_N)*N + (long)grow*N + 2*p + dimc] = accum + cur;
        }
    }
}

// =======================================================================
// Fused edge GEMM v4: one CTA = 64 rows x ALL 256 cols, 3 CTAs/SM.
// Phase 1: build 64x256 bf16 A tile once. Phase 2: two 128-col halves,
// double-buffered B k-loop, warp tile 32x32.
// =======================================================================
#define A_ROWS   64
#define AK_PAD   264                      // k-extent pad (bf16), stride 528B
#define A_BYTES  (A_ROWS*AK_PAD*2)        // 33792
#define B_BYTES  (2*128*40*2)             // 20480
#define EDGE_SMEM (A_BYTES + B_BYTES + 1024)

__global__ __launch_bounds__(256, 3)
void edge_gemm2_bf16(const float* __restrict__ xTop, const float* __restrict__ xBot,
                     const float* __restrict__ b1,
                     const __nv_bfloat16* __restrict__ w2t, const float* __restrict__ b2,
                     const int* __restrict__ recv_idx, const int* __restrict__ send_idx,
                     float* __restrict__ h2) {
    extern __shared__ char smraw[];
    __nv_bfloat16* Afull = reinterpret_cast<__nv_bfloat16*>(smraw);           // [64][264]
    __nv_bfloat16* Bsn   = reinterpret_cast<__nv_bfloat16*>(smraw + A_BYTES); // [2][128][40]
    int* topBase = reinterpret_cast<int*>(smraw + A_BYTES + B_BYTES);
    int* botBase = topBase + A_ROWS;

    const int tid  = threadIdx.x;
    const int lane = tid & 31;
    const int warp = tid >> 5;
    const int warpM = warp & 1;          // rows warpM*32
    const int warpN = warp >> 1;         // cols warpN*32 within 128-half
    const int row0 = blockIdx.x * A_ROWS;

    if (tid < A_ROWS) {
        int grow = row0 + tid;
        int b = grow / EE;
        int e = grow - b * EE;
        topBase[tid] = (b*NN + recv_idx[e]) * HH;
        botBase[tid] = (b*NN + send_idx[e]) * HH;
    }
    __syncthreads();

    // ---- Phase 1: build A tile (64 rows x 256 k), coalesced ----
    {
        const int kq = tid & 63;
        const int rb = tid >> 6;           // 0..3
        const int kb = kq * 4;
        float4 bb = *reinterpret_cast<const float4*>(&b1[kb]);
        #pragma unroll
        for (int it = 0; it < 16; it++) {
            int row = it*4 + rb;
            float4 a  = *reinterpret_cast<const float4*>(&xTop[topBase[row] + kb]);
            float4 bv = *reinterpret_cast<const float4*>(&xBot[botBase[row] + kb]);
            unsigned p0 = packbf2(elu_ff(a.x + bv.x + bb.x), elu_ff(a.y + bv.y + bb.y));
            unsigned p1 = packbf2(elu_ff(a.z + bv.z + bb.z), elu_ff(a.w + bv.w + bb.w));
            *reinterpret_cast<uint2*>(&Afull[row*AK_PAD + kb]) = make_uint2(p0, p1);
        }
    }

    // B staging tasks (k-major lanes)
    int bn[2], bkh[2];
    #pragma unroll
    for (int it = 0; it < 2; it++) {
        int task = it*256 + tid;
        bkh[it] = task & 3;
        bn[it]  = task >> 2;
    }
    uint4 pw[2];

    // ldmatrix lane decomposition
    const int lt  = lane >> 3;
    const int lrw = lane & 7;
    const int mrow0 = warpM * 32;
    const int ncol0 = warpN * 32;
    const uint32_t aBase = smem_u32(Afull);
    const uint32_t bBase0 = smem_u32(Bsn);
    const uint32_t BSTG = 128u * 40u * 2u;       // 10240 bytes per stage
    const uint32_t aLanePart = (uint32_t)(mrow0 + (lt & 1)*8 + lrw) * (AK_PAD*2u)
                             + (uint32_t)(lt >> 1) * 16u;
    // B: one LDSM4 covers the warp's 32 cols (4 tiles of 8) at one kh
    const uint32_t bLanePart = (uint32_t)(ncol0 + lt*8 + lrw) * 80u;

    __syncthreads();   // A tile ready

    const int g  = lane >> 2;
    const int t4 = lane & 3;

    #pragma unroll 1
    for (int half = 0; half < 2; half++) {
        const int col0 = half * 128;

        // prime B stage 0
        #pragma unroll
        for (int it = 0; it < 2; it++)
            pw[it] = *reinterpret_cast<const uint4*>(&w2t[(long)(col0 + bn[it])*HH + bkh[it]*8]);
        #pragma unroll
        for (int it = 0; it < 2; it++)
            *reinterpret_cast<uint4*>(&Bsn[bn[it]*40 + bkh[it]*8]) = pw[it];
        __syncthreads();

        float acc[2][4][4] = {};

        #pragma unroll 1
        for (int i = 0; i < 8; i++) {
            int cur = i & 1;
            if (i < 7) {
                int kn = (i+1) * 32;
                #pragma unroll
                for (int it = 0; it < 2; it++)
                    pw[it] = *reinterpret_cast<const uint4*>(&w2t[(long)(col0 + bn[it])*HH + kn + bkh[it]*8]);
            }

            const uint32_t aCur = aBase + aLanePart + (uint32_t)i * 64u;  // 32 k * 2B
            const uint32_t bCur = bBase0 + (uint32_t)cur * BSTG + bLanePart;

            #pragma unroll
            for (int ks = 0; ks < 32; ks += 16) {
                unsigned afr[2][4];
                #pragma unroll
                for (int ii = 0; ii < 2; ii++) {
                    LDSM4(afr[ii][0], afr[ii][1], afr[ii][2], afr[ii][3],
                          aCur + (uint32_t)ii*(16u*AK_PAD*2u) + (uint32_t)ks*2u);
                }
                unsigned bfr[4][2];
                #pragma unroll
                for (int kh = 0; kh < 2; kh++) {
                    unsigned t0, t1, t2, t3;
                    LDSM4(t0, t1, t2, t3,
                          bCur + (uint32_t)ks*2u + (uint32_t)kh*16u);
                    bfr[0][kh] = t0;
                    bfr[1][kh] = t1;
                    bfr[2][kh] = t2;
                    bfr[3][kh] = t3;
                }
                #pragma unroll
                for (int j = 0; j < 4; j++) {
                    #pragma unroll
                    for (int ii = 0; ii < 2; ii++)
                        asm volatile(
                            "mma.sync.aligned.m16n8k16.row.col.f32.bf16.bf16.f32 "
                            "{%0,%1,%2,%3}, {%4,%5,%6,%7}, {%8,%9}, {%0,%1,%2,%3};"
                            : "+f"(acc[ii][j][0]), "+f"(acc[ii][j][1]),
                              "+f"(acc[ii][j][2]), "+f"(acc[ii][j][3])
                            : "r"(afr[ii][0]), "r"(afr[ii][1]), "r"(afr[ii][2]), "r"(afr[ii][3]),
                              "r"(bfr[j][0]), "r"(bfr[j][1]));
                }
            }
            if (i < 7) {
                int nxt = cur ^ 1;
                #pragma unroll
                for (int it = 0; it < 2; it++)
                    *reinterpret_cast<uint4*>(&Bsn[nxt*(128*40) + bn[it]*40 + bkh[it]*8]) = pw[it];
            }
            __syncthreads();
        }

        // epilogue for this half
        #pragma unroll
        for (int i = 0; i < 2; i++) {
            int r_lo = row0 + mrow0 + i*16 + g;
            #pragma unroll
            for (int j = 0; j < 4; j++) {
                int c = col0 + ncol0 + j*8 + t4*2;
                float bb0 = b2[c], bb1 = b2[c+1];
                h2[(long)r_lo*HH + c    ]     = elu_ff(acc[i][j][0] + bb0);
                h2[(long)r_lo*HH + c + 1]     = elu_ff(acc[i][j][1] + bb1);
                h2[(long)(r_lo+8)*HH + c    ] = elu_ff(acc[i][j][2] + bb0);
                h2[(long)(r_lo+8)*HH + c + 1] = elu_ff(acc[i][j][3] + bb1);
            }
        }
        __syncthreads();
    }
}

// ---------------- combined per-node gather sums ----------------
__global__ void scatter_kernel(const float* __restrict__ h2,
                               const int* __restrict__ list_rec, const int* __restrict__ cnt_rec,
                               const int* __restrict__ list_send, const int* __restrict__ cnt_send,
                               float* __restrict__ inc_raw, float* __restrict__ sq_part,
                               float* __restrict__ out_raw) {
    int id = blockIdx.x;
    bool isOut = id >= ROWS_N;
    int bn = id & (ROWS_N-1);
    int b = bn >> 6, n = bn & 63;
    int h = threadIdx.x;
    if (!isOut) {
        int cnt = cnt_rec[n];
        float acc = 0.f, accsq = 0.f;
        for (int k = 0; k < cnt; k++) {
            int e = list_rec[n*EE + k];
            float v = h2[(long)(b*EE + e)*HH + h];
            acc += v; accsq += v*v;
        }
        inc_raw[bn*HH + h] = acc;
        sq_part[bn*HH + h] = accsq;
    } else {
        int cnt = cnt_send[n];
        float acc = 0.f;
        for (int k = 0; k < cnt; k++) {
            int e = list_send[n*EE + k];
            acc += h2[(long)(b*EE + e)*HH + h];
        }
        out_raw[bn*HH + h] = acc;
    }
}

// ---------------- BN stats -> affine (a,c) ----------------
template<bool SRC_SQ>
__global__ void stats_kernel(const float* __restrict__ sum_part, const float* __restrict__ sq_part,
                             const float* __restrict__ gamma, const float* __restrict__ beta,
                             float* __restrict__ a, float* __restrict__ c,
                             int nrows, float count) {
    int h = blockIdx.x;
    float s = 0.f, sq = 0.f;
    for (int r = threadIdx.x; r < nrows; r += 256) {
        float v = sum_part[r*HH + h];
        s += v;
        if (SRC_SQ) sq += v*v; else sq += sq_part[r*HH + h];
    }
    __shared__ float ss[256], ssq[256];
    ss[threadIdx.x] = s; ssq[threadIdx.x] = sq;
    __syncthreads();
    for (int st = 128; st > 0; st >>= 1) {
        if (threadIdx.x < st) { ss[threadIdx.x] += ss[threadIdx.x+st]; ssq[threadIdx.x] += ssq[threadIdx.x+st]; }
        __syncthreads();
    }
    if (threadIdx.x == 0) {
        float mu = ss[0] / count;
        float var = ssq[0] / count - mu*mu;
        float av = gamma[h] * rsqrtf(var + 1e-5f);
        a[h] = av;
        c[h] = beta[h] - mu * av;
    }
}

// ---------------- launcher ----------------
extern "C" void kernel_launch(void* const* d_in, const int* in_sizes, int n_in,
                              void* d_out, int out_size) {
    const float* centers  = (const float*)d_in[0];
    const float* rel_rec  = (const float*)d_in[1];
    const float* rel_send = (const float*)d_in[2];
    const float* W_traj   = (const float*)d_in[3];
    const float* b_traj   = (const float*)d_in[4];
    const float* n2e_W1   = (const float*)d_in[5];
    const float* n2e_b1   = (const float*)d_in[6];
    const float* n2e_W2   = (const float*)d_in[7];
    const float* n2e_b2   = (const float*)d_in[8];
    const float* n2e_g    = (const float*)d_in[9];
    const float* n2e_be   = (const float*)d_in[10];
    const float* e2n_W1   = (const float*)d_in[11];
    const float* e2n_b1   = (const float*)d_in[12];
    const float* e2n_W2   = (const float*)d_in[13];
    const float* e2n_b2   = (const float*)d_in[14];
    const float* e2n_g    = (const float*)d_in[15];
    const float* e2n_be   = (const float*)d_in[16];
    const float* W_fuse   = (const float*)d_in[17];
    const float* b_fuse   = (const float*)d_in[18];
    const float* W_pred   = (const float*)d_in[19];
    const float* b_pred   = (const float*)d_in[20];
    float* out = (float*)d_out;

    float *p_x, *p_xTop, *p_xBot, *p_h2, *p_inc, *p_incsq, *p_outg;
    float *p_nh1, *p_mraw, *p_fused;
    float *p_ae, *p_ce, *p_an, *p_cn, *p_idr, *p_ids;
    int *p_recv, *p_send, *p_lr, *p_ls, *p_cr, *p_cs;
    __nv_bfloat16 *p_w2t;
    cudaGetSymbolAddress((void**)&p_x, d_x);
    cudaGetSymbolAddress((void**)&p_xTop, d_xTop);
    cudaGetSymbolAddress((void**)&p_xBot, d_xBot);
    cudaGetSymbolAddress((void**)&p_h2, d_h2);
    cudaGetSymbolAddress((void**)&p_inc, d_inc);
    cudaGetSymbolAddress((void**)&p_incsq, d_incsq);
    cudaGetSymbolAddress((void**)&p_outg, d_outg);
    cudaGetSymbolAddress((void**)&p_nh1, d_nh1);
    cudaGetSymbolAddress((void**)&p_mraw, d_mraw);
    cudaGetSymbolAddress((void**)&p_fused, d_fused);
    cudaGetSymbolAddress((void**)&p_ae, d_ae);
    cudaGetSymbolAddress((void**)&p_ce, d_ce);
    cudaGetSymbolAddress((void**)&p_an, d_an);
    cudaGetSymbolAddress((void**)&p_cn, d_cn);
    cudaGetSymbolAddress((void**)&p_idr, d_invdegrec);
    cudaGetSymbolAddress((void**)&p_ids, d_invdegsend);
    cudaGetSymbolAddress((void**)&p_recv, d_recv);
    cudaGetSymbolAddress((void**)&p_send, d_send);
    cudaGetSymbolAddress((void**)&p_lr, d_listrec);
    cudaGetSymbolAddress((void**)&p_ls, d_listsend);
    cudaGetSymbolAddress((void**)&p_cr, d_cntrec);
    cudaGetSymbolAddress((void**)&p_cs, d_cntsend);
    cudaGetSymbolAddress((void**)&p_w2t, d_w2t);

    cudaFuncSetAttribute(edge_gemm2_bf16, cudaFuncAttributeMaxDynamicSharedMemorySize, EDGE_SMEM);

    // 1. fused prep: derive + traj + W2^T
    prep_kernel<<<16 + ROWS_N + HH, HH>>>(rel_rec, rel_send, p_recv, p_send,
                                          centers, W_traj, b_traj, n2e_W2, p_w2t, p_x);

    // 2. per-node edge lists
    build_lists_kernel<<<128, 64>>>(p_recv, p_send, p_lr, p_ls, p_cr, p_cs, p_idr, p_ids);

    // 3. xTop/xBot (dual-output, double-buffered tf32)
    mma_gemm_v2<0,false,false><<<dim3(HH/64, ROWS_N/64, 2), 256>>>(
        p_x, nullptr, nullptr, nullptr, nullptr, nullptr,
        n2e_W1, n2e_W1 + HH*HH, nullptr, p_xTop, p_xBot, ROWS_N, HH, HH);

    // 4. fused edge MLP v4 (64-row CTAs, 3/SM)  <-- profiled launch
    edge_gemm2_bf16<<<ROWS_E/A_ROWS, 256, EDGE_SMEM>>>(p_xTop, p_xBot, n2e_b1,
                                                       p_w2t, n2e_b2,
                                                       p_recv, p_send, p_h2);

    // 5. scatter sums + edge BN stats
    scatter_kernel<<<2*ROWS_N, HH>>>(p_h2, p_lr, p_cr, p_ls, p_cs, p_inc, p_incsq, p_outg);
    stats_kernel<false><<<HH, 256>>>(p_inc, p_incsq, n2e_g, n2e_be, p_ae, p_ce, ROWS_N, (float)ROWS_E);

    // 6. node MLP
    mma_gemm_v2<1,true,false><<<dim3(HH/64, ROWS_N/64, 1), 256>>>(
        p_inc, p_outg, p_ae, p_ce, p_idr, p_ids,
        e2n_W1, e2n_W1, e2n_b1, p_nh1, p_nh1, ROWS_N, HH, 2*HH);
    mma_gemm_v2<0,true,false><<<dim3(HH/64, ROWS_N/64, 1), 256>>>(
        p_nh1, nullptr, nullptr, nullptr, nullptr, nullptr,
        e2n_W2, e2n_W2, e2n_b2, p_mraw, p_mraw, ROWS_N, HH, HH);
    stats_kernel<true><<<HH, 256>>>(p_mraw, nullptr, e2n_g, e2n_be, p_an, p_cn, ROWS_N, (float)ROWS_N);

    // 7. fuse + predict (+ fused cumsum epilogue)
    mma_gemm_v2<2,false,false><<<dim3(HH/64, ROWS_N/64, 1), 256>>>(
        p_x, p_mraw, p_an, p_cn, nullptr, nullptr,
        W_fuse, W_fuse, b_fuse, p_fused, p_fused, ROWS_N, HH, 2*HH);
    pred_pos_kernel<<<dim3(1, ROWS_N/64), 256>>>(p_fused, W_pred, b_pred, centers, out);
}

// round 11
// speedup vs baseline: 3.4523x; 1.0114x over previous
#include <cuda_runtime.h>
#include <cuda_bf16.h>
#include <math.h>
#include <stdint.h>

#define BB   16
#define NN   64
#define PREV 6
#define PRED 30
#define HH   256
#define EE   (NN*(NN-1))      // 4032
#define ROWS_E (BB*EE)        // 64512
#define ROWS_N (BB*NN)        // 1024

// ---------------- static scratch ----------------
__device__ float d_x[ROWS_N*HH];
__device__ float d_xTop[ROWS_N*HH];
__device__ float d_xBot[ROWS_N*HH];
__device__ float d_h2[ROWS_E*HH];
__device__ float d_inc[ROWS_N*HH];
__device__ float d_incsq[ROWS_N*HH];
__device__ float d_outg[ROWS_N*HH];
__device__ float d_nh1[ROWS_N*HH];
__device__ float d_mraw[ROWS_N*HH];
__device__ float d_fused[ROWS_N*HH];
__device__ float d_ae[HH], d_ce[HH], d_an[HH], d_cn[HH];
__device__ int   d_recv[EE], d_send[EE];
__device__ int   d_listrec[NN*EE], d_listsend[NN*EE];
__device__ int   d_cntrec[NN], d_cntsend[NN];
__device__ float d_invdegrec[NN], d_invdegsend[NN];
__device__ __nv_bfloat16 d_w2t[HH*HH];   // W2^T in bf16: [n][k]

__device__ __forceinline__ float elu_f(float x)  { return x > 0.f ? x : (expf(x) - 1.f); }
__device__ __forceinline__ float elu_ff(float x) { return x > 0.f ? x : (__expf(x) - 1.f); }

__device__ __forceinline__ unsigned f2tf32(float x) {
    unsigned r;
    asm("cvt.rna.tf32.f32 %0, %1;" : "=r"(r) : "f"(x));
    return r;
}
__device__ __forceinline__ unsigned packbf2(float lo, float hi) {
    __nv_bfloat162 v = __floats2bfloat162_rn(lo, hi);
    return *reinterpret_cast<unsigned*>(&v);
}
__device__ __forceinline__ uint32_t smem_u32(const void* p) {
    uint32_t a;
    asm("{ .reg .u64 t; cvta.to.shared.u64 t, %1; cvt.u32.u64 %0, t; }" : "=r"(a) : "l"(p));
    return a;
}

#define LDSM4(r0,r1,r2,r3,addr) \
    asm volatile("ldmatrix.sync.aligned.m8n8.x4.shared.b16 {%0,%1,%2,%3}, [%4];" \
        : "=r"(r0), "=r"(r1), "=r"(r2), "=r"(r3) : "r"(addr))

#define CP_ASYNC16(dst, src) \
    asm volatile("cp.async.ca.shared.global [%0], [%1], 16;" :: "r"(dst), "l"(src) : "memory")
#define CP_COMMIT() asm volatile("cp.async.commit_group;" ::: "memory")
#define CP_WAIT(n)  asm volatile("cp.async.wait_group %0;" :: "n"(n) : "memory")

// ---------------- fused prep: derive edges + traj embed + W2^T ----------------
__global__ void prep_kernel(const float* __restrict__ rel_rec,
                            const float* __restrict__ rel_send,
                            int* __restrict__ recv_idx, int* __restrict__ send_idx,
                            const float* __restrict__ centers,
                            const float* __restrict__ W, const float* __restrict__ bias,
                            const float* __restrict__ W2, __nv_bfloat16* __restrict__ w2t,
                            float* __restrict__ x) {
    if (blockIdx.x < 16) {
        int e = blockIdx.x * 256 + threadIdx.x;
        if (e >= EE) return;
        int r = 0, s = 0; float br = -1.f, bs = -1.f;
        for (int n = 0; n < NN; n++) {
            float vr = rel_rec[e*NN + n];
            float vs = rel_send[e*NN + n];
            if (vr > br) { br = vr; r = n; }
            if (vs > bs) { bs = vs; s = n; }
        }
        recv_idx[e] = r; send_idx[e] = s;
        return;
    }
    if (blockIdx.x >= 16 + ROWS_N) {
        int n = blockIdx.x - 16 - ROWS_N;
        int k = threadIdx.x;
        w2t[n*HH + k] = __float2bfloat16(W2[k*HH + n]);
        return;
    }
    int row = blockIdx.x - 16;
    int h = threadIdx.x;
    __shared__ float rp[PREV*2];
    if (h < PREV*2) {
        int p = h >> 1, c = h & 1;
        float v = 0.f;
        if (p > 0) v = centers[row*PREV*2 + p*2 + c] - centers[row*PREV*2 + (p-1)*2 + c];
        rp[h] = v;
    }
    __syncthreads();
    float acc = bias[h];
    #pragma unroll
    for (int k = 0; k < PREV*2; k++) acc += rp[k] * W[k*HH + h];
    x[row*HH + h] = acc;
}

// ---------------- parallel deterministic list build ----------------
__global__ void build_lists_kernel(const int* __restrict__ recv_idx,
                                   const int* __restrict__ send_idx,
                                   int* __restrict__ list_rec, int* __restrict__ list_send,
                                   int* __restrict__ cnt_rec, int* __restrict__ cnt_send,
                                   float* __restrict__ invdeg_rec, float* __restrict__ invdeg_send) {
    const bool isSend = blockIdx.x >= NN;
    const int n = blockIdx.x & (NN-1);
    const int* __restrict__ idx = isSend ? send_idx : recv_idx;
    int* __restrict__ list = (isSend ? list_send : list_rec) + n*EE;
    const int t = threadIdx.x;            // 64 threads
    const int CH = EE / 64;               // 63
    const int base = t * CH;
    int c = 0;
    for (int i = 0; i < CH; i++) c += (idx[base+i] == n) ? 1 : 0;
    __shared__ int pre[64];
    pre[t] = c;
    __syncthreads();
    for (int off = 1; off < 64; off <<= 1) {
        int v = (t >= off) ? pre[t-off] : 0;
        __syncthreads();
        pre[t] += v;
        __syncthreads();
    }
    int offset = pre[t] - c;
    for (int i = 0; i < CH; i++) {
        int e = base + i;
        if (idx[e] == n) list[offset++] = e;
    }
    if (t == 63) {
        int tot = pre[63];
        float iv = tot ? 1.f/(float)tot : 1.f;
        if (isSend) { cnt_send[n] = tot; invdeg_send[n] = iv; }
        else        { cnt_rec[n]  = tot; invdeg_rec[n]  = iv; }
    }
}

// =======================================================================
// Generic double-buffered tf32 GEMM (unchanged)
// =======================================================================
template<int AMODE, bool ELU, bool GUARD_N>
__global__ __launch_bounds__(256)
void mma_gemm_v2(const float* __restrict__ A0, const float* __restrict__ A1,
                 const float* __restrict__ aVec, const float* __restrict__ cVec,
                 const float* __restrict__ invDegR, const float* __restrict__ invDegS,
                 const float* __restrict__ B0, const float* __restrict__ B1,
                 const float* __restrict__ bias,
                 float* __restrict__ C0, float* __restrict__ C1,
                 int M, int N, int K) {
    const float* __restrict__ Bm = (blockIdx.z == 0) ? B0 : B1;
    float* __restrict__ C = (blockIdx.z == 0) ? C0 : C1;

    __shared__ unsigned Asm[2][64][36];
    __shared__ unsigned Bsm[2][32][72];
    const int tid  = threadIdx.x;
    const int lane = tid & 31;
    const int warp = tid >> 5;
    const int warpM = warp & 1;
    const int warpN = warp >> 1;
    const int g  = lane >> 2;
    const int t4 = lane & 3;
    const int row0 = blockIdx.y * 64;
    const int col0 = blockIdx.x * 64;

    int arow[2], akq[2], bkk[2], bq[2];
    #pragma unroll
    for (int it = 0; it < 2; it++) {
        int ta = it*256 + tid;
        akq[it] = ta & 7;  arow[it] = ta >> 3;
        bkk[it] = ta >> 4; bq[it]  = ta & 15;
    }

    float4 pa[2], pb[2];

    auto prefetch = [&](int k0) {
        #pragma unroll
        for (int it = 0; it < 2; it++) {
            int gk = k0 + akq[it]*4;
            if (AMODE == 0) {
                pa[it] = *reinterpret_cast<const float4*>(&A0[(long)(row0+arow[it])*K + gk]);
            } else {
                const float* src = (gk >= HH) ? A1 : A0;
                pa[it] = *reinterpret_cast<const float4*>(&src[(long)(row0+arow[it])*HH + (gk & (HH-1))]);
            }
            int c0 = col0 + bq[it]*4;
            if (!GUARD_N) {
                pb[it] = *reinterpret_cast<const float4*>(&Bm[(long)(k0+bkk[it])*N + c0]);
            } else {
                float4 v;
                v.x = (c0+0 < N) ? Bm[(long)(k0+bkk[it])*N + c0+0] : 0.f;
                v.y = (c0+1 < N) ? Bm[(long)(k0+bkk[it])*N + c0+1] : 0.f;
                v.z = (c0+2 < N) ? Bm[(long)(k0+bkk[it])*N + c0+2] : 0.f;
                v.w = (c0+3 < N) ? Bm[(long)(k0+bkk[it])*N + c0+3] : 0.f;
                pb[it] = v;
            }
        }
    };

    auto store = [&](int s, int k0) {
        #pragma unroll
        for (int it = 0; it < 2; it++) {
            int gk = k0 + akq[it]*4;
            float4 v = pa[it];
            if (AMODE == 1) {
                int col = gk & (HH-1);
                float invd = ((gk >= HH) ? invDegS : invDegR)[(row0+arow[it]) & (NN-1)];
                float4 a4 = *reinterpret_cast<const float4*>(&aVec[col]);
                float4 c4 = *reinterpret_cast<const float4*>(&cVec[col]);
                v.x = a4.x*(v.x*invd)+c4.x; v.y = a4.y*(v.y*invd)+c4.y;
                v.z = a4.z*(v.z*invd)+c4.z; v.w = a4.w*(v.w*invd)+c4.w;
            } else if (AMODE == 2) {
                if (gk >= HH) {
                    int col = gk & (HH-1);
                    float4 a4 = *reinterpret_cast<const float4*>(&aVec[col]);
                    float4 c4 = *reinterpret_cast<const float4*>(&cVec[col]);
                    v.x = a4.x*v.x+c4.x; v.y = a4.y*v.y+c4.y;
                    v.z = a4.z*v.z+c4.z; v.w = a4.w*v.w+c4.w;
                }
            }
            Asm[s][arow[it]][akq[it]*4+0] = f2tf32(v.x);
            Asm[s][arow[it]][akq[it]*4+1] = f2tf32(v.y);
            Asm[s][arow[it]][akq[it]*4+2] = f2tf32(v.z);
            Asm[s][arow[it]][akq[it]*4+3] = f2tf32(v.w);

            float4 w = pb[it];
            Bsm[s][bkk[it]][bq[it]*4+0] = f2tf32(w.x);
            Bsm[s][bkk[it]][bq[it]*4+1] = f2tf32(w.y);
            Bsm[s][bkk[it]][bq[it]*4+2] = f2tf32(w.z);
            Bsm[s][bkk[it]][bq[it]*4+3] = f2tf32(w.w);
        }
    };

    float acc[2][2][4] = {};
    const int nIter = K >> 5;

    prefetch(0);
    store(0, 0);
    __syncthreads();

    for (int i = 0; i < nIter; i++) {
        int cur = i & 1;
        if (i + 1 < nIter) prefetch((i+1) * 32);

        #pragma unroll
        for (int ks = 0; ks < 32; ks += 8) {
            unsigned afr[2][4];
            #pragma unroll
            for (int ii = 0; ii < 2; ii++) {
                int r = warpM*32 + ii*16;
                afr[ii][0] = Asm[cur][r + g    ][ks + t4    ];
                afr[ii][1] = Asm[cur][r + g + 8][ks + t4    ];
                afr[ii][2] = Asm[cur][r + g    ][ks + t4 + 4];
                afr[ii][3] = Asm[cur][r + g + 8][ks + t4 + 4];
            }
            unsigned bfr[2][2];
            #pragma unroll
            for (int j = 0; j < 2; j++) {
                int nn = warpN*16 + j*8 + g;
                bfr[j][0] = Bsm[cur][ks + t4    ][nn];
                bfr[j][1] = Bsm[cur][ks + t4 + 4][nn];
            }
            #pragma unroll
            for (int ii = 0; ii < 2; ii++)
                #pragma unroll
                for (int j = 0; j < 2; j++)
                    asm volatile(
                        "mma.sync.aligned.m16n8k8.row.col.f32.tf32.tf32.f32 "
                        "{%0,%1,%2,%3}, {%4,%5,%6,%7}, {%8,%9}, {%0,%1,%2,%3};"
                        : "+f"(acc[ii][j][0]), "+f"(acc[ii][j][1]),
                          "+f"(acc[ii][j][2]), "+f"(acc[ii][j][3])
                        : "r"(afr[ii][0]), "r"(afr[ii][1]), "r"(afr[ii][2]), "r"(afr[ii][3]),
                          "r"(bfr[j][0]), "r"(bfr[j][1]));
        }
        if (i + 1 < nIter) store(cur ^ 1, (i+1) * 32);
        __syncthreads();
    }

    #pragma unroll
    for (int i = 0; i < 2; i++) {
        int r = row0 + warpM*32 + i*16 + g;
        #pragma unroll
        for (int j = 0; j < 2; j++) {
            int c = col0 + warpN*16 + j*8 + t4*2;
            #pragma unroll
            for (int h = 0; h < 2; h++) {
                int cc = c + h;
                if (GUARD_N && cc >= N) continue;
                float bb = bias ? bias[cc] : 0.f;
                float v0 = acc[i][j][h]   + bb;
                float v1 = acc[i][j][2+h] + bb;
                if (ELU) { v0 = elu_f(v0); v1 = elu_f(v1); }
                C[(long)r*N + cc]     = v0;
                C[(long)(r+8)*N + cc] = v1;
            }
        }
    }
}

// =======================================================================
// Pred GEMM + cumsum epilogue (unchanged)
// =======================================================================
__global__ __launch_bounds__(256)
void pred_pos_kernel(const float* __restrict__ A0, const float* __restrict__ Bm,
                     const float* __restrict__ bias, const float* __restrict__ centers,
                     float* __restrict__ out) {
    const int N = PRED*2;
    const int K = HH;
    __shared__ unsigned Asm[64][36];
    __shared__ unsigned Bsm[32][72];
    __shared__ float Cs[64][64];
    const int tid  = threadIdx.x;
    const int lane = tid & 31;
    const int warp = tid >> 5;
    const int warpM = warp & 1;
    const int warpN = warp >> 1;
    const int g  = lane >> 2;
    const int t4 = lane & 3;
    const int row0 = blockIdx.y * 64;

    int arow[2], akq[2], bkk[2], bq[2];
    #pragma unroll
    for (int it = 0; it < 2; it++) {
        int ta = it*256 + tid;
        akq[it] = ta & 7;  arow[it] = ta >> 3;
        bkk[it] = ta >> 4; bq[it]  = ta & 15;
    }
    float4 pa[2], pb[2];
    #pragma unroll
    for (int it = 0; it < 2; it++) {
        pa[it] = *reinterpret_cast<const float4*>(&A0[(long)(row0+arow[it])*K + akq[it]*4]);
        int c0 = bq[it]*4;
        float4 v;
        v.x = (c0+0 < N) ? Bm[(long)bkk[it]*N + c0+0] : 0.f;
        v.y = (c0+1 < N) ? Bm[(long)bkk[it]*N + c0+1] : 0.f;
        v.z = (c0+2 < N) ? Bm[(long)bkk[it]*N + c0+2] : 0.f;
        v.w = (c0+3 < N) ? Bm[(long)bkk[it]*N + c0+3] : 0.f;
        pb[it] = v;
    }

    float acc[2][2][4] = {};
    for (int k0 = 0; k0 < K; k0 += 32) {
        #pragma unroll
        for (int it = 0; it < 2; it++) {
            float4 v = pa[it];
            Asm[arow[it]][akq[it]*4+0] = f2tf32(v.x);
            Asm[arow[it]][akq[it]*4+1] = f2tf32(v.y);
            Asm[arow[it]][akq[it]*4+2] = f2tf32(v.z);
            Asm[arow[it]][akq[it]*4+3] = f2tf32(v.w);
            float4 w = pb[it];
            Bsm[bkk[it]][bq[it]*4+0] = f2tf32(w.x);
            Bsm[bkk[it]][bq[it]*4+1] = f2tf32(w.y);
            Bsm[bkk[it]][bq[it]*4+2] = f2tf32(w.z);
            Bsm[bkk[it]][bq[it]*4+3] = f2tf32(w.w);
        }
        if (k0 + 32 < K) {
            int kn = k0 + 32;
            #pragma unroll
            for (int it = 0; it < 2; it++) {
                pa[it] = *reinterpret_cast<const float4*>(&A0[(long)(row0+arow[it])*K + kn + akq[it]*4]);
                int c0 = bq[it]*4;
                float4 v;
                v.x = (c0+0 < N) ? Bm[(long)(kn+bkk[it])*N + c0+0] : 0.f;
                v.y = (c0+1 < N) ? Bm[(long)(kn+bkk[it])*N + c0+1] : 0.f;
                v.z = (c0+2 < N) ? Bm[(long)(kn+bkk[it])*N + c0+2] : 0.f;
                v.w = (c0+3 < N) ? Bm[(long)(kn+bkk[it])*N + c0+3] : 0.f;
                pb[it] = v;
            }
        }
        __syncthreads();
        #pragma unroll
        for (int ks = 0; ks < 32; ks += 8) {
            unsigned afr[2][4];
            #pragma unroll
            for (int i = 0; i < 2; i++) {
                int r = warpM*32 + i*16;
                afr[i][0] = Asm[r + g    ][ks + t4    ];
                afr[i][1] = Asm[r + g + 8][ks + t4    ];
                afr[i][2] = Asm[r + g    ][ks + t4 + 4];
                afr[i][3] = Asm[r + g + 8][ks + t4 + 4];
            }
            unsigned bfr[2][2];
            #pragma unroll
            for (int j = 0; j < 2; j++) {
                int nn = warpN*16 + j*8 + g;
                bfr[j][0] = Bsm[ks + t4    ][nn];
                bfr[j][1] = Bsm[ks + t4 + 4][nn];
            }
            #pragma unroll
            for (int i = 0; i < 2; i++)
                #pragma unroll
                for (int j = 0; j < 2; j++)
                    asm volatile(
                        "mma.sync.aligned.m16n8k8.row.col.f32.tf32.tf32.f32 "
                        "{%0,%1,%2,%3}, {%4,%5,%6,%7}, {%8,%9}, {%0,%1,%2,%3};"
                        : "+f"(acc[i][j][0]), "+f"(acc[i][j][1]),
                          "+f"(acc[i][j][2]), "+f"(acc[i][j][3])
                        : "r"(afr[i][0]), "r"(afr[i][1]), "r"(afr[i][2]), "r"(afr[i][3]),
                          "r"(bfr[j][0]), "r"(bfr[j][1]));
        }
        __syncthreads();
    }

    #pragma unroll
    for (int i = 0; i < 2; i++) {
        int r = warpM*32 + i*16 + g;
        #pragma unroll
        for (int j = 0; j < 2; j++) {
            int c = warpN*16 + j*8 + t4*2;
            #pragma unroll
            for (int h = 0; h < 2; h++) {
                int cc = c + h;
                float bb = (cc < N) ? bias[cc] : 0.f;
                Cs[r][cc]   = acc[i][j][h]   + bb;
                Cs[r+8][cc] = acc[i][j][2+h] + bb;
            }
        }
    }
    __syncthreads();

    if (tid < 128) {
        int lrow = tid >> 1, dimc = tid & 1;
        int grow = row0 + lrow;
        float cur = centers[grow*PREV*2 + (PREV-1)*2 + dimc];
        float accum = 0.f;
        #pragma unroll
        for (int p = 0; p < PRED; p++) {
            float v = Cs[lrow][2*p + dimc];
            out[(long)grow*N + 2*p + dimc] = v;
            accum += v;
            out[(long)(ROWS_N)*N + (long)grow*N + 2*p + dimc] = accum + cur;
        }
    }
}

// =======================================================================
// Fused edge GEMM v5: 64-row CTAs, 3/SM, cp.async B staging.
// =======================================================================
#define A_ROWS   64
#define AK_PAD   264
#define A_BYTES  (A_ROWS*AK_PAD*2)        // 33792
#define B_BYTES  (2*128*40*2)             // 20480
#define EDGE_SMEM (A_BYTES + B_BYTES + 1024)

__global__ __launch_bounds__(256, 3)
void edge_gemm2_bf16(const float* __restrict__ xTop, const float* __restrict__ xBot,
                     const float* __restrict__ b1,
                     const __nv_bfloat16* __restrict__ w2t, const float* __restrict__ b2,
                     const int* __restrict__ recv_idx, const int* __restrict__ send_idx,
                     float* __restrict__ h2) {
    extern __shared__ char smraw[];
    __nv_bfloat16* Afull = reinterpret_cast<__nv_bfloat16*>(smraw);           // [64][264]
    __nv_bfloat16* Bsn   = reinterpret_cast<__nv_bfloat16*>(smraw + A_BYTES); // [2][128][40]
    int* topBase = reinterpret_cast<int*>(smraw + A_BYTES + B_BYTES);
    int* botBase = topBase + A_ROWS;

    const int tid  = threadIdx.x;
    const int lane = tid & 31;
    const int warp = tid >> 5;
    const int warpM = warp & 1;
    const int warpN = warp >> 1;
    const int row0 = blockIdx.x * A_ROWS;

    if (tid < A_ROWS) {
        int grow = row0 + tid;
        int b = grow / EE;
        int e = grow - b * EE;
        topBase[tid] = (b*NN + recv_idx[e]) * HH;
        botBase[tid] = (b*NN + send_idx[e]) * HH;
    }
    __syncthreads();

    // ---- Phase 1: build A tile (64 rows x 256 k), coalesced ----
    {
        const int kq = tid & 63;
        const int rb = tid >> 6;
        const int kb = kq * 4;
        float4 bb = *reinterpret_cast<const float4*>(&b1[kb]);
        #pragma unroll
        for (int it = 0; it < 16; it++) {
            int row = it*4 + rb;
            float4 a  = *reinterpret_cast<const float4*>(&xTop[topBase[row] + kb]);
            float4 bv = *reinterpret_cast<const float4*>(&xBot[botBase[row] + kb]);
            unsigned p0 = packbf2(elu_ff(a.x + bv.x + bb.x), elu_ff(a.y + bv.y + bb.y));
            unsigned p1 = packbf2(elu_ff(a.z + bv.z + bb.z), elu_ff(a.w + bv.w + bb.w));
            *reinterpret_cast<uint2*>(&Afull[row*AK_PAD + kb]) = make_uint2(p0, p1);
        }
    }

    // B staging tasks (k-major lanes), via cp.async
    int bn[2], bkh[2];
    #pragma unroll
    for (int it = 0; it < 2; it++) {
        int task = it*256 + tid;
        bkh[it] = task & 3;
        bn[it]  = task >> 2;
    }

    const int lt  = lane >> 3;
    const int lrw = lane & 7;
    const int mrow0 = warpM * 32;
    const int ncol0 = warpN * 32;
    const uint32_t aBase = smem_u32(Afull);
    const uint32_t bBase0 = smem_u32(Bsn);
    const uint32_t BSTG = 128u * 40u * 2u;
    const uint32_t aLanePart = (uint32_t)(mrow0 + (lt & 1)*8 + lrw) * (AK_PAD*2u)
                             + (uint32_t)(lt >> 1) * 16u;
    const uint32_t bLanePart = (uint32_t)(ncol0 + lt*8 + lrw) * 80u;

    auto issueB = [&](int col0, int k0, int stage) {
        #pragma unroll
        for (int it = 0; it < 2; it++) {
            uint32_t dst = bBase0 + (uint32_t)stage * BSTG
                         + (uint32_t)(bn[it]*80 + bkh[it]*16);
            const void* src = &w2t[(long)(col0 + bn[it])*HH + k0 + bkh[it]*8];
            CP_ASYNC16(dst, src);
        }
    };

    __syncthreads();   // A tile ready

    const int g  = lane >> 2;
    const int t4 = lane & 3;

    #pragma unroll 1
    for (int half = 0; half < 2; half++) {
        const int col0 = half * 128;

        issueB(col0, 0, 0);
        CP_COMMIT();

        float acc[2][4][4] = {};

        #pragma unroll 1
        for (int i = 0; i < 8; i++) {
            int cur = i & 1;
            if (i < 7) {
                issueB(col0, (i+1)*32, cur ^ 1);
                CP_COMMIT();
                CP_WAIT(1);
            } else {
                CP_WAIT(0);
            }
            __syncthreads();   // stage i visible to all threads

            const uint32_t aCur = aBase + aLanePart + (uint32_t)i * 64u;
            const uint32_t bCur = bBase0 + (uint32_t)cur * BSTG + bLanePart;

            #pragma unroll
            for (int ks = 0; ks < 32; ks += 16) {
                unsigned afr[2][4];
                #pragma unroll
                for (int ii = 0; ii < 2; ii++) {
                    LDSM4(afr[ii][0], afr[ii][1], afr[ii][2], afr[ii][3],
                          aCur + (uint32_t)ii*(16u*AK_PAD*2u) + (uint32_t)ks*2u);
                }
                unsigned bfr[4][2];
                #pragma unroll
                for (int kh = 0; kh < 2; kh++) {
                    unsigned t0, t1, t2, t3;
                    LDSM4(t0, t1, t2, t3,
                          bCur + (uint32_t)ks*2u + (uint32_t)kh*16u);
                    bfr[0][kh] = t0;
                    bfr[1][kh] = t1;
                    bfr[2][kh] = t2;
                    bfr[3][kh] = t3;
                }
                #pragma unroll
                for (int j = 0; j < 4; j++) {
                    #pragma unroll
                    for (int ii = 0; ii < 2; ii++)
                        asm volatile(
                            "mma.sync.aligned.m16n8k16.row.col.f32.bf16.bf16.f32 "
                            "{%0,%1,%2,%3}, {%4,%5,%6,%7}, {%8,%9}, {%0,%1,%2,%3};"
                            : "+f"(acc[ii][j][0]), "+f"(acc[ii][j][1]),
                              "+f"(acc[ii][j][2]), "+f"(acc[ii][j][3])
                            : "r"(afr[ii][0]), "r"(afr[ii][1]), "r"(afr[ii][2]), "r"(afr[ii][3]),
                              "r"(bfr[j][0]), "r"(bfr[j][1]));
                }
            }
            __syncthreads();   // all reads of stage i done before buffer reuse
        }

        // epilogue for this half
        #pragma unroll
        for (int i = 0; i < 2; i++) {
            int r_lo = row0 + mrow0 + i*16 + g;
            #pragma unroll
            for (int j = 0; j < 4; j++) {
                int c = col0 + ncol0 + j*8 + t4*2;
                float bb0 = b2[c], bb1 = b2[c+1];
                h2[(long)r_lo*HH + c    ]     = elu_ff(acc[i][j][0] + bb0);
                h2[(long)r_lo*HH + c + 1]     = elu_ff(acc[i][j][1] + bb1);
                h2[(long)(r_lo+8)*HH + c    ] = elu_ff(acc[i][j][2] + bb0);
                h2[(long)(r_lo+8)*HH + c + 1] = elu_ff(acc[i][j][3] + bb1);
            }
        }
        __syncthreads();
    }
}

// ---------------- vectorized per-node gather sums (float4 lanes) ----------------
__global__ void scatter_kernel(const float* __restrict__ h2,
                               const int* __restrict__ list_rec, const int* __restrict__ cnt_rec,
                               const int* __restrict__ list_send, const int* __restrict__ cnt_send,
                               float* __restrict__ inc_raw, float* __restrict__ sq_part,
                               float* __restrict__ out_raw) {
    int id = blockIdx.x;
    bool isOut = id >= ROWS_N;
    int bn = id & (ROWS_N-1);
    int b = bn >> 6, n = bn & 63;
    const int tid = threadIdx.x;
    const int c4 = tid & 63;          // column group (4 floats)
    const int rs = tid >> 6;          // row-slice 0..3
    const int* __restrict__ list = (isOut ? list_send : list_rec) + n*EE;
    const int cnt = (isOut ? cnt_send : cnt_rec)[n];

    float4 acc = make_float4(0.f, 0.f, 0.f, 0.f);
    float4 asq = make_float4(0.f, 0.f, 0.f, 0.f);
    for (int k = rs; k < cnt; k += 4) {
        int e = list[k];
        float4 v = *reinterpret_cast<const float4*>(&h2[(long)(b*EE + e)*HH + c4*4]);
        acc.x += v.x; acc.y += v.y; acc.z += v.z; acc.w += v.w;
        if (!isOut) {
            asq.x += v.x*v.x; asq.y += v.y*v.y; asq.z += v.z*v.z; asq.w += v.w*v.w;
        }
    }
    __shared__ float4 sa[4][64];
    __shared__ float4 sq[4][64];
    sa[rs][c4] = acc;
    if (!isOut) sq[rs][c4] = asq;
    __syncthreads();
    if (rs == 0) {
        float4 t = sa[0][c4];
        #pragma unroll
        for (int r = 1; r < 4; r++) {
            float4 u = sa[r][c4];
            t.x += u.x; t.y += u.y; t.z += u.z; t.w += u.w;
        }
        if (!isOut) {
            float4 s = sq[0][c4];
            #pragma unroll
            for (int r = 1; r < 4; r++) {
                float4 u = sq[r][c4];
                s.x += u.x; s.y += u.y; s.z += u.z; s.w += u.w;
            }
            *reinterpret_cast<float4*>(&inc_raw[bn*HH + c4*4]) = t;
            *reinterpret_cast<float4*>(&sq_part[bn*HH + c4*4]) = s;
        } else {
            *reinterpret_cast<float4*>(&out_raw[bn*HH + c4*4]) = t;
        }
    }
}

// ---------------- BN stats -> affine (a,c) ----------------
template<bool SRC_SQ>
__global__ void stats_kernel(const float* __restrict__ sum_part, const float* __restrict__ sq_part,
                             const float* __restrict__ gamma, const float* __restrict__ beta,
                             float* __restrict__ a, float* __restrict__ c,
                             int nrows, float count) {
    int h = blockIdx.x;
    float s = 0.f, sq = 0.f;
    for (int r = threadIdx.x; r < nrows; r += 256) {
        float v = sum_part[r*HH + h];
        s += v;
        if (SRC_SQ) sq += v*v; else sq += sq_part[r*HH + h];
    }
    __shared__ float ss[256], ssq[256];
    ss[threadIdx.x] = s; ssq[threadIdx.x] = sq;
    __syncthreads();
    for (int st = 128; st > 0; st >>= 1) {
        if (threadIdx.x < st) { ss[threadIdx.x] += ss[threadIdx.x+st]; ssq[threadIdx.x] += ssq[threadIdx.x+st]; }
        __syncthreads();
    }
    if (threadIdx.x == 0) {
        float mu = ss[0] / count;
        float var = ssq[0] / count - mu*mu;
        float av = gamma[h] * rsqrtf(var + 1e-5f);
        a[h] = av;
        c[h] = beta[h] - mu * av;
    }
}

// ---------------- launcher ----------------
extern "C" void kernel_launch(void* const* d_in, const int* in_sizes, int n_in,
                              void* d_out, int out_size) {
    const float* centers  = (const float*)d_in[0];
    const float* rel_rec  = (const float*)d_in[1];
    const float* rel_send = (const float*)d_in[2];
    const float* W_traj   = (const float*)d_in[3];
    const float* b_traj   = (const float*)d_in[4];
    const float* n2e_W1   = (const float*)d_in[5];
    const float* n2e_b1   = (const float*)d_in[6];
    const float* n2e_W2   = (const float*)d_in[7];
    const float* n2e_b2   = (const float*)d_in[8];
    const float* n2e_g    = (const float*)d_in[9];
    const float* n2e_be   = (const float*)d_in[10];
    const float* e2n_W1   = (const float*)d_in[11];
    const float* e2n_b1   = (const float*)d_in[12];
    const float* e2n_W2   = (const float*)d_in[13];
    const float* e2n_b2   = (const float*)d_in[14];
    const float* e2n_g    = (const float*)d_in[15];
    const float* e2n_be   = (const float*)d_in[16];
    const float* W_fuse   = (const float*)d_in[17];
    const float* b_fuse   = (const float*)d_in[18];
    const float* W_pred   = (const float*)d_in[19];
    const float* b_pred   = (const float*)d_in[20];
    float* out = (float*)d_out;

    float *p_x, *p_xTop, *p_xBot, *p_h2, *p_inc, *p_incsq, *p_outg;
    float *p_nh1, *p_mraw, *p_fused;
    float *p_ae, *p_ce, *p_an, *p_cn, *p_idr, *p_ids;
    int *p_recv, *p_send, *p_lr, *p_ls, *p_cr, *p_cs;
    __nv_bfloat16 *p_w2t;
    cudaGetSymbolAddress((void**)&p_x, d_x);
    cudaGetSymbolAddress((void**)&p_xTop, d_xTop);
    cudaGetSymbolAddress((void**)&p_xBot, d_xBot);
    cudaGetSymbolAddress((void**)&p_h2, d_h2);
    cudaGetSymbolAddress((void**)&p_inc, d_inc);
    cudaGetSymbolAddress((void**)&p_incsq, d_incsq);
    cudaGetSymbolAddress((void**)&p_outg, d_outg);
    cudaGetSymbolAddress((void**)&p_nh1, d_nh1);
    cudaGetSymbolAddress((void**)&p_mraw, d_mraw);
    cudaGetSymbolAddress((void**)&p_fused, d_fused);
    cudaGetSymbolAddress((void**)&p_ae, d_ae);
    cudaGetSymbolAddress((void**)&p_ce, d_ce);
    cudaGetSymbolAddress((void**)&p_an, d_an);
    cudaGetSymbolAddress((void**)&p_cn, d_cn);
    cudaGetSymbolAddress((void**)&p_idr, d_invdegrec);
    cudaGetSymbolAddress((void**)&p_ids, d_invdegsend);
    cudaGetSymbolAddress((void**)&p_recv, d_recv);
    cudaGetSymbolAddress((void**)&p_send, d_send);
    cudaGetSymbolAddress((void**)&p_lr, d_listrec);
    cudaGetSymbolAddress((void**)&p_ls, d_listsend);
    cudaGetSymbolAddress((void**)&p_cr, d_cntrec);
    cudaGetSymbolAddress((void**)&p_cs, d_cntsend);
    cudaGetSymbolAddress((void**)&p_w2t, d_w2t);

    cudaFuncSetAttribute(edge_gemm2_bf16, cudaFuncAttributeMaxDynamicSharedMemorySize, EDGE_SMEM);

    // 1. fused prep: derive + traj + W2^T
    prep_kernel<<<16 + ROWS_N + HH, HH>>>(rel_rec, rel_send, p_recv, p_send,
                                          centers, W_traj, b_traj, n2e_W2, p_w2t, p_x);

    // 2. per-node edge lists
    build_lists_kernel<<<128, 64>>>(p_recv, p_send, p_lr, p_ls, p_cr, p_cs, p_idr, p_ids);

    // 3. xTop/xBot (dual-output, double-buffered tf32)
    mma_gemm_v2<0,false,false><<<dim3(HH/64, ROWS_N/64, 2), 256>>>(
        p_x, nullptr, nullptr, nullptr, nullptr, nullptr,
        n2e_W1, n2e_W1 + HH*HH, nullptr, p_xTop, p_xBot, ROWS_N, HH, HH);

    // 4. fused edge MLP v5 (cp.async B)  <-- profiled launch
    edge_gemm2_bf16<<<ROWS_E/A_ROWS, 256, EDGE_SMEM>>>(p_xTop, p_xBot, n2e_b1,
                                                       p_w2t, n2e_b2,
                                                       p_recv, p_send, p_h2);

    // 5. scatter sums (vectorized) + edge BN stats
    scatter_kernel<<<2*ROWS_N, 256>>>(p_h2, p_lr, p_cr, p_ls, p_cs, p_inc, p_incsq, p_outg);
    stats_kernel<false><<<HH, 256>>>(p_inc, p_incsq, n2e_g, n2e_be, p_ae, p_ce, ROWS_N, (float)ROWS_E);

    // 6. node MLP
    mma_gemm_v2<1,true,false><<<dim3(HH/64, ROWS_N/64, 1), 256>>>(
        p_inc, p_outg, p_ae, p_ce, p_idr, p_ids,
        e2n_W1, e2n_W1, e2n_b1, p_nh1, p_nh1, ROWS_N, HH, 2*HH);
    mma_gemm_v2<0,true,false><<<dim3(HH/64, ROWS_N/64, 1), 256>>>(
        p_nh1, nullptr, nullptr, nullptr, nullptr, nullptr,
        e2n_W2, e2n_W2, e2n_b2, p_mraw, p_mraw, ROWS_N, HH, HH);
    stats_kernel<true><<<HH, 256>>>(p_mraw, nullptr, e2n_g, e2n_be, p_an, p_cn, ROWS_N, (float)ROWS_N);

    // 7. fuse + predict (+ fused cumsum epilogue)
    mma_gemm_v2<2,false,false><<<dim3(HH/64, ROWS_N/64, 1), 256>>>(
        p_x, p_mraw, p_an, p_cn, nullptr, nullptr,
        W_fuse, W_fuse, b_fuse, p_fused, p_fused, ROWS_N, HH, 2*HH);
    pred_pos_kernel<<<dim3(1, ROWS_N/64), 256>>>(p_fused, W_pred, b_pred, centers, out);
}

// round 12
// speedup vs baseline: 3.8062x; 1.1025x over previous
#include <cuda_runtime.h>
#include <cuda_bf16.h>
#include <math.h>
#include <stdint.h>

#define BB   16
#define NN   64
#define PREV 6
#define PRED 30
#define HH   256
#define EE   (NN*(NN-1))      // 4032
#define ROWS_E (BB*EE)        // 64512
#define ROWS_N (BB*NN)        // 1024

// ---------------- static scratch ----------------
__device__ float d_x[ROWS_N*HH];
__device__ float d_xTop[ROWS_N*HH];
__device__ float d_xBot[ROWS_N*HH];
__device__ __nv_bfloat16 d_h2[ROWS_E*HH];     // h2 now bf16
__device__ float d_inc[ROWS_N*HH];
__device__ float d_incsq[ROWS_N*HH];
__device__ float d_outg[ROWS_N*HH];
__device__ float d_nh1[ROWS_N*HH];
__device__ float d_mraw[ROWS_N*HH];
__device__ float d_fused[ROWS_N*HH];
__device__ float d_ae[HH], d_ce[HH], d_an[HH], d_cn[HH];
__device__ int   d_recv[EE], d_send[EE];
__device__ int   d_listrec[NN*EE], d_listsend[NN*EE];
__device__ int   d_cntrec[NN], d_cntsend[NN];
__device__ float d_invdegrec[NN], d_invdegsend[NN];
__device__ __nv_bfloat16 d_w2t[HH*HH];   // W2^T in bf16: [n][k]

__device__ __forceinline__ float elu_f(float x)  { return x > 0.f ? x : (expf(x) - 1.f); }
__device__ __forceinline__ float elu_ff(float x) { return x > 0.f ? x : (__expf(x) - 1.f); }

__device__ __forceinline__ unsigned f2tf32(float x) {
    unsigned r;
    asm("cvt.rna.tf32.f32 %0, %1;" : "=r"(r) : "f"(x));
    return r;
}
__device__ __forceinline__ unsigned packbf2(float lo, float hi) {
    __nv_bfloat162 v = __floats2bfloat162_rn(lo, hi);
    return *reinterpret_cast<unsigned*>(&v);
}
__device__ __forceinline__ uint32_t smem_u32(const void* p) {
    uint32_t a;
    asm("{ .reg .u64 t; cvta.to.shared.u64 t, %1; cvt.u32.u64 %0, t; }" : "=r"(a) : "l"(p));
    return a;
}

#define LDSM4(r0,r1,r2,r3,addr) \
    asm volatile("ldmatrix.sync.aligned.m8n8.x4.shared.b16 {%0,%1,%2,%3}, [%4];" \
        : "=r"(r0), "=r"(r1), "=r"(r2), "=r"(r3) : "r"(addr))

#define CP_ASYNC16(dst, src) \
    asm volatile("cp.async.ca.shared.global [%0], [%1], 16;" :: "r"(dst), "l"(src) : "memory")
#define CP_COMMIT() asm volatile("cp.async.commit_group;" ::: "memory")
#define CP_WAIT(n)  asm volatile("cp.async.wait_group %0;" :: "n"(n) : "memory")

// ---------------- fused prep: derive edges + traj embed + W2^T ----------------
__global__ void prep_kernel(const float* __restrict__ rel_rec,
                            const float* __restrict__ rel_send,
                            int* __restrict__ recv_idx, int* __restrict__ send_idx,
                            const float* __restrict__ centers,
                            const float* __restrict__ W, const float* __restrict__ bias,
                            const float* __restrict__ W2, __nv_bfloat16* __restrict__ w2t,
                            float* __restrict__ x) {
    if (blockIdx.x < 16) {
        int e = blockIdx.x * 256 + threadIdx.x;
        if (e >= EE) return;
        int r = 0, s = 0; float br = -1.f, bs = -1.f;
        for (int n = 0; n < NN; n++) {
            float vr = rel_rec[e*NN + n];
            float vs = rel_send[e*NN + n];
            if (vr > br) { br = vr; r = n; }
            if (vs > bs) { bs = vs; s = n; }
        }
        recv_idx[e] = r; send_idx[e] = s;
        return;
    }
    if (blockIdx.x >= 16 + ROWS_N) {
        int n = blockIdx.x - 16 - ROWS_N;
        int k = threadIdx.x;
        w2t[n*HH + k] = __float2bfloat16(W2[k*HH + n]);
        return;
    }
    int row = blockIdx.x - 16;
    int h = threadIdx.x;
    __shared__ float rp[PREV*2];
    if (h < PREV*2) {
        int p = h >> 1, c = h & 1;
        float v = 0.f;
        if (p > 0) v = centers[row*PREV*2 + p*2 + c] - centers[row*PREV*2 + (p-1)*2 + c];
        rp[h] = v;
    }
    __syncthreads();
    float acc = bias[h];
    #pragma unroll
    for (int k = 0; k < PREV*2; k++) acc += rp[k] * W[k*HH + h];
    x[row*HH + h] = acc;
}

// ---------------- parallel deterministic list build ----------------
__global__ void build_lists_kernel(const int* __restrict__ recv_idx,
                                   const int* __restrict__ send_idx,
                                   int* __restrict__ list_rec, int* __restrict__ list_send,
                                   int* __restrict__ cnt_rec, int* __restrict__ cnt_send,
                                   float* __restrict__ invdeg_rec, float* __restrict__ invdeg_send) {
    const bool isSend = blockIdx.x >= NN;
    const int n = blockIdx.x & (NN-1);
    const int* __restrict__ idx = isSend ? send_idx : recv_idx;
    int* __restrict__ list = (isSend ? list_send : list_rec) + n*EE;
    const int t = threadIdx.x;            // 64 threads
    const int CH = EE / 64;               // 63
    const int base = t * CH;
    int c = 0;
    for (int i = 0; i < CH; i++) c += (idx[base+i] == n) ? 1 : 0;
    __shared__ int pre[64];
    pre[t] = c;
    __syncthreads();
    for (int off = 1; off < 64; off <<= 1) {
        int v = (t >= off) ? pre[t-off] : 0;
        __syncthreads();
        pre[t] += v;
        __syncthreads();
    }
    int offset = pre[t] - c;
    for (int i = 0; i < CH; i++) {
        int e = base + i;
        if (idx[e] == n) list[offset++] = e;
    }
    if (t == 63) {
        int tot = pre[63];
        float iv = tot ? 1.f/(float)tot : 1.f;
        if (isSend) { cnt_send[n] = tot; invdeg_send[n] = iv; }
        else        { cnt_rec[n]  = tot; invdeg_rec[n]  = iv; }
    }
}

// =======================================================================
// Generic double-buffered tf32 GEMM (unchanged)
// =======================================================================
template<int AMODE, bool ELU, bool GUARD_N>
__global__ __launch_bounds__(256)
void mma_gemm_v2(const float* __restrict__ A0, const float* __restrict__ A1,
                 const float* __restrict__ aVec, const float* __restrict__ cVec,
                 const float* __restrict__ invDegR, const float* __restrict__ invDegS,
                 const float* __restrict__ B0, const float* __restrict__ B1,
                 const float* __restrict__ bias,
                 float* __restrict__ C0, float* __restrict__ C1,
                 int M, int N, int K) {
    const float* __restrict__ Bm = (blockIdx.z == 0) ? B0 : B1;
    float* __restrict__ C = (blockIdx.z == 0) ? C0 : C1;

    __shared__ unsigned Asm[2][64][36];
    __shared__ unsigned Bsm[2][32][72];
    const int tid  = threadIdx.x;
    const int lane = tid & 31;
    const int warp = tid >> 5;
    const int warpM = warp & 1;
    const int warpN = warp >> 1;
    const int g  = lane >> 2;
    const int t4 = lane & 3;
    const int row0 = blockIdx.y * 64;
    const int col0 = blockIdx.x * 64;

    int arow[2], akq[2], bkk[2], bq[2];
    #pragma unroll
    for (int it = 0; it < 2; it++) {
        int ta = it*256 + tid;
        akq[it] = ta & 7;  arow[it] = ta >> 3;
        bkk[it] = ta >> 4; bq[it]  = ta & 15;
    }

    float4 pa[2], pb[2];

    auto prefetch = [&](int k0) {
        #pragma unroll
        for (int it = 0; it < 2; it++) {
            int gk = k0 + akq[it]*4;
            if (AMODE == 0) {
                pa[it] = *reinterpret_cast<const float4*>(&A0[(long)(row0+arow[it])*K + gk]);
            } else {
                const float* src = (gk >= HH) ? A1 : A0;
                pa[it] = *reinterpret_cast<const float4*>(&src[(long)(row0+arow[it])*HH + (gk & (HH-1))]);
            }
            int c0 = col0 + bq[it]*4;
            if (!GUARD_N) {
                pb[it] = *reinterpret_cast<const float4*>(&Bm[(long)(k0+bkk[it])*N + c0]);
            } else {
                float4 v;
                v.x = (c0+0 < N) ? Bm[(long)(k0+bkk[it])*N + c0+0] : 0.f;
                v.y = (c0+1 < N) ? Bm[(long)(k0+bkk[it])*N + c0+1] : 0.f;
                v.z = (c0+2 < N) ? Bm[(long)(k0+bkk[it])*N + c0+2] : 0.f;
                v.w = (c0+3 < N) ? Bm[(long)(k0+bkk[it])*N + c0+3] : 0.f;
                pb[it] = v;
            }
        }
    };

    auto store = [&](int s, int k0) {
        #pragma unroll
        for (int it = 0; it < 2; it++) {
            int gk = k0 + akq[it]*4;
            float4 v = pa[it];
            if (AMODE == 1) {
                int col = gk & (HH-1);
                float invd = ((gk >= HH) ? invDegS : invDegR)[(row0+arow[it]) & (NN-1)];
                float4 a4 = *reinterpret_cast<const float4*>(&aVec[col]);
                float4 c4 = *reinterpret_cast<const float4*>(&cVec[col]);
                v.x = a4.x*(v.x*invd)+c4.x; v.y = a4.y*(v.y*invd)+c4.y;
                v.z = a4.z*(v.z*invd)+c4.z; v.w = a4.w*(v.w*invd)+c4.w;
            } else if (AMODE == 2) {
                if (gk >= HH) {
                    int col = gk & (HH-1);
                    float4 a4 = *reinterpret_cast<const float4*>(&aVec[col]);
                    float4 c4 = *reinterpret_cast<const float4*>(&cVec[col]);
                    v.x = a4.x*v.x+c4.x; v.y = a4.y*v.y+c4.y;
                    v.z = a4.z*v.z+c4.z; v.w = a4.w*v.w+c4.w;
                }
            }
            Asm[s][arow[it]][akq[it]*4+0] = f2tf32(v.x);
            Asm[s][arow[it]][akq[it]*4+1] = f2tf32(v.y);
            Asm[s][arow[it]][akq[it]*4+2] = f2tf32(v.z);
            Asm[s][arow[it]][akq[it]*4+3] = f2tf32(v.w);

            float4 w = pb[it];
            Bsm[s][bkk[it]][bq[it]*4+0] = f2tf32(w.x);
            Bsm[s][bkk[it]][bq[it]*4+1] = f2tf32(w.y);
            Bsm[s][bkk[it]][bq[it]*4+2] = f2tf32(w.z);
            Bsm[s][bkk[it]][bq[it]*4+3] = f2tf32(w.w);
        }
    };

    float acc[2][2][4] = {};
    const int nIter = K >> 5;

    prefetch(0);
    store(0, 0);
    __syncthreads();

    for (int i = 0; i < nIter; i++) {
        int cur = i & 1;
        if (i + 1 < nIter) prefetch((i+1) * 32);

        #pragma unroll
        for (int ks = 0; ks < 32; ks += 8) {
            unsigned afr[2][4];
            #pragma unroll
            for (int ii = 0; ii < 2; ii++) {
                int r = warpM*32 + ii*16;
                afr[ii][0] = Asm[cur][r + g    ][ks + t4    ];
                afr[ii][1] = Asm[cur][r + g + 8][ks + t4    ];
                afr[ii][2] = Asm[cur][r + g    ][ks + t4 + 4];
                afr[ii][3] = Asm[cur][r + g + 8][ks + t4 + 4];
            }
            unsigned bfr[2][2];
            #pragma unroll
            for (int j = 0; j < 2; j++) {
                int nn = warpN*16 + j*8 + g;
                bfr[j][0] = Bsm[cur][ks + t4    ][nn];
                bfr[j][1] = Bsm[cur][ks + t4 + 4][nn];
            }
            #pragma unroll
            for (int ii = 0; ii < 2; ii++)
                #pragma unroll
                for (int j = 0; j < 2; j++)
                    asm volatile(
                        "mma.sync.aligned.m16n8k8.row.col.f32.tf32.tf32.f32 "
                        "{%0,%1,%2,%3}, {%4,%5,%6,%7}, {%8,%9}, {%0,%1,%2,%3};"
                        : "+f"(acc[ii][j][0]), "+f"(acc[ii][j][1]),
                          "+f"(acc[ii][j][2]), "+f"(acc[ii][j][3])
                        : "r"(afr[ii][0]), "r"(afr[ii][1]), "r"(afr[ii][2]), "r"(afr[ii][3]),
                          "r"(bfr[j][0]), "r"(bfr[j][1]));
        }
        if (i + 1 < nIter) store(cur ^ 1, (i+1) * 32);
        __syncthreads();
    }

    #pragma unroll
    for (int i = 0; i < 2; i++) {
        int r = row0 + warpM*32 + i*16 + g;
        #pragma unroll
        for (int j = 0; j < 2; j++) {
            int c = col0 + warpN*16 + j*8 + t4*2;
            #pragma unroll
            for (int h = 0; h < 2; h++) {
                int cc = c + h;
                if (GUARD_N && cc >= N) continue;
                float bb = bias ? bias[cc] : 0.f;
                float v0 = acc[i][j][h]   + bb;
                float v1 = acc[i][j][2+h] + bb;
                if (ELU) { v0 = elu_f(v0); v1 = elu_f(v1); }
                C[(long)r*N + cc]     = v0;
                C[(long)(r+8)*N + cc] = v1;
            }
        }
    }
}

// =======================================================================
// Pred GEMM + cumsum epilogue (unchanged)
// =======================================================================
__global__ __launch_bounds__(256)
void pred_pos_kernel(const float* __restrict__ A0, const float* __restrict__ Bm,
                     const float* __restrict__ bias, const float* __restrict__ centers,
                     float* __restrict__ out) {
    const int N = PRED*2;
    const int K = HH;
    __shared__ unsigned Asm[64][36];
    __shared__ unsigned Bsm[32][72];
    __shared__ float Cs[64][64];
    const int tid  = threadIdx.x;
    const int lane = tid & 31;
    const int warp = tid >> 5;
    const int warpM = warp & 1;
    const int warpN = warp >> 1;
    const int g  = lane >> 2;
    const int t4 = lane & 3;
    const int row0 = blockIdx.y * 64;

    int arow[2], akq[2], bkk[2], bq[2];
    #pragma unroll
    for (int it = 0; it < 2; it++) {
        int ta = it*256 + tid;
        akq[it] = ta & 7;  arow[it] = ta >> 3;
        bkk[it] = ta >> 4; bq[it]  = ta & 15;
    }
    float4 pa[2], pb[2];
    #pragma unroll
    for (int it = 0; it < 2; it++) {
        pa[it] = *reinterpret_cast<const float4*>(&A0[(long)(row0+arow[it])*K + akq[it]*4]);
        int c0 = bq[it]*4;
        float4 v;
        v.x = (c0+0 < N) ? Bm[(long)bkk[it]*N + c0+0] : 0.f;
        v.y = (c0+1 < N) ? Bm[(long)bkk[it]*N + c0+1] : 0.f;
        v.z = (c0+2 < N) ? Bm[(long)bkk[it]*N + c0+2] : 0.f;
        v.w = (c0+3 < N) ? Bm[(long)bkk[it]*N + c0+3] : 0.f;
        pb[it] = v;
    }

    float acc[2][2][4] = {};
    for (int k0 = 0; k0 < K; k0 += 32) {
        #pragma unroll
        for (int it = 0; it < 2; it++) {
            float4 v = pa[it];
            Asm[arow[it]][akq[it]*4+0] = f2tf32(v.x);
            Asm[arow[it]][akq[it]*4+1] = f2tf32(v.y);
            Asm[arow[it]][akq[it]*4+2] = f2tf32(v.z);
            Asm[arow[it]][akq[it]*4+3] = f2tf32(v.w);
            float4 w = pb[it];
            Bsm[bkk[it]][bq[it]*4+0] = f2tf32(w.x);
            Bsm[bkk[it]][bq[it]*4+1] = f2tf32(w.y);
            Bsm[bkk[it]][bq[it]*4+2] = f2tf32(w.z);
            Bsm[bkk[it]][bq[it]*4+3] = f2tf32(w.w);
        }
        if (k0 + 32 < K) {
            int kn = k0 + 32;
            #pragma unroll
            for (int it = 0; it < 2; it++) {
                pa[it] = *reinterpret_cast<const float4*>(&A0[(long)(row0+arow[it])*K + kn + akq[it]*4]);
                int c0 = bq[it]*4;
                float4 v;
                v.x = (c0+0 < N) ? Bm[(long)(kn+bkk[it])*N + c0+0] : 0.f;
                v.y = (c0+1 < N) ? Bm[(long)(kn+bkk[it])*N + c0+1] : 0.f;
                v.z = (c0+2 < N) ? Bm[(long)(kn+bkk[it])*N + c0+2] : 0.f;
                v.w = (c0+3 < N) ? Bm[(long)(kn+bkk[it])*N + c0+3] : 0.f;
                pb[it] = v;
            }
        }
        __syncthreads();
        #pragma unroll
        for (int ks = 0; ks < 32; ks += 8) {
            unsigned afr[2][4];
            #pragma unroll
            for (int i = 0; i < 2; i++) {
                int r = warpM*32 + i*16;
                afr[i][0] = Asm[r + g    ][ks + t4    ];
                afr[i][1] = Asm[r + g + 8][ks + t4    ];
                afr[i][2] = Asm[r + g    ][ks + t4 + 4];
                afr[i][3] = Asm[r + g + 8][ks + t4 + 4];
            }
            unsigned bfr[2][2];
            #pragma unroll
            for (int j = 0; j < 2; j++) {
                int nn = warpN*16 + j*8 + g;
                bfr[j][0] = Bsm[ks + t4    ][nn];
                bfr[j][1] = Bsm[ks + t4 + 4][nn];
            }
            #pragma unroll
            for (int i = 0; i < 2; i++)
                #pragma unroll
                for (int j = 0; j < 2; j++)
                    asm volatile(
                        "mma.sync.aligned.m16n8k8.row.col.f32.tf32.tf32.f32 "
                        "{%0,%1,%2,%3}, {%4,%5,%6,%7}, {%8,%9}, {%0,%1,%2,%3};"
                        : "+f"(acc[i][j][0]), "+f"(acc[i][j][1]),
                          "+f"(acc[i][j][2]), "+f"(acc[i][j][3])
                        : "r"(afr[i][0]), "r"(afr[i][1]), "r"(afr[i][2]), "r"(afr[i][3]),
                          "r"(bfr[j][0]), "r"(bfr[j][1]));
        }
        __syncthreads();
    }

    #pragma unroll
    for (int i = 0; i < 2; i++) {
        int r = warpM*32 + i*16 + g;
        #pragma unroll
        for (int j = 0; j < 2; j++) {
            int c = warpN*16 + j*8 + t4*2;
            #pragma unroll
            for (int h = 0; h < 2; h++) {
                int cc = c + h;
                float bb = (cc < N) ? bias[cc] : 0.f;
                Cs[r][cc]   = acc[i][j][h]   + bb;
                Cs[r+8][cc] = acc[i][j][2+h] + bb;
            }
        }
    }
    __syncthreads();

    if (tid < 128) {
        int lrow = tid >> 1, dimc = tid & 1;
        int grow = row0 + lrow;
        float cur = centers[grow*PREV*2 + (PREV-1)*2 + dimc];
        float accum = 0.f;
        #pragma unroll
        for (int p = 0; p < PRED; p++) {
            float v = Cs[lrow][2*p + dimc];
            out[(long)grow*N + 2*p + dimc] = v;
            accum += v;
            out[(long)(ROWS_N)*N + (long)grow*N + 2*p + dimc] = accum + cur;
        }
    }
}

// =======================================================================
// Fused edge GEMM v6: 64-row CTAs, 3/SM, cp.async B staging, bf16 h2 out.
// =======================================================================
#define A_ROWS   64
#define AK_PAD   264
#define A_BYTES  (A_ROWS*AK_PAD*2)        // 33792
#define B_BYTES  (2*128*40*2)             // 20480
#define EDGE_SMEM (A_BYTES + B_BYTES + 1024)

__global__ __launch_bounds__(256, 3)
void edge_gemm2_bf16(const float* __restrict__ xTop, const float* __restrict__ xBot,
                     const float* __restrict__ b1,
                     const __nv_bfloat16* __restrict__ w2t, const float* __restrict__ b2,
                     const int* __restrict__ recv_idx, const int* __restrict__ send_idx,
                     __nv_bfloat16* __restrict__ h2) {
    extern __shared__ char smraw[];
    __nv_bfloat16* Afull = reinterpret_cast<__nv_bfloat16*>(smraw);           // [64][264]
    __nv_bfloat16* Bsn   = reinterpret_cast<__nv_bfloat16*>(smraw + A_BYTES); // [2][128][40]
    int* topBase = reinterpret_cast<int*>(smraw + A_BYTES + B_BYTES);
    int* botBase = topBase + A_ROWS;

    const int tid  = threadIdx.x;
    const int lane = tid & 31;
    const int warp = tid >> 5;
    const int warpM = warp & 1;
    const int warpN = warp >> 1;
    const int row0 = blockIdx.x * A_ROWS;

    if (tid < A_ROWS) {
        int grow = row0 + tid;
        int b = grow / EE;
        int e = grow - b * EE;
        topBase[tid] = (b*NN + recv_idx[e]) * HH;
        botBase[tid] = (b*NN + send_idx[e]) * HH;
    }
    __syncthreads();

    // ---- Phase 1: build A tile (64 rows x 256 k), coalesced ----
    {
        const int kq = tid & 63;
        const int rb = tid >> 6;
        const int kb = kq * 4;
        float4 bb = *reinterpret_cast<const float4*>(&b1[kb]);
        #pragma unroll
        for (int it = 0; it < 16; it++) {
            int row = it*4 + rb;
            float4 a  = *reinterpret_cast<const float4*>(&xTop[topBase[row] + kb]);
            float4 bv = *reinterpret_cast<const float4*>(&xBot[botBase[row] + kb]);
            unsigned p0 = packbf2(elu_ff(a.x + bv.x + bb.x), elu_ff(a.y + bv.y + bb.y));
            unsigned p1 = packbf2(elu_ff(a.z + bv.z + bb.z), elu_ff(a.w + bv.w + bb.w));
            *reinterpret_cast<uint2*>(&Afull[row*AK_PAD + kb]) = make_uint2(p0, p1);
        }
    }

    int bn[2], bkh[2];
    #pragma unroll
    for (int it = 0; it < 2; it++) {
        int task = it*256 + tid;
        bkh[it] = task & 3;
        bn[it]  = task >> 2;
    }

    const int lt  = lane >> 3;
    const int lrw = lane & 7;
    const int mrow0 = warpM * 32;
    const int ncol0 = warpN * 32;
    const uint32_t aBase = smem_u32(Afull);
    const uint32_t bBase0 = smem_u32(Bsn);
    const uint32_t BSTG = 128u * 40u * 2u;
    const uint32_t aLanePart = (uint32_t)(mrow0 + (lt & 1)*8 + lrw) * (AK_PAD*2u)
                             + (uint32_t)(lt >> 1) * 16u;
    const uint32_t bLanePart = (uint32_t)(ncol0 + lt*8 + lrw) * 80u;

    auto issueB = [&](int col0, int k0, int stage) {
        #pragma unroll
        for (int it = 0; it < 2; it++) {
            uint32_t dst = bBase0 + (uint32_t)stage * BSTG
                         + (uint32_t)(bn[it]*80 + bkh[it]*16);
            const void* src = &w2t[(long)(col0 + bn[it])*HH + k0 + bkh[it]*8];
            CP_ASYNC16(dst, src);
        }
    };

    __syncthreads();   // A tile ready

    const int g  = lane >> 2;
    const int t4 = lane & 3;

    #pragma unroll 1
    for (int half = 0; half < 2; half++) {
        const int col0 = half * 128;

        issueB(col0, 0, 0);
        CP_COMMIT();

        float acc[2][4][4] = {};

        #pragma unroll 1
        for (int i = 0; i < 8; i++) {
            int cur = i & 1;
            if (i < 7) {
                issueB(col0, (i+1)*32, cur ^ 1);
                CP_COMMIT();
                CP_WAIT(1);
            } else {
                CP_WAIT(0);
            }
            __syncthreads();

            const uint32_t aCur = aBase + aLanePart + (uint32_t)i * 64u;
            const uint32_t bCur = bBase0 + (uint32_t)cur * BSTG + bLanePart;

            #pragma unroll
            for (int ks = 0; ks < 32; ks += 16) {
                unsigned afr[2][4];
                #pragma unroll
                for (int ii = 0; ii < 2; ii++) {
                    LDSM4(afr[ii][0], afr[ii][1], afr[ii][2], afr[ii][3],
                          aCur + (uint32_t)ii*(16u*AK_PAD*2u) + (uint32_t)ks*2u);
                }
                unsigned bfr[4][2];
                #pragma unroll
                for (int kh = 0; kh < 2; kh++) {
                    unsigned t0, t1, t2, t3;
                    LDSM4(t0, t1, t2, t3,
                          bCur + (uint32_t)ks*2u + (uint32_t)kh*16u);
                    bfr[0][kh] = t0;
                    bfr[1][kh] = t1;
                    bfr[2][kh] = t2;
                    bfr[3][kh] = t3;
                }
                #pragma unroll
                for (int j = 0; j < 4; j++) {
                    #pragma unroll
                    for (int ii = 0; ii < 2; ii++)
                        asm volatile(
                            "mma.sync.aligned.m16n8k16.row.col.f32.bf16.bf16.f32 "
                            "{%0,%1,%2,%3}, {%4,%5,%6,%7}, {%8,%9}, {%0,%1,%2,%3};"
                            : "+f"(acc[ii][j][0]), "+f"(acc[ii][j][1]),
                              "+f"(acc[ii][j][2]), "+f"(acc[ii][j][3])
                            : "r"(afr[ii][0]), "r"(afr[ii][1]), "r"(afr[ii][2]), "r"(afr[ii][3]),
                              "r"(bfr[j][0]), "r"(bfr[j][1]));
                }
            }
            __syncthreads();
        }

        // epilogue for this half: bias + elu -> bf16 packed stores
        #pragma unroll
        for (int i = 0; i < 2; i++) {
            int r_lo = row0 + mrow0 + i*16 + g;
            #pragma unroll
            for (int j = 0; j < 4; j++) {
                int c = col0 + ncol0 + j*8 + t4*2;
                float bb0 = b2[c], bb1 = b2[c+1];
                *reinterpret_cast<unsigned*>(&h2[(long)r_lo*HH + c]) =
                    packbf2(elu_ff(acc[i][j][0] + bb0), elu_ff(acc[i][j][1] + bb1));
                *reinterpret_cast<unsigned*>(&h2[(long)(r_lo+8)*HH + c]) =
                    packbf2(elu_ff(acc[i][j][2] + bb0), elu_ff(acc[i][j][3] + bb1));
            }
        }
        __syncthreads();
    }
}

// ---------------- vectorized per-node gather sums (bf16 h2) ----------------
__global__ void scatter_kernel(const __nv_bfloat16* __restrict__ h2,
                               const int* __restrict__ list_rec, const int* __restrict__ cnt_rec,
                               const int* __restrict__ list_send, const int* __restrict__ cnt_send,
                               float* __restrict__ inc_raw, float* __restrict__ sq_part,
                               float* __restrict__ out_raw) {
    int id = blockIdx.x;
    bool isOut = id >= ROWS_N;
    int bn = id & (ROWS_N-1);
    int b = bn >> 6, n = bn & 63;
    const int tid = threadIdx.x;
    const int c4 = tid & 63;          // column group (4 cols)
    const int rs = tid >> 6;          // row-slice 0..3
    const int* __restrict__ list = (isOut ? list_send : list_rec) + n*EE;
    const int cnt = (isOut ? cnt_send : cnt_rec)[n];

    float4 acc = make_float4(0.f, 0.f, 0.f, 0.f);
    float4 asq = make_float4(0.f, 0.f, 0.f, 0.f);
    for (int k = rs; k < cnt; k += 4) {
        int e = list[k];
        uint2 u = *reinterpret_cast<const uint2*>(&h2[(long)(b*EE + e)*HH + c4*4]);
        __nv_bfloat162 p0 = *reinterpret_cast<__nv_bfloat162*>(&u.x);
        __nv_bfloat162 p1 = *reinterpret_cast<__nv_bfloat162*>(&u.y);
        float v0 = __bfloat162float(p0.x), v1 = __bfloat162float(p0.y);
        float v2 = __bfloat162float(p1.x), v3 = __bfloat162float(p1.y);
        acc.x += v0; acc.y += v1; acc.z += v2; acc.w += v3;
        if (!isOut) {
            asq.x += v0*v0; asq.y += v1*v1; asq.z += v2*v2; asq.w += v3*v3;
        }
    }
    __shared__ float4 sa[4][64];
    __shared__ float4 sq[4][64];
    sa[rs][c4] = acc;
    if (!isOut) sq[rs][c4] = asq;
    __syncthreads();
    if (rs == 0) {
        float4 t = sa[0][c4];
        #pragma unroll
        for (int r = 1; r < 4; r++) {
            float4 u = sa[r][c4];
            t.x += u.x; t.y += u.y; t.z += u.z; t.w += u.w;
        }
        if (!isOut) {
            float4 s = sq[0][c4];
            #pragma unroll
            for (int r = 1; r < 4; r++) {
                float4 u = sq[r][c4];
                s.x += u.x; s.y += u.y; s.z += u.z; s.w += u.w;
            }
            *reinterpret_cast<float4*>(&inc_raw[bn*HH + c4*4]) = t;
            *reinterpret_cast<float4*>(&sq_part[bn*HH + c4*4]) = s;
        } else {
            *reinterpret_cast<float4*>(&out_raw[bn*HH + c4*4]) = t;
        }
    }
}

// ---------------- BN stats -> affine (a,c) ----------------
template<bool SRC_SQ>
__global__ void stats_kernel(const float* __restrict__ sum_part, const float* __restrict__ sq_part,
                             const float* __restrict__ gamma, const float* __restrict__ beta,
                             float* __restrict__ a, float* __restrict__ c,
                             int nrows, float count) {
    int h = blockIdx.x;
    float s = 0.f, sq = 0.f;
    for (int r = threadIdx.x; r < nrows; r += 256) {
        float v = sum_part[r*HH + h];
        s += v;
        if (SRC_SQ) sq += v*v; else sq += sq_part[r*HH + h];
    }
    __shared__ float ss[256], ssq[256];
    ss[threadIdx.x] = s; ssq[threadIdx.x] = sq;
    __syncthreads();
    for (int st = 128; st > 0; st >>= 1) {
        if (threadIdx.x < st) { ss[threadIdx.x] += ss[threadIdx.x+st]; ssq[threadIdx.x] += ssq[threadIdx.x+st]; }
        __syncthreads();
    }
    if (threadIdx.x == 0) {
        float mu = ss[0] / count;
        float var = ssq[0] / count - mu*mu;
        float av = gamma[h] * rsqrtf(var + 1e-5f);
        a[h] = av;
        c[h] = beta[h] - mu * av;
    }
}

// ---------------- launcher ----------------
extern "C" void kernel_launch(void* const* d_in, const int* in_sizes, int n_in,
                              void* d_out, int out_size) {
    const float* centers  = (const float*)d_in[0];
    const float* rel_rec  = (const float*)d_in[1];
    const float* rel_send = (const float*)d_in[2];
    const float* W_traj   = (const float*)d_in[3];
    const float* b_traj   = (const float*)d_in[4];
    const float* n2e_W1   = (const float*)d_in[5];
    const float* n2e_b1   = (const float*)d_in[6];
    const float* n2e_W2   = (const float*)d_in[7];
    const float* n2e_b2   = (const float*)d_in[8];
    const float* n2e_g    = (const float*)d_in[9];
    const float* n2e_be   = (const float*)d_in[10];
    const float* e2n_W1   = (const float*)d_in[11];
    const float* e2n_b1   = (const float*)d_in[12];
    const float* e2n_W2   = (const float*)d_in[13];
    const float* e2n_b2   = (const float*)d_in[14];
    const float* e2n_g    = (const float*)d_in[15];
    const float* e2n_be   = (const float*)d_in[16];
    const float* W_fuse   = (const float*)d_in[17];
    const float* b_fuse   = (const float*)d_in[18];
    const float* W_pred   = (const float*)d_in[19];
    const float* b_pred   = (const float*)d_in[20];
    float* out = (float*)d_out;

    float *p_x, *p_xTop, *p_xBot, *p_inc, *p_incsq, *p_outg;
    float *p_nh1, *p_mraw, *p_fused;
    float *p_ae, *p_ce, *p_an, *p_cn, *p_idr, *p_ids;
    int *p_recv, *p_send, *p_lr, *p_ls, *p_cr, *p_cs;
    __nv_bfloat16 *p_w2t, *p_h2;
    cudaGetSymbolAddress((void**)&p_x, d_x);
    cudaGetSymbolAddress((void**)&p_xTop, d_xTop);
    cudaGetSymbolAddress((void**)&p_xBot, d_xBot);
    cudaGetSymbolAddress((void**)&p_h2, d_h2);
    cudaGetSymbolAddress((void**)&p_inc, d_inc);
    cudaGetSymbolAddress((void**)&p_incsq, d_incsq);
    cudaGetSymbolAddress((void**)&p_outg, d_outg);
    cudaGetSymbolAddress((void**)&p_nh1, d_nh1);
    cudaGetSymbolAddress((void**)&p_mraw, d_mraw);
    cudaGetSymbolAddress((void**)&p_fused, d_fused);
    cudaGetSymbolAddress((void**)&p_ae, d_ae);
    cudaGetSymbolAddress((void**)&p_ce, d_ce);
    cudaGetSymbolAddress((void**)&p_an, d_an);
    cudaGetSymbolAddress((void**)&p_cn, d_cn);
    cudaGetSymbolAddress((void**)&p_idr, d_invdegrec);
    cudaGetSymbolAddress((void**)&p_ids, d_invdegsend);
    cudaGetSymbolAddress((void**)&p_recv, d_recv);
    cudaGetSymbolAddress((void**)&p_send, d_send);
    cudaGetSymbolAddress((void**)&p_lr, d_listrec);
    cudaGetSymbolAddress((void**)&p_ls, d_listsend);
    cudaGetSymbolAddress((void**)&p_cr, d_cntrec);
    cudaGetSymbolAddress((void**)&p_cs, d_cntsend);
    cudaGetSymbolAddress((void**)&p_w2t, d_w2t);

    cudaFuncSetAttribute(edge_gemm2_bf16, cudaFuncAttributeMaxDynamicSharedMemorySize, EDGE_SMEM);

    // 1. fused prep: derive + traj + W2^T
    prep_kernel<<<16 + ROWS_N + HH, HH>>>(rel_rec, rel_send, p_recv, p_send,
                                          centers, W_traj, b_traj, n2e_W2, p_w2t, p_x);

    // 2. per-node edge lists
    build_lists_kernel<<<128, 64>>>(p_recv, p_send, p_lr, p_ls, p_cr, p_cs, p_idr, p_ids);

    // 3. xTop/xBot (dual-output, double-buffered tf32)
    mma_gemm_v2<0,false,false><<<dim3(HH/64, ROWS_N/64, 2), 256>>>(
        p_x, nullptr, nullptr, nullptr, nullptr, nullptr,
        n2e_W1, n2e_W1 + HH*HH, nullptr, p_xTop, p_xBot, ROWS_N, HH, HH);

    // 4. fused edge MLP v6 (bf16 h2 out)  <-- profiled launch
    edge_gemm2_bf16<<<ROWS_E/A_ROWS, 256, EDGE_SMEM>>>(p_xTop, p_xBot, n2e_b1,
                                                       p_w2t, n2e_b2,
                                                       p_recv, p_send, p_h2);

    // 5. scatter sums (bf16 reads) + edge BN stats
    scatter_kernel<<<2*ROWS_N, 256>>>(p_h2, p_lr, p_cr, p_ls, p_cs, p_inc, p_incsq, p_outg);
    stats_kernel<false><<<HH, 256>>>(p_inc, p_incsq, n2e_g, n2e_be, p_ae, p_ce, ROWS_N, (float)ROWS_E);

    // 6. node MLP
    mma_gemm_v2<1,true,false><<<dim3(HH/64, ROWS_N/64, 1), 256>>>(
        p_inc, p_outg, p_ae, p_ce, p_idr, p_ids,
        e2n_W1, e2n_W1, e2n_b1, p_nh1, p_nh1, ROWS_N, HH, 2*HH);
    mma_gemm_v2<0,true,false><<<dim3(HH/64, ROWS_N/64, 1), 256>>>(
        p_nh1, nullptr, nullptr, nullptr, nullptr, nullptr,
        e2n_W2, e2n_W2, e2n_b2, p_mraw, p_mraw, ROWS_N, HH, HH);
    stats_kernel<true><<<HH, 256>>>(p_mraw, nullptr, e2n_g, e2n_be, p_an, p_cn, ROWS_N, (float)ROWS_N);

    // 7. fuse + predict (+ fused cumsum epilogue)
    mma_gemm_v2<2,false,false><<<dim3(HH/64, ROWS_N/64, 1), 256>>>(
        p_x, p_mraw, p_an, p_cn, nullptr, nullptr,
        W_fuse, W_fuse, b_fuse, p_fused, p_fused, ROWS_N, HH, 2*HH);
    pred_pos_kernel<<<dim3(1, ROWS_N/64), 256>>>(p_fused, W_pred, b_pred, centers, out);
}

// round 13
// speedup vs baseline: 3.8903x; 1.0221x over previous
#include <cuda_runtime.h>
#include <cuda_bf16.h>
#include <math.h>
#include <stdint.h>

#define BB   16
#define NN   64
#define PREV 6
#define PRED 30
#define HH   256
#define EE   (NN*(NN-1))      // 4032
#define ROWS_E (BB*EE)        // 64512
#define ROWS_N (BB*NN)        // 1024

// ---------------- static scratch ----------------
__device__ float d_x[ROWS_N*HH];
__device__ float d_xTop[ROWS_N*HH];
__device__ float d_xBot[ROWS_N*HH];
__device__ __nv_bfloat16 d_h2[ROWS_E*HH];     // h2 bf16
__device__ float d_inc[ROWS_N*HH];
__device__ float d_incsq[ROWS_N*HH];
__device__ float d_outg[ROWS_N*HH];
__device__ float d_nh1[ROWS_N*HH];
__device__ float d_mraw[ROWS_N*HH];
__device__ float d_fused[ROWS_N*HH];
__device__ float d_ae[HH], d_ce[HH], d_an[HH], d_cn[HH];
__device__ int   d_recv[EE], d_send[EE];
__device__ int   d_listrec[NN*EE], d_listsend[NN*EE];
__device__ int   d_cntrec[NN], d_cntsend[NN];
__device__ float d_invdegrec[NN], d_invdegsend[NN];
__device__ __nv_bfloat16 d_w2t[HH*HH];   // W2^T in bf16: [n][k]

__device__ __forceinline__ float elu_f(float x)  { return x > 0.f ? x : (expf(x) - 1.f); }
__device__ __forceinline__ float elu_ff(float x) { return x > 0.f ? x : (__expf(x) - 1.f); }

__device__ __forceinline__ unsigned f2tf32(float x) {
    unsigned r;
    asm("cvt.rna.tf32.f32 %0, %1;" : "=r"(r) : "f"(x));
    return r;
}
__device__ __forceinline__ unsigned packbf2(float lo, float hi) {
    __nv_bfloat162 v = __floats2bfloat162_rn(lo, hi);
    return *reinterpret_cast<unsigned*>(&v);
}
__device__ __forceinline__ uint32_t smem_u32(const void* p) {
    uint32_t a;
    asm("{ .reg .u64 t; cvta.to.shared.u64 t, %1; cvt.u32.u64 %0, t; }" : "=r"(a) : "l"(p));
    return a;
}

#define LDSM4(r0,r1,r2,r3,addr) \
    asm volatile("ldmatrix.sync.aligned.m8n8.x4.shared.b16 {%0,%1,%2,%3}, [%4];" \
        : "=r"(r0), "=r"(r1), "=r"(r2), "=r"(r3) : "r"(addr))

#define CP_ASYNC16(dst, src) \
    asm volatile("cp.async.ca.shared.global [%0], [%1], 16;" :: "r"(dst), "l"(src) : "memory")
#define CP_COMMIT() asm volatile("cp.async.commit_group;" ::: "memory")
#define CP_WAIT(n)  asm volatile("cp.async.wait_group %0;" :: "n"(n) : "memory")

// ---------------- fused prep: derive + traj + W2^T + per-node lists ----------------
// blocks [0,16): derive; [16,1040): traj; [1040,1296): w2t; [1296,1424): lists
__global__ void prep_kernel(const float* __restrict__ rel_rec,
                            const float* __restrict__ rel_send,
                            int* __restrict__ recv_idx, int* __restrict__ send_idx,
                            const float* __restrict__ centers,
                            const float* __restrict__ W, const float* __restrict__ bias,
                            const float* __restrict__ W2, __nv_bfloat16* __restrict__ w2t,
                            float* __restrict__ x,
                            int* __restrict__ list_rec, int* __restrict__ list_send,
                            int* __restrict__ cnt_rec, int* __restrict__ cnt_send,
                            float* __restrict__ invdeg_rec, float* __restrict__ invdeg_send) {
    if (blockIdx.x < 16) {
        int e = blockIdx.x * 256 + threadIdx.x;
        if (e >= EE) return;
        int r = 0, s = 0; float br = -1.f, bs = -1.f;
        for (int n = 0; n < NN; n++) {
            float vr = rel_rec[e*NN + n];
            float vs = rel_send[e*NN + n];
            if (vr > br) { br = vr; r = n; }
            if (vs > bs) { bs = vs; s = n; }
        }
        recv_idx[e] = r; send_idx[e] = s;
        return;
    }
    if (blockIdx.x >= 1296) {
        // per-node list build directly from one-hot (batch 0), e-ascending order
        int id = blockIdx.x - 1296;            // 0..127
        if (threadIdx.x >= 64) return;
        const bool isSend = id >= NN;
        const int n = id & (NN-1);
        const float* __restrict__ oneHot = (isSend ? rel_send : rel_rec);
        int* __restrict__ list = (isSend ? list_send : list_rec) + n*EE;
        const int t = threadIdx.x;             // 64 threads
        const int CH = EE / 64;                // 63
        const int base = t * CH;
        int c = 0;
        for (int i = 0; i < CH; i++) c += (oneHot[(base+i)*NN + n] > 0.5f) ? 1 : 0;
        __shared__ int pre[64];
        pre[t] = c;
        __syncthreads();
        for (int off = 1; off < 64; off <<= 1) {
            int v = (t >= off) ? pre[t-off] : 0;
            __syncthreads();
            pre[t] += v;
            __syncthreads();
        }
        int offset = pre[t] - c;
        for (int i = 0; i < CH; i++) {
            int e = base + i;
            if (oneHot[e*NN + n] > 0.5f) list[offset++] = e;
        }
        if (t == 63) {
            int tot = pre[63];
            float iv = tot ? 1.f/(float)tot : 1.f;
            if (isSend) { cnt_send[n] = tot; invdeg_send[n] = iv; }
            else        { cnt_rec[n]  = tot; invdeg_rec[n]  = iv; }
        }
        return;
    }
    if (blockIdx.x >= 16 + ROWS_N) {
        int n = blockIdx.x - 16 - ROWS_N;
        int k = threadIdx.x;
        w2t[n*HH + k] = __float2bfloat16(W2[k*HH + n]);
        return;
    }
    int row = blockIdx.x - 16;
    int h = threadIdx.x;
    __shared__ float rp[PREV*2];
    if (h < PREV*2) {
        int p = h >> 1, c = h & 1;
        float v = 0.f;
        if (p > 0) v = centers[row*PREV*2 + p*2 + c] - centers[row*PREV*2 + (p-1)*2 + c];
        rp[h] = v;
    }
    __syncthreads();
    float acc = bias[h];
    #pragma unroll
    for (int k = 0; k < PREV*2; k++) acc += rp[k] * W[k*HH + h];
    x[row*HH + h] = acc;
}

// =======================================================================
// Generic double-buffered tf32 GEMM (unchanged)
// =======================================================================
template<int AMODE, bool ELU, bool GUARD_N>
__global__ __launch_bounds__(256)
void mma_gemm_v2(const float* __restrict__ A0, const float* __restrict__ A1,
                 const float* __restrict__ aVec, const float* __restrict__ cVec,
                 const float* __restrict__ invDegR, const float* __restrict__ invDegS,
                 const float* __restrict__ B0, const float* __restrict__ B1,
                 const float* __restrict__ bias,
                 float* __restrict__ C0, float* __restrict__ C1,
                 int M, int N, int K) {
    const float* __restrict__ Bm = (blockIdx.z == 0) ? B0 : B1;
    float* __restrict__ C = (blockIdx.z == 0) ? C0 : C1;

    __shared__ unsigned Asm[2][64][36];
    __shared__ unsigned Bsm[2][32][72];
    const int tid  = threadIdx.x;
    const int lane = tid & 31;
    const int warp = tid >> 5;
    const int warpM = warp & 1;
    const int warpN = warp >> 1;
    const int g  = lane >> 2;
    const int t4 = lane & 3;
    const int row0 = blockIdx.y * 64;
    const int col0 = blockIdx.x * 64;

    int arow[2], akq[2], bkk[2], bq[2];
    #pragma unroll
    for (int it = 0; it < 2; it++) {
        int ta = it*256 + tid;
        akq[it] = ta & 7;  arow[it] = ta >> 3;
        bkk[it] = ta >> 4; bq[it]  = ta & 15;
    }

    float4 pa[2], pb[2];

    auto prefetch = [&](int k0) {
        #pragma unroll
        for (int it = 0; it < 2; it++) {
            int gk = k0 + akq[it]*4;
            if (AMODE == 0) {
                pa[it] = *reinterpret_cast<const float4*>(&A0[(long)(row0+arow[it])*K + gk]);
            } else {
                const float* src = (gk >= HH) ? A1 : A0;
                pa[it] = *reinterpret_cast<const float4*>(&src[(long)(row0+arow[it])*HH + (gk & (HH-1))]);
            }
            int c0 = col0 + bq[it]*4;
            if (!GUARD_N) {
                pb[it] = *reinterpret_cast<const float4*>(&Bm[(long)(k0+bkk[it])*N + c0]);
            } else {
                float4 v;
                v.x = (c0+0 < N) ? Bm[(long)(k0+bkk[it])*N + c0+0] : 0.f;
                v.y = (c0+1 < N) ? Bm[(long)(k0+bkk[it])*N + c0+1] : 0.f;
                v.z = (c0+2 < N) ? Bm[(long)(k0+bkk[it])*N + c0+2] : 0.f;
                v.w = (c0+3 < N) ? Bm[(long)(k0+bkk[it])*N + c0+3] : 0.f;
                pb[it] = v;
            }
        }
    };

    auto store = [&](int s, int k0) {
        #pragma unroll
        for (int it = 0; it < 2; it++) {
            int gk = k0 + akq[it]*4;
            float4 v = pa[it];
            if (AMODE == 1) {
                int col = gk & (HH-1);
                float invd = ((gk >= HH) ? invDegS : invDegR)[(row0+arow[it]) & (NN-1)];
                float4 a4 = *reinterpret_cast<const float4*>(&aVec[col]);
                float4 c4 = *reinterpret_cast<const float4*>(&cVec[col]);
                v.x = a4.x*(v.x*invd)+c4.x; v.y = a4.y*(v.y*invd)+c4.y;
                v.z = a4.z*(v.z*invd)+c4.z; v.w = a4.w*(v.w*invd)+c4.w;
            } else if (AMODE == 2) {
                if (gk >= HH) {
                    int col = gk & (HH-1);
                    float4 a4 = *reinterpret_cast<const float4*>(&aVec[col]);
                    float4 c4 = *reinterpret_cast<const float4*>(&cVec[col]);
                    v.x = a4.x*v.x+c4.x; v.y = a4.y*v.y+c4.y;
                    v.z = a4.z*v.z+c4.z; v.w = a4.w*v.w+c4.w;
                }
            }
            Asm[s][arow[it]][akq[it]*4+0] = f2tf32(v.x);
            Asm[s][arow[it]][akq[it]*4+1] = f2tf32(v.y);
            Asm[s][arow[it]][akq[it]*4+2] = f2tf32(v.z);
            Asm[s][arow[it]][akq[it]*4+3] = f2tf32(v.w);

            float4 w = pb[it];
            Bsm[s][bkk[it]][bq[it]*4+0] = f2tf32(w.x);
            Bsm[s][bkk[it]][bq[it]*4+1] = f2tf32(w.y);
            Bsm[s][bkk[it]][bq[it]*4+2] = f2tf32(w.z);
            Bsm[s][bkk[it]][bq[it]*4+3] = f2tf32(w.w);
        }
    };

    float acc[2][2][4] = {};
    const int nIter = K >> 5;

    prefetch(0);
    store(0, 0);
    __syncthreads();

    for (int i = 0; i < nIter; i++) {
        int cur = i & 1;
        if (i + 1 < nIter) prefetch((i+1) * 32);

        #pragma unroll
        for (int ks = 0; ks < 32; ks += 8) {
            unsigned afr[2][4];
            #pragma unroll
            for (int ii = 0; ii < 2; ii++) {
                int r = warpM*32 + ii*16;
                afr[ii][0] = Asm[cur][r + g    ][ks + t4    ];
                afr[ii][1] = Asm[cur][r + g + 8][ks + t4    ];
                afr[ii][2] = Asm[cur][r + g    ][ks + t4 + 4];
                afr[ii][3] = Asm[cur][r + g + 8][ks + t4 + 4];
            }
            unsigned bfr[2][2];
            #pragma unroll
            for (int j = 0; j < 2; j++) {
                int nn = warpN*16 + j*8 + g;
                bfr[j][0] = Bsm[cur][ks + t4    ][nn];
                bfr[j][1] = Bsm[cur][ks + t4 + 4][nn];
            }
            #pragma unroll
            for (int ii = 0; ii < 2; ii++)
                #pragma unroll
                for (int j = 0; j < 2; j++)
                    asm volatile(
                        "mma.sync.aligned.m16n8k8.row.col.f32.tf32.tf32.f32 "
                        "{%0,%1,%2,%3}, {%4,%5,%6,%7}, {%8,%9}, {%0,%1,%2,%3};"
                        : "+f"(acc[ii][j][0]), "+f"(acc[ii][j][1]),
                          "+f"(acc[ii][j][2]), "+f"(acc[ii][j][3])
                        : "r"(afr[ii][0]), "r"(afr[ii][1]), "r"(afr[ii][2]), "r"(afr[ii][3]),
                          "r"(bfr[j][0]), "r"(bfr[j][1]));
        }
        if (i + 1 < nIter) store(cur ^ 1, (i+1) * 32);
        __syncthreads();
    }

    #pragma unroll
    for (int i = 0; i < 2; i++) {
        int r = row0 + warpM*32 + i*16 + g;
        #pragma unroll
        for (int j = 0; j < 2; j++) {
            int c = col0 + warpN*16 + j*8 + t4*2;
            #pragma unroll
            for (int h = 0; h < 2; h++) {
                int cc = c + h;
                if (GUARD_N && cc >= N) continue;
                float bb = bias ? bias[cc] : 0.f;
                float v0 = acc[i][j][h]   + bb;
                float v1 = acc[i][j][2+h] + bb;
                if (ELU) { v0 = elu_f(v0); v1 = elu_f(v1); }
                C[(long)r*N + cc]     = v0;
                C[(long)(r+8)*N + cc] = v1;
            }
        }
    }
}

// =======================================================================
// Pred GEMM + cumsum epilogue (unchanged)
// =======================================================================
__global__ __launch_bounds__(256)
void pred_pos_kernel(const float* __restrict__ A0, const float* __restrict__ Bm,
                     const float* __restrict__ bias, const float* __restrict__ centers,
                     float* __restrict__ out) {
    const int N = PRED*2;
    const int K = HH;
    __shared__ unsigned Asm[64][36];
    __shared__ unsigned Bsm[32][72];
    __shared__ float Cs[64][64];
    const int tid  = threadIdx.x;
    const int lane = tid & 31;
    const int warp = tid >> 5;
    const int warpM = warp & 1;
    const int warpN = warp >> 1;
    const int g  = lane >> 2;
    const int t4 = lane & 3;
    const int row0 = blockIdx.y * 64;

    int arow[2], akq[2], bkk[2], bq[2];
    #pragma unroll
    for (int it = 0; it < 2; it++) {
        int ta = it*256 + tid;
        akq[it] = ta & 7;  arow[it] = ta >> 3;
        bkk[it] = ta >> 4; bq[it]  = ta & 15;
    }
    float4 pa[2], pb[2];
    #pragma unroll
    for (int it = 0; it < 2; it++) {
        pa[it] = *reinterpret_cast<const float4*>(&A0[(long)(row0+arow[it])*K + akq[it]*4]);
        int c0 = bq[it]*4;
        float4 v;
        v.x = (c0+0 < N) ? Bm[(long)bkk[it]*N + c0+0] : 0.f;
        v.y = (c0+1 < N) ? Bm[(long)bkk[it]*N + c0+1] : 0.f;
        v.z = (c0+2 < N) ? Bm[(long)bkk[it]*N + c0+2] : 0.f;
        v.w = (c0+3 < N) ? Bm[(long)bkk[it]*N + c0+3] : 0.f;
        pb[it] = v;
    }

    float acc[2][2][4] = {};
    for (int k0 = 0; k0 < K; k0 += 32) {
        #pragma unroll
        for (int it = 0; it < 2; it++) {
            float4 v = pa[it];
            Asm[arow[it]][akq[it]*4+0] = f2tf32(v.x);
            Asm[arow[it]][akq[it]*4+1] = f2tf32(v.y);
            Asm[arow[it]][akq[it]*4+2] = f2tf32(v.z);
            Asm[arow[it]][akq[it]*4+3] = f2tf32(v.w);
            float4 w = pb[it];
            Bsm[bkk[it]][bq[it]*4+0] = f2tf32(w.x);
            Bsm[bkk[it]][bq[it]*4+1] = f2tf32(w.y);
            Bsm[bkk[it]][bq[it]*4+2] = f2tf32(w.z);
            Bsm[bkk[it]][bq[it]*4+3] = f2tf32(w.w);
        }
        if (k0 + 32 < K) {
            int kn = k0 + 32;
            #pragma unroll
            for (int it = 0; it < 2; it++) {
                pa[it] = *reinterpret_cast<const float4*>(&A0[(long)(row0+arow[it])*K + kn + akq[it]*4]);
                int c0 = bq[it]*4;
                float4 v;
                v.x = (c0+0 < N) ? Bm[(long)(kn+bkk[it])*N + c0+0] : 0.f;
                v.y = (c0+1 < N) ? Bm[(long)(kn+bkk[it])*N + c0+1] : 0.f;
                v.z = (c0+2 < N) ? Bm[(long)(kn+bkk[it])*N + c0+2] : 0.f;
                v.w = (c0+3 < N) ? Bm[(long)(kn+bkk[it])*N + c0+3] : 0.f;
                pb[it] = v;
            }
        }
        __syncthreads();
        #pragma unroll
        for (int ks = 0; ks < 32; ks += 8) {
            unsigned afr[2][4];
            #pragma unroll
            for (int i = 0; i < 2; i++) {
                int r = warpM*32 + i*16;
                afr[i][0] = Asm[r + g    ][ks + t4    ];
                afr[i][1] = Asm[r + g + 8][ks + t4    ];
                afr[i][2] = Asm[r + g    ][ks + t4 + 4];
                afr[i][3] = Asm[r + g + 8][ks + t4 + 4];
            }
            unsigned bfr[2][2];
            #pragma unroll
            for (int j = 0; j < 2; j++) {
                int nn = warpN*16 + j*8 + g;
                bfr[j][0] = Bsm[ks + t4    ][nn];
                bfr[j][1] = Bsm[ks + t4 + 4][nn];
            }
            #pragma unroll
            for (int i = 0; i < 2; i++)
                #pragma unroll
                for (int j = 0; j < 2; j++)
                    asm volatile(
                        "mma.sync.aligned.m16n8k8.row.col.f32.tf32.tf32.f32 "
                        "{%0,%1,%2,%3}, {%4,%5,%6,%7}, {%8,%9}, {%0,%1,%2,%3};"
                        : "+f"(acc[i][j][0]), "+f"(acc[i][j][1]),
                          "+f"(acc[i][j][2]), "+f"(acc[i][j][3])
                        : "r"(afr[i][0]), "r"(afr[i][1]), "r"(afr[i][2]), "r"(afr[i][3]),
                          "r"(bfr[j][0]), "r"(bfr[j][1]));
        }
        __syncthreads();
    }

    #pragma unroll
    for (int i = 0; i < 2; i++) {
        int r = warpM*32 + i*16 + g;
        #pragma unroll
        for (int j = 0; j < 2; j++) {
            int c = warpN*16 + j*8 + t4*2;
            #pragma unroll
            for (int h = 0; h < 2; h++) {
                int cc = c + h;
                float bb = (cc < N) ? bias[cc] : 0.f;
                Cs[r][cc]   = acc[i][j][h]   + bb;
                Cs[r+8][cc] = acc[i][j][2+h] + bb;
            }
        }
    }
    __syncthreads();

    if (tid < 128) {
        int lrow = tid >> 1, dimc = tid & 1;
        int grow = row0 + lrow;
        float cur = centers[grow*PREV*2 + (PREV-1)*2 + dimc];
        float accum = 0.f;
        #pragma unroll
        for (int p = 0; p < PRED; p++) {
            float v = Cs[lrow][2*p + dimc];
            out[(long)grow*N + 2*p + dimc] = v;
            accum += v;
            out[(long)(ROWS_N)*N + (long)grow*N + 2*p + dimc] = accum + cur;
        }
    }
}

// =======================================================================
// Fused edge GEMM v7: 64-row CTAs, 3/SM, 3-stage cp.async B, 1 sync/iter,
// hoisted addressing, bf16 h2 out.
// =======================================================================
#define A_ROWS   64
#define AK_PAD   264
#define A_BYTES  (A_ROWS*AK_PAD*2)        // 33792
#define B_BYTES  (3*128*40*2)             // 30720 (3 stages)
#define EDGE_SMEM (A_BYTES + B_BYTES + 1024)

__global__ __launch_bounds__(256, 3)
void edge_gemm2_bf16(const float* __restrict__ xTop, const float* __restrict__ xBot,
                     const float* __restrict__ b1,
                     const __nv_bfloat16* __restrict__ w2t, const float* __restrict__ b2,
                     const int* __restrict__ recv_idx, const int* __restrict__ send_idx,
                     __nv_bfloat16* __restrict__ h2) {
    extern __shared__ char smraw[];
    __nv_bfloat16* Afull = reinterpret_cast<__nv_bfloat16*>(smraw);           // [64][264]
    __nv_bfloat16* Bsn   = reinterpret_cast<__nv_bfloat16*>(smraw + A_BYTES); // [3][128][40]
    int* topBase = reinterpret_cast<int*>(smraw + A_BYTES + B_BYTES);
    int* botBase = topBase + A_ROWS;

    const int tid  = threadIdx.x;
    const int lane = tid & 31;
    const int warp = tid >> 5;
    const int warpM = warp & 1;
    const int warpN = warp >> 1;
    const int row0 = blockIdx.x * A_ROWS;

    if (tid < A_ROWS) {
        int grow = row0 + tid;
        int b = grow / EE;
        int e = grow - b * EE;
        topBase[tid] = (b*NN + recv_idx[e]) * HH;
        botBase[tid] = (b*NN + send_idx[e]) * HH;
    }
    __syncthreads();

    // ---- Phase 1: build A tile (64 rows x 256 k), coalesced ----
    {
        const int kq = tid & 63;
        const int rb = tid >> 6;
        const int kb = kq * 4;
        float4 bb = *reinterpret_cast<const float4*>(&b1[kb]);
        #pragma unroll
        for (int it = 0; it < 16; it++) {
            int row = it*4 + rb;
            float4 a  = *reinterpret_cast<const float4*>(&xTop[topBase[row] + kb]);
            float4 bv = *reinterpret_cast<const float4*>(&xBot[botBase[row] + kb]);
            unsigned p0 = packbf2(elu_ff(a.x + bv.x + bb.x), elu_ff(a.y + bv.y + bb.y));
            unsigned p1 = packbf2(elu_ff(a.z + bv.z + bb.z), elu_ff(a.w + bv.w + bb.w));
            *reinterpret_cast<uint2*>(&Afull[row*AK_PAD + kb]) = make_uint2(p0, p1);
        }
    }

    int bn[2], bkh[2];
    #pragma unroll
    for (int it = 0; it < 2; it++) {
        int task = it*256 + tid;
        bkh[it] = task & 3;
        bn[it]  = task >> 2;
    }

    const int lt  = lane >> 3;
    const int lrw = lane & 7;
    const int mrow0 = warpM * 32;
    const int ncol0 = warpN * 32;
    const uint32_t aBase = smem_u32(Afull);
    const uint32_t bBase0 = smem_u32(Bsn);
    const uint32_t BSTG = 128u * 40u * 2u;       // 10240 per stage
    const uint32_t aLanePart = (uint32_t)(mrow0 + (lt & 1)*8 + lrw) * (AK_PAD*2u)
                             + (uint32_t)(lt >> 1) * 16u;
    const uint32_t bLanePart = (uint32_t)(ncol0 + lt*8 + lrw) * 80u;
    // hoisted B addressing
    uint32_t dstPart[2];
    #pragma unroll
    for (int it = 0; it < 2; it++) dstPart[it] = (uint32_t)(bn[it]*80 + bkh[it]*16);

    __syncthreads();   // A tile ready

    const int g  = lane >> 2;
    const int t4 = lane & 3;

    #pragma unroll 1
    for (int half = 0; half < 2; half++) {
        const int col0 = half * 128;
        const __nv_bfloat16* srcB[2];
        #pragma unroll
        for (int it = 0; it < 2; it++)
            srcB[it] = &w2t[(long)(col0 + bn[it])*HH + bkh[it]*8];

        // prologue: issue stages 0 and 1 (groups G0, G1)
        #pragma unroll
        for (int s = 0; s < 2; s++) {
            #pragma unroll
            for (int it = 0; it < 2; it++)
                CP_ASYNC16(bBase0 + (uint32_t)s*BSTG + dstPart[it], srcB[it] + s*32);
            CP_COMMIT();
        }

        float acc[2][4][4] = {};

        #pragma unroll 1
        for (int i = 0; i < 8; i++) {
            const int stg = i - (i >= 3 ? 3 : 0) - (i >= 6 ? 3 : 0);   // i % 3
            if (i < 7) { CP_WAIT(1); } else { CP_WAIT(0); }
            __syncthreads();
            if (i + 2 < 8) {
                int s2 = (i+2) - ((i+2) >= 3 ? 3 : 0) - ((i+2) >= 6 ? 3 : 0);
                #pragma unroll
                for (int it = 0; it < 2; it++)
                    CP_ASYNC16(bBase0 + (uint32_t)s2*BSTG + dstPart[it], srcB[it] + (i+2)*32);
                CP_COMMIT();
            }

            const uint32_t aCur = aBase + aLanePart + (uint32_t)i * 64u;
            const uint32_t bCur = bBase0 + (uint32_t)stg * BSTG + bLanePart;

            #pragma unroll
            for (int ks = 0; ks < 32; ks += 16) {
                unsigned afr[2][4];
                #pragma unroll
                for (int ii = 0; ii < 2; ii++) {
                    LDSM4(afr[ii][0], afr[ii][1], afr[ii][2], afr[ii][3],
                          aCur + (uint32_t)ii*(16u*AK_PAD*2u) + (uint32_t)ks*2u);
                }
                unsigned bfr[4][2];
                #pragma unroll
                for (int kh = 0; kh < 2; kh++) {
                    unsigned t0, t1, t2, t3;
                    LDSM4(t0, t1, t2, t3,
                          bCur + (uint32_t)ks*2u + (uint32_t)kh*16u);
                    bfr[0][kh] = t0;
                    bfr[1][kh] = t1;
                    bfr[2][kh] = t2;
                    bfr[3][kh] = t3;
                }
                #pragma unroll
                for (int j = 0; j < 4; j++) {
                    #pragma unroll
                    for (int ii = 0; ii < 2; ii++)
                        asm volatile(
                            "mma.sync.aligned.m16n8k16.row.col.f32.bf16.bf16.f32 "
                            "{%0,%1,%2,%3}, {%4,%5,%6,%7}, {%8,%9}, {%0,%1,%2,%3};"
                            : "+f"(acc[ii][j][0]), "+f"(acc[ii][j][1]),
                              "+f"(acc[ii][j][2]), "+f"(acc[ii][j][3])
                            : "r"(afr[ii][0]), "r"(afr[ii][1]), "r"(afr[ii][2]), "r"(afr[ii][3]),
                              "r"(bfr[j][0]), "r"(bfr[j][1]));
                }
            }
        }

        // epilogue for this half: bias + elu -> bf16 packed stores
        #pragma unroll
        for (int i = 0; i < 2; i++) {
            int r_lo = row0 + mrow0 + i*16 + g;
            #pragma unroll
            for (int j = 0; j < 4; j++) {
                int c = col0 + ncol0 + j*8 + t4*2;
                float bb0 = b2[c], bb1 = b2[c+1];
                *reinterpret_cast<unsigned*>(&h2[(long)r_lo*HH + c]) =
                    packbf2(elu_ff(acc[i][j][0] + bb0), elu_ff(acc[i][j][1] + bb1));
                *reinterpret_cast<unsigned*>(&h2[(long)(r_lo+8)*HH + c]) =
                    packbf2(elu_ff(acc[i][j][2] + bb0), elu_ff(acc[i][j][3] + bb1));
            }
        }
        __syncthreads();   // all MMA reads done before next half re-primes stages
    }
}

// ---------------- vectorized per-node gather sums (bf16 h2) ----------------
__global__ void scatter_kernel(const __nv_bfloat16* __restrict__ h2,
                               const int* __restrict__ list_rec, const int* __restrict__ cnt_rec,
                               const int* __restrict__ list_send, const int* __restrict__ cnt_send,
                               float* __restrict__ inc_raw, float* __restrict__ sq_part,
                               float* __restrict__ out_raw) {
    int id = blockIdx.x;
    bool isOut = id >= ROWS_N;
    int bn = id & (ROWS_N-1);
    int b = bn >> 6, n = bn & 63;
    const int tid = threadIdx.x;
    const int c4 = tid & 63;
    const int rs = tid >> 6;
    const int* __restrict__ list = (isOut ? list_send : list_rec) + n*EE;
    const int cnt = (isOut ? cnt_send : cnt_rec)[n];

    float4 acc = make_float4(0.f, 0.f, 0.f, 0.f);
    float4 asq = make_float4(0.f, 0.f, 0.f, 0.f);
    for (int k = rs; k < cnt; k += 4) {
        int e = list[k];
        uint2 u = *reinterpret_cast<const uint2*>(&h2[(long)(b*EE + e)*HH + c4*4]);
        __nv_bfloat162 p0 = *reinterpret_cast<__nv_bfloat162*>(&u.x);
        __nv_bfloat162 p1 = *reinterpret_cast<__nv_bfloat162*>(&u.y);
        float v0 = __bfloat162float(p0.x), v1 = __bfloat162float(p0.y);
        float v2 = __bfloat162float(p1.x), v3 = __bfloat162float(p1.y);
        acc.x += v0; acc.y += v1; acc.z += v2; acc.w += v3;
        if (!isOut) {
            asq.x += v0*v0; asq.y += v1*v1; asq.z += v2*v2; asq.w += v3*v3;
        }
    }
    __shared__ float4 sa[4][64];
    __shared__ float4 sq[4][64];
    sa[rs][c4] = acc;
    if (!isOut) sq[rs][c4] = asq;
    __syncthreads();
    if (rs == 0) {
        float4 t = sa[0][c4];
        #pragma unroll
        for (int r = 1; r < 4; r++) {
            float4 u = sa[r][c4];
            t.x += u.x; t.y += u.y; t.z += u.z; t.w += u.w;
        }
        if (!isOut) {
            float4 s = sq[0][c4];
            #pragma unroll
            for (int r = 1; r < 4; r++) {
                float4 u = sq[r][c4];
                s.x += u.x; s.y += u.y; s.z += u.z; s.w += u.w;
            }
            *reinterpret_cast<float4*>(&inc_raw[bn*HH + c4*4]) = t;
            *reinterpret_cast<float4*>(&sq_part[bn*HH + c4*4]) = s;
        } else {
            *reinterpret_cast<float4*>(&out_raw[bn*HH + c4*4]) = t;
        }
    }
}

// ---------------- BN stats -> affine (a,c) ----------------
template<bool SRC_SQ>
__global__ void stats_kernel(const float* __restrict__ sum_part, const float* __restrict__ sq_part,
                             const float* __restrict__ gamma, const float* __restrict__ beta,
                             float* __restrict__ a, float* __restrict__ c,
                             int nrows, float count) {
    int h = blockIdx.x;
    float s = 0.f, sq = 0.f;
    for (int r = threadIdx.x; r < nrows; r += 256) {
        float v = sum_part[r*HH + h];
        s += v;
        if (SRC_SQ) sq += v*v; else sq += sq_part[r*HH + h];
    }
    __shared__ float ss[256], ssq[256];
    ss[threadIdx.x] = s; ssq[threadIdx.x] = sq;
    __syncthreads();
    for (int st = 128; st > 0; st >>= 1) {
        if (threadIdx.x < st) { ss[threadIdx.x] += ss[threadIdx.x+st]; ssq[threadIdx.x] += ssq[threadIdx.x+st]; }
        __syncthreads();
    }
    if (threadIdx.x == 0) {
        float mu = ss[0] / count;
        float var = ssq[0] / count - mu*mu;
        float av = gamma[h] * rsqrtf(var + 1e-5f);
        a[h] = av;
        c[h] = beta[h] - mu * av;
    }
}

// ---------------- launcher ----------------
extern "C" void kernel_launch(void* const* d_in, const int* in_sizes, int n_in,
                              void* d_out, int out_size) {
    const float* centers  = (const float*)d_in[0];
    const float* rel_rec  = (const float*)d_in[1];
    const float* rel_send = (const float*)d_in[2];
    const float* W_traj   = (const float*)d_in[3];
    const float* b_traj   = (const float*)d_in[4];
    const float* n2e_W1   = (const float*)d_in[5];
    const float* n2e_b1   = (const float*)d_in[6];
    const float* n2e_W2   = (const float*)d_in[7];
    const float* n2e_b2   = (const float*)d_in[8];
    const float* n2e_g    = (const float*)d_in[9];
    const float* n2e_be   = (const float*)d_in[10];
    const float* e2n_W1   = (const float*)d_in[11];
    const float* e2n_b1   = (const float*)d_in[12];
    const float* e2n_W2   = (const float*)d_in[13];
    const float* e2n_b2   = (const float*)d_in[14];
    const float* e2n_g    = (const float*)d_in[15];
    const float* e2n_be   = (const float*)d_in[16];
    const float* W_fuse   = (const float*)d_in[17];
    const float* b_fuse   = (const float*)d_in[18];
    const float* W_pred   = (const float*)d_in[19];
    const float* b_pred   = (const float*)d_in[20];
    float* out = (float*)d_out;

    float *p_x, *p_xTop, *p_xBot, *p_inc, *p_incsq, *p_outg;
    float *p_nh1, *p_mraw, *p_fused;
    float *p_ae, *p_ce, *p_an, *p_cn, *p_idr, *p_ids;
    int *p_recv, *p_send, *p_lr, *p_ls, *p_cr, *p_cs;
    __nv_bfloat16 *p_w2t, *p_h2;
    cudaGetSymbolAddress((void**)&p_x, d_x);
    cudaGetSymbolAddress((void**)&p_xTop, d_xTop);
    cudaGetSymbolAddress((void**)&p_xBot, d_xBot);
    cudaGetSymbolAddress((void**)&p_h2, d_h2);
    cudaGetSymbolAddress((void**)&p_inc, d_inc);
    cudaGetSymbolAddress((void**)&p_incsq, d_incsq);
    cudaGetSymbolAddress((void**)&p_outg, d_outg);
    cudaGetSymbolAddress((void**)&p_nh1, d_nh1);
    cudaGetSymbolAddress((void**)&p_mraw, d_mraw);
    cudaGetSymbolAddress((void**)&p_fused, d_fused);
    cudaGetSymbolAddress((void**)&p_ae, d_ae);
    cudaGetSymbolAddress((void**)&p_ce, d_ce);
    cudaGetSymbolAddress((void**)&p_an, d_an);
    cudaGetSymbolAddress((void**)&p_cn, d_cn);
    cudaGetSymbolAddress((void**)&p_idr, d_invdegrec);
    cudaGetSymbolAddress((void**)&p_ids, d_invdegsend);
    cudaGetSymbolAddress((void**)&p_recv, d_recv);
    cudaGetSymbolAddress((void**)&p_send, d_send);
    cudaGetSymbolAddress((void**)&p_lr, d_listrec);
    cudaGetSymbolAddress((void**)&p_ls, d_listsend);
    cudaGetSymbolAddress((void**)&p_cr, d_cntrec);
    cudaGetSymbolAddress((void**)&p_cs, d_cntsend);
    cudaGetSymbolAddress((void**)&p_w2t, d_w2t);

    cudaFuncSetAttribute(edge_gemm2_bf16, cudaFuncAttributeMaxDynamicSharedMemorySize, EDGE_SMEM);

    // 1. fused prep: derive + traj + W2^T + per-node lists
    prep_kernel<<<16 + ROWS_N + HH + 128, HH>>>(rel_rec, rel_send, p_recv, p_send,
                                                centers, W_traj, b_traj, n2e_W2, p_w2t, p_x,
                                                p_lr, p_ls, p_cr, p_cs, p_idr, p_ids);

    // 2. xTop/xBot (dual-output, double-buffered tf32)
    mma_gemm_v2<0,false,false><<<dim3(HH/64, ROWS_N/64, 2), 256>>>(
        p_x, nullptr, nullptr, nullptr, nullptr, nullptr,
        n2e_W1, n2e_W1 + HH*HH, nullptr, p_xTop, p_xBot, ROWS_N, HH, HH);

    // 3. (slot kept so edge remains 4th launch is no longer needed; order: prep, gemm, edge)
    // fused edge MLP v7 (3-stage cp.async, 1 sync/iter)
    edge_gemm2_bf16<<<ROWS_E/A_ROWS, 256, EDGE_SMEM>>>(p_xTop, p_xBot, n2e_b1,
                                                       p_w2t, n2e_b2,
                                                       p_recv, p_send, p_h2);

    // 4. scatter sums + edge BN stats
    scatter_kernel<<<2*ROWS_N, 256>>>(p_h2, p_lr, p_cr, p_ls, p_cs, p_inc, p_incsq, p_outg);
    stats_kernel<false><<<HH, 256>>>(p_inc, p_incsq, n2e_g, n2e_be, p_ae, p_ce, ROWS_N, (float)ROWS_E);

    // 5. node MLP
    mma_gemm_v2<1,true,false><<<dim3(HH/64, ROWS_N/64, 1), 256>>>(
        p_inc, p_outg, p_ae, p_ce, p_idr, p_ids,
        e2n_W1, e2n_W1, e2n_b1, p_nh1, p_nh1, ROWS_N, HH, 2*HH);
    mma_gemm_v2<0,true,false><<<dim3(HH/64, ROWS_N/64, 1), 256>>>(
        p_nh1, nullptr, nullptr, nullptr, nullptr, nullptr,
        e2n_W2, e2n_W2, e2n_b2, p_mraw, p_mraw, ROWS_N, HH, HH);
    stats_kernel<true><<<HH, 256>>>(p_mraw, nullptr, e2n_g, e2n_be, p_an, p_cn, ROWS_N, (float)ROWS_N);

    // 6. fuse + predict (+ fused cumsum epilogue)
    mma_gemm_v2<2,false,false><<<dim3(HH/64, ROWS_N/64, 1), 256>>>(
        p_x, p_mraw, p_an, p_cn, nullptr, nullptr,
        W_fuse, W_fuse, b_fuse, p_fused, p_fused, ROWS_N, HH, 2*HH);
    pred_pos_kernel<<<dim3(1, ROWS_N/64), 256>>>(p_fused, W_pred, b_pred, centers, out);
}

// round 14
// speedup vs baseline: 4.0624x; 1.0442x over previous
#include <cuda_runtime.h>
#include <cuda_bf16.h>
#include <math.h>
#include <stdint.h>

#define BB   16
#define NN   64
#define PREV 6
#define PRED 30
#define HH   256
#define EE   (NN*(NN-1))      // 4032
#define ROWS_E (BB*EE)        // 64512
#define ROWS_N (BB*NN)        // 1024

// ---------------- static scratch ----------------
__device__ float d_x[ROWS_N*HH];
__device__ float d_xTop[ROWS_N*HH];
__device__ float d_xBot[ROWS_N*HH];
__device__ __nv_bfloat16 d_h2[ROWS_E*HH];     // h2 bf16
__device__ float d_inc[ROWS_N*HH];
__device__ float d_incsq[ROWS_N*HH];
__device__ float d_outg[ROWS_N*HH];
__device__ float d_nh1[ROWS_N*HH];
__device__ float d_mraw[ROWS_N*HH];
__device__ float d_fused[ROWS_N*HH];
__device__ float d_ae[HH], d_ce[HH], d_an[HH], d_cn[HH];
__device__ int   d_recv[EE], d_send[EE];
__device__ int   d_listrec[NN*EE], d_listsend[NN*EE];
__device__ int   d_cntrec[NN], d_cntsend[NN];
__device__ float d_invdegrec[NN], d_invdegsend[NN];
__device__ __nv_bfloat16 d_w2t[HH*HH];   // W2^T in bf16: [n][k]

__device__ __forceinline__ float elu_f(float x)  { return x > 0.f ? x : (expf(x) - 1.f); }
__device__ __forceinline__ float elu_ff(float x) { return x > 0.f ? x : (__expf(x) - 1.f); }

__device__ __forceinline__ unsigned f2tf32(float x) {
    unsigned r;
    asm("cvt.rna.tf32.f32 %0, %1;" : "=r"(r) : "f"(x));
    return r;
}
__device__ __forceinline__ unsigned packbf2(float lo, float hi) {
    __nv_bfloat162 v = __floats2bfloat162_rn(lo, hi);
    return *reinterpret_cast<unsigned*>(&v);
}
__device__ __forceinline__ uint32_t smem_u32(const void* p) {
    uint32_t a;
    asm("{ .reg .u64 t; cvta.to.shared.u64 t, %1; cvt.u32.u64 %0, t; }" : "=r"(a) : "l"(p));
    return a;
}

#define LDSM4(r0,r1,r2,r3,addr) \
    asm volatile("ldmatrix.sync.aligned.m8n8.x4.shared.b16 {%0,%1,%2,%3}, [%4];" \
        : "=r"(r0), "=r"(r1), "=r"(r2), "=r"(r3) : "r"(addr))

#define CP_ASYNC16(dst, src) \
    asm volatile("cp.async.ca.shared.global [%0], [%1], 16;" :: "r"(dst), "l"(src) : "memory")
#define CP_COMMIT() asm volatile("cp.async.commit_group;" ::: "memory")
#define CP_WAIT(n)  asm volatile("cp.async.wait_group %0;" :: "n"(n) : "memory")

// ---------------- fused prep: derive + traj + W2^T + per-node lists ----------------
__global__ void prep_kernel(const float* __restrict__ rel_rec,
                            const float* __restrict__ rel_send,
                            int* __restrict__ recv_idx, int* __restrict__ send_idx,
                            const float* __restrict__ centers,
                            const float* __restrict__ W, const float* __restrict__ bias,
                            const float* __restrict__ W2, __nv_bfloat16* __restrict__ w2t,
                            float* __restrict__ x,
                            int* __restrict__ list_rec, int* __restrict__ list_send,
                            int* __restrict__ cnt_rec, int* __restrict__ cnt_send,
                            float* __restrict__ invdeg_rec, float* __restrict__ invdeg_send) {
    if (blockIdx.x < 16) {
        int e = blockIdx.x * 256 + threadIdx.x;
        if (e >= EE) return;
        int r = 0, s = 0; float br = -1.f, bs = -1.f;
        for (int n = 0; n < NN; n++) {
            float vr = rel_rec[e*NN + n];
            float vs = rel_send[e*NN + n];
            if (vr > br) { br = vr; r = n; }
            if (vs > bs) { bs = vs; s = n; }
        }
        recv_idx[e] = r; send_idx[e] = s;
        return;
    }
    if (blockIdx.x >= 1296) {
        int id = blockIdx.x - 1296;
        if (threadIdx.x >= 64) return;
        const bool isSend = id >= NN;
        const int n = id & (NN-1);
        const float* __restrict__ oneHot = (isSend ? rel_send : rel_rec);
        int* __restrict__ list = (isSend ? list_send : list_rec) + n*EE;
        const int t = threadIdx.x;
        const int CH = EE / 64;
        const int base = t * CH;
        int c = 0;
        for (int i = 0; i < CH; i++) c += (oneHot[(base+i)*NN + n] > 0.5f) ? 1 : 0;
        __shared__ int pre[64];
        pre[t] = c;
        __syncthreads();
        for (int off = 1; off < 64; off <<= 1) {
            int v = (t >= off) ? pre[t-off] : 0;
            __syncthreads();
            pre[t] += v;
            __syncthreads();
        }
        int offset = pre[t] - c;
        for (int i = 0; i < CH; i++) {
            int e = base + i;
            if (oneHot[e*NN + n] > 0.5f) list[offset++] = e;
        }
        if (t == 63) {
            int tot = pre[63];
            float iv = tot ? 1.f/(float)tot : 1.f;
            if (isSend) { cnt_send[n] = tot; invdeg_send[n] = iv; }
            else        { cnt_rec[n]  = tot; invdeg_rec[n]  = iv; }
        }
        return;
    }
    if (blockIdx.x >= 16 + ROWS_N) {
        int n = blockIdx.x - 16 - ROWS_N;
        int k = threadIdx.x;
        w2t[n*HH + k] = __float2bfloat16(W2[k*HH + n]);
        return;
    }
    int row = blockIdx.x - 16;
    int h = threadIdx.x;
    __shared__ float rp[PREV*2];
    if (h < PREV*2) {
        int p = h >> 1, c = h & 1;
        float v = 0.f;
        if (p > 0) v = centers[row*PREV*2 + p*2 + c] - centers[row*PREV*2 + (p-1)*2 + c];
        rp[h] = v;
    }
    __syncthreads();
    float acc = bias[h];
    #pragma unroll
    for (int k = 0; k < PREV*2; k++) acc += rp[k] * W[k*HH + h];
    x[row*HH + h] = acc;
}

// =======================================================================
// Small-GEMM v3: K-step 64, dynamic smem, register-prefetch double buffer.
// AMODE 0: A' = A0 (row stride K)
// AMODE 1: A' = [a*(inc*invDegR)+c , a*(outg*invDegS)+c]  (K=512)
// AMODE 2: A' = [x , a*mraw+c]                            (K=512)
// M mult of 64, N mult of 64 (N=256 at all call sites), K mult of 64.
// Smem: A[2][64][68] + B[2][64][72] floats = 71680 B.
// =======================================================================
#define GEMM_SMEM ((2*64*68 + 2*64*72)*4)

template<int AMODE, bool ELU>
__global__ __launch_bounds__(256)
void mma_gemm_v3(const float* __restrict__ A0, const float* __restrict__ A1,
                 const float* __restrict__ aVec, const float* __restrict__ cVec,
                 const float* __restrict__ invDegR, const float* __restrict__ invDegS,
                 const float* __restrict__ B0, const float* __restrict__ B1,
                 const float* __restrict__ bias,
                 float* __restrict__ C0, float* __restrict__ C1,
                 int M, int N, int K) {
    const float* __restrict__ Bm = (blockIdx.z == 0) ? B0 : B1;
    float* __restrict__ C = (blockIdx.z == 0) ? C0 : C1;

    extern __shared__ float gsm[];
    float* Asm = gsm;                       // [2][64][68]
    float* Bsm = gsm + 2*64*68;             // [2][64][72]

    const int tid  = threadIdx.x;
    const int lane = tid & 31;
    const int warp = tid >> 5;
    const int warpM = warp & 1;
    const int warpN = warp >> 1;
    const int g  = lane >> 2;
    const int t4 = lane & 3;
    const int row0 = blockIdx.y * 64;
    const int col0 = blockIdx.x * 64;

    // tasks: 1024 each for A (row,kquad) and B (k,nquad)
    int arow[4], akq[4], bkk[4], bq[4];
    #pragma unroll
    for (int it = 0; it < 4; it++) {
        int ta = it*256 + tid;
        akq[it] = ta & 15;  arow[it] = ta >> 4;
        bq[it]  = ta & 15;  bkk[it]  = ta >> 4;
    }

    float4 pa[4], pb[4];

    auto prefetch = [&](int k0) {
        #pragma unroll
        for (int it = 0; it < 4; it++) {
            int gk = k0 + akq[it]*4;
            if (AMODE == 0) {
                pa[it] = *reinterpret_cast<const float4*>(&A0[(long)(row0+arow[it])*K + gk]);
            } else {
                const float* src = (gk >= HH) ? A1 : A0;
                pa[it] = *reinterpret_cast<const float4*>(&src[(long)(row0+arow[it])*HH + (gk & (HH-1))]);
            }
            int c0 = col0 + bq[it]*4;
            pb[it] = *reinterpret_cast<const float4*>(&Bm[(long)(k0+bkk[it])*N + c0]);
        }
    };

    auto store = [&](int s, int k0) {
        #pragma unroll
        for (int it = 0; it < 4; it++) {
            int gk = k0 + akq[it]*4;
            float4 v = pa[it];
            if (AMODE == 1) {
                int col = gk & (HH-1);
                float invd = ((gk >= HH) ? invDegS : invDegR)[(row0+arow[it]) & (NN-1)];
                float4 a4 = *reinterpret_cast<const float4*>(&aVec[col]);
                float4 c4 = *reinterpret_cast<const float4*>(&cVec[col]);
                v.x = a4.x*(v.x*invd)+c4.x; v.y = a4.y*(v.y*invd)+c4.y;
                v.z = a4.z*(v.z*invd)+c4.z; v.w = a4.w*(v.w*invd)+c4.w;
            } else if (AMODE == 2) {
                if (gk >= HH) {
                    int col = gk & (HH-1);
                    float4 a4 = *reinterpret_cast<const float4*>(&aVec[col]);
                    float4 c4 = *reinterpret_cast<const float4*>(&cVec[col]);
                    v.x = a4.x*v.x+c4.x; v.y = a4.y*v.y+c4.y;
                    v.z = a4.z*v.z+c4.z; v.w = a4.w*v.w+c4.w;
                }
            }
            float* ap = &Asm[(s*64 + arow[it])*68 + akq[it]*4];
            reinterpret_cast<unsigned*>(ap)[0] = f2tf32(v.x);
            reinterpret_cast<unsigned*>(ap)[1] = f2tf32(v.y);
            reinterpret_cast<unsigned*>(ap)[2] = f2tf32(v.z);
            reinterpret_cast<unsigned*>(ap)[3] = f2tf32(v.w);

            float4 w = pb[it];
            float* bp = &Bsm[(s*64 + bkk[it])*72 + bq[it]*4];
            reinterpret_cast<unsigned*>(bp)[0] = f2tf32(w.x);
            reinterpret_cast<unsigned*>(bp)[1] = f2tf32(w.y);
            reinterpret_cast<unsigned*>(bp)[2] = f2tf32(w.z);
            reinterpret_cast<unsigned*>(bp)[3] = f2tf32(w.w);
        }
    };

    float acc[2][2][4] = {};
    const int nIter = K >> 6;

    prefetch(0);
    store(0, 0);
    __syncthreads();

    for (int i = 0; i < nIter; i++) {
        int cur = i & 1;
        if (i + 1 < nIter) prefetch((i+1) * 64);

        const unsigned* Ac = reinterpret_cast<const unsigned*>(&Asm[(cur*64)*68]);
        const unsigned* Bc = reinterpret_cast<const unsigned*>(&Bsm[(cur*64)*72]);

        #pragma unroll
        for (int ks = 0; ks < 64; ks += 8) {
            unsigned afr[2][4];
            #pragma unroll
            for (int ii = 0; ii < 2; ii++) {
                int r = warpM*32 + ii*16;
                afr[ii][0] = Ac[(r + g    )*68 + ks + t4    ];
                afr[ii][1] = Ac[(r + g + 8)*68 + ks + t4    ];
                afr[ii][2] = Ac[(r + g    )*68 + ks + t4 + 4];
                afr[ii][3] = Ac[(r + g + 8)*68 + ks + t4 + 4];
            }
            unsigned bfr[2][2];
            #pragma unroll
            for (int j = 0; j < 2; j++) {
                int nn = warpN*16 + j*8 + g;
                bfr[j][0] = Bc[(ks + t4    )*72 + nn];
                bfr[j][1] = Bc[(ks + t4 + 4)*72 + nn];
            }
            #pragma unroll
            for (int ii = 0; ii < 2; ii++)
                #pragma unroll
                for (int j = 0; j < 2; j++)
                    asm volatile(
                        "mma.sync.aligned.m16n8k8.row.col.f32.tf32.tf32.f32 "
                        "{%0,%1,%2,%3}, {%4,%5,%6,%7}, {%8,%9}, {%0,%1,%2,%3};"
                        : "+f"(acc[ii][j][0]), "+f"(acc[ii][j][1]),
                          "+f"(acc[ii][j][2]), "+f"(acc[ii][j][3])
                        : "r"(afr[ii][0]), "r"(afr[ii][1]), "r"(afr[ii][2]), "r"(afr[ii][3]),
                          "r"(bfr[j][0]), "r"(bfr[j][1]));
        }
        if (i + 1 < nIter) store(cur ^ 1, (i+1) * 64);
        __syncthreads();
    }

    #pragma unroll
    for (int i = 0; i < 2; i++) {
        int r = row0 + warpM*32 + i*16 + g;
        #pragma unroll
        for (int j = 0; j < 2; j++) {
            int c = col0 + warpN*16 + j*8 + t4*2;
            #pragma unroll
            for (int h = 0; h < 2; h++) {
                int cc = c + h;
                float bb = bias ? bias[cc] : 0.f;
                float v0 = acc[i][j][h]   + bb;
                float v1 = acc[i][j][2+h] + bb;
                if (ELU) { v0 = elu_f(v0); v1 = elu_f(v1); }
                C[(long)r*N + cc]     = v0;
                C[(long)(r+8)*N + cc] = v1;
            }
        }
    }
}

// =======================================================================
// Pred GEMM + cumsum epilogue (unchanged)
// =======================================================================
__global__ __launch_bounds__(256)
void pred_pos_kernel(const float* __restrict__ A0, const float* __restrict__ Bm,
                     const float* __restrict__ bias, const float* __restrict__ centers,
                     float* __restrict__ out) {
    const int N = PRED*2;
    const int K = HH;
    __shared__ unsigned Asm[64][36];
    __shared__ unsigned Bsm[32][72];
    __shared__ float Cs[64][64];
    const int tid  = threadIdx.x;
    const int lane = tid & 31;
    const int warp = tid >> 5;
    const int warpM = warp & 1;
    const int warpN = warp >> 1;
    const int g  = lane >> 2;
    const int t4 = lane & 3;
    const int row0 = blockIdx.y * 64;

    int arow[2], akq[2], bkk[2], bq[2];
    #pragma unroll
    for (int it = 0; it < 2; it++) {
        int ta = it*256 + tid;
        akq[it] = ta & 7;  arow[it] = ta >> 3;
        bkk[it] = ta >> 4; bq[it]  = ta & 15;
    }
    float4 pa[2], pb[2];
    #pragma unroll
    for (int it = 0; it < 2; it++) {
        pa[it] = *reinterpret_cast<const float4*>(&A0[(long)(row0+arow[it])*K + akq[it]*4]);
        int c0 = bq[it]*4;
        float4 v;
        v.x = (c0+0 < N) ? Bm[(long)bkk[it]*N + c0+0] : 0.f;
        v.y = (c0+1 < N) ? Bm[(long)bkk[it]*N + c0+1] : 0.f;
        v.z = (c0+2 < N) ? Bm[(long)bkk[it]*N + c0+2] : 0.f;
        v.w = (c0+3 < N) ? Bm[(long)bkk[it]*N + c0+3] : 0.f;
        pb[it] = v;
    }

    float acc[2][2][4] = {};
    for (int k0 = 0; k0 < K; k0 += 32) {
        #pragma unroll
        for (int it = 0; it < 2; it++) {
            float4 v = pa[it];
            Asm[arow[it]][akq[it]*4+0] = f2tf32(v.x);
            Asm[arow[it]][akq[it]*4+1] = f2tf32(v.y);
            Asm[arow[it]][akq[it]*4+2] = f2tf32(v.z);
            Asm[arow[it]][akq[it]*4+3] = f2tf32(v.w);
            float4 w = pb[it];
            Bsm[bkk[it]][bq[it]*4+0] = f2tf32(w.x);
            Bsm[bkk[it]][bq[it]*4+1] = f2tf32(w.y);
            Bsm[bkk[it]][bq[it]*4+2] = f2tf32(w.z);
            Bsm[bkk[it]][bq[it]*4+3] = f2tf32(w.w);
        }
        if (k0 + 32 < K) {
            int kn = k0 + 32;
            #pragma unroll
            for (int it = 0; it < 2; it++) {
                pa[it] = *reinterpret_cast<const float4*>(&A0[(long)(row0+arow[it])*K + kn + akq[it]*4]);
                int c0 = bq[it]*4;
                float4 v;
                v.x = (c0+0 < N) ? Bm[(long)(kn+bkk[it])*N + c0+0] : 0.f;
                v.y = (c0+1 < N) ? Bm[(long)(kn+bkk[it])*N + c0+1] : 0.f;
                v.z = (c0+2 < N) ? Bm[(long)(kn+bkk[it])*N + c0+2] : 0.f;
                v.w = (c0+3 < N) ? Bm[(long)(kn+bkk[it])*N + c0+3] : 0.f;
                pb[it] = v;
            }
        }
        __syncthreads();
        #pragma unroll
        for (int ks = 0; ks < 32; ks += 8) {
            unsigned afr[2][4];
            #pragma unroll
            for (int i = 0; i < 2; i++) {
                int r = warpM*32 + i*16;
                afr[i][0] = Asm[r + g    ][ks + t4    ];
                afr[i][1] = Asm[r + g + 8][ks + t4    ];
                afr[i][2] = Asm[r + g    ][ks + t4 + 4];
                afr[i][3] = Asm[r + g + 8][ks + t4 + 4];
            }
            unsigned bfr[2][2];
            #pragma unroll
            for (int j = 0; j < 2; j++) {
                int nn = warpN*16 + j*8 + g;
                bfr[j][0] = Bsm[ks + t4    ][nn];
                bfr[j][1] = Bsm[ks + t4 + 4][nn];
            }
            #pragma unroll
            for (int i = 0; i < 2; i++)
                #pragma unroll
                for (int j = 0; j < 2; j++)
                    asm volatile(
                        "mma.sync.aligned.m16n8k8.row.col.f32.tf32.tf32.f32 "
                        "{%0,%1,%2,%3}, {%4,%5,%6,%7}, {%8,%9}, {%0,%1,%2,%3};"
                        : "+f"(acc[i][j][0]), "+f"(acc[i][j][1]),
                          "+f"(acc[i][j][2]), "+f"(acc[i][j][3])
                        : "r"(afr[i][0]), "r"(afr[i][1]), "r"(afr[i][2]), "r"(afr[i][3]),
                          "r"(bfr[j][0]), "r"(bfr[j][1]));
        }
        __syncthreads();
    }

    #pragma unroll
    for (int i = 0; i < 2; i++) {
        int r = warpM*32 + i*16 + g;
        #pragma unroll
        for (int j = 0; j < 2; j++) {
            int c = warpN*16 + j*8 + t4*2;
            #pragma unroll
            for (int h = 0; h < 2; h++) {
                int cc = c + h;
                float bb = (cc < N) ? bias[cc] : 0.f;
                Cs[r][cc]   = acc[i][j][h]   + bb;
                Cs[r+8][cc] = acc[i][j][2+h] + bb;
            }
        }
    }
    __syncthreads();

    if (tid < 128) {
        int lrow = tid >> 1, dimc = tid & 1;
        int grow = row0 + lrow;
        float cur = centers[grow*PREV*2 + (PREV-1)*2 + dimc];
        float accum = 0.f;
        #pragma unroll
        for (int p = 0; p < PRED; p++) {
            float v = Cs[lrow][2*p + dimc];
            out[(long)grow*N + 2*p + dimc] = v;
            accum += v;
            out[(long)(ROWS_N)*N + (long)grow*N + 2*p + dimc] = accum + cur;
        }
    }
}

// =======================================================================
// Fused edge GEMM v7 (unchanged from R13 passing version)
// =======================================================================
#define A_ROWS   64
#define AK_PAD   264
#define A_BYTES  (A_ROWS*AK_PAD*2)        // 33792
#define B_BYTES  (3*128*40*2)             // 30720 (3 stages)
#define EDGE_SMEM (A_BYTES + B_BYTES + 1024)

__global__ __launch_bounds__(256, 3)
void edge_gemm2_bf16(const float* __restrict__ xTop, const float* __restrict__ xBot,
                     const float* __restrict__ b1,
                     const __nv_bfloat16* __restrict__ w2t, const float* __restrict__ b2,
                     const int* __restrict__ recv_idx, const int* __restrict__ send_idx,
                     __nv_bfloat16* __restrict__ h2) {
    extern __shared__ char smraw[];
    __nv_bfloat16* Afull = reinterpret_cast<__nv_bfloat16*>(smraw);
    __nv_bfloat16* Bsn   = reinterpret_cast<__nv_bfloat16*>(smraw + A_BYTES);
    int* topBase = reinterpret_cast<int*>(smraw + A_BYTES + B_BYTES);
    int* botBase = topBase + A_ROWS;

    const int tid  = threadIdx.x;
    const int lane = tid & 31;
    const int warp = tid >> 5;
    const int warpM = warp & 1;
    const int warpN = warp >> 1;
    const int row0 = blockIdx.x * A_ROWS;

    if (tid < A_ROWS) {
        int grow = row0 + tid;
        int b = grow / EE;
        int e = grow - b * EE;
        topBase[tid] = (b*NN + recv_idx[e]) * HH;
        botBase[tid] = (b*NN + send_idx[e]) * HH;
    }
    __syncthreads();

    {
        const int kq = tid & 63;
        const int rb = tid >> 6;
        const int kb = kq * 4;
        float4 bb = *reinterpret_cast<const float4*>(&b1[kb]);
        #pragma unroll
        for (int it = 0; it < 16; it++) {
            int row = it*4 + rb;
            float4 a  = *reinterpret_cast<const float4*>(&xTop[topBase[row] + kb]);
            float4 bv = *reinterpret_cast<const float4*>(&xBot[botBase[row] + kb]);
            unsigned p0 = packbf2(elu_ff(a.x + bv.x + bb.x), elu_ff(a.y + bv.y + bb.y));
            unsigned p1 = packbf2(elu_ff(a.z + bv.z + bb.z), elu_ff(a.w + bv.w + bb.w));
            *reinterpret_cast<uint2*>(&Afull[row*AK_PAD + kb]) = make_uint2(p0, p1);
        }
    }

    int bn[2], bkh[2];
    #pragma unroll
    for (int it = 0; it < 2; it++) {
        int task = it*256 + tid;
        bkh[it] = task & 3;
        bn[it]  = task >> 2;
    }

    const int lt  = lane >> 3;
    const int lrw = lane & 7;
    const int mrow0 = warpM * 32;
    const int ncol0 = warpN * 32;
    const uint32_t aBase = smem_u32(Afull);
    const uint32_t bBase0 = smem_u32(Bsn);
    const uint32_t BSTG = 128u * 40u * 2u;
    const uint32_t aLanePart = (uint32_t)(mrow0 + (lt & 1)*8 + lrw) * (AK_PAD*2u)
                             + (uint32_t)(lt >> 1) * 16u;
    const uint32_t bLanePart = (uint32_t)(ncol0 + lt*8 + lrw) * 80u;
    uint32_t dstPart[2];
    #pragma unroll
    for (int it = 0; it < 2; it++) dstPart[it] = (uint32_t)(bn[it]*80 + bkh[it]*16);

    __syncthreads();

    const int g  = lane >> 2;
    const int t4 = lane & 3;

    #pragma unroll 1
    for (int half = 0; half < 2; half++) {
        const int col0 = half * 128;
        const __nv_bfloat16* srcB[2];
        #pragma unroll
        for (int it = 0; it < 2; it++)
            srcB[it] = &w2t[(long)(col0 + bn[it])*HH + bkh[it]*8];

        #pragma unroll
        for (int s = 0; s < 2; s++) {
            #pragma unroll
            for (int it = 0; it < 2; it++)
                CP_ASYNC16(bBase0 + (uint32_t)s*BSTG + dstPart[it], srcB[it] + s*32);
            CP_COMMIT();
        }

        float acc[2][4][4] = {};

        #pragma unroll 1
        for (int i = 0; i < 8; i++) {
            const int stg = i - (i >= 3 ? 3 : 0) - (i >= 6 ? 3 : 0);
            if (i < 7) { CP_WAIT(1); } else { CP_WAIT(0); }
            __syncthreads();
            if (i + 2 < 8) {
                int s2 = (i+2) - ((i+2) >= 3 ? 3 : 0) - ((i+2) >= 6 ? 3 : 0);
                #pragma unroll
                for (int it = 0; it < 2; it++)
                    CP_ASYNC16(bBase0 + (uint32_t)s2*BSTG + dstPart[it], srcB[it] + (i+2)*32);
                CP_COMMIT();
            }

            const uint32_t aCur = aBase + aLanePart + (uint32_t)i * 64u;
            const uint32_t bCur = bBase0 + (uint32_t)stg * BSTG + bLanePart;

            #pragma unroll
            for (int ks = 0; ks < 32; ks += 16) {
                unsigned afr[2][4];
                #pragma unroll
                for (int ii = 0; ii < 2; ii++) {
                    LDSM4(afr[ii][0], afr[ii][1], afr[ii][2], afr[ii][3],
                          aCur + (uint32_t)ii*(16u*AK_PAD*2u) + (uint32_t)ks*2u);
                }
                unsigned bfr[4][2];
                #pragma unroll
                for (int kh = 0; kh < 2; kh++) {
                    unsigned t0, t1, t2, t3;
                    LDSM4(t0, t1, t2, t3,
                          bCur + (uint32_t)ks*2u + (uint32_t)kh*16u);
                    bfr[0][kh] = t0;
                    bfr[1][kh] = t1;
                    bfr[2][kh] = t2;
                    bfr[3][kh] = t3;
                }
                #pragma unroll
                for (int j = 0; j < 4; j++) {
                    #pragma unroll
                    for (int ii = 0; ii < 2; ii++)
                        asm volatile(
                            "mma.sync.aligned.m16n8k16.row.col.f32.bf16.bf16.f32 "
                            "{%0,%1,%2,%3}, {%4,%5,%6,%7}, {%8,%9}, {%0,%1,%2,%3};"
                            : "+f"(acc[ii][j][0]), "+f"(acc[ii][j][1]),
                              "+f"(acc[ii][j][2]), "+f"(acc[ii][j][3])
                            : "r"(afr[ii][0]), "r"(afr[ii][1]), "r"(afr[ii][2]), "r"(afr[ii][3]),
                              "r"(bfr[j][0]), "r"(bfr[j][1]));
                }
            }
        }

        #pragma unroll
        for (int i = 0; i < 2; i++) {
            int r_lo = row0 + mrow0 + i*16 + g;
            #pragma unroll
            for (int j = 0; j < 4; j++) {
                int c = col0 + ncol0 + j*8 + t4*2;
                float bb0 = b2[c], bb1 = b2[c+1];
                *reinterpret_cast<unsigned*>(&h2[(long)r_lo*HH + c]) =
                    packbf2(elu_ff(acc[i][j][0] + bb0), elu_ff(acc[i][j][1] + bb1));
                *reinterpret_cast<unsigned*>(&h2[(long)(r_lo+8)*HH + c]) =
                    packbf2(elu_ff(acc[i][j][2] + bb0), elu_ff(acc[i][j][3] + bb1));
            }
        }
        __syncthreads();
    }
}

// ---------------- vectorized per-node gather sums (bf16 h2) ----------------
__global__ void scatter_kernel(const __nv_bfloat16* __restrict__ h2,
                               const int* __restrict__ list_rec, const int* __restrict__ cnt_rec,
                               const int* __restrict__ list_send, const int* __restrict__ cnt_send,
                               float* __restrict__ inc_raw, float* __restrict__ sq_part,
                               float* __restrict__ out_raw) {
    int id = blockIdx.x;
    bool isOut = id >= ROWS_N;
    int bn = id & (ROWS_N-1);
    int b = bn >> 6, n = bn & 63;
    const int tid = threadIdx.x;
    const int c4 = tid & 63;
    const int rs = tid >> 6;
    const int* __restrict__ list = (isOut ? list_send : list_rec) + n*EE;
    const int cnt = (isOut ? cnt_send : cnt_rec)[n];

    float4 acc = make_float4(0.f, 0.f, 0.f, 0.f);
    float4 asq = make_float4(0.f, 0.f, 0.f, 0.f);
    for (int k = rs; k < cnt; k += 4) {
        int e = list[k];
        uint2 u = *reinterpret_cast<const uint2*>(&h2[(long)(b*EE + e)*HH + c4*4]);
        __nv_bfloat162 p0 = *reinterpret_cast<__nv_bfloat162*>(&u.x);
        __nv_bfloat162 p1 = *reinterpret_cast<__nv_bfloat162*>(&u.y);
        float v0 = __bfloat162float(p0.x), v1 = __bfloat162float(p0.y);
        float v2 = __bfloat162float(p1.x), v3 = __bfloat162float(p1.y);
        acc.x += v0; acc.y += v1; acc.z += v2; acc.w += v3;
        if (!isOut) {
            asq.x += v0*v0; asq.y += v1*v1; asq.z += v2*v2; asq.w += v3*v3;
        }
    }
    __shared__ float4 sa[4][64];
    __shared__ float4 sq[4][64];
    sa[rs][c4] = acc;
    if (!isOut) sq[rs][c4] = asq;
    __syncthreads();
    if (rs == 0) {
        float4 t = sa[0][c4];
        #pragma unroll
        for (int r = 1; r < 4; r++) {
            float4 u = sa[r][c4];
            t.x += u.x; t.y += u.y; t.z += u.z; t.w += u.w;
        }
        if (!isOut) {
            float4 s = sq[0][c4];
            #pragma unroll
            for (int r = 1; r < 4; r++) {
                float4 u = sq[r][c4];
                s.x += u.x; s.y += u.y; s.z += u.z; s.w += u.w;
            }
            *reinterpret_cast<float4*>(&inc_raw[bn*HH + c4*4]) = t;
            *reinterpret_cast<float4*>(&sq_part[bn*HH + c4*4]) = s;
        } else {
            *reinterpret_cast<float4*>(&out_raw[bn*HH + c4*4]) = t;
        }
    }
}

// ---------------- BN stats -> affine (a,c) ----------------
template<bool SRC_SQ>
__global__ void stats_kernel(const float* __restrict__ sum_part, const float* __restrict__ sq_part,
                             const float* __restrict__ gamma, const float* __restrict__ beta,
                             float* __restrict__ a, float* __restrict__ c,
                             int nrows, float count) {
    int h = blockIdx.x;
    float s = 0.f, sq = 0.f;
    for (int r = threadIdx.x; r < nrows; r += 256) {
        float v = sum_part[r*HH + h];
        s += v;
        if (SRC_SQ) sq += v*v; else sq += sq_part[r*HH + h];
    }
    __shared__ float ss[256], ssq[256];
    ss[threadIdx.x] = s; ssq[threadIdx.x] = sq;
    __syncthreads();
    for (int st = 128; st > 0; st >>= 1) {
        if (threadIdx.x < st) { ss[threadIdx.x] += ss[threadIdx.x+st]; ssq[threadIdx.x] += ssq[threadIdx.x+st]; }
        __syncthreads();
    }
    if (threadIdx.x == 0) {
        float mu = ss[0] / count;
        float var = ssq[0] / count - mu*mu;
        float av = gamma[h] * rsqrtf(var + 1e-5f);
        a[h] = av;
        c[h] = beta[h] - mu * av;
    }
}

// ---------------- launcher ----------------
extern "C" void kernel_launch(void* const* d_in, const int* in_sizes, int n_in,
                              void* d_out, int out_size) {
    const float* centers  = (const float*)d_in[0];
    const float* rel_rec  = (const float*)d_in[1];
    const float* rel_send = (const float*)d_in[2];
    const float* W_traj   = (const float*)d_in[3];
    const float* b_traj   = (const float*)d_in[4];
    const float* n2e_W1   = (const float*)d_in[5];
    const float* n2e_b1   = (const float*)d_in[6];
    const float* n2e_W2   = (const float*)d_in[7];
    const float* n2e_b2   = (const float*)d_in[8];
    const float* n2e_g    = (const float*)d_in[9];
    const float* n2e_be   = (const float*)d_in[10];
    const float* e2n_W1   = (const float*)d_in[11];
    const float* e2n_b1   = (const float*)d_in[12];
    const float* e2n_W2   = (const float*)d_in[13];
    const float* e2n_b2   = (const float*)d_in[14];
    const float* e2n_g    = (const float*)d_in[15];
    const float* e2n_be   = (const float*)d_in[16];
    const float* W_fuse   = (const float*)d_in[17];
    const float* b_fuse   = (const float*)d_in[18];
    const float* W_pred   = (const float*)d_in[19];
    const float* b_pred   = (const float*)d_in[20];
    float* out = (float*)d_out;

    float *p_x, *p_xTop, *p_xBot, *p_inc, *p_incsq, *p_outg;
    float *p_nh1, *p_mraw, *p_fused;
    float *p_ae, *p_ce, *p_an, *p_cn, *p_idr, *p_ids;
    int *p_recv, *p_send, *p_lr, *p_ls, *p_cr, *p_cs;
    __nv_bfloat16 *p_w2t, *p_h2;
    cudaGetSymbolAddress((void**)&p_x, d_x);
    cudaGetSymbolAddress((void**)&p_xTop, d_xTop);
    cudaGetSymbolAddress((void**)&p_xBot, d_xBot);
    cudaGetSymbolAddress((void**)&p_h2, d_h2);
    cudaGetSymbolAddress((void**)&p_inc, d_inc);
    cudaGetSymbolAddress((void**)&p_incsq, d_incsq);
    cudaGetSymbolAddress((void**)&p_outg, d_outg);
    cudaGetSymbolAddress((void**)&p_nh1, d_nh1);
    cudaGetSymbolAddress((void**)&p_mraw, d_mraw);
    cudaGetSymbolAddress((void**)&p_fused, d_fused);
    cudaGetSymbolAddress((void**)&p_ae, d_ae);
    cudaGetSymbolAddress((void**)&p_ce, d_ce);
    cudaGetSymbolAddress((void**)&p_an, d_an);
    cudaGetSymbolAddress((void**)&p_cn, d_cn);
    cudaGetSymbolAddress((void**)&p_idr, d_invdegrec);
    cudaGetSymbolAddress((void**)&p_ids, d_invdegsend);
    cudaGetSymbolAddress((void**)&p_recv, d_recv);
    cudaGetSymbolAddress((void**)&p_send, d_send);
    cudaGetSymbolAddress((void**)&p_lr, d_listrec);
    cudaGetSymbolAddress((void**)&p_ls, d_listsend);
    cudaGetSymbolAddress((void**)&p_cr, d_cntrec);
    cudaGetSymbolAddress((void**)&p_cs, d_cntsend);
    cudaGetSymbolAddress((void**)&p_w2t, d_w2t);

    cudaFuncSetAttribute(edge_gemm2_bf16, cudaFuncAttributeMaxDynamicSharedMemorySize, EDGE_SMEM);
    cudaFuncSetAttribute(mma_gemm_v3<0,false>, cudaFuncAttributeMaxDynamicSharedMemorySize, GEMM_SMEM);
    cudaFuncSetAttribute(mma_gemm_v3<1,true>,  cudaFuncAttributeMaxDynamicSharedMemorySize, GEMM_SMEM);
    cudaFuncSetAttribute(mma_gemm_v3<0,true>,  cudaFuncAttributeMaxDynamicSharedMemorySize, GEMM_SMEM);
    cudaFuncSetAttribute(mma_gemm_v3<2,false>, cudaFuncAttributeMaxDynamicSharedMemorySize, GEMM_SMEM);

    // 1. fused prep: derive + traj + W2^T + per-node lists
    prep_kernel<<<16 + ROWS_N + HH + 128, HH>>>(rel_rec, rel_send, p_recv, p_send,
                                                centers, W_traj, b_traj, n2e_W2, p_w2t, p_x,
                                                p_lr, p_ls, p_cr, p_cs, p_idr, p_ids);

    // 2. xTop/xBot (dual-output, K-step 64)
    mma_gemm_v3<0,false><<<dim3(HH/64, ROWS_N/64, 2), 256, GEMM_SMEM>>>(
        p_x, nullptr, nullptr, nullptr, nullptr, nullptr,
        n2e_W1, n2e_W1 + HH*HH, nullptr, p_xTop, p_xBot, ROWS_N, HH, HH);

    // 3. fused edge MLP v7
    edge_gemm2_bf16<<<ROWS_E/A_ROWS, 256, EDGE_SMEM>>>(p_xTop, p_xBot, n2e_b1,
                                                       p_w2t, n2e_b2,
                                                       p_recv, p_send, p_h2);

    // 4. scatter sums + edge BN stats
    scatter_kernel<<<2*ROWS_N, 256>>>(p_h2, p_lr, p_cr, p_ls, p_cs, p_inc, p_incsq, p_outg);
    stats_kernel<false><<<HH, 256>>>(p_inc, p_incsq, n2e_g, n2e_be, p_ae, p_ce, ROWS_N, (float)ROWS_E);

    // 5. node MLP (K-step 64)
    mma_gemm_v3<1,true><<<dim3(HH/64, ROWS_N/64, 1), 256, GEMM_SMEM>>>(
        p_inc, p_outg, p_ae, p_ce, p_idr, p_ids,
        e2n_W1, e2n_W1, e2n_b1, p_nh1, p_nh1, ROWS_N, HH, 2*HH);
    mma_gemm_v3<0,true><<<dim3(HH/64, ROWS_N/64, 1), 256, GEMM_SMEM>>>(
        p_nh1, nullptr, nullptr, nullptr, nullptr, nullptr,
        e2n_W2, e2n_W2, e2n_b2, p_mraw, p_mraw, ROWS_N, HH, HH);
    stats_kernel<true><<<HH, 256>>>(p_mraw, nullptr, e2n_g, e2n_be, p_an, p_cn, ROWS_N, (float)ROWS_N);

    // 6. fuse + predict (+ fused cumsum epilogue)
    mma_gemm_v3<2,false><<<dim3(HH/64, ROWS_N/64, 1), 256, GEMM_SMEM>>>(
        p_x, p_mraw, p_an, p_cn, nullptr, nullptr,
        W_fuse, W_fuse, b_fuse, p_fused, p_fused, ROWS_N, HH, 2*HH);
    pred_pos_kernel<<<dim3(1, ROWS_N/64), 256>>>(p_fused, W_pred, b_pred, centers, out);
}